// round 6
// baseline (speedup 1.0000x reference)
#include <cuda_runtime.h>
#include <cuda_bf16.h>
#include <math.h>
#include <stdint.h>

// Problem constants
#define B_    128
#define S_    256
#define D_    1536
#define DIN_  768
#define NH_   8
#define DH_   192
#define FF_   2048
#define BS_   (B_*S_)   // 32768
#define KP_   3072      // hi||lo width = 2*D_

// ---------------- scratch (device globals; no cudaMalloc allowed) -------------
__device__ float g_t0 [B_*D_];
__device__ float g_v  [B_*D_];
__device__ float g_sa [B_*D_];
__device__ float g_t1 [B_*D_];
__device__ float g_qp [B_*D_];
__device__ float g_g  [B_*NH_*D_];
__device__ float g_scores[B_*NH_*S_];
__device__ float g_mt [B_*NH_*D_];
__device__ float g_o  [B_*D_];
__device__ float g_ca [B_*D_];
__device__ float g_t2 [B_*D_];
__device__ float g_h1 [B_*FF_];
__device__ float g_ff [B_*D_];
__device__ float g_t3 [B_*D_];
__device__ float g_xsq[B_*D_];
__device__ float g_qp2[B_*D_];
__device__ float g_qt [B_*D_];
__device__ float g_S  [(size_t)2*B_*BS_];
__device__ float g_nm [B_*S_];
__device__ float g_nx [B_];
__device__ float g_part[1600*1024];                 // K-split partials
__device__ __nv_bfloat16 g_mb[(size_t)BS_*KP_];     // memory hi||lo bf16
__device__ __nv_bfloat16 g_ab[256*KP_];             // A hi||lo bf16

// =================== common mma.sync macros =====================================
#define LDSM4(R0,R1,R2,R3,ADDR) \
    asm volatile("ldmatrix.sync.aligned.m8n8.x4.shared.b16 {%0,%1,%2,%3}, [%4];" \
        : "=r"(R0),"=r"(R1),"=r"(R2),"=r"(R3) : "r"(ADDR))
#define MMA16816(D,A,B0,B1) \
    asm volatile("mma.sync.aligned.m16n8k16.row.col.f32.bf16.bf16.f32 " \
        "{%0,%1,%2,%3}, {%4,%5,%6,%7}, {%8,%9}, {%0,%1,%2,%3};" \
        : "+f"((D)[0]),"+f"((D)[1]),"+f"((D)[2]),"+f"((D)[3]) \
        : "r"((A)[0]),"r"((A)[1]),"r"((A)[2]),"r"((A)[3]),"r"(B0),"r"(B1))

// =================== tensor small GEMM: C = A(128,K) @ W(N,K)^T + bias ==========
// bf16 3-product split done in-kernel (fp32 loads -> hi/lo bf16 smem).
// Block: 256 thr, tile 128(M) x 64(N), BK=32 fp32. grid = (N/64, nz).
#define TLD 40   // smem row stride in bf16 elems (80B) -> conflict-free ldmatrix

__global__ void __launch_bounds__(256) gemm_nt_tc(
    const float* __restrict__ A, int lda, long long strideA,
    const float* __restrict__ W, int ldw, long long strideW,
    const float* __restrict__ bias, int strideBias,
    float* __restrict__ C, int ldc, long long strideC,
    int K, int relu)
{
    extern __shared__ __nv_bfloat16 sm[];
    __nv_bfloat16* sAh = sm;                        // [2][128*TLD]
    __nv_bfloat16* sAl = sAh + 2*128*TLD;           // [2][128*TLD]
    __nv_bfloat16* sWh = sAl + 2*128*TLD;           // [2][ 64*TLD]
    __nv_bfloat16* sWl = sWh + 2*64*TLD;            // [2][ 64*TLD]

    const int z = blockIdx.y;
    A += (long long)z*strideA;
    W += (long long)z*strideW;
    C += (long long)z*strideC;
    if (bias) bias += (long long)z*strideBias;

    const int tid = threadIdx.x;
    const int warp = tid>>5, lane = tid&31;
    const int wm = warp>>1, wn = warp&1;            // 4 x 2 warps -> 32x32 per warp
    const int bn = blockIdx.x*64;

    float acc[2][4][4];
    #pragma unroll
    for (int i=0;i<2;i++)
        #pragma unroll
        for (int j=0;j<4;j++)
            #pragma unroll
            for (int c=0;c<4;c++) acc[i][j][c]=0.f;

    const int lr  = tid>>3;          // base row (A: +256i/8)
    const int lc4 = tid&7;           // float4 column

    float4 ra[4], rw[2];
    #define LOADG(IT) do {                                                    \
        int k0=(IT)*32;                                                       \
        _Pragma("unroll")                                                     \
        for (int i=0;i<4;i++)                                                 \
            ra[i] = *(const float4*)(A + (size_t)(lr+i*32)*lda + k0 + lc4*4); \
        _Pragma("unroll")                                                     \
        for (int i=0;i<2;i++)                                                 \
            rw[i] = *(const float4*)(W + (size_t)(bn+lr+i*32)*ldw + k0 + lc4*4);\
    } while(0)

    #define CVT_ST(DSTH,DSTL,V,ROW) do {                                     \
        __align__(8) __nv_bfloat16 hh[4], ll[4];                              \
        float ff4[4] = {(V).x,(V).y,(V).z,(V).w};                             \
        _Pragma("unroll")                                                     \
        for (int c=0;c<4;c++) {                                               \
            hh[c] = __float2bfloat16(ff4[c]);                                 \
            ll[c] = __float2bfloat16(ff4[c] - __bfloat162float(hh[c]));       \
        }                                                                     \
        *(uint64_t*)((DSTH) + (ROW)*TLD + lc4*4) = *(uint64_t*)hh;            \
        *(uint64_t*)((DSTL) + (ROW)*TLD + lc4*4) = *(uint64_t*)ll;            \
    } while(0)

    const int nIter = K/32;
    LOADG(0);
    for (int it=0; it<nIter; it++) {
        const int b = it & 1;
        __nv_bfloat16* ah = sAh + b*128*TLD;
        __nv_bfloat16* al = sAl + b*128*TLD;
        __nv_bfloat16* wh = sWh + b*64*TLD;
        __nv_bfloat16* wl = sWl + b*64*TLD;
        #pragma unroll
        for (int i=0;i<4;i++) CVT_ST(ah, al, ra[i], lr + i*32);
        #pragma unroll
        for (int i=0;i<2;i++) CVT_ST(wh, wl, rw[i], lr + i*32);
        if (it+1 < nIter) LOADG(it+1);
        __syncthreads();
        #pragma unroll
        for (int kk=0; kk<2; kk++) {
            const int kb = kk*16;
            uint32_t fah[2][4], fal[2][4], fbh[4][2], fbl[4][2];
            #pragma unroll
            for (int mf=0; mf<2; mf++) {
                int row = wm*32 + mf*16 + (lane&15);
                int ko  = kb + ((lane>>4)<<3);
                uint32_t adh = (uint32_t)__cvta_generic_to_shared(&ah[row*TLD + ko]);
                uint32_t adl = (uint32_t)__cvta_generic_to_shared(&al[row*TLD + ko]);
                LDSM4(fah[mf][0],fah[mf][1],fah[mf][2],fah[mf][3], adh);
                LDSM4(fal[mf][0],fal[mf][1],fal[mf][2],fal[mf][3], adl);
            }
            #pragma unroll
            for (int p=0; p<2; p++) {
                int nrow = wn*32 + p*16 + ((lane>>4)<<3) + (lane&7);
                int ko   = kb + (((lane>>3)&1)<<3);
                uint32_t adh = (uint32_t)__cvta_generic_to_shared(&wh[nrow*TLD + ko]);
                uint32_t adl = (uint32_t)__cvta_generic_to_shared(&wl[nrow*TLD + ko]);
                LDSM4(fbh[2*p][0],fbh[2*p][1],fbh[2*p+1][0],fbh[2*p+1][1], adh);
                LDSM4(fbl[2*p][0],fbl[2*p][1],fbl[2*p+1][0],fbl[2*p+1][1], adl);
            }
            #pragma unroll
            for (int mf=0; mf<2; mf++)
                #pragma unroll
                for (int nf=0; nf<4; nf++) {
                    MMA16816(acc[mf][nf], fah[mf], fbh[nf][0], fbh[nf][1]);
                    MMA16816(acc[mf][nf], fah[mf], fbl[nf][0], fbl[nf][1]);
                    MMA16816(acc[mf][nf], fal[mf], fbh[nf][0], fbh[nf][1]);
                }
        }
        // single sync per iter: next STORE targets the other buffer
        if (it+1 < nIter) { /* fallthrough; sync happens at next iter via store order */ }
        __syncthreads();
    }
    // epilogue
    #pragma unroll
    for (int mf=0; mf<2; mf++) {
        int m0 = wm*32 + mf*16 + (lane>>2);
        #pragma unroll
        for (int nf=0; nf<4; nf++) {
            int n = bn + wn*32 + nf*8 + ((lane&3)<<1);
            float b0 = bias ? bias[n] : 0.f, b1 = bias ? bias[n+1] : 0.f;
            float v0 = acc[mf][nf][0]+b0, v1 = acc[mf][nf][1]+b1;
            float v2 = acc[mf][nf][2]+b0, v3 = acc[mf][nf][3]+b1;
            if (relu){ v0=fmaxf(v0,0.f); v1=fmaxf(v1,0.f); v2=fmaxf(v2,0.f); v3=fmaxf(v3,0.f); }
            *(float2*)&C[(size_t)m0*ldc + n]     = make_float2(v0,v1);
            *(float2*)&C[(size_t)(m0+8)*ldc + n] = make_float2(v2,v3);
        }
    }
}
#define SMEM_NTTC ((2*128*TLD + 2*128*TLD + 2*64*TLD + 2*64*TLD)*2)

// =================== fp32 gemm_nn (kept for gg / qt) + K-split reduce ===========
template<int BM,int BN,int BK,int TM,int TN>
__global__ void __launch_bounds__(256) gemm_nn(
    const float* __restrict__ A, int lda, long long strideA,
    const float* __restrict__ W, int ldw, long long strideW,
    const float* __restrict__ bias, int strideBias,
    float* __restrict__ C, int ldc, long long strideC,
    int K, int KS, float* __restrict__ partial)
{
    const int zb = blockIdx.z / KS, chunk = blockIdx.z % KS;
    const int Kc = K / KS;
    A += (long long)zb*strideA + chunk*Kc;
    W += (long long)zb*strideW + (size_t)chunk*Kc*ldw;
    C += (long long)zb*strideC;
    if (bias) bias += (long long)zb*strideBias;

    __shared__ float sA[BK][BM];
    __shared__ float sW[BK][BN];
    const int tid = threadIdx.x;
    const int bm = blockIdx.y*BM, bn = blockIdx.x*BN;
    const int tx = tid % (BN/TN), ty = tid / (BN/TN);
    float acc[TM][TN];
    #pragma unroll
    for (int i=0;i<TM;i++)
        #pragma unroll
        for (int j=0;j<TN;j++) acc[i][j]=0.f;

    for (int k0=0;k0<Kc;k0+=BK) {
        for (int i=tid;i<BM*(BK/4);i+=256) {
            int r=i/(BK/4), kv=i%(BK/4);
            float4 v=*(const float4*)(A+(size_t)(bm+r)*lda + k0 + kv*4);
            sA[kv*4+0][r]=v.x; sA[kv*4+1][r]=v.y; sA[kv*4+2][r]=v.z; sA[kv*4+3][r]=v.w;
        }
        for (int i=tid;i<BK*(BN/4);i+=256) {
            int kk=i/(BN/4), nv=i%(BN/4);
            *(float4*)&sW[kk][nv*4] = *(const float4*)(W+(size_t)(k0+kk)*ldw + bn + nv*4);
        }
        __syncthreads();
        #pragma unroll
        for (int kk=0;kk<BK;kk++) {
            float a[TM], w[TN];
            #pragma unroll
            for (int i=0;i<TM;i+=4) *(float4*)&a[i] = *(const float4*)&sA[kk][ty*TM+i];
            #pragma unroll
            for (int j=0;j<TN;j+=4) *(float4*)&w[j] = *(const float4*)&sW[kk][tx*TN+j];
            #pragma unroll
            for (int i=0;i<TM;i++)
                #pragma unroll
                for (int j=0;j<TN;j++) acc[i][j] = fmaf(a[i], w[j], acc[i][j]);
        }
        __syncthreads();
    }
    if (partial) {
        const int Mtot = gridDim.y*BM, Ntot = gridDim.x*BN;
        #pragma unroll
        for (int i=0;i<TM;i++) {
            int m = bm + ty*TM + i;
            #pragma unroll
            for (int j=0;j<TN;j+=4)
                *(float4*)&partial[((size_t)blockIdx.z*Mtot + m)*Ntot + bn + tx*TN + j]
                    = *(float4*)&acc[i][j];
        }
    } else {
        #pragma unroll
        for (int i=0;i<TM;i++) {
            int gm = bm + ty*TM + i;
            #pragma unroll
            for (int j=0;j<TN;j++) {
                int gn = bn + tx*TN + j;
                C[(size_t)gm*ldc + gn] = acc[i][j] + (bias ? bias[gn] : 0.f);
            }
        }
    }
}

__global__ void __launch_bounds__(256) reduce_ks(
    const float* __restrict__ partial, const float* __restrict__ bias, int strideBias,
    float* __restrict__ C, int ldc, long long strideC,
    int Mtot, int Ntot, int KS, int relu)
{
    const int zb = blockIdx.y;
    int idx = blockIdx.x*256 + threadIdx.x;
    if (idx >= Mtot*Ntot) return;
    int m = idx / Ntot, n = idx % Ntot;
    float s = 0.f;
    for (int c=0;c<KS;c++)
        s += partial[((size_t)(zb*KS+c)*Mtot + m)*Ntot + n];
    if (bias) s += bias[(size_t)zb*strideBias + n];
    if (relu) s = fmaxf(s, 0.f);
    C[(size_t)zb*strideC + (size_t)m*ldc + n] = s;
}

// =================== bf16 split conversion ======================================
__global__ void __launch_bounds__(256) conv_mem_kernel(const float* __restrict__ mem)
{
    const int row = blockIdx.x*8 + (threadIdx.x>>5);
    const int lane = threadIdx.x&31;
    const float* p = mem + (size_t)row*D_;
    __nv_bfloat16* oh = g_mb + (size_t)row*KP_;
    float ss = 0.f;
    #pragma unroll
    for (int i=0;i<12;i++) {
        int e = lane*4 + i*128;
        float4 v = *(const float4*)(p+e);
        ss += v.x*v.x + v.y*v.y + v.z*v.z + v.w*v.w;
        __align__(8) __nv_bfloat16 h[4], l[4];
        float f[4] = {v.x,v.y,v.z,v.w};
        #pragma unroll
        for (int c=0;c<4;c++) {
            h[c] = __float2bfloat16(f[c]);
            l[c] = __float2bfloat16(f[c] - __bfloat162float(h[c]));
        }
        *(uint64_t*)(oh + e)       = *(uint64_t*)h;
        *(uint64_t*)(oh + D_ + e)  = *(uint64_t*)l;
    }
    for (int o=16;o;o>>=1) ss += __shfl_xor_sync(~0u, ss, o);
    if (lane==0) g_nm[row] = sqrtf(ss);
}

__global__ void __launch_bounds__(256) conv_a_kernel()
{
    const int row = blockIdx.x*8 + (threadIdx.x>>5);
    const int lane = threadIdx.x&31;
    const float sc = (row < B_) ? rsqrtf((float)D_) : 1.0f;
    const float* p = (row < B_) ? (g_qt + (size_t)row*D_) : (g_xsq + (size_t)(row-B_)*D_);
    __nv_bfloat16* oh = g_ab + (size_t)row*KP_;
    #pragma unroll
    for (int i=0;i<12;i++) {
        int e = lane*4 + i*128;
        float4 v = *(const float4*)(p+e);
        float f[4] = {v.x*sc, v.y*sc, v.z*sc, v.w*sc};
        __align__(8) __nv_bfloat16 h[4], l[4];
        #pragma unroll
        for (int c=0;c<4;c++) {
            h[c] = __float2bfloat16(f[c]);
            l[c] = __float2bfloat16(f[c] - __bfloat162float(h[c]));
        }
        *(uint64_t*)(oh + e)      = *(uint64_t*)h;
        *(uint64_t*)(oh + D_ + e) = *(uint64_t*)l;
    }
}

// =================== big mma.sync GEMM (proven round-4 version) =================
#define SLD 40
#define SEGC 48

__global__ void __launch_bounds__(256) bigmm_kernel()
{
    __shared__ __align__(16) __nv_bfloat16 sA[2][128*SLD];
    __shared__ __align__(16) __nv_bfloat16 sB[2][128*SLD];
    const int tid = threadIdx.x;
    const int warp = tid>>5, lane = tid&31;
    const int wm = warp>>2, wn = warp&3;
    const int nbase = blockIdx.x*128, mbase = blockIdx.y*128;

    float acc[4][4][4];
    #pragma unroll
    for (int i=0;i<4;i++)
        #pragma unroll
        for (int j=0;j<4;j++)
            #pragma unroll
            for (int c=0;c<4;c++) acc[i][j][c]=0.f;

    const int r0 = tid>>1;
    const int seg0 = (tid&1)*2;

    #define LOAD_TILES(BUF,KC) do {                                              \
        int seg_ = (KC)/SEGC;                                                     \
        int k0_  = ((KC)%SEGC)*32;                                                \
        int aOff_ = (seg_==2) ? D_ : 0;                                           \
        int bOff_ = (seg_==1) ? D_ : 0;                                           \
        _Pragma("unroll")                                                        \
        for (int i=0;i<2;i++) {                                                  \
            int seg = seg0 + i;                                                  \
            uint32_t sa_ = (uint32_t)__cvta_generic_to_shared(                   \
                &sA[BUF][r0*SLD + seg*8]);                                       \
            const void* ga_ = g_ab + (size_t)(mbase+r0)*KP_ + aOff_ + k0_ + seg*8;\
            asm volatile("cp.async.ca.shared.global [%0], [%1], 16;"             \
                :: "r"(sa_), "l"(ga_));                                          \
            uint32_t sb_ = (uint32_t)__cvta_generic_to_shared(                   \
                &sB[BUF][r0*SLD + seg*8]);                                       \
            const void* gb_ = g_mb + (size_t)(nbase+r0)*KP_ + bOff_ + k0_ + seg*8;\
            asm volatile("cp.async.ca.shared.global [%0], [%1], 16;"             \
                :: "r"(sb_), "l"(gb_));                                          \
        }                                                                        \
        asm volatile("cp.async.commit_group;");                                  \
    } while(0)

    LOAD_TILES(0, 0);
    const int KC = 3*SEGC;
    for (int kc=0; kc<KC; kc++) {
        int buf = kc & 1;
        asm volatile("cp.async.wait_group 0;");
        __syncthreads();
        if (kc+1 < KC) LOAD_TILES(buf^1, kc+1);
        #pragma unroll
        for (int kk=0; kk<2; kk++) {
            const int kb = kk*16;
            uint32_t a[4][4], b[4][2];
            #pragma unroll
            for (int mf=0; mf<4; mf++) {
                int row = wm*64 + mf*16 + (lane&15);
                int ko  = kb + ((lane>>4)<<3);
                uint32_t ad = (uint32_t)__cvta_generic_to_shared(&sA[buf][row*SLD + ko]);
                LDSM4(a[mf][0],a[mf][1],a[mf][2],a[mf][3], ad);
            }
            #pragma unroll
            for (int p=0; p<2; p++) {
                int nrow = wn*32 + p*16 + ((lane>>4)<<3) + (lane&7);
                int ko   = kb + (((lane>>3)&1)<<3);
                uint32_t ad = (uint32_t)__cvta_generic_to_shared(&sB[buf][nrow*SLD + ko]);
                LDSM4(b[2*p][0],b[2*p][1],b[2*p+1][0],b[2*p+1][1], ad);
            }
            #pragma unroll
            for (int mf=0; mf<4; mf++)
                #pragma unroll
                for (int nf=0; nf<4; nf++)
                    MMA16816(acc[mf][nf], a[mf], b[nf][0], b[nf][1]);
        }
        __syncthreads();
    }
    #pragma unroll
    for (int mf=0; mf<4; mf++) {
        int m = mbase + wm*64 + mf*16 + (lane>>2);
        #pragma unroll
        for (int nf=0; nf<4; nf++) {
            int n = nbase + wn*32 + nf*8 + ((lane&3)<<1);
            *(float2*)&g_S[(size_t)m*BS_ + n]     = make_float2(acc[mf][nf][0], acc[mf][nf][1]);
            *(float2*)&g_S[(size_t)(m+8)*BS_ + n] = make_float2(acc[mf][nf][2], acc[mf][nf][3]);
        }
    }
}

// =================== LayerNorm / CA / softmax / reduce ==========================
__global__ void __launch_bounds__(256) ln_kernel(
    const float* __restrict__ a, const float* __restrict__ r,
    const float* __restrict__ w, const float* __restrict__ bb,
    float* __restrict__ out, float* __restrict__ norm_out)
{
    const int row = blockIdx.x, tid = threadIdx.x;
    const float* ap = a + (size_t)row*D_;
    const float* rp = r ? r + (size_t)row*D_ : nullptr;
    float vals[6]; float s1=0.f, s2=0.f;
    #pragma unroll
    for (int i=0;i<6;i++) {
        int e = tid + i*256;
        float v = ap[e] + (rp ? rp[e] : 0.f);
        vals[i]=v; s1+=v; s2+=v*v;
    }
    __shared__ float red[16];
    int lane=tid&31, wid=tid>>5;
    for (int o=16;o;o>>=1){ s1+=__shfl_xor_sync(~0u,s1,o); s2+=__shfl_xor_sync(~0u,s2,o); }
    if (lane==0){ red[wid]=s1; red[8+wid]=s2; }
    __syncthreads();
    if (tid==0){ float a1=0,a2=0; for(int k=0;k<8;k++){a1+=red[k];a2+=red[8+k];} red[0]=a1; red[8]=a2; }
    __syncthreads();
    float mean = red[0]*(1.0f/D_);
    float var  = red[8]*(1.0f/D_) - mean*mean;
    float rstd = rsqrtf(var + 1e-5f);
    float ss = 0.f;
    #pragma unroll
    for (int i=0;i<6;i++) {
        int e = tid + i*256;
        float y = (vals[i]-mean)*rstd*w[e] + bb[e];
        out[(size_t)row*D_+e] = y;
        ss += y*y;
    }
    if (norm_out) {
        for (int o=16;o;o>>=1) ss+=__shfl_xor_sync(~0u,ss,o);
        __syncthreads();
        if (lane==0) red[wid]=ss;
        __syncthreads();
        if (tid==0){ float t=0; for(int k=0;k<8;k++) t+=red[k]; norm_out[row]=sqrtf(t); }
    }
}

__global__ void __launch_bounds__(256) ca_scores_kernel(const float* __restrict__ mem)
{
    __shared__ float gs[NH_*D_];
    const int b = blockIdx.x, tid = threadIdx.x;
    const float4* gsrc = (const float4*)(g_g + (size_t)b*NH_*D_);
    for (int i=tid;i<NH_*D_/4;i+=256) ((float4*)gs)[i]=gsrc[i];
    __syncthreads();
    const int warp=tid>>5, lane=tid&31;
    const float* mb = mem + (size_t)b*S_*D_;
    const float scale = rsqrtf((float)DH_);
    const int sbase = blockIdx.y*128 + warp*16;
    for (int grp=0;grp<4;grp++) {
        int s0 = sbase + grp*4;
        float acc[NH_][4];
        #pragma unroll
        for (int h=0;h<NH_;h++)
            #pragma unroll
            for (int r2=0;r2<4;r2++) acc[h][r2]=0.f;
        #pragma unroll
        for (int i=0;i<12;i++) {
            int e = lane*4 + i*128;
            float4 m[4];
            #pragma unroll
            for (int r2=0;r2<4;r2++) m[r2]=*(const float4*)(mb+(size_t)(s0+r2)*D_+e);
            #pragma unroll
            for (int h=0;h<NH_;h++) {
                float4 gv=*(const float4*)(gs + h*D_ + e);
                #pragma unroll
                for (int r2=0;r2<4;r2++)
                    acc[h][r2] += gv.x*m[r2].x + gv.y*m[r2].y + gv.z*m[r2].z + gv.w*m[r2].w;
            }
        }
        #pragma unroll
        for (int h=0;h<NH_;h++)
            #pragma unroll
            for (int r2=0;r2<4;r2++) {
                float v=acc[h][r2];
                for (int o=16;o;o>>=1) v+=__shfl_xor_sync(~0u,v,o);
                if (lane==0) g_scores[((size_t)b*NH_+h)*S_ + s0+r2] = v*scale;
            }
    }
}

__global__ void __launch_bounds__(256) ca_softmax_kernel()
{
    const int row=blockIdx.x, tid=threadIdx.x;
    float* sp = g_scores + (size_t)row*S_;
    float v = sp[tid];
    __shared__ float red[16];
    int lane=tid&31, wid=tid>>5;
    float m=v;
    for (int o=16;o;o>>=1) m=fmaxf(m,__shfl_xor_sync(~0u,m,o));
    if (lane==0) red[wid]=m;
    __syncthreads();
    if (tid==0){ float mm=red[0]; for(int k=1;k<8;k++) mm=fmaxf(mm,red[k]); red[0]=mm; }
    __syncthreads();
    m=red[0];
    float e=__expf(v-m);
    float s=e;
    for (int o=16;o;o>>=1) s+=__shfl_xor_sync(~0u,s,o);
    __syncthreads();
    if (lane==0) red[8+wid]=s;
    __syncthreads();
    if (tid==0){ float t=0; for(int k=0;k<8;k++) t+=red[8+k]; red[8]=t; }
    __syncthreads();
    sp[tid]=e/red[8];
}

__global__ void __launch_bounds__(256) mtilde_kernel(const float* __restrict__ mem)
{
    __shared__ float at[NH_*S_];
    const int b=blockIdx.x, tid=threadIdx.x;
    for (int i=tid;i<NH_*S_;i+=256) at[i]=g_scores[(size_t)b*NH_*S_+i];
    __syncthreads();
    const int e = blockIdx.y*512 + tid*2;
    const float* mb = mem + (size_t)b*S_*D_;
    float2 acc[NH_];
    #pragma unroll
    for (int h=0;h<NH_;h++){ acc[h].x=0.f; acc[h].y=0.f; }
    for (int s=0;s<S_;s++) {
        float2 mv=*(const float2*)(mb+(size_t)s*D_+e);
        #pragma unroll
        for (int h=0;h<NH_;h++){
            float a=at[h*S_+s];
            acc[h].x=fmaf(a,mv.x,acc[h].x);
            acc[h].y=fmaf(a,mv.y,acc[h].y);
        }
    }
    #pragma unroll
    for (int h=0;h<NH_;h++)
        *(float2*)(g_mt + (size_t)b*NH_*D_ + h*D_ + e) = acc[h];
}

__global__ void __launch_bounds__(256) pool_reduce_kernel(
    const float* __restrict__ ls, float* __restrict__ out)
{
    const int j=blockIdx.x, i=blockIdx.y, s=threadIdx.x;
    float Sv = g_S[(size_t)i*BS_ + j*S_ + s];
    float Cv = g_S[(size_t)(B_+i)*BS_ + j*S_ + s];
    float nmv = g_nm[j*S_+s];
    __shared__ float red[16];
    int lane=s&31, wid=s>>5;
    float m=Sv;
    for (int o=16;o;o>>=1) m=fmaxf(m,__shfl_xor_sync(~0u,m,o));
    if (lane==0) red[wid]=m;
    __syncthreads();
    if (s==0){ float mm=red[0]; for(int k=1;k<8;k++) mm=fmaxf(mm,red[k]); red[0]=mm; }
    __syncthreads();
    m=red[0];
    float e = expf(Sv-m);
    float t1=e, t2=e*Cv/nmv;
    for (int o=16;o;o>>=1){ t1+=__shfl_xor_sync(~0u,t1,o); t2+=__shfl_xor_sync(~0u,t2,o); }
    __syncthreads();
    if (lane==0){ red[wid]=t1; red[8+wid]=t2; }
    __syncthreads();
    if (s==0) {
        float Z=0.f, Wv=0.f;
        for (int k=0;k<8;k++){ Z+=red[k]; Wv+=red[8+k]; }
        float val = expf(ls[0]) * Wv / (Z * g_nx[i]);
        out[(size_t)i*B_ + j] = val;
        out[(size_t)B_*B_ + (size_t)j*B_ + i] = val;
    }
}

__global__ void copy_xsq_kernel(float* __restrict__ out)
{
    int idx = blockIdx.x*256 + threadIdx.x;
    out[(size_t)2*B_*B_ + idx] = g_xsq[idx];
}

// =================== host =======================================================
template<typename T> static float* sym(T& s){ void* p=nullptr; cudaGetSymbolAddress(&p, s); return (float*)p; }

extern "C" void kernel_launch(void* const* d_in, const int* in_sizes, int n_in,
                              void* d_out, int out_size)
{
    const float* x        =(const float*)d_in[0];
    const float* mem      =(const float*)d_in[1];
    const float* emb_w    =(const float*)d_in[2];
    const float* emb_b    =(const float*)d_in[3];
    const float* sa_in_w  =(const float*)d_in[4];
    const float* sa_in_b  =(const float*)d_in[5];
    const float* sa_out_w =(const float*)d_in[6];
    const float* sa_out_b =(const float*)d_in[7];
    const float* ca_in_w  =(const float*)d_in[8];
    const float* ca_in_b  =(const float*)d_in[9];
    const float* ca_out_w =(const float*)d_in[10];
    const float* ca_out_b =(const float*)d_in[11];
    const float* lin1_w   =(const float*)d_in[12];
    const float* lin1_b   =(const float*)d_in[13];
    const float* lin2_w   =(const float*)d_in[14];
    const float* lin2_b   =(const float*)d_in[15];
    const float* ln1_w    =(const float*)d_in[16];
    const float* ln1_b    =(const float*)d_in[17];
    const float* ln2_w    =(const float*)d_in[18];
    const float* ln2_b    =(const float*)d_in[19];
    const float* ln3_w    =(const float*)d_in[20];
    const float* ln3_b    =(const float*)d_in[21];
    const float* fin_w    =(const float*)d_in[22];
    const float* fin_b    =(const float*)d_in[23];
    const float* attn_in_w=(const float*)d_in[24];
    const float* attn_in_b=(const float*)d_in[25];
    const float* logit_sc =(const float*)d_in[26];
    float* out = (float*)d_out;

    float* t0 = sym(g_t0);  float* v   = sym(g_v);   float* sa  = sym(g_sa);
    float* t1 = sym(g_t1);  float* qp  = sym(g_qp);  float* gg  = sym(g_g);
    float* mt = sym(g_mt);  float* o   = sym(g_o);   float* ca  = sym(g_ca);
    float* t2 = sym(g_t2);  float* h1  = sym(g_h1);  float* ff  = sym(g_ff);
    float* t3 = sym(g_t3);  float* xsq = sym(g_xsq); float* qp2 = sym(g_qp2);
    float* qt = sym(g_qt);  float* nx  = sym(g_nx);  float* pt  = sym(g_part);

    const float* NOB = nullptr;
    static bool attr_done = false;
    if (!attr_done) {
        cudaFuncSetAttribute(gemm_nt_tc, cudaFuncAttributeMaxDynamicSharedMemorySize, SMEM_NTTC);
        attr_done = true;
    }

    #define TC(GX,GZ, A_,LDA,SA_, W_,LDW,SW_, B_P,SB_, C_,LDC,SC_, K_, RELU_) \
        gemm_nt_tc<<<dim3(GX,GZ), 256, SMEM_NTTC>>>(A_,LDA,SA_, W_,LDW,SW_, B_P,SB_, C_,LDC,SC_, K_, RELU_)

    // 0. memory -> bf16 hi/lo + row norms
    conv_mem_kernel<<<BS_/8, 256>>>(mem);

    // 1. t0 = x @ emb_w.T + emb_b
    TC(D_/64, 1, x, DIN_, 0, emb_w, DIN_, 0, emb_b, 0, t0, D_, 0, DIN_, 0);
    // 2. SA (L=1): v = t0 @ wv.T + bv ; sa = v @ out_w.T + out_b
    TC(D_/64, 1, t0, D_, 0, sa_in_w + (size_t)2*D_*D_, D_, 0, sa_in_b + 2*D_, 0, v, D_, 0, D_, 0);
    TC(D_/64, 1, v, D_, 0, sa_out_w, D_, 0, sa_out_b, 0, sa, D_, 0, D_, 0);
    // 3. t1 = LN(t0 + sa)
    ln_kernel<<<B_, 256>>>(t0, sa, ln1_w, ln1_b, t1, nullptr);
    // 4. CA q-proj, then g[b,h] = qp_h @ wk_h (batched heads, fp32 nn, K=192)
    TC(D_/64, 1, t1, D_, 0, ca_in_w, D_, 0, ca_in_b, 0, qp, D_, 0, D_, 0);
    gemm_nn<64,64,16,4,4><<<dim3(D_/64, B_/64, NH_), 256>>>(
        qp, D_, DH_, ca_in_w + (size_t)D_*D_, D_, (long long)DH_*D_,
        NOB, 0, gg, NH_*D_, D_, DH_, 1, nullptr);
    // 5. CA scores / softmax / weighted memory
    ca_scores_kernel<<<dim3(B_,2), 256>>>(mem);
    ca_softmax_kernel<<<B_*NH_, 256>>>();
    mtilde_kernel<<<dim3(B_,3), 256>>>(mem);
    // 6. o_h = m~_h @ wv_h.T + bv_h (batched heads); ca = o @ out_w.T + out_b
    TC(DH_/64, NH_, mt, NH_*D_, D_,
       ca_in_w + (size_t)2*D_*D_, D_, (long long)DH_*D_,
       ca_in_b + 2*D_, DH_, o, D_, DH_, D_, 0);
    TC(D_/64, 1, o, D_, 0, ca_out_w, D_, 0, ca_out_b, 0, ca, D_, 0, D_, 0);
    // 7. t2 = LN(t1 + ca)
    ln_kernel<<<B_, 256>>>(t1, ca, ln2_w, ln2_b, t2, nullptr);
    // 8. FF
    TC(FF_/64, 1, t2, D_, 0, lin1_w, D_, 0, lin1_b, 0, h1, FF_, 0, D_, 1);
    TC(D_/64, 1, h1, FF_, 0, lin2_w, FF_, 0, lin2_b, 0, ff, D_, 0, FF_, 0);
    // 9. t3 = LN(t2 + ff) ; x_sq = LN(t3) with row norm
    ln_kernel<<<B_, 256>>>(t2, ff, ln3_w, ln3_b, t3, nullptr);
    ln_kernel<<<B_, 256>>>(t3, nullptr, fin_w, fin_b, xsq, nx);
    // 10. pooling projections: qp2 (tc) ; qt = qp2@wk2 (fp32 nn, KS=6 + reduce)
    TC(D_/64, 1, xsq, D_, 0, attn_in_w, D_, 0, attn_in_b, 0, qp2, D_, 0, D_, 0);
    gemm_nn<64,64,16,4,4><<<dim3(D_/64, B_/64, 6), 256>>>(
        qp2, D_, 0, attn_in_w + (size_t)D_*D_, D_, 0,
        NOB, 0, nullptr, 0, 0, D_, 6, pt);
    reduce_ks<<<dim3((B_*D_+255)/256, 1), 256>>>(pt, NOB, 0, qt, D_, 0, B_, D_, 6, 0);

    // 11. A -> bf16 hi/lo ; big mma.sync GEMM (3-product split, K'=4608)
    conv_a_kernel<<<32, 256>>>();
    bigmm_kernel<<<dim3(BS_/128, 2), 256>>>();

    // 12. final softmax-weighted cosine reduce; third output
    pool_reduce_kernel<<<dim3(B_, B_), 256>>>(logit_sc, out);
    copy_xsq_kernel<<<(B_*D_)/256, 256>>>(out);

    (void)in_sizes; (void)n_in; (void)out_size;
}

// round 7
// speedup vs baseline: 1.2628x; 1.2628x over previous
#include <cuda_runtime.h>
#include <cuda_bf16.h>
#include <math.h>
#include <stdint.h>

// Problem constants
#define B_    128
#define S_    256
#define D_    1536
#define DIN_  768
#define NH_   8
#define DH_   192
#define FF_   2048
#define BS_   (B_*S_)   // 32768
#define KP_   3072      // hi||lo width = 2*D_

// ---------------- scratch (device globals; no cudaMalloc allowed) -------------
__device__ float g_t0 [B_*D_];
__device__ float g_v  [B_*D_];
__device__ float g_sa [B_*D_];
__device__ float g_t1 [B_*D_];
__device__ float g_qp [B_*D_];
__device__ float g_g  [B_*NH_*D_];
__device__ float g_scores[B_*NH_*S_];
__device__ float g_mt [B_*NH_*D_];
__device__ float g_o  [B_*D_];
__device__ float g_ca [B_*D_];
__device__ float g_t2 [B_*D_];
__device__ float g_h1 [B_*FF_];
__device__ float g_ff [B_*D_];
__device__ float g_t3 [B_*D_];
__device__ float g_xsq[B_*D_];
__device__ float g_qp2[B_*D_];
__device__ float g_qt [B_*D_];
__device__ float g_S  [(size_t)2*B_*BS_];
__device__ float g_nm [B_*S_];
__device__ float g_nx [B_];
__device__ float g_part[1600*1024];                 // K-split partials
__device__ __nv_bfloat16 g_mb[(size_t)BS_*KP_];     // memory hi||lo bf16
__device__ __nv_bfloat16 g_ab[256*KP_];             // bigmm A hi||lo bf16
// activation + weight bf16 (hi||lo) buffers
__device__ __nv_bfloat16 g_a2 [128*4096];
__device__ __nv_bfloat16 g_mt2[128*NH_*3072];
__device__ __nv_bfloat16 g_w_emb  [1536*1536];
__device__ __nv_bfloat16 g_w_savv [1536*3072];
__device__ __nv_bfloat16 g_w_saout[1536*3072];
__device__ __nv_bfloat16 g_w_cawq [1536*3072];
__device__ __nv_bfloat16 g_w_cawv [1536*3072];
__device__ __nv_bfloat16 g_w_caout[1536*3072];
__device__ __nv_bfloat16 g_w_lin1 [2048*3072];
__device__ __nv_bfloat16 g_w_lin2 [1536*4096];
__device__ __nv_bfloat16 g_w_attnq[1536*3072];

// =================== common mma.sync macros =====================================
#define LDSM4(R0,R1,R2,R3,ADDR) \
    asm volatile("ldmatrix.sync.aligned.m8n8.x4.shared.b16 {%0,%1,%2,%3}, [%4];" \
        : "=r"(R0),"=r"(R1),"=r"(R2),"=r"(R3) : "r"(ADDR))
#define MMA16816(D,A,B0,B1) \
    asm volatile("mma.sync.aligned.m16n8k16.row.col.f32.bf16.bf16.f32 " \
        "{%0,%1,%2,%3}, {%4,%5,%6,%7}, {%8,%9}, {%0,%1,%2,%3};" \
        : "+f"((D)[0]),"+f"((D)[1]),"+f"((D)[2]),"+f"((D)[3]) \
        : "r"((A)[0]),"r"((A)[1]),"r"((A)[2]),"r"((A)[3]),"r"(B0),"r"(B1))
#define CPA16(DST,SRC) \
    asm volatile("cp.async.ca.shared.global [%0], [%1], 16;" \
        :: "r"((uint32_t)__cvta_generic_to_shared(DST)), "l"(SRC))

__device__ __forceinline__ void split_bf16(float f, __nv_bfloat16& h, __nv_bfloat16& l){
    h = __float2bfloat16(f);
    l = __float2bfloat16(f - __bfloat162float(h));
}

// =================== gemm64_tc: tensor small GEMM ===============================
// partial[(z*KS+y)*128 + m][Ntot] += A2(128, [hi K|lo K]) @ W2(N, [hi K|lo K])^T
// 3-product bf16 split via K' = 3K chunk segments. BM=128, BN=64, 256 thr.
#define GSLD 40

__global__ void __launch_bounds__(256) gemm64_tc(
    const __nv_bfloat16* __restrict__ A2, int lda2, long long strideA2,
    const __nv_bfloat16* __restrict__ W2, int ldw2, long long strideW2,
    float* __restrict__ partial, int K)
{
    __shared__ __align__(16) __nv_bfloat16 sA[2][128*GSLD];
    __shared__ __align__(16) __nv_bfloat16 sW[2][64*GSLD];
    const int tid = threadIdx.x;
    const int warp = tid>>5, lane = tid&31;
    const int wm = warp>>1, wn = warp&1;                 // 4(m) x 2(n)
    const int bn = blockIdx.x*64;
    const int KS = gridDim.y;
    const int z  = blockIdx.z;
    const int Ntot = gridDim.x*64;
    A2 += (long long)z*strideA2;
    W2 += (long long)z*strideW2;
    const int segc = K/32;
    const int nck  = (3*segc)/KS;
    const int g0   = blockIdx.y*nck;

    float acc[2][4][4];
    #pragma unroll
    for (int i=0;i<2;i++)
        #pragma unroll
        for (int j=0;j<4;j++)
            #pragma unroll
            for (int c=0;c<4;c++) acc[i][j][c]=0.f;

    #define G64_LOAD(BUF,C) do {                                              \
        int g_   = g0 + (C);                                                   \
        int seg_ = g_ / segc;                                                  \
        int k0_  = (g_ - seg_*segc)*32;                                        \
        int aOff_ = (seg_==2) ? K : 0;                                         \
        int bOff_ = (seg_==1) ? K : 0;                                         \
        _Pragma("unroll")                                                      \
        for (int i=0;i<2;i++) {                                                \
            int l = tid + i*256;                                               \
            int r = l>>2, sg = l&3;                                            \
            CPA16(&sA[BUF][r*GSLD + sg*8],                                     \
                  A2 + (size_t)r*lda2 + aOff_ + k0_ + sg*8);                   \
        }                                                                      \
        { int r = tid>>2, sg = tid&3;                                          \
          CPA16(&sW[BUF][r*GSLD + sg*8],                                       \
                W2 + (size_t)(bn+r)*ldw2 + bOff_ + k0_ + sg*8); }              \
        asm volatile("cp.async.commit_group;");                                \
    } while(0)

    G64_LOAD(0, 0);
    for (int c=0; c<nck; c++) {
        int buf = c & 1;
        asm volatile("cp.async.wait_group 0;");
        __syncthreads();
        if (c+1 < nck) G64_LOAD(buf^1, c+1);
        #pragma unroll
        for (int kk=0; kk<2; kk++) {
            const int kb = kk*16;
            uint32_t a[2][4], b[4][2];
            #pragma unroll
            for (int mf=0; mf<2; mf++) {
                int row = wm*32 + mf*16 + (lane&15);
                int ko  = kb + ((lane>>4)<<3);
                uint32_t ad = (uint32_t)__cvta_generic_to_shared(&sA[buf][row*GSLD + ko]);
                LDSM4(a[mf][0],a[mf][1],a[mf][2],a[mf][3], ad);
            }
            #pragma unroll
            for (int p=0; p<2; p++) {
                int nrow = wn*32 + p*16 + ((lane>>4)<<3) + (lane&7);
                int ko   = kb + (((lane>>3)&1)<<3);
                uint32_t ad = (uint32_t)__cvta_generic_to_shared(&sW[buf][nrow*GSLD + ko]);
                LDSM4(b[2*p][0],b[2*p][1],b[2*p+1][0],b[2*p+1][1], ad);
            }
            #pragma unroll
            for (int mf=0; mf<2; mf++)
                #pragma unroll
                for (int nf=0; nf<4; nf++)
                    MMA16816(acc[mf][nf], a[mf], b[nf][0], b[nf][1]);
        }
        __syncthreads();
    }
    const size_t pbase = (size_t)(z*KS + blockIdx.y)*128;
    #pragma unroll
    for (int mf=0; mf<2; mf++) {
        int m = wm*32 + mf*16 + (lane>>2);
        #pragma unroll
        for (int nf=0; nf<4; nf++) {
            int n = bn + wn*32 + nf*8 + ((lane&3)<<1);
            *(float2*)&partial[(pbase + m)*Ntot + n]     = make_float2(acc[mf][nf][0], acc[mf][nf][1]);
            *(float2*)&partial[(pbase + m+8)*Ntot + n]   = make_float2(acc[mf][nf][2], acc[mf][nf][3]);
        }
    }
}

// =================== reduce K-split partials (+bias/relu, + bf16 a2 out) ========
__global__ void __launch_bounds__(256) reduce_ks(
    const float* __restrict__ partial, const float* __restrict__ bias, int strideBias,
    float* __restrict__ C, int ldc, long long strideC,
    int Mtot, int Ntot, int KS, int relu,
    __nv_bfloat16* __restrict__ a2, int lda2, int loOff, int a2strideZ)
{
    const int zb = blockIdx.y;
    int idx = blockIdx.x*256 + threadIdx.x;
    if (idx >= Mtot*Ntot) return;
    int m = idx / Ntot, n = idx % Ntot;
    float s = 0.f;
    for (int c=0;c<KS;c++)
        s += partial[((size_t)(zb*KS+c)*Mtot + m)*Ntot + n];
    if (bias) s += bias[(size_t)zb*strideBias + n];
    if (relu) s = fmaxf(s, 0.f);
    C[(size_t)zb*strideC + (size_t)m*ldc + n] = s;
    if (a2) {
        __nv_bfloat16 h,l; split_bf16(s,h,l);
        size_t base = (size_t)zb*a2strideZ + (size_t)m*lda2 + n;
        a2[base] = h;
        a2[base + loOff] = l;
    }
}

// =================== fp32 gemm_nn (for gg / qt) ==================================
template<int BM,int BN,int BK,int TM,int TN>
__global__ void __launch_bounds__(256) gemm_nn(
    const float* __restrict__ A, int lda, long long strideA,
    const float* __restrict__ W, int ldw, long long strideW,
    const float* __restrict__ bias, int strideBias,
    float* __restrict__ C, int ldc, long long strideC,
    int K, int KS, float* __restrict__ partial)
{
    const int zb = blockIdx.z / KS, chunk = blockIdx.z % KS;
    const int Kc = K / KS;
    A += (long long)zb*strideA + chunk*Kc;
    W += (long long)zb*strideW + (size_t)chunk*Kc*ldw;
    C += (long long)zb*strideC;
    if (bias) bias += (long long)zb*strideBias;

    __shared__ float sA[BK][BM];
    __shared__ float sW[BK][BN];
    const int tid = threadIdx.x;
    const int bm = blockIdx.y*BM, bn = blockIdx.x*BN;
    const int tx = tid % (BN/TN), ty = tid / (BN/TN);
    float acc[TM][TN];
    #pragma unroll
    for (int i=0;i<TM;i++)
        #pragma unroll
        for (int j=0;j<TN;j++) acc[i][j]=0.f;

    for (int k0=0;k0<Kc;k0+=BK) {
        for (int i=tid;i<BM*(BK/4);i+=256) {
            int r=i/(BK/4), kv=i%(BK/4);
            float4 v=*(const float4*)(A+(size_t)(bm+r)*lda + k0 + kv*4);
            sA[kv*4+0][r]=v.x; sA[kv*4+1][r]=v.y; sA[kv*4+2][r]=v.z; sA[kv*4+3][r]=v.w;
        }
        for (int i=tid;i<BK*(BN/4);i+=256) {
            int kk=i/(BN/4), nv=i%(BN/4);
            *(float4*)&sW[kk][nv*4] = *(const float4*)(W+(size_t)(k0+kk)*ldw + bn + nv*4);
        }
        __syncthreads();
        #pragma unroll
        for (int kk=0;kk<BK;kk++) {
            float a[TM], w[TN];
            #pragma unroll
            for (int i=0;i<TM;i+=4) *(float4*)&a[i] = *(const float4*)&sA[kk][ty*TM+i];
            #pragma unroll
            for (int j=0;j<TN;j+=4) *(float4*)&w[j] = *(const float4*)&sW[kk][tx*TN+j];
            #pragma unroll
            for (int i=0;i<TM;i++)
                #pragma unroll
                for (int j=0;j<TN;j++) acc[i][j] = fmaf(a[i], w[j], acc[i][j]);
        }
        __syncthreads();
    }
    if (partial) {
        const int Mtot = gridDim.y*BM, Ntot = gridDim.x*BN;
        #pragma unroll
        for (int i=0;i<TM;i++) {
            int m = bm + ty*TM + i;
            #pragma unroll
            for (int j=0;j<TN;j+=4)
                *(float4*)&partial[((size_t)blockIdx.z*Mtot + m)*Ntot + bn + tx*TN + j]
                    = *(float4*)&acc[i][j];
        }
    } else {
        #pragma unroll
        for (int i=0;i<TM;i++) {
            int gm = bm + ty*TM + i;
            #pragma unroll
            for (int j=0;j<TN;j++) {
                int gn = bn + tx*TN + j;
                C[(size_t)gm*ldc + gn] = acc[i][j] + (bias ? bias[gn] : 0.f);
            }
        }
    }
}

// =================== conversions =================================================
__global__ void __launch_bounds__(256) conv_mem_kernel(const float* __restrict__ mem)
{
    const int row = blockIdx.x*8 + (threadIdx.x>>5);
    const int lane = threadIdx.x&31;
    const float* p = mem + (size_t)row*D_;
    __nv_bfloat16* oh = g_mb + (size_t)row*KP_;
    float ss = 0.f;
    #pragma unroll
    for (int i=0;i<12;i++) {
        int e = lane*4 + i*128;
        float4 v = *(const float4*)(p+e);
        ss += v.x*v.x + v.y*v.y + v.z*v.z + v.w*v.w;
        __align__(8) __nv_bfloat16 h[4], l[4];
        float f[4] = {v.x,v.y,v.z,v.w};
        #pragma unroll
        for (int c=0;c<4;c++) split_bf16(f[c], h[c], l[c]);
        *(uint64_t*)(oh + e)       = *(uint64_t*)h;
        *(uint64_t*)(oh + D_ + e)  = *(uint64_t*)l;
    }
    for (int o=16;o;o>>=1) ss += __shfl_xor_sync(~0u, ss, o);
    if (lane==0) g_nm[row] = sqrtf(ss);
}

// generic weight conversion: src (rows x K) -> dst (rows x [hi K | lo K])
__global__ void __launch_bounds__(256) conv_w_kernel(
    const float* __restrict__ src, __nv_bfloat16* __restrict__ dst, int K)
{
    const int row = blockIdx.x*8 + (threadIdx.x>>5);
    const int lane = threadIdx.x&31;
    const float* p = src + (size_t)row*K;
    __nv_bfloat16* o = dst + (size_t)row*2*K;
    for (int e=lane*4; e<K; e+=128) {
        float4 v = *(const float4*)(p+e);
        __align__(8) __nv_bfloat16 h[4], l[4];
        float f[4] = {v.x,v.y,v.z,v.w};
        #pragma unroll
        for (int c=0;c<4;c++) split_bf16(f[c], h[c], l[c]);
        *(uint64_t*)(o + e)     = *(uint64_t*)h;
        *(uint64_t*)(o + K + e) = *(uint64_t*)l;
    }
}

__global__ void __launch_bounds__(256) conv_a_kernel()
{
    const int row = blockIdx.x*8 + (threadIdx.x>>5);
    const int lane = threadIdx.x&31;
    const float sc = (row < B_) ? rsqrtf((float)D_) : 1.0f;
    const float* p = (row < B_) ? (g_qt + (size_t)row*D_) : (g_xsq + (size_t)(row-B_)*D_);
    __nv_bfloat16* oh = g_ab + (size_t)row*KP_;
    #pragma unroll
    for (int i=0;i<12;i++) {
        int e = lane*4 + i*128;
        float4 v = *(const float4*)(p+e);
        float f[4] = {v.x*sc, v.y*sc, v.z*sc, v.w*sc};
        __align__(8) __nv_bfloat16 h[4], l[4];
        #pragma unroll
        for (int c=0;c<4;c++) split_bf16(f[c], h[c], l[c]);
        *(uint64_t*)(oh + e)      = *(uint64_t*)h;
        *(uint64_t*)(oh + D_ + e) = *(uint64_t*)l;
    }
}

// =================== big mma.sync GEMM (proven R4 version) ======================
#define SLD 40
#define SEGC 48

__global__ void __launch_bounds__(256) bigmm_kernel()
{
    __shared__ __align__(16) __nv_bfloat16 sA[2][128*SLD];
    __shared__ __align__(16) __nv_bfloat16 sB[2][128*SLD];
    const int tid = threadIdx.x;
    const int warp = tid>>5, lane = tid&31;
    const int wm = warp>>2, wn = warp&3;
    const int nbase = blockIdx.x*128, mbase = blockIdx.y*128;

    float acc[4][4][4];
    #pragma unroll
    for (int i=0;i<4;i++)
        #pragma unroll
        for (int j=0;j<4;j++)
            #pragma unroll
            for (int c=0;c<4;c++) acc[i][j][c]=0.f;

    const int r0 = tid>>1;
    const int seg0 = (tid&1)*2;

    #define LOAD_TILES(BUF,KC) do {                                              \
        int seg_ = (KC)/SEGC;                                                     \
        int k0_  = ((KC)%SEGC)*32;                                                \
        int aOff_ = (seg_==2) ? D_ : 0;                                           \
        int bOff_ = (seg_==1) ? D_ : 0;                                           \
        _Pragma("unroll")                                                        \
        for (int i=0;i<2;i++) {                                                  \
            int seg = seg0 + i;                                                  \
            CPA16(&sA[BUF][r0*SLD + seg*8],                                      \
                  g_ab + (size_t)(mbase+r0)*KP_ + aOff_ + k0_ + seg*8);          \
            CPA16(&sB[BUF][r0*SLD + seg*8],                                      \
                  g_mb + (size_t)(nbase+r0)*KP_ + bOff_ + k0_ + seg*8);          \
        }                                                                        \
        asm volatile("cp.async.commit_group;");                                  \
    } while(0)

    LOAD_TILES(0, 0);
    const int KC = 3*SEGC;
    for (int kc=0; kc<KC; kc++) {
        int buf = kc & 1;
        asm volatile("cp.async.wait_group 0;");
        __syncthreads();
        if (kc+1 < KC) LOAD_TILES(buf^1, kc+1);
        #pragma unroll
        for (int kk=0; kk<2; kk++) {
            const int kb = kk*16;
            uint32_t a[4][4], b[4][2];
            #pragma unroll
            for (int mf=0; mf<4; mf++) {
                int row = wm*64 + mf*16 + (lane&15);
                int ko  = kb + ((lane>>4)<<3);
                uint32_t ad = (uint32_t)__cvta_generic_to_shared(&sA[buf][row*SLD + ko]);
                LDSM4(a[mf][0],a[mf][1],a[mf][2],a[mf][3], ad);
            }
            #pragma unroll
            for (int p=0; p<2; p++) {
                int nrow = wn*32 + p*16 + ((lane>>4)<<3) + (lane&7);
                int ko   = kb + (((lane>>3)&1)<<3);
                uint32_t ad = (uint32_t)__cvta_generic_to_shared(&sB[buf][nrow*SLD + ko]);
                LDSM4(b[2*p][0],b[2*p][1],b[2*p+1][0],b[2*p+1][1], ad);
            }
            #pragma unroll
            for (int mf=0; mf<4; mf++)
                #pragma unroll
                for (int nf=0; nf<4; nf++)
                    MMA16816(acc[mf][nf], a[mf], b[nf][0], b[nf][1]);
        }
        __syncthreads();
    }
    #pragma unroll
    for (int mf=0; mf<4; mf++) {
        int m = mbase + wm*64 + mf*16 + (lane>>2);
        #pragma unroll
        for (int nf=0; nf<4; nf++) {
            int n = nbase + wn*32 + nf*8 + ((lane&3)<<1);
            *(float2*)&g_S[(size_t)m*BS_ + n]     = make_float2(acc[mf][nf][0], acc[mf][nf][1]);
            *(float2*)&g_S[(size_t)(m+8)*BS_ + n] = make_float2(acc[mf][nf][2], acc[mf][nf][3]);
        }
    }
}

// =================== LayerNorm (+bf16 a2 out) / CA / softmax / reduce ===========
__global__ void __launch_bounds__(256) ln_kernel(
    const float* __restrict__ a, const float* __restrict__ r,
    const float* __restrict__ w, const float* __restrict__ bb,
    float* __restrict__ out, float* __restrict__ norm_out,
    __nv_bfloat16* __restrict__ a2)
{
    const int row = blockIdx.x, tid = threadIdx.x;
    const float* ap = a + (size_t)row*D_;
    const float* rp = r ? r + (size_t)row*D_ : nullptr;
    float vals[6]; float s1=0.f, s2=0.f;
    #pragma unroll
    for (int i=0;i<6;i++) {
        int e = tid + i*256;
        float v = ap[e] + (rp ? rp[e] : 0.f);
        vals[i]=v; s1+=v; s2+=v*v;
    }
    __shared__ float red[16];
    int lane=tid&31, wid=tid>>5;
    for (int o=16;o;o>>=1){ s1+=__shfl_xor_sync(~0u,s1,o); s2+=__shfl_xor_sync(~0u,s2,o); }
    if (lane==0){ red[wid]=s1; red[8+wid]=s2; }
    __syncthreads();
    if (tid==0){ float a1=0,a2s=0; for(int k=0;k<8;k++){a1+=red[k];a2s+=red[8+k];} red[0]=a1; red[8]=a2s; }
    __syncthreads();
    float mean = red[0]*(1.0f/D_);
    float var  = red[8]*(1.0f/D_) - mean*mean;
    float rstd = rsqrtf(var + 1e-5f);
    float ss = 0.f;
    #pragma unroll
    for (int i=0;i<6;i++) {
        int e = tid + i*256;
        float y = (vals[i]-mean)*rstd*w[e] + bb[e];
        out[(size_t)row*D_+e] = y;
        if (a2) {
            __nv_bfloat16 h,l; split_bf16(y,h,l);
            a2[(size_t)row*2*D_ + e]      = h;
            a2[(size_t)row*2*D_ + D_ + e] = l;
        }
        ss += y*y;
    }
    if (norm_out) {
        for (int o=16;o;o>>=1) ss+=__shfl_xor_sync(~0u,ss,o);
        __syncthreads();
        if (lane==0) red[wid]=ss;
        __syncthreads();
        if (tid==0){ float t=0; for(int k=0;k<8;k++) t+=red[k]; norm_out[row]=sqrtf(t); }
    }
}

__global__ void __launch_bounds__(256) ca_scores_kernel(const float* __restrict__ mem)
{
    __shared__ float gs[NH_*D_];
    const int b = blockIdx.x, tid = threadIdx.x;
    const float4* gsrc = (const float4*)(g_g + (size_t)b*NH_*D_);
    for (int i=tid;i<NH_*D_/4;i+=256) ((float4*)gs)[i]=gsrc[i];
    __syncthreads();
    const int warp=tid>>5, lane=tid&31;
    const float* mb = mem + (size_t)b*S_*D_;
    const float scale = rsqrtf((float)DH_);
    const int sbase = blockIdx.y*128 + warp*16;
    for (int grp=0;grp<4;grp++) {
        int s0 = sbase + grp*4;
        float acc[NH_][4];
        #pragma unroll
        for (int h=0;h<NH_;h++)
            #pragma unroll
            for (int r2=0;r2<4;r2++) acc[h][r2]=0.f;
        #pragma unroll
        for (int i=0;i<12;i++) {
            int e = lane*4 + i*128;
            float4 m[4];
            #pragma unroll
            for (int r2=0;r2<4;r2++) m[r2]=*(const float4*)(mb+(size_t)(s0+r2)*D_+e);
            #pragma unroll
            for (int h=0;h<NH_;h++) {
                float4 gv=*(const float4*)(gs + h*D_ + e);
                #pragma unroll
                for (int r2=0;r2<4;r2++)
                    acc[h][r2] += gv.x*m[r2].x + gv.y*m[r2].y + gv.z*m[r2].z + gv.w*m[r2].w;
            }
        }
        #pragma unroll
        for (int h=0;h<NH_;h++)
            #pragma unroll
            for (int r2=0;r2<4;r2++) {
                float v=acc[h][r2];
                for (int o=16;o;o>>=1) v+=__shfl_xor_sync(~0u,v,o);
                if (lane==0) g_scores[((size_t)b*NH_+h)*S_ + s0+r2] = v*scale;
            }
    }
}

__global__ void __launch_bounds__(256) ca_softmax_kernel()
{
    const int row=blockIdx.x, tid=threadIdx.x;
    float* sp = g_scores + (size_t)row*S_;
    float v = sp[tid];
    __shared__ float red[16];
    int lane=tid&31, wid=tid>>5;
    float m=v;
    for (int o=16;o;o>>=1) m=fmaxf(m,__shfl_xor_sync(~0u,m,o));
    if (lane==0) red[wid]=m;
    __syncthreads();
    if (tid==0){ float mm=red[0]; for(int k=1;k<8;k++) mm=fmaxf(mm,red[k]); red[0]=mm; }
    __syncthreads();
    m=red[0];
    float e=__expf(v-m);
    float s=e;
    for (int o=16;o;o>>=1) s+=__shfl_xor_sync(~0u,s,o);
    __syncthreads();
    if (lane==0) red[8+wid]=s;
    __syncthreads();
    if (tid==0){ float t=0; for(int k=0;k<8;k++) t+=red[8+k]; red[8]=t; }
    __syncthreads();
    sp[tid]=e/red[8];
}

__global__ void __launch_bounds__(256) mtilde_kernel(const float* __restrict__ mem)
{
    __shared__ float at[NH_*S_];
    const int b=blockIdx.x, tid=threadIdx.x;
    for (int i=tid;i<NH_*S_;i+=256) at[i]=g_scores[(size_t)b*NH_*S_+i];
    __syncthreads();
    const int e = blockIdx.y*512 + tid*2;
    const float* mb = mem + (size_t)b*S_*D_;
    float2 acc[NH_];
    #pragma unroll
    for (int h=0;h<NH_;h++){ acc[h].x=0.f; acc[h].y=0.f; }
    for (int s=0;s<S_;s++) {
        float2 mv=*(const float2*)(mb+(size_t)s*D_+e);
        #pragma unroll
        for (int h=0;h<NH_;h++){
            float a=at[h*S_+s];
            acc[h].x=fmaf(a,mv.x,acc[h].x);
            acc[h].y=fmaf(a,mv.y,acc[h].y);
        }
    }
    #pragma unroll
    for (int h=0;h<NH_;h++) {
        *(float2*)(g_mt + (size_t)b*NH_*D_ + h*D_ + e) = acc[h];
        __nv_bfloat16 hx,lx,hy,ly;
        split_bf16(acc[h].x,hx,lx); split_bf16(acc[h].y,hy,ly);
        size_t base = (size_t)b*NH_*3072 + h*3072;
        g_mt2[base + e]   = hx; g_mt2[base + e+1]   = hy;
        g_mt2[base + D_ + e] = lx; g_mt2[base + D_ + e+1] = ly;
    }
}

// x (128 x 768) -> g_a2 [hi 768 | lo 768]
__global__ void __launch_bounds__(256) conv_x_kernel(const float* __restrict__ x)
{
    const int row = blockIdx.x*8 + (threadIdx.x>>5);
    const int lane = threadIdx.x&31;
    const float* p = x + (size_t)row*DIN_;
    __nv_bfloat16* o = g_a2 + (size_t)row*2*DIN_;
    #pragma unroll
    for (int i=0;i<6;i++) {
        int e = lane*4 + i*128;
        float4 v = *(const float4*)(p+e);
        __align__(8) __nv_bfloat16 h[4], l[4];
        float f[4] = {v.x,v.y,v.z,v.w};
        #pragma unroll
        for (int c=0;c<4;c++) split_bf16(f[c], h[c], l[c]);
        *(uint64_t*)(o + e)        = *(uint64_t*)h;
        *(uint64_t*)(o + DIN_ + e) = *(uint64_t*)l;
    }
}

__global__ void __launch_bounds__(256) pool_reduce_kernel(
    const float* __restrict__ ls, float* __restrict__ out)
{
    const int j=blockIdx.x, i=blockIdx.y, s=threadIdx.x;
    float Sv = g_S[(size_t)i*BS_ + j*S_ + s];
    float Cv = g_S[(size_t)(B_+i)*BS_ + j*S_ + s];
    float nmv = g_nm[j*S_+s];
    __shared__ float red[16];
    int lane=s&31, wid=s>>5;
    float m=Sv;
    for (int o=16;o;o>>=1) m=fmaxf(m,__shfl_xor_sync(~0u,m,o));
    if (lane==0) red[wid]=m;
    __syncthreads();
    if (s==0){ float mm=red[0]; for(int k=1;k<8;k++) mm=fmaxf(mm,red[k]); red[0]=mm; }
    __syncthreads();
    m=red[0];
    float e = expf(Sv-m);
    float t1=e, t2=e*Cv/nmv;
    for (int o=16;o;o>>=1){ t1+=__shfl_xor_sync(~0u,t1,o); t2+=__shfl_xor_sync(~0u,t2,o); }
    __syncthreads();
    if (lane==0){ red[wid]=t1; red[8+wid]=t2; }
    __syncthreads();
    if (s==0) {
        float Z=0.f, Wv=0.f;
        for (int k=0;k<8;k++){ Z+=red[k]; Wv+=red[8+k]; }
        float val = expf(ls[0]) * Wv / (Z * g_nx[i]);
        out[(size_t)i*B_ + j] = val;
        out[(size_t)B_*B_ + (size_t)j*B_ + i] = val;
    }
}

__global__ void copy_xsq_kernel(float* __restrict__ out)
{
    int idx = blockIdx.x*256 + threadIdx.x;
    out[(size_t)2*B_*B_ + idx] = g_xsq[idx];
}

// =================== host =======================================================
template<typename T> static float* symf(T& s){ void* p=nullptr; cudaGetSymbolAddress(&p, s); return (float*)p; }
template<typename T> static __nv_bfloat16* symb(T& s){ void* p=nullptr; cudaGetSymbolAddress(&p, s); return (__nv_bfloat16*)p; }

extern "C" void kernel_launch(void* const* d_in, const int* in_sizes, int n_in,
                              void* d_out, int out_size)
{
    const float* x        =(const float*)d_in[0];
    const float* mem      =(const float*)d_in[1];
    const float* emb_w    =(const float*)d_in[2];
    const float* emb_b    =(const float*)d_in[3];
    const float* sa_in_w  =(const float*)d_in[4];
    const float* sa_in_b  =(const float*)d_in[5];
    const float* sa_out_w =(const float*)d_in[6];
    const float* sa_out_b =(const float*)d_in[7];
    const float* ca_in_w  =(const float*)d_in[8];
    const float* ca_in_b  =(const float*)d_in[9];
    const float* ca_out_w =(const float*)d_in[10];
    const float* ca_out_b =(const float*)d_in[11];
    const float* lin1_w   =(const float*)d_in[12];
    const float* lin1_b   =(const float*)d_in[13];
    const float* lin2_w   =(const float*)d_in[14];
    const float* lin2_b   =(const float*)d_in[15];
    const float* ln1_w    =(const float*)d_in[16];
    const float* ln1_b    =(const float*)d_in[17];
    const float* ln2_w    =(const float*)d_in[18];
    const float* ln2_b    =(const float*)d_in[19];
    const float* ln3_w    =(const float*)d_in[20];
    const float* ln3_b    =(const float*)d_in[21];
    const float* fin_w    =(const float*)d_in[22];
    const float* fin_b    =(const float*)d_in[23];
    const float* attn_in_w=(const float*)d_in[24];
    const float* attn_in_b=(const float*)d_in[25];
    const float* logit_sc =(const float*)d_in[26];
    float* out = (float*)d_out;

    float* t0 = symf(g_t0);  float* v   = symf(g_v);   float* sa  = symf(g_sa);
    float* t1 = symf(g_t1);  float* qp  = symf(g_qp);  float* gg  = symf(g_g);
    float* o   = symf(g_o);  float* ca  = symf(g_ca);
    float* t2 = symf(g_t2);  float* h1  = symf(g_h1);  float* ff  = symf(g_ff);
    float* t3 = symf(g_t3);  float* xsq = symf(g_xsq); float* qp2 = symf(g_qp2);
    float* qt = symf(g_qt);  float* nx  = symf(g_nx);  float* pt  = symf(g_part);
    __nv_bfloat16* a2   = symb(g_a2);
    __nv_bfloat16* mt2  = symb(g_mt2);
    __nv_bfloat16* wEmb = symb(g_w_emb);
    __nv_bfloat16* wSaV = symb(g_w_savv);
    __nv_bfloat16* wSaO = symb(g_w_saout);
    __nv_bfloat16* wCaQ = symb(g_w_cawq);
    __nv_bfloat16* wCaV = symb(g_w_cawv);
    __nv_bfloat16* wCaO = symb(g_w_caout);
    __nv_bfloat16* wL1  = symb(g_w_lin1);
    __nv_bfloat16* wL2  = symb(g_w_lin2);
    __nv_bfloat16* wAtQ = symb(g_w_attnq);

    const float* NOB = nullptr;
    __nv_bfloat16* NOA = nullptr;

    // 0. conversions (memory + weights + x)
    conv_mem_kernel<<<BS_/8, 256>>>(mem);
    conv_w_kernel<<<1536/8, 256>>>(emb_w, wEmb, DIN_);
    conv_w_kernel<<<1536/8, 256>>>(sa_in_w + (size_t)2*D_*D_, wSaV, D_);
    conv_w_kernel<<<1536/8, 256>>>(sa_out_w, wSaO, D_);
    conv_w_kernel<<<1536/8, 256>>>(ca_in_w, wCaQ, D_);
    conv_w_kernel<<<1536/8, 256>>>(ca_in_w + (size_t)2*D_*D_, wCaV, D_);
    conv_w_kernel<<<1536/8, 256>>>(ca_out_w, wCaO, D_);
    conv_w_kernel<<<2048/8, 256>>>(lin1_w, wL1, D_);
    conv_w_kernel<<<1536/8, 256>>>(lin2_w, wL2, FF_);
    conv_w_kernel<<<1536/8, 256>>>(attn_in_w, wAtQ, D_);
    conv_x_kernel<<<16, 256>>>(x);

    // 1. t0 = x @ emb_w.T + emb_b  (tc, K=768)
    gemm64_tc<<<dim3(24,6,1),256>>>(a2, 2*DIN_, 0, wEmb, 2*DIN_, 0, pt, DIN_);
    reduce_ks<<<dim3((B_*D_+255)/256,1),256>>>(pt, emb_b, 0, t0, D_, 0, 128, 1536, 6, 0,
                                               a2, 2*D_, D_, 0);
    // 2. SA (L=1): v = t0 @ wv.T + bv ; sa = v @ out_w.T + out_b
    gemm64_tc<<<dim3(24,6,1),256>>>(a2, 2*D_, 0, wSaV, 2*D_, 0, pt, D_);
    reduce_ks<<<dim3((B_*D_+255)/256,1),256>>>(pt, sa_in_b+2*D_, 0, v, D_, 0, 128, 1536, 6, 0,
                                               a2, 2*D_, D_, 0);
    gemm64_tc<<<dim3(24,6,1),256>>>(a2, 2*D_, 0, wSaO, 2*D_, 0, pt, D_);
    reduce_ks<<<dim3((B_*D_+255)/256,1),256>>>(pt, sa_out_b, 0, sa, D_, 0, 128, 1536, 6, 0,
                                               NOA, 0, 0, 0);
    // 3. t1 = LN(t0 + sa) (+a2)
    ln_kernel<<<B_, 256>>>(t0, sa, ln1_w, ln1_b, t1, nullptr, a2);
    // 4. CA q-proj (tc), then g[b,h] = qp_h @ wk_h (fp32 nn, batched heads)
    gemm64_tc<<<dim3(24,6,1),256>>>(a2, 2*D_, 0, wCaQ, 2*D_, 0, pt, D_);
    reduce_ks<<<dim3((B_*D_+255)/256,1),256>>>(pt, ca_in_b, 0, qp, D_, 0, 128, 1536, 6, 0,
                                               NOA, 0, 0, 0);
    gemm_nn<64,64,16,4,4><<<dim3(D_/64, B_/64, NH_), 256>>>(
        qp, D_, DH_, ca_in_w + (size_t)D_*D_, D_, (long long)DH_*D_,
        NOB, 0, gg, NH_*D_, D_, DH_, 1, nullptr);
    // 5. CA scores / softmax / weighted memory (+mt2)
    ca_scores_kernel<<<dim3(B_,2), 256>>>(mem);
    ca_softmax_kernel<<<B_*NH_, 256>>>();
    mtilde_kernel<<<dim3(B_,3), 256>>>(mem);
    // 6. o_h = m~_h @ wv_h.T + bv_h (tc batched); ca = o @ out_w.T + out_b
    gemm64_tc<<<dim3(3,6,NH_),256>>>(mt2, NH_*3072, 3072, wCaV, 2*D_, (long long)DH_*2*D_, pt, D_);
    reduce_ks<<<dim3((128*DH_+255)/256,NH_),256>>>(pt, ca_in_b+2*D_, DH_, o, D_, DH_, 128, DH_, 6, 0,
                                                   a2, 2*D_, D_, DH_);
    gemm64_tc<<<dim3(24,6,1),256>>>(a2, 2*D_, 0, wCaO, 2*D_, 0, pt, D_);
    reduce_ks<<<dim3((B_*D_+255)/256,1),256>>>(pt, ca_out_b, 0, ca, D_, 0, 128, 1536, 6, 0,
                                               NOA, 0, 0, 0);
    // 7. t2 = LN(t1 + ca) (+a2)
    ln_kernel<<<B_, 256>>>(t1, ca, ln2_w, ln2_b, t2, nullptr, a2);
    // 8. FF: lin1 (relu, +a2) ; lin2
    gemm64_tc<<<dim3(32,6,1),256>>>(a2, 2*D_, 0, wL1, 2*D_, 0, pt, D_);
    reduce_ks<<<dim3((B_*FF_+255)/256,1),256>>>(pt, lin1_b, 0, h1, FF_, 0, 128, 2048, 6, 1,
                                                a2, 2*FF_, FF_, 0);
    gemm64_tc<<<dim3(24,6,1),256>>>(a2, 2*FF_, 0, wL2, 2*FF_, 0, pt, FF_);
    reduce_ks<<<dim3((B_*D_+255)/256,1),256>>>(pt, lin2_b, 0, ff, D_, 0, 128, 1536, 6, 0,
                                               NOA, 0, 0, 0);
    // 9. t3 = LN(t2 + ff) ; x_sq = LN(t3) (+a2, +norm)
    ln_kernel<<<B_, 256>>>(t2, ff, ln3_w, ln3_b, t3, nullptr, nullptr);
    ln_kernel<<<B_, 256>>>(t3, nullptr, fin_w, fin_b, xsq, nx, a2);
    // 10. pooling projections: qp2 (tc) ; qt = qp2@wk2 (fp32 nn KS=6 + reduce)
    gemm64_tc<<<dim3(24,6,1),256>>>(a2, 2*D_, 0, wAtQ, 2*D_, 0, pt, D_);
    reduce_ks<<<dim3((B_*D_+255)/256,1),256>>>(pt, attn_in_b, 0, qp2, D_, 0, 128, 1536, 6, 0,
                                               NOA, 0, 0, 0);
    gemm_nn<64,64,16,4,4><<<dim3(D_/64, B_/64, 6), 256>>>(
        qp2, D_, 0, attn_in_w + (size_t)D_*D_, D_, 0,
        NOB, 0, nullptr, 0, 0, D_, 6, pt);
    reduce_ks<<<dim3((B_*D_+255)/256,1),256>>>(pt, NOB, 0, qt, D_, 0, 128, 1536, 6, 0,
                                               NOA, 0, 0, 0);

    // 11. A -> bf16 hi/lo ; big mma.sync GEMM (3-product split)
    conv_a_kernel<<<32, 256>>>();
    bigmm_kernel<<<dim3(BS_/128, 2), 256>>>();

    // 12. final softmax-weighted cosine reduce; third output
    pool_reduce_kernel<<<dim3(B_, B_), 256>>>(logit_sc, out);
    copy_xsq_kernel<<<(B_*D_)/256, 256>>>(out);

    (void)in_sizes; (void)n_in; (void)out_size;
}

// round 8
// speedup vs baseline: 1.2789x; 1.0128x over previous
#include <cuda_runtime.h>
#include <cuda_bf16.h>
#include <math.h>
#include <stdint.h>

// Problem constants
#define B_    128
#define S_    256
#define D_    1536
#define DIN_  768
#define NH_   8
#define DH_   192
#define FF_   2048
#define BS_   (B_*S_)   // 32768
#define KP_   3072      // hi||lo width = 2*D_

// ---------------- scratch (device globals; no cudaMalloc allowed) -------------
__device__ float g_t0 [B_*D_];
__device__ float g_v  [B_*D_];
__device__ float g_t1 [B_*D_];
__device__ float g_qp [B_*D_];
__device__ float g_g  [B_*NH_*D_];
__device__ float g_scores[B_*NH_*S_];
__device__ float g_mt [B_*NH_*D_];
__device__ float g_o  [B_*D_];
__device__ float g_t2 [B_*D_];
__device__ float g_h1 [B_*FF_];
__device__ float g_t3 [B_*D_];
__device__ float g_xsq[B_*D_];
__device__ float g_qp2[B_*D_];
__device__ float g_qt [B_*D_];
__device__ float g_S  [(size_t)2*B_*BS_];
__device__ float g_nm [B_*S_];
__device__ float g_nx [B_];
__device__ float g_part[1600*1024];                 // K-split partials
__device__ __nv_bfloat16 g_mb[(size_t)BS_*KP_];     // memory hi||lo bf16
__device__ __nv_bfloat16 g_ab[256*KP_];             // bigmm A hi||lo bf16
// activation + weight bf16 (hi||lo) buffers
__device__ __nv_bfloat16 g_a2 [128*4096];
__device__ __nv_bfloat16 g_mt2[128*NH_*3072];
__device__ __nv_bfloat16 g_w_emb  [1536*1536];
__device__ __nv_bfloat16 g_w_savv [1536*3072];
__device__ __nv_bfloat16 g_w_saout[1536*3072];
__device__ __nv_bfloat16 g_w_cawq [1536*3072];
__device__ __nv_bfloat16 g_w_cawv [1536*3072];
__device__ __nv_bfloat16 g_w_caout[1536*3072];
__device__ __nv_bfloat16 g_w_lin1 [2048*3072];
__device__ __nv_bfloat16 g_w_lin2 [1536*4096];
__device__ __nv_bfloat16 g_w_attnq[1536*3072];

// =================== common mma.sync macros =====================================
#define LDSM4(R0,R1,R2,R3,ADDR) \
    asm volatile("ldmatrix.sync.aligned.m8n8.x4.shared.b16 {%0,%1,%2,%3}, [%4];" \
        : "=r"(R0),"=r"(R1),"=r"(R2),"=r"(R3) : "r"(ADDR))
#define MMA16816(D,A,B0,B1) \
    asm volatile("mma.sync.aligned.m16n8k16.row.col.f32.bf16.bf16.f32 " \
        "{%0,%1,%2,%3}, {%4,%5,%6,%7}, {%8,%9}, {%0,%1,%2,%3};" \
        : "+f"((D)[0]),"+f"((D)[1]),"+f"((D)[2]),"+f"((D)[3]) \
        : "r"((A)[0]),"r"((A)[1]),"r"((A)[2]),"r"((A)[3]),"r"(B0),"r"(B1))
#define CPA16(DST,SRC) \
    asm volatile("cp.async.ca.shared.global [%0], [%1], 16;" \
        :: "r"((uint32_t)__cvta_generic_to_shared(DST)), "l"(SRC))

__device__ __forceinline__ void split_bf16(float f, __nv_bfloat16& h, __nv_bfloat16& l){
    h = __float2bfloat16(f);
    l = __float2bfloat16(f - __bfloat162float(h));
}

// =================== gemm64_tc: tensor small GEMM (proven R7) ===================
#define GSLD 40

__global__ void __launch_bounds__(256) gemm64_tc(
    const __nv_bfloat16* __restrict__ A2, int lda2, long long strideA2,
    const __nv_bfloat16* __restrict__ W2, int ldw2, long long strideW2,
    float* __restrict__ partial, int K)
{
    __shared__ __align__(16) __nv_bfloat16 sA[2][128*GSLD];
    __shared__ __align__(16) __nv_bfloat16 sW[2][64*GSLD];
    const int tid = threadIdx.x;
    const int warp = tid>>5, lane = tid&31;
    const int wm = warp>>1, wn = warp&1;
    const int bn = blockIdx.x*64;
    const int KS = gridDim.y;
    const int z  = blockIdx.z;
    const int Ntot = gridDim.x*64;
    A2 += (long long)z*strideA2;
    W2 += (long long)z*strideW2;
    const int segc = K/32;
    const int nck  = (3*segc)/KS;
    const int g0   = blockIdx.y*nck;

    float acc[2][4][4];
    #pragma unroll
    for (int i=0;i<2;i++)
        #pragma unroll
        for (int j=0;j<4;j++)
            #pragma unroll
            for (int c=0;c<4;c++) acc[i][j][c]=0.f;

    #define G64_LOAD(BUF,C) do {                                              \
        int g_   = g0 + (C);                                                   \
        int seg_ = g_ / segc;                                                  \
        int k0_  = (g_ - seg_*segc)*32;                                        \
        int aOff_ = (seg_==2) ? K : 0;                                         \
        int bOff_ = (seg_==1) ? K : 0;                                         \
        _Pragma("unroll")                                                      \
        for (int i=0;i<2;i++) {                                                \
            int l = tid + i*256;                                               \
            int r = l>>2, sg = l&3;                                            \
            CPA16(&sA[BUF][r*GSLD + sg*8],                                     \
                  A2 + (size_t)r*lda2 + aOff_ + k0_ + sg*8);                   \
        }                                                                      \
        { int r = tid>>2, sg = tid&3;                                          \
          CPA16(&sW[BUF][r*GSLD + sg*8],                                       \
                W2 + (size_t)(bn+r)*ldw2 + bOff_ + k0_ + sg*8); }              \
        asm volatile("cp.async.commit_group;");                                \
    } while(0)

    G64_LOAD(0, 0);
    for (int c=0; c<nck; c++) {
        int buf = c & 1;
        asm volatile("cp.async.wait_group 0;");
        __syncthreads();
        if (c+1 < nck) G64_LOAD(buf^1, c+1);
        #pragma unroll
        for (int kk=0; kk<2; kk++) {
            const int kb = kk*16;
            uint32_t a[2][4], b[4][2];
            #pragma unroll
            for (int mf=0; mf<2; mf++) {
                int row = wm*32 + mf*16 + (lane&15);
                int ko  = kb + ((lane>>4)<<3);
                uint32_t ad = (uint32_t)__cvta_generic_to_shared(&sA[buf][row*GSLD + ko]);
                LDSM4(a[mf][0],a[mf][1],a[mf][2],a[mf][3], ad);
            }
            #pragma unroll
            for (int p=0; p<2; p++) {
                int nrow = wn*32 + p*16 + ((lane>>4)<<3) + (lane&7);
                int ko   = kb + (((lane>>3)&1)<<3);
                uint32_t ad = (uint32_t)__cvta_generic_to_shared(&sW[buf][nrow*GSLD + ko]);
                LDSM4(b[2*p][0],b[2*p][1],b[2*p+1][0],b[2*p+1][1], ad);
            }
            #pragma unroll
            for (int mf=0; mf<2; mf++)
                #pragma unroll
                for (int nf=0; nf<4; nf++)
                    MMA16816(acc[mf][nf], a[mf], b[nf][0], b[nf][1]);
        }
        __syncthreads();
    }
    const size_t pbase = (size_t)(z*KS + blockIdx.y)*128;
    #pragma unroll
    for (int mf=0; mf<2; mf++) {
        int m = wm*32 + mf*16 + (lane>>2);
        #pragma unroll
        for (int nf=0; nf<4; nf++) {
            int n = bn + wn*32 + nf*8 + ((lane&3)<<1);
            *(float2*)&partial[(pbase + m)*Ntot + n]     = make_float2(acc[mf][nf][0], acc[mf][nf][1]);
            *(float2*)&partial[(pbase + m+8)*Ntot + n]   = make_float2(acc[mf][nf][2], acc[mf][nf][3]);
        }
    }
}

// =================== reduce K-split partials (+bias/relu, + bf16 a2 out) ========
__global__ void __launch_bounds__(256) reduce_ks(
    const float* __restrict__ partial, const float* __restrict__ bias, int strideBias,
    float* __restrict__ C, int ldc, long long strideC,
    int Mtot, int Ntot, int KS, int relu,
    __nv_bfloat16* __restrict__ a2, int lda2, int loOff, int a2strideZ)
{
    const int zb = blockIdx.y;
    int idx = blockIdx.x*256 + threadIdx.x;
    if (idx >= Mtot*Ntot) return;
    int m = idx / Ntot, n = idx % Ntot;
    float s = 0.f;
    for (int c=0;c<KS;c++)
        s += partial[((size_t)(zb*KS+c)*Mtot + m)*Ntot + n];
    if (bias) s += bias[(size_t)zb*strideBias + n];
    if (relu) s = fmaxf(s, 0.f);
    C[(size_t)zb*strideC + (size_t)m*ldc + n] = s;
    if (a2) {
        __nv_bfloat16 h,l; split_bf16(s,h,l);
        size_t base = (size_t)zb*a2strideZ + (size_t)m*lda2 + n;
        a2[base] = h;
        a2[base + loOff] = l;
    }
}

// =================== fused reduce + residual + LayerNorm (+a2) ==================
// One block per row (Mtot=128, N=D_). value = sum_c partial + bias + resid.
__global__ void __launch_bounds__(256) reduce_ln(
    const float* __restrict__ partial, const float* __restrict__ bias,
    const float* __restrict__ resid,
    const float* __restrict__ w, const float* __restrict__ bb,
    float* __restrict__ out, __nv_bfloat16* __restrict__ a2, int KS)
{
    const int row = blockIdx.x, tid = threadIdx.x;
    float vals[6]; float s1=0.f, s2=0.f;
    #pragma unroll
    for (int i=0;i<6;i++) {
        int e = tid + i*256;
        float s = bias ? bias[e] : 0.f;
        for (int c=0;c<KS;c++)
            s += partial[((size_t)c*128 + row)*D_ + e];
        if (resid) s += resid[(size_t)row*D_ + e];
        vals[i]=s; s1+=s; s2+=s*s;
    }
    __shared__ float red[16];
    int lane=tid&31, wid=tid>>5;
    for (int o=16;o;o>>=1){ s1+=__shfl_xor_sync(~0u,s1,o); s2+=__shfl_xor_sync(~0u,s2,o); }
    if (lane==0){ red[wid]=s1; red[8+wid]=s2; }
    __syncthreads();
    if (tid==0){ float a1=0,a2s=0; for(int k=0;k<8;k++){a1+=red[k];a2s+=red[8+k];} red[0]=a1; red[8]=a2s; }
    __syncthreads();
    float mean = red[0]*(1.0f/D_);
    float var  = red[8]*(1.0f/D_) - mean*mean;
    float rstd = rsqrtf(var + 1e-5f);
    #pragma unroll
    for (int i=0;i<6;i++) {
        int e = tid + i*256;
        float y = (vals[i]-mean)*rstd*w[e] + bb[e];
        out[(size_t)row*D_+e] = y;
        if (a2) {
            __nv_bfloat16 h,l; split_bf16(y,h,l);
            a2[(size_t)row*2*D_ + e]      = h;
            a2[(size_t)row*2*D_ + D_ + e] = l;
        }
    }
}

// =================== fp32 gemm_nn (for gg / qt) ==================================
template<int BM,int BN,int BK,int TM,int TN>
__global__ void __launch_bounds__(256) gemm_nn(
    const float* __restrict__ A, int lda, long long strideA,
    const float* __restrict__ W, int ldw, long long strideW,
    const float* __restrict__ bias, int strideBias,
    float* __restrict__ C, int ldc, long long strideC,
    int K, int KS, float* __restrict__ partial)
{
    const int zb = blockIdx.z / KS, chunk = blockIdx.z % KS;
    const int Kc = K / KS;
    A += (long long)zb*strideA + chunk*Kc;
    W += (long long)zb*strideW + (size_t)chunk*Kc*ldw;
    C += (long long)zb*strideC;
    if (bias) bias += (long long)zb*strideBias;

    __shared__ float sA[BK][BM];
    __shared__ float sW[BK][BN];
    const int tid = threadIdx.x;
    const int bm = blockIdx.y*BM, bn = blockIdx.x*BN;
    const int tx = tid % (BN/TN), ty = tid / (BN/TN);
    float acc[TM][TN];
    #pragma unroll
    for (int i=0;i<TM;i++)
        #pragma unroll
        for (int j=0;j<TN;j++) acc[i][j]=0.f;

    for (int k0=0;k0<Kc;k0+=BK) {
        for (int i=tid;i<BM*(BK/4);i+=256) {
            int r=i/(BK/4), kv=i%(BK/4);
            float4 v=*(const float4*)(A+(size_t)(bm+r)*lda + k0 + kv*4);
            sA[kv*4+0][r]=v.x; sA[kv*4+1][r]=v.y; sA[kv*4+2][r]=v.z; sA[kv*4+3][r]=v.w;
        }
        for (int i=tid;i<BK*(BN/4);i+=256) {
            int kk=i/(BN/4), nv=i%(BN/4);
            *(float4*)&sW[kk][nv*4] = *(const float4*)(W+(size_t)(k0+kk)*ldw + bn + nv*4);
        }
        __syncthreads();
        #pragma unroll
        for (int kk=0;kk<BK;kk++) {
            float a[TM], w[TN];
            #pragma unroll
            for (int i=0;i<TM;i+=4) *(float4*)&a[i] = *(const float4*)&sA[kk][ty*TM+i];
            #pragma unroll
            for (int j=0;j<TN;j+=4) *(float4*)&w[j] = *(const float4*)&sW[kk][tx*TN+j];
            #pragma unroll
            for (int i=0;i<TM;i++)
                #pragma unroll
                for (int j=0;j<TN;j++) acc[i][j] = fmaf(a[i], w[j], acc[i][j]);
        }
        __syncthreads();
    }
    if (partial) {
        const int Mtot = gridDim.y*BM, Ntot = gridDim.x*BN;
        #pragma unroll
        for (int i=0;i<TM;i++) {
            int m = bm + ty*TM + i;
            #pragma unroll
            for (int j=0;j<TN;j+=4)
                *(float4*)&partial[((size_t)blockIdx.z*Mtot + m)*Ntot + bn + tx*TN + j]
                    = *(float4*)&acc[i][j];
        }
    } else {
        #pragma unroll
        for (int i=0;i<TM;i++) {
            int gm = bm + ty*TM + i;
            #pragma unroll
            for (int j=0;j<TN;j++) {
                int gn = bn + tx*TN + j;
                C[(size_t)gm*ldc + gn] = acc[i][j] + (bias ? bias[gn] : 0.f);
            }
        }
    }
}

// =================== conversions =================================================
__global__ void __launch_bounds__(256) conv_mem_kernel(const float* __restrict__ mem)
{
    const int row = blockIdx.x*8 + (threadIdx.x>>5);
    const int lane = threadIdx.x&31;
    const float* p = mem + (size_t)row*D_;
    __nv_bfloat16* oh = g_mb + (size_t)row*KP_;
    float ss = 0.f;
    #pragma unroll
    for (int i=0;i<12;i++) {
        int e = lane*4 + i*128;
        float4 v = *(const float4*)(p+e);
        ss += v.x*v.x + v.y*v.y + v.z*v.z + v.w*v.w;
        __align__(8) __nv_bfloat16 h[4], l[4];
        float f[4] = {v.x,v.y,v.z,v.w};
        #pragma unroll
        for (int c=0;c<4;c++) split_bf16(f[c], h[c], l[c]);
        *(uint64_t*)(oh + e)       = *(uint64_t*)h;
        *(uint64_t*)(oh + D_ + e)  = *(uint64_t*)l;
    }
    for (int o=16;o;o>>=1) ss += __shfl_xor_sync(~0u, ss, o);
    if (lane==0) g_nm[row] = sqrtf(ss);
}

// batched weight conversion: 9 jobs in one launch. blockIdx.y = job.
struct ConvJob { const float* src; __nv_bfloat16* dst; int K; int rows; };
struct ConvJobs { ConvJob j[9]; };

__global__ void __launch_bounds__(256) conv_w_all(ConvJobs jobs)
{
    const ConvJob jb = jobs.j[blockIdx.y];
    const int row = blockIdx.x*8 + (threadIdx.x>>5);
    if (row >= jb.rows) return;
    const int lane = threadIdx.x&31;
    const int K = jb.K;
    const float* p = jb.src + (size_t)row*K;
    __nv_bfloat16* o = jb.dst + (size_t)row*2*K;
    for (int e=lane*4; e<K; e+=128) {
        float4 v = *(const float4*)(p+e);
        __align__(8) __nv_bfloat16 h[4], l[4];
        float f[4] = {v.x,v.y,v.z,v.w};
        #pragma unroll
        for (int c=0;c<4;c++) split_bf16(f[c], h[c], l[c]);
        *(uint64_t*)(o + e)     = *(uint64_t*)h;
        *(uint64_t*)(o + K + e) = *(uint64_t*)l;
    }
}

__global__ void __launch_bounds__(256) conv_a_kernel()
{
    const int row = blockIdx.x*8 + (threadIdx.x>>5);
    const int lane = threadIdx.x&31;
    const float sc = (row < B_) ? rsqrtf((float)D_) : 1.0f;
    const float* p = (row < B_) ? (g_qt + (size_t)row*D_) : (g_xsq + (size_t)(row-B_)*D_);
    __nv_bfloat16* oh = g_ab + (size_t)row*KP_;
    #pragma unroll
    for (int i=0;i<12;i++) {
        int e = lane*4 + i*128;
        float4 v = *(const float4*)(p+e);
        float f[4] = {v.x*sc, v.y*sc, v.z*sc, v.w*sc};
        __align__(8) __nv_bfloat16 h[4], l[4];
        #pragma unroll
        for (int c=0;c<4;c++) split_bf16(f[c], h[c], l[c]);
        *(uint64_t*)(oh + e)      = *(uint64_t*)h;
        *(uint64_t*)(oh + D_ + e) = *(uint64_t*)l;
    }
}

// x (128 x 768) -> g_a2 [hi 768 | lo 768]
__global__ void __launch_bounds__(256) conv_x_kernel(const float* __restrict__ x)
{
    const int row = blockIdx.x*8 + (threadIdx.x>>5);
    const int lane = threadIdx.x&31;
    const float* p = x + (size_t)row*DIN_;
    __nv_bfloat16* o = g_a2 + (size_t)row*2*DIN_;
    #pragma unroll
    for (int i=0;i<6;i++) {
        int e = lane*4 + i*128;
        float4 v = *(const float4*)(p+e);
        __align__(8) __nv_bfloat16 h[4], l[4];
        float f[4] = {v.x,v.y,v.z,v.w};
        #pragma unroll
        for (int c=0;c<4;c++) split_bf16(f[c], h[c], l[c]);
        *(uint64_t*)(o + e)        = *(uint64_t*)h;
        *(uint64_t*)(o + DIN_ + e) = *(uint64_t*)l;
    }
}

// =================== big mma.sync GEMM (proven R4 version) ======================
#define SLD 40
#define SEGC 48

__global__ void __launch_bounds__(256) bigmm_kernel()
{
    __shared__ __align__(16) __nv_bfloat16 sA[2][128*SLD];
    __shared__ __align__(16) __nv_bfloat16 sB[2][128*SLD];
    const int tid = threadIdx.x;
    const int warp = tid>>5, lane = tid&31;
    const int wm = warp>>2, wn = warp&3;
    const int nbase = blockIdx.x*128, mbase = blockIdx.y*128;

    float acc[4][4][4];
    #pragma unroll
    for (int i=0;i<4;i++)
        #pragma unroll
        for (int j=0;j<4;j++)
            #pragma unroll
            for (int c=0;c<4;c++) acc[i][j][c]=0.f;

    const int r0 = tid>>1;
    const int seg0 = (tid&1)*2;

    #define LOAD_TILES(BUF,KC) do {                                              \
        int seg_ = (KC)/SEGC;                                                     \
        int k0_  = ((KC)%SEGC)*32;                                                \
        int aOff_ = (seg_==2) ? D_ : 0;                                           \
        int bOff_ = (seg_==1) ? D_ : 0;                                           \
        _Pragma("unroll")                                                        \
        for (int i=0;i<2;i++) {                                                  \
            int seg = seg0 + i;                                                  \
            CPA16(&sA[BUF][r0*SLD + seg*8],                                      \
                  g_ab + (size_t)(mbase+r0)*KP_ + aOff_ + k0_ + seg*8);          \
            CPA16(&sB[BUF][r0*SLD + seg*8],                                      \
                  g_mb + (size_t)(nbase+r0)*KP_ + bOff_ + k0_ + seg*8);          \
        }                                                                        \
        asm volatile("cp.async.commit_group;");                                  \
    } while(0)

    LOAD_TILES(0, 0);
    const int KC = 3*SEGC;
    for (int kc=0; kc<KC; kc++) {
        int buf = kc & 1;
        asm volatile("cp.async.wait_group 0;");
        __syncthreads();
        if (kc+1 < KC) LOAD_TILES(buf^1, kc+1);
        #pragma unroll
        for (int kk=0; kk<2; kk++) {
            const int kb = kk*16;
            uint32_t a[4][4], b[4][2];
            #pragma unroll
            for (int mf=0; mf<4; mf++) {
                int row = wm*64 + mf*16 + (lane&15);
                int ko  = kb + ((lane>>4)<<3);
                uint32_t ad = (uint32_t)__cvta_generic_to_shared(&sA[buf][row*SLD + ko]);
                LDSM4(a[mf][0],a[mf][1],a[mf][2],a[mf][3], ad);
            }
            #pragma unroll
            for (int p=0; p<2; p++) {
                int nrow = wn*32 + p*16 + ((lane>>4)<<3) + (lane&7);
                int ko   = kb + (((lane>>3)&1)<<3);
                uint32_t ad = (uint32_t)__cvta_generic_to_shared(&sB[buf][nrow*SLD + ko]);
                LDSM4(b[2*p][0],b[2*p][1],b[2*p+1][0],b[2*p+1][1], ad);
            }
            #pragma unroll
            for (int mf=0; mf<4; mf++)
                #pragma unroll
                for (int nf=0; nf<4; nf++)
                    MMA16816(acc[mf][nf], a[mf], b[nf][0], b[nf][1]);
        }
        __syncthreads();
    }
    #pragma unroll
    for (int mf=0; mf<4; mf++) {
        int m = mbase + wm*64 + mf*16 + (lane>>2);
        #pragma unroll
        for (int nf=0; nf<4; nf++) {
            int n = nbase + wn*32 + nf*8 + ((lane&3)<<1);
            *(float2*)&g_S[(size_t)m*BS_ + n]     = make_float2(acc[mf][nf][0], acc[mf][nf][1]);
            *(float2*)&g_S[(size_t)(m+8)*BS_ + n] = make_float2(acc[mf][nf][2], acc[mf][nf][3]);
        }
    }
}

// =================== LayerNorm (standalone, for fin) ============================
__global__ void __launch_bounds__(256) ln_kernel(
    const float* __restrict__ a, const float* __restrict__ r,
    const float* __restrict__ w, const float* __restrict__ bb,
    float* __restrict__ out, float* __restrict__ norm_out,
    __nv_bfloat16* __restrict__ a2)
{
    const int row = blockIdx.x, tid = threadIdx.x;
    const float* ap = a + (size_t)row*D_;
    const float* rp = r ? r + (size_t)row*D_ : nullptr;
    float vals[6]; float s1=0.f, s2=0.f;
    #pragma unroll
    for (int i=0;i<6;i++) {
        int e = tid + i*256;
        float v = ap[e] + (rp ? rp[e] : 0.f);
        vals[i]=v; s1+=v; s2+=v*v;
    }
    __shared__ float red[16];
    int lane=tid&31, wid=tid>>5;
    for (int o=16;o;o>>=1){ s1+=__shfl_xor_sync(~0u,s1,o); s2+=__shfl_xor_sync(~0u,s2,o); }
    if (lane==0){ red[wid]=s1; red[8+wid]=s2; }
    __syncthreads();
    if (tid==0){ float a1=0,a2s=0; for(int k=0;k<8;k++){a1+=red[k];a2s+=red[8+k];} red[0]=a1; red[8]=a2s; }
    __syncthreads();
    float mean = red[0]*(1.0f/D_);
    float var  = red[8]*(1.0f/D_) - mean*mean;
    float rstd = rsqrtf(var + 1e-5f);
    float ss = 0.f;
    #pragma unroll
    for (int i=0;i<6;i++) {
        int e = tid + i*256;
        float y = (vals[i]-mean)*rstd*w[e] + bb[e];
        out[(size_t)row*D_+e] = y;
        if (a2) {
            __nv_bfloat16 h,l; split_bf16(y,h,l);
            a2[(size_t)row*2*D_ + e]      = h;
            a2[(size_t)row*2*D_ + D_ + e] = l;
        }
        ss += y*y;
    }
    if (norm_out) {
        for (int o=16;o;o>>=1) ss+=__shfl_xor_sync(~0u,ss,o);
        __syncthreads();
        if (lane==0) red[wid]=ss;
        __syncthreads();
        if (tid==0){ float t=0; for(int k=0;k<8;k++) t+=red[k]; norm_out[row]=sqrtf(t); }
    }
}

__global__ void __launch_bounds__(256) ca_scores_kernel(const float* __restrict__ mem)
{
    __shared__ float gs[NH_*D_];
    const int b = blockIdx.x, tid = threadIdx.x;
    const float4* gsrc = (const float4*)(g_g + (size_t)b*NH_*D_);
    for (int i=tid;i<NH_*D_/4;i+=256) ((float4*)gs)[i]=gsrc[i];
    __syncthreads();
    const int warp=tid>>5, lane=tid&31;
    const float* mb = mem + (size_t)b*S_*D_;
    const float scale = rsqrtf((float)DH_);
    const int sbase = blockIdx.y*128 + warp*16;
    for (int grp=0;grp<4;grp++) {
        int s0 = sbase + grp*4;
        float acc[NH_][4];
        #pragma unroll
        for (int h=0;h<NH_;h++)
            #pragma unroll
            for (int r2=0;r2<4;r2++) acc[h][r2]=0.f;
        #pragma unroll
        for (int i=0;i<12;i++) {
            int e = lane*4 + i*128;
            float4 m[4];
            #pragma unroll
            for (int r2=0;r2<4;r2++) m[r2]=*(const float4*)(mb+(size_t)(s0+r2)*D_+e);
            #pragma unroll
            for (int h=0;h<NH_;h++) {
                float4 gv=*(const float4*)(gs + h*D_ + e);
                #pragma unroll
                for (int r2=0;r2<4;r2++)
                    acc[h][r2] += gv.x*m[r2].x + gv.y*m[r2].y + gv.z*m[r2].z + gv.w*m[r2].w;
            }
        }
        #pragma unroll
        for (int h=0;h<NH_;h++)
            #pragma unroll
            for (int r2=0;r2<4;r2++) {
                float v=acc[h][r2];
                for (int o=16;o;o>>=1) v+=__shfl_xor_sync(~0u,v,o);
                if (lane==0) g_scores[((size_t)b*NH_+h)*S_ + s0+r2] = v*scale;
            }
    }
}

__global__ void __launch_bounds__(256) ca_softmax_kernel()
{
    const int row=blockIdx.x, tid=threadIdx.x;
    float* sp = g_scores + (size_t)row*S_;
    float v = sp[tid];
    __shared__ float red[16];
    int lane=tid&31, wid=tid>>5;
    float m=v;
    for (int o=16;o;o>>=1) m=fmaxf(m,__shfl_xor_sync(~0u,m,o));
    if (lane==0) red[wid]=m;
    __syncthreads();
    if (tid==0){ float mm=red[0]; for(int k=1;k<8;k++) mm=fmaxf(mm,red[k]); red[0]=mm; }
    __syncthreads();
    m=red[0];
    float e=__expf(v-m);
    float s=e;
    for (int o=16;o;o>>=1) s+=__shfl_xor_sync(~0u,s,o);
    __syncthreads();
    if (lane==0) red[8+wid]=s;
    __syncthreads();
    if (tid==0){ float t=0; for(int k=0;k<8;k++) t+=red[8+k]; red[8]=t; }
    __syncthreads();
    sp[tid]=e/red[8];
}

__global__ void __launch_bounds__(256) mtilde_kernel(const float* __restrict__ mem)
{
    __shared__ float at[NH_*S_];
    const int b=blockIdx.x, tid=threadIdx.x;
    for (int i=tid;i<NH_*S_;i+=256) at[i]=g_scores[(size_t)b*NH_*S_+i];
    __syncthreads();
    const int e = blockIdx.y*512 + tid*2;
    const float* mb = mem + (size_t)b*S_*D_;
    float2 acc[NH_];
    #pragma unroll
    for (int h=0;h<NH_;h++){ acc[h].x=0.f; acc[h].y=0.f; }
    for (int s=0;s<S_;s++) {
        float2 mv=*(const float2*)(mb+(size_t)s*D_+e);
        #pragma unroll
        for (int h=0;h<NH_;h++){
            float a=at[h*S_+s];
            acc[h].x=fmaf(a,mv.x,acc[h].x);
            acc[h].y=fmaf(a,mv.y,acc[h].y);
        }
    }
    #pragma unroll
    for (int h=0;h<NH_;h++) {
        *(float2*)(g_mt + (size_t)b*NH_*D_ + h*D_ + e) = acc[h];
        __nv_bfloat16 hx,lx,hy,ly;
        split_bf16(acc[h].x,hx,lx); split_bf16(acc[h].y,hy,ly);
        size_t base = (size_t)b*NH_*3072 + h*3072;
        g_mt2[base + e]   = hx; g_mt2[base + e+1]   = hy;
        g_mt2[base + D_ + e] = lx; g_mt2[base + D_ + e+1] = ly;
    }
}

__global__ void __launch_bounds__(256) pool_reduce_kernel(
    const float* __restrict__ ls, float* __restrict__ out)
{
    const int j=blockIdx.x, i=blockIdx.y, s=threadIdx.x;
    float Sv = g_S[(size_t)i*BS_ + j*S_ + s];
    float Cv = g_S[(size_t)(B_+i)*BS_ + j*S_ + s];
    float nmv = g_nm[j*S_+s];
    __shared__ float red[16];
    int lane=s&31, wid=s>>5;
    float m=Sv;
    for (int o=16;o;o>>=1) m=fmaxf(m,__shfl_xor_sync(~0u,m,o));
    if (lane==0) red[wid]=m;
    __syncthreads();
    if (s==0){ float mm=red[0]; for(int k=1;k<8;k++) mm=fmaxf(mm,red[k]); red[0]=mm; }
    __syncthreads();
    m=red[0];
    float e = expf(Sv-m);
    float t1=e, t2=e*Cv/nmv;
    for (int o=16;o;o>>=1){ t1+=__shfl_xor_sync(~0u,t1,o); t2+=__shfl_xor_sync(~0u,t2,o); }
    __syncthreads();
    if (lane==0){ red[wid]=t1; red[8+wid]=t2; }
    __syncthreads();
    if (s==0) {
        float Z=0.f, Wv=0.f;
        for (int k=0;k<8;k++){ Z+=red[k]; Wv+=red[8+k]; }
        float val = expf(ls[0]) * Wv / (Z * g_nx[i]);
        out[(size_t)i*B_ + j] = val;
        out[(size_t)B_*B_ + (size_t)j*B_ + i] = val;
    }
}

__global__ void copy_xsq_kernel(float* __restrict__ out)
{
    int idx = blockIdx.x*256 + threadIdx.x;
    out[(size_t)2*B_*B_ + idx] = g_xsq[idx];
}

// =================== host =======================================================
template<typename T> static float* symf(T& s){ void* p=nullptr; cudaGetSymbolAddress(&p, s); return (float*)p; }
template<typename T> static __nv_bfloat16* symb(T& s){ void* p=nullptr; cudaGetSymbolAddress(&p, s); return (__nv_bfloat16*)p; }

extern "C" void kernel_launch(void* const* d_in, const int* in_sizes, int n_in,
                              void* d_out, int out_size)
{
    const float* x        =(const float*)d_in[0];
    const float* mem      =(const float*)d_in[1];
    const float* emb_w    =(const float*)d_in[2];
    const float* emb_b    =(const float*)d_in[3];
    const float* sa_in_w  =(const float*)d_in[4];
    const float* sa_in_b  =(const float*)d_in[5];
    const float* sa_out_w =(const float*)d_in[6];
    const float* sa_out_b =(const float*)d_in[7];
    const float* ca_in_w  =(const float*)d_in[8];
    const float* ca_in_b  =(const float*)d_in[9];
    const float* ca_out_w =(const float*)d_in[10];
    const float* ca_out_b =(const float*)d_in[11];
    const float* lin1_w   =(const float*)d_in[12];
    const float* lin1_b   =(const float*)d_in[13];
    const float* lin2_w   =(const float*)d_in[14];
    const float* lin2_b   =(const float*)d_in[15];
    const float* ln1_w    =(const float*)d_in[16];
    const float* ln1_b    =(const float*)d_in[17];
    const float* ln2_w    =(const float*)d_in[18];
    const float* ln2_b    =(const float*)d_in[19];
    const float* ln3_w    =(const float*)d_in[20];
    const float* ln3_b    =(const float*)d_in[21];
    const float* fin_w    =(const float*)d_in[22];
    const float* fin_b    =(const float*)d_in[23];
    const float* attn_in_w=(const float*)d_in[24];
    const float* attn_in_b=(const float*)d_in[25];
    const float* logit_sc =(const float*)d_in[26];
    float* out = (float*)d_out;

    float* t0 = symf(g_t0);  float* v   = symf(g_v);
    float* t1 = symf(g_t1);  float* qp  = symf(g_qp);  float* gg  = symf(g_g);
    float* o   = symf(g_o);
    float* t2 = symf(g_t2);  float* h1  = symf(g_h1);
    float* t3 = symf(g_t3);  float* xsq = symf(g_xsq); float* qp2 = symf(g_qp2);
    float* qt = symf(g_qt);  float* nx  = symf(g_nx);  float* pt  = symf(g_part);
    __nv_bfloat16* a2   = symb(g_a2);
    __nv_bfloat16* mt2  = symb(g_mt2);
    __nv_bfloat16* wEmb = symb(g_w_emb);
    __nv_bfloat16* wSaV = symb(g_w_savv);
    __nv_bfloat16* wSaO = symb(g_w_saout);
    __nv_bfloat16* wCaQ = symb(g_w_cawq);
    __nv_bfloat16* wCaV = symb(g_w_cawv);
    __nv_bfloat16* wCaO = symb(g_w_caout);
    __nv_bfloat16* wL1  = symb(g_w_lin1);
    __nv_bfloat16* wL2  = symb(g_w_lin2);
    __nv_bfloat16* wAtQ = symb(g_w_attnq);

    const float* NOB = nullptr;
    __nv_bfloat16* NOA = nullptr;

    // side stream + fork/join events (created once, host-side only)
    static cudaStream_t s2 = nullptr;
    static cudaEvent_t evFork = nullptr, evW = nullptr, evMem = nullptr;
    if (!s2) {
        cudaStreamCreateWithFlags(&s2, cudaStreamNonBlocking);
        cudaEventCreateWithFlags(&evFork, cudaEventDisableTiming);
        cudaEventCreateWithFlags(&evW,    cudaEventDisableTiming);
        cudaEventCreateWithFlags(&evMem,  cudaEventDisableTiming);
    }

    // ---- fork: side stream converts 8 weights then memory --------------------
    cudaEventRecord(evFork, 0);
    cudaStreamWaitEvent(s2, evFork, 0);
    {
        ConvJobs jobs;
        jobs.j[0] = { sa_in_w + (size_t)2*D_*D_, wSaV, D_, 1536 };
        jobs.j[1] = { sa_out_w,                  wSaO, D_, 1536 };
        jobs.j[2] = { ca_in_w,                   wCaQ, D_, 1536 };
        jobs.j[3] = { ca_in_w + (size_t)2*D_*D_, wCaV, D_, 1536 };
        jobs.j[4] = { ca_out_w,                  wCaO, D_, 1536 };
        jobs.j[5] = { lin1_w,                    wL1,  D_, 2048 };
        jobs.j[6] = { lin2_w,                    wL2,  FF_, 1536 };
        jobs.j[7] = { attn_in_w,                 wAtQ, D_, 1536 };
        jobs.j[8] = { emb_w,                     wEmb, DIN_, 1536 };  // spare slot: also batched
        conv_w_all<<<dim3(256, 9), 256, 0, s2>>>(jobs);
        cudaEventRecord(evW, s2);
        conv_mem_kernel<<<BS_/8, 256, 0, s2>>>(mem);
        cudaEventRecord(evMem, s2);
    }

    // ---- main stream: x conversion (independent of weights) ------------------
    conv_x_kernel<<<16, 256>>>(x);
    cudaStreamWaitEvent(0, evW, 0);    // weights ready (≈13 µs, overlapped by conv_x + launch setup)

    // 1. t0 = x @ emb_w.T + emb_b  (tc, K=768)
    gemm64_tc<<<dim3(24,6,1),256>>>(a2, 2*DIN_, 0, wEmb, 2*DIN_, 0, pt, DIN_);
    reduce_ks<<<dim3((B_*D_+255)/256,1),256>>>(pt, emb_b, 0, t0, D_, 0, 128, 1536, 6, 0,
                                               a2, 2*D_, D_, 0);
    // 2. SA (L=1): v = t0 @ wv.T + bv ; then sa partials -> fused LN1
    gemm64_tc<<<dim3(24,6,1),256>>>(a2, 2*D_, 0, wSaV, 2*D_, 0, pt, D_);
    reduce_ks<<<dim3((B_*D_+255)/256,1),256>>>(pt, sa_in_b+2*D_, 0, v, D_, 0, 128, 1536, 6, 0,
                                               a2, 2*D_, D_, 0);
    gemm64_tc<<<dim3(24,6,1),256>>>(a2, 2*D_, 0, wSaO, 2*D_, 0, pt, D_);
    // 3. t1 = LN(t0 + sa)  [fused reduce+LN, +a2]
    reduce_ln<<<B_, 256>>>(pt, sa_out_b, t0, ln1_w, ln1_b, t1, a2, 6);
    // 4. CA q-proj (tc), then g[b,h] = qp_h @ wk_h (fp32 nn, batched heads)
    gemm64_tc<<<dim3(24,6,1),256>>>(a2, 2*D_, 0, wCaQ, 2*D_, 0, pt, D_);
    reduce_ks<<<dim3((B_*D_+255)/256,1),256>>>(pt, ca_in_b, 0, qp, D_, 0, 128, 1536, 6, 0,
                                               NOA, 0, 0, 0);
    gemm_nn<64,64,16,4,4><<<dim3(D_/64, B_/64, NH_), 256>>>(
        qp, D_, DH_, ca_in_w + (size_t)D_*D_, D_, (long long)DH_*D_,
        NOB, 0, gg, NH_*D_, D_, DH_, 1, nullptr);
    // 5. CA scores / softmax / weighted memory (+mt2)
    ca_scores_kernel<<<dim3(B_,2), 256>>>(mem);
    ca_softmax_kernel<<<B_*NH_, 256>>>();
    mtilde_kernel<<<dim3(B_,3), 256>>>(mem);
    // 6. o_h = m~_h @ wv_h.T + bv_h (tc batched); ca partials -> fused LN2
    gemm64_tc<<<dim3(3,6,NH_),256>>>(mt2, NH_*3072, 3072, wCaV, 2*D_, (long long)DH_*2*D_, pt, D_);
    reduce_ks<<<dim3((128*DH_+255)/256,NH_),256>>>(pt, ca_in_b+2*D_, DH_, o, D_, DH_, 128, DH_, 6, 0,
                                                   a2, 2*D_, D_, DH_);
    gemm64_tc<<<dim3(24,6,1),256>>>(a2, 2*D_, 0, wCaO, 2*D_, 0, pt, D_);
    // 7. t2 = LN(t1 + ca)  [fused, +a2]
    reduce_ln<<<B_, 256>>>(pt, ca_out_b, t1, ln2_w, ln2_b, t2, a2, 6);
    // 8. FF: lin1 (relu, +a2) ; lin2 partials -> fused LN3
    gemm64_tc<<<dim3(32,6,1),256>>>(a2, 2*D_, 0, wL1, 2*D_, 0, pt, D_);
    reduce_ks<<<dim3((B_*FF_+255)/256,1),256>>>(pt, lin1_b, 0, h1, FF_, 0, 128, 2048, 6, 1,
                                                a2, 2*FF_, FF_, 0);
    gemm64_tc<<<dim3(24,6,1),256>>>(a2, 2*FF_, 0, wL2, 2*FF_, 0, pt, FF_);
    // 9. t3 = LN(t2 + ff)  [fused, no a2] ; x_sq = LN(t3) (+a2, +norm)
    reduce_ln<<<B_, 256>>>(pt, lin2_b, t2, ln3_w, ln3_b, t3, NOA, 6);
    ln_kernel<<<B_, 256>>>(t3, nullptr, fin_w, fin_b, xsq, nx, a2);
    // 10. pooling projections: qp2 (tc) ; qt = qp2@wk2 (fp32 nn KS=6 + reduce)
    gemm64_tc<<<dim3(24,6,1),256>>>(a2, 2*D_, 0, wAtQ, 2*D_, 0, pt, D_);
    reduce_ks<<<dim3((B_*D_+255)/256,1),256>>>(pt, attn_in_b, 0, qp2, D_, 0, 128, 1536, 6, 0,
                                               NOA, 0, 0, 0);
    gemm_nn<64,64,16,4,4><<<dim3(D_/64, B_/64, 6), 256>>>(
        qp2, D_, 0, attn_in_w + (size_t)D_*D_, D_, 0,
        NOB, 0, nullptr, 0, 0, D_, 6, pt);
    reduce_ks<<<dim3((B_*D_+255)/256,1),256>>>(pt, NOB, 0, qt, D_, 0, 128, 1536, 6, 0,
                                               NOA, 0, 0, 0);

    // 11. join conv_mem; A -> bf16 hi/lo ; big mma.sync GEMM
    conv_a_kernel<<<32, 256>>>();
    cudaStreamWaitEvent(0, evMem, 0);   // g_mb / g_nm ready (long since done)
    bigmm_kernel<<<dim3(BS_/128, 2), 256>>>();

    // 12. final softmax-weighted cosine reduce; third output
    pool_reduce_kernel<<<dim3(B_, B_), 256>>>(logit_sc, out);
    copy_xsq_kernel<<<(B_*D_)/256, 256>>>(out);

    (void)in_sizes; (void)n_in; (void)out_size;
}

// round 11
// speedup vs baseline: 1.6396x; 1.2820x over previous
#include <cuda_runtime.h>
#include <cuda_bf16.h>
#include <cuda_fp16.h>
#include <math.h>
#include <stdint.h>

// Problem constants
#define B_    128
#define S_    256
#define D_    1536
#define DIN_  768
#define NH_   8
#define DH_   192
#define FF_   2048
#define BS_   (B_*S_)   // 32768

// ---------------- scratch (device globals; no cudaMalloc allowed) -------------
__device__ float g_t0 [B_*D_];
__device__ float g_v  [B_*D_];
__device__ float g_t1 [B_*D_];
__device__ float g_qp [B_*D_];
__device__ float g_g  [B_*NH_*D_];
__device__ float g_scores[B_*NH_*S_];
__device__ float g_mt [B_*NH_*D_];
__device__ float g_o  [B_*D_];
__device__ float g_t2 [B_*D_];
__device__ float g_h1 [B_*FF_];
__device__ float g_t3 [B_*D_];
__device__ float g_xsq[B_*D_];
__device__ float g_qp2[B_*D_];
__device__ float g_qt [B_*D_];
__device__ float g_S  [(size_t)2*B_*BS_];
__device__ float g_nm [B_*S_];
__device__ float g_nx [B_];
__device__ float g_part[1600*1024];                 // K-split partials
__device__ __half g_mb [(size_t)BS_*D_];            // memory fp16 (hi only)
__device__ __half g_abh[256*2*D_];                  // pooling A: [Ah(1536)|Al(1536)] per row
// activation + weight bf16 (hi||lo) buffers
__device__ __nv_bfloat16 g_a2 [128*4096];
__device__ __nv_bfloat16 g_mt2[128*NH_*3072];
__device__ __nv_bfloat16 g_w_emb  [1536*1536];
__device__ __nv_bfloat16 g_w_savv [1536*3072];
__device__ __nv_bfloat16 g_w_saout[1536*3072];
__device__ __nv_bfloat16 g_w_cawq [1536*3072];
__device__ __nv_bfloat16 g_w_cawv [1536*3072];
__device__ __nv_bfloat16 g_w_caout[1536*3072];
__device__ __nv_bfloat16 g_w_lin1 [2048*3072];
__device__ __nv_bfloat16 g_w_lin2 [1536*4096];
__device__ __nv_bfloat16 g_w_attnq[1536*3072];

// =================== common mma.sync macros =====================================
#define LDSM4(R0,R1,R2,R3,ADDR) \
    asm volatile("ldmatrix.sync.aligned.m8n8.x4.shared.b16 {%0,%1,%2,%3}, [%4];" \
        : "=r"(R0),"=r"(R1),"=r"(R2),"=r"(R3) : "r"(ADDR))
#define MMA16816(D,A,B0,B1) \
    asm volatile("mma.sync.aligned.m16n8k16.row.col.f32.bf16.bf16.f32 " \
        "{%0,%1,%2,%3}, {%4,%5,%6,%7}, {%8,%9}, {%0,%1,%2,%3};" \
        : "+f"((D)[0]),"+f"((D)[1]),"+f"((D)[2]),"+f"((D)[3]) \
        : "r"((A)[0]),"r"((A)[1]),"r"((A)[2]),"r"((A)[3]),"r"(B0),"r"(B1))
#define MMAF16(D,A,B0,B1) \
    asm volatile("mma.sync.aligned.m16n8k16.row.col.f32.f16.f16.f32 " \
        "{%0,%1,%2,%3}, {%4,%5,%6,%7}, {%8,%9}, {%0,%1,%2,%3};" \
        : "+f"((D)[0]),"+f"((D)[1]),"+f"((D)[2]),"+f"((D)[3]) \
        : "r"((A)[0]),"r"((A)[1]),"r"((A)[2]),"r"((A)[3]),"r"(B0),"r"(B1))
#define CPA16(DST,SRC) \
    asm volatile("cp.async.ca.shared.global [%0], [%1], 16;" \
        :: "r"((uint32_t)__cvta_generic_to_shared(DST)), "l"(SRC))

__device__ __forceinline__ void split_bf16(float f, __nv_bfloat16& h, __nv_bfloat16& l){
    h = __float2bfloat16(f);
    l = __float2bfloat16(f - __bfloat162float(h));
}
__device__ __forceinline__ void split_f16(float f, __half& h, __half& l){
    h = __float2half(f);
    l = __float2half(f - __half2float(h));
}

// =================== gemm64_tc: tensor small GEMM (proven) ======================
#define GSLD 40

__global__ void __launch_bounds__(256) gemm64_tc(
    const __nv_bfloat16* __restrict__ A2, int lda2, long long strideA2,
    const __nv_bfloat16* __restrict__ W2, int ldw2, long long strideW2,
    float* __restrict__ partial, int K)
{
    __shared__ __align__(16) __nv_bfloat16 sA[2][128*GSLD];
    __shared__ __align__(16) __nv_bfloat16 sW[2][64*GSLD];
    const int tid = threadIdx.x;
    const int warp = tid>>5, lane = tid&31;
    const int wm = warp>>1, wn = warp&1;
    const int bn = blockIdx.x*64;
    const int KS = gridDim.y;
    const int z  = blockIdx.z;
    const int Ntot = gridDim.x*64;
    A2 += (long long)z*strideA2;
    W2 += (long long)z*strideW2;
    const int segc = K/32;
    const int nck  = (3*segc)/KS;
    const int g0   = blockIdx.y*nck;

    float acc[2][4][4];
    #pragma unroll
    for (int i=0;i<2;i++)
        #pragma unroll
        for (int j=0;j<4;j++)
            #pragma unroll
            for (int c=0;c<4;c++) acc[i][j][c]=0.f;

    #define G64_LOAD(BUF,C) do {                                              \
        int g_   = g0 + (C);                                                   \
        int seg_ = g_ / segc;                                                  \
        int k0_  = (g_ - seg_*segc)*32;                                        \
        int aOff_ = (seg_==2) ? K : 0;                                         \
        int bOff_ = (seg_==1) ? K : 0;                                         \
        _Pragma("unroll")                                                      \
        for (int i=0;i<2;i++) {                                                \
            int l = tid + i*256;                                               \
            int r = l>>2, sg = l&3;                                            \
            CPA16(&sA[BUF][r*GSLD + sg*8],                                     \
                  A2 + (size_t)r*lda2 + aOff_ + k0_ + sg*8);                   \
        }                                                                      \
        { int r = tid>>2, sg = tid&3;                                          \
          CPA16(&sW[BUF][r*GSLD + sg*8],                                       \
                W2 + (size_t)(bn+r)*ldw2 + bOff_ + k0_ + sg*8); }              \
        asm volatile("cp.async.commit_group;");                                \
    } while(0)

    G64_LOAD(0, 0);
    for (int c=0; c<nck; c++) {
        int buf = c & 1;
        asm volatile("cp.async.wait_group 0;");
        __syncthreads();
        if (c+1 < nck) G64_LOAD(buf^1, c+1);
        #pragma unroll
        for (int kk=0; kk<2; kk++) {
            const int kb = kk*16;
            uint32_t a[2][4], b[4][2];
            #pragma unroll
            for (int mf=0; mf<2; mf++) {
                int row = wm*32 + mf*16 + (lane&15);
                int ko  = kb + ((lane>>4)<<3);
                uint32_t ad = (uint32_t)__cvta_generic_to_shared(&sA[buf][row*GSLD + ko]);
                LDSM4(a[mf][0],a[mf][1],a[mf][2],a[mf][3], ad);
            }
            #pragma unroll
            for (int p=0; p<2; p++) {
                int nrow = wn*32 + p*16 + ((lane>>4)<<3) + (lane&7);
                int ko   = kb + (((lane>>3)&1)<<3);
                uint32_t ad = (uint32_t)__cvta_generic_to_shared(&sW[buf][nrow*GSLD + ko]);
                LDSM4(b[2*p][0],b[2*p][1],b[2*p+1][0],b[2*p+1][1], ad);
            }
            #pragma unroll
            for (int mf=0; mf<2; mf++)
                #pragma unroll
                for (int nf=0; nf<4; nf++)
                    MMA16816(acc[mf][nf], a[mf], b[nf][0], b[nf][1]);
        }
        __syncthreads();
    }
    const size_t pbase = (size_t)(z*KS + blockIdx.y)*128;
    #pragma unroll
    for (int mf=0; mf<2; mf++) {
        int m = wm*32 + mf*16 + (lane>>2);
        #pragma unroll
        for (int nf=0; nf<4; nf++) {
            int n = bn + wn*32 + nf*8 + ((lane&3)<<1);
            *(float2*)&partial[(pbase + m)*Ntot + n]     = make_float2(acc[mf][nf][0], acc[mf][nf][1]);
            *(float2*)&partial[(pbase + m+8)*Ntot + n]   = make_float2(acc[mf][nf][2], acc[mf][nf][3]);
        }
    }
}

// =================== reduce K-split partials (+bias/relu, + bf16 a2 out) ========
__global__ void __launch_bounds__(256) reduce_ks(
    const float* __restrict__ partial, const float* __restrict__ bias, int strideBias,
    float* __restrict__ C, int ldc, long long strideC,
    int Mtot, int Ntot, int KS, int relu,
    __nv_bfloat16* __restrict__ a2, int lda2, int loOff, int a2strideZ)
{
    const int zb = blockIdx.y;
    int idx = blockIdx.x*256 + threadIdx.x;
    if (idx >= Mtot*Ntot) return;
    int m = idx / Ntot, n = idx % Ntot;
    float s = 0.f;
    for (int c=0;c<KS;c++)
        s += partial[((size_t)(zb*KS+c)*Mtot + m)*Ntot + n];
    if (bias) s += bias[(size_t)zb*strideBias + n];
    if (relu) s = fmaxf(s, 0.f);
    C[(size_t)zb*strideC + (size_t)m*ldc + n] = s;
    if (a2) {
        __nv_bfloat16 h,l; split_bf16(s,h,l);
        size_t base = (size_t)zb*a2strideZ + (size_t)m*lda2 + n;
        a2[base] = h;
        a2[base + loOff] = l;
    }
}

// =================== fused reduce + residual + LayerNorm (+a2) ==================
__global__ void __launch_bounds__(256) reduce_ln(
    const float* __restrict__ partial, const float* __restrict__ bias,
    const float* __restrict__ resid,
    const float* __restrict__ w, const float* __restrict__ bb,
    float* __restrict__ out, __nv_bfloat16* __restrict__ a2, int KS)
{
    const int row = blockIdx.x, tid = threadIdx.x;
    float vals[6]; float s1=0.f, s2=0.f;
    #pragma unroll
    for (int i=0;i<6;i++) {
        int e = tid + i*256;
        float s = bias ? bias[e] : 0.f;
        for (int c=0;c<KS;c++)
            s += partial[((size_t)c*128 + row)*D_ + e];
        if (resid) s += resid[(size_t)row*D_ + e];
        vals[i]=s; s1+=s; s2+=s*s;
    }
    __shared__ float red[16];
    int lane=tid&31, wid=tid>>5;
    for (int o=16;o;o>>=1){ s1+=__shfl_xor_sync(~0u,s1,o); s2+=__shfl_xor_sync(~0u,s2,o); }
    if (lane==0){ red[wid]=s1; red[8+wid]=s2; }
    __syncthreads();
    if (tid==0){ float a1=0,a2s=0; for(int k=0;k<8;k++){a1+=red[k];a2s+=red[8+k];} red[0]=a1; red[8]=a2s; }
    __syncthreads();
    float mean = red[0]*(1.0f/D_);
    float var  = red[8]*(1.0f/D_) - mean*mean;
    float rstd = rsqrtf(var + 1e-5f);
    #pragma unroll
    for (int i=0;i<6;i++) {
        int e = tid + i*256;
        float y = (vals[i]-mean)*rstd*w[e] + bb[e];
        out[(size_t)row*D_+e] = y;
        if (a2) {
            __nv_bfloat16 h,l; split_bf16(y,h,l);
            a2[(size_t)row*2*D_ + e]      = h;
            a2[(size_t)row*2*D_ + D_ + e] = l;
        }
    }
}

// =================== fp32 gemm_nn (for gg / qt) ==================================
template<int BM,int BN,int BK,int TM,int TN>
__global__ void __launch_bounds__(256) gemm_nn(
    const float* __restrict__ A, int lda, long long strideA,
    const float* __restrict__ W, int ldw, long long strideW,
    const float* __restrict__ bias, int strideBias,
    float* __restrict__ C, int ldc, long long strideC,
    int K, int KS, float* __restrict__ partial)
{
    const int zb = blockIdx.z / KS, chunk = blockIdx.z % KS;
    const int Kc = K / KS;
    A += (long long)zb*strideA + chunk*Kc;
    W += (long long)zb*strideW + (size_t)chunk*Kc*ldw;
    C += (long long)zb*strideC;
    if (bias) bias += (long long)zb*strideBias;

    __shared__ float sA[BK][BM];
    __shared__ float sW[BK][BN];
    const int tid = threadIdx.x;
    const int bm = blockIdx.y*BM, bn = blockIdx.x*BN;
    const int tx = tid % (BN/TN), ty = tid / (BN/TN);
    float acc[TM][TN];
    #pragma unroll
    for (int i=0;i<TM;i++)
        #pragma unroll
        for (int j=0;j<TN;j++) acc[i][j]=0.f;

    for (int k0=0;k0<Kc;k0+=BK) {
        for (int i=tid;i<BM*(BK/4);i+=256) {
            int r=i/(BK/4), kv=i%(BK/4);
            float4 v=*(const float4*)(A+(size_t)(bm+r)*lda + k0 + kv*4);
            sA[kv*4+0][r]=v.x; sA[kv*4+1][r]=v.y; sA[kv*4+2][r]=v.z; sA[kv*4+3][r]=v.w;
        }
        for (int i=tid;i<BK*(BN/4);i+=256) {
            int kk=i/(BN/4), nv=i%(BN/4);
            *(float4*)&sW[kk][nv*4] = *(const float4*)(W+(size_t)(k0+kk)*ldw + bn + nv*4);
        }
        __syncthreads();
        #pragma unroll
        for (int kk=0;kk<BK;kk++) {
            float a[TM], w[TN];
            #pragma unroll
            for (int i=0;i<TM;i+=4) *(float4*)&a[i] = *(const float4*)&sA[kk][ty*TM+i];
            #pragma unroll
            for (int j=0;j<TN;j+=4) *(float4*)&w[j] = *(const float4*)&sW[kk][tx*TN+j];
            #pragma unroll
            for (int i=0;i<TM;i++)
                #pragma unroll
                for (int j=0;j<TN;j++) acc[i][j] = fmaf(a[i], w[j], acc[i][j]);
        }
        __syncthreads();
    }
    if (partial) {
        const int Mtot = gridDim.y*BM, Ntot = gridDim.x*BN;
        #pragma unroll
        for (int i=0;i<TM;i++) {
            int m = bm + ty*TM + i;
            #pragma unroll
            for (int j=0;j<TN;j+=4)
                *(float4*)&partial[((size_t)blockIdx.z*Mtot + m)*Ntot + bn + tx*TN + j]
                    = *(float4*)&acc[i][j];
        }
    } else {
        #pragma unroll
        for (int i=0;i<TM;i++) {
            int gm = bm + ty*TM + i;
            #pragma unroll
            for (int j=0;j<TN;j++) {
                int gn = bn + tx*TN + j;
                C[(size_t)gm*ldc + gn] = acc[i][j] + (bias ? bias[gn] : 0.f);
            }
        }
    }
}

// =================== conversions =================================================
// memory -> fp16 (hi only) + row norms
__global__ void __launch_bounds__(256) conv_mem_kernel(const float* __restrict__ mem)
{
    const int row = blockIdx.x*8 + (threadIdx.x>>5);
    const int lane = threadIdx.x&31;
    const float* p = mem + (size_t)row*D_;
    __half* oh = g_mb + (size_t)row*D_;
    float ss = 0.f;
    #pragma unroll
    for (int i=0;i<12;i++) {
        int e = lane*4 + i*128;
        float4 v = *(const float4*)(p+e);
        ss += v.x*v.x + v.y*v.y + v.z*v.z + v.w*v.w;
        __align__(8) __half h[4];
        h[0]=__float2half(v.x); h[1]=__float2half(v.y);
        h[2]=__float2half(v.z); h[3]=__float2half(v.w);
        *(uint64_t*)(oh + e) = *(uint64_t*)h;
    }
    for (int o=16;o;o>>=1) ss += __shfl_xor_sync(~0u, ss, o);
    if (lane==0) g_nm[row] = sqrtf(ss);
}

// batched weight conversion: 9 jobs in one launch. blockIdx.y = job.
struct ConvJob { const float* src; __nv_bfloat16* dst; int K; int rows; };
struct ConvJobs { ConvJob j[9]; };

__global__ void __launch_bounds__(256) conv_w_all(ConvJobs jobs)
{
    const ConvJob jb = jobs.j[blockIdx.y];
    const int row = blockIdx.x*8 + (threadIdx.x>>5);
    if (row >= jb.rows) return;
    const int lane = threadIdx.x&31;
    const int K = jb.K;
    const float* p = jb.src + (size_t)row*K;
    __nv_bfloat16* o = jb.dst + (size_t)row*2*K;
    for (int e=lane*4; e<K; e+=128) {
        float4 v = *(const float4*)(p+e);
        __align__(8) __nv_bfloat16 h[4], l[4];
        float f[4] = {v.x,v.y,v.z,v.w};
        #pragma unroll
        for (int c=0;c<4;c++) split_bf16(f[c], h[c], l[c]);
        *(uint64_t*)(o + e)     = *(uint64_t*)h;
        *(uint64_t*)(o + K + e) = *(uint64_t*)l;
    }
}

// qt (128 x D) -> g_abh rows 0-127 (fp16 Ah|Al); scale applied in pool_reduce
__global__ void __launch_bounds__(256) conv_qt_kernel()
{
    const int row = blockIdx.x*8 + (threadIdx.x>>5);
    const int lane = threadIdx.x&31;
    const float* p = g_qt + (size_t)row*D_;
    __half* o = g_abh + (size_t)row*2*D_;
    #pragma unroll
    for (int i=0;i<12;i++) {
        int e = lane*4 + i*128;
        float4 v = *(const float4*)(p+e);
        __align__(8) __half h[4], l[4];
        float f[4] = {v.x,v.y,v.z,v.w};
        #pragma unroll
        for (int c=0;c<4;c++) split_f16(f[c], h[c], l[c]);
        *(uint64_t*)(o + e)      = *(uint64_t*)h;
        *(uint64_t*)(o + D_ + e) = *(uint64_t*)l;
    }
}

// x (128 x 768) -> g_a2 [hi 768 | lo 768]
__global__ void __launch_bounds__(256) conv_x_kernel(const float* __restrict__ x)
{
    const int row = blockIdx.x*8 + (threadIdx.x>>5);
    const int lane = threadIdx.x&31;
    const float* p = x + (size_t)row*DIN_;
    __nv_bfloat16* o = g_a2 + (size_t)row*2*DIN_;
    #pragma unroll
    for (int i=0;i<6;i++) {
        int e = lane*4 + i*128;
        float4 v = *(const float4*)(p+e);
        __align__(8) __nv_bfloat16 h[4], l[4];
        float f[4] = {v.x,v.y,v.z,v.w};
        #pragma unroll
        for (int c=0;c<4;c++) split_bf16(f[c], h[c], l[c]);
        *(uint64_t*)(o + e)        = *(uint64_t*)h;
        *(uint64_t*)(o + DIN_ + e) = *(uint64_t*)l;
    }
}

// =================== bigmm_half: fp16 2-product, M=128 x N=32768 ================
// g_S[outBase+m][n] = (Ah[m]+Al[m]) . Bh[n]  over K = D_.
// PROVEN tile geometry from bigmm (32-wide k chunks, stride 40).
#define HSLD 40
#define HCHUNK 48          // 1536 / 32

__global__ void __launch_bounds__(256) bigmm_half(int aBase, int outBase)
{
    extern __shared__ __half hsm[];
    __half* sAh = hsm;                       // [2][128*HSLD]
    __half* sAl = sAh + 2*128*HSLD;
    __half* sB  = sAl + 2*128*HSLD;
    const int tid = threadIdx.x;
    const int warp = tid>>5, lane = tid&31;
    const int wm = warp>>2, wn = warp&3;
    const int nbase = blockIdx.x*128;

    float acc[4][4][4];
    #pragma unroll
    for (int i=0;i<4;i++)
        #pragma unroll
        for (int j=0;j<4;j++)
            #pragma unroll
            for (int c=0;c<4;c++) acc[i][j][c]=0.f;

    const int r0 = tid>>1;            // 0..127
    const int seg0 = (tid&1)*2;       // 0 or 2

    #define BH_LOAD(BUF,KC) do {                                               \
        int k0_ = (KC)*32;                                                      \
        _Pragma("unroll")                                                       \
        for (int i=0;i<2;i++) {                                                 \
            int seg = seg0 + i;                                                 \
            CPA16(&sAh[(BUF)*128*HSLD + r0*HSLD + seg*8],                       \
                  g_abh + (size_t)(aBase+r0)*2*D_ + k0_ + seg*8);               \
            CPA16(&sAl[(BUF)*128*HSLD + r0*HSLD + seg*8],                       \
                  g_abh + (size_t)(aBase+r0)*2*D_ + D_ + k0_ + seg*8);          \
            CPA16(&sB [(BUF)*128*HSLD + r0*HSLD + seg*8],                       \
                  g_mb + (size_t)(nbase+r0)*D_ + k0_ + seg*8);                  \
        }                                                                       \
        asm volatile("cp.async.commit_group;");                                 \
    } while(0)

    BH_LOAD(0, 0);
    for (int kc=0; kc<HCHUNK; kc++) {
        int buf = kc & 1;
        asm volatile("cp.async.wait_group 0;");
        __syncthreads();
        if (kc+1 < HCHUNK) BH_LOAD(buf^1, kc+1);
        __half* ah = sAh + buf*128*HSLD;
        __half* al = sAl + buf*128*HSLD;
        __half* bt = sB  + buf*128*HSLD;
        #pragma unroll
        for (int kk=0; kk<2; kk++) {
            const int kb = kk*16;
            uint32_t fah[4][4], fal[4][4], b[4][2];
            #pragma unroll
            for (int mf=0; mf<4; mf++) {
                int row = wm*64 + mf*16 + (lane&15);
                int ko  = kb + ((lane>>4)<<3);
                uint32_t adh = (uint32_t)__cvta_generic_to_shared(&ah[row*HSLD + ko]);
                uint32_t adl = (uint32_t)__cvta_generic_to_shared(&al[row*HSLD + ko]);
                LDSM4(fah[mf][0],fah[mf][1],fah[mf][2],fah[mf][3], adh);
                LDSM4(fal[mf][0],fal[mf][1],fal[mf][2],fal[mf][3], adl);
            }
            #pragma unroll
            for (int p=0; p<2; p++) {
                int nrow = wn*32 + p*16 + ((lane>>4)<<3) + (lane&7);
                int ko   = kb + (((lane>>3)&1)<<3);
                uint32_t ad = (uint32_t)__cvta_generic_to_shared(&bt[nrow*HSLD + ko]);
                LDSM4(b[2*p][0],b[2*p][1],b[2*p+1][0],b[2*p+1][1], ad);
            }
            #pragma unroll
            for (int mf=0; mf<4; mf++)
                #pragma unroll
                for (int nf=0; nf<4; nf++) {
                    MMAF16(acc[mf][nf], fah[mf], b[nf][0], b[nf][1]);
                    MMAF16(acc[mf][nf], fal[mf], b[nf][0], b[nf][1]);
                }
        }
        __syncthreads();
    }
    #pragma unroll
    for (int mf=0; mf<4; mf++) {
        int m = outBase + wm*64 + mf*16 + (lane>>2);
        #pragma unroll
        for (int nf=0; nf<4; nf++) {
            int n = nbase + wn*32 + nf*8 + ((lane&3)<<1);
            *(float2*)&g_S[(size_t)m*BS_ + n]     = make_float2(acc[mf][nf][0], acc[mf][nf][1]);
            *(float2*)&g_S[(size_t)(m+8)*BS_ + n] = make_float2(acc[mf][nf][2], acc[mf][nf][3]);
        }
    }
}
#define SMEM_BH (3*2*128*HSLD*2)   // 61440 bytes

// =================== LayerNorm (standalone, for fin; +fp16 abh out) =============
__global__ void __launch_bounds__(256) ln_kernel(
    const float* __restrict__ a, const float* __restrict__ r,
    const float* __restrict__ w, const float* __restrict__ bb,
    float* __restrict__ out, float* __restrict__ norm_out,
    __nv_bfloat16* __restrict__ a2, __half* __restrict__ abh)
{
    const int row = blockIdx.x, tid = threadIdx.x;
    const float* ap = a + (size_t)row*D_;
    const float* rp = r ? r + (size_t)row*D_ : nullptr;
    float vals[6]; float s1=0.f, s2=0.f;
    #pragma unroll
    for (int i=0;i<6;i++) {
        int e = tid + i*256;
        float v = ap[e] + (rp ? rp[e] : 0.f);
        vals[i]=v; s1+=v; s2+=v*v;
    }
    __shared__ float red[16];
    int lane=tid&31, wid=tid>>5;
    for (int o=16;o;o>>=1){ s1+=__shfl_xor_sync(~0u,s1,o); s2+=__shfl_xor_sync(~0u,s2,o); }
    if (lane==0){ red[wid]=s1; red[8+wid]=s2; }
    __syncthreads();
    if (tid==0){ float a1=0,a2s=0; for(int k=0;k<8;k++){a1+=red[k];a2s+=red[8+k];} red[0]=a1; red[8]=a2s; }
    __syncthreads();
    float mean = red[0]*(1.0f/D_);
    float var  = red[8]*(1.0f/D_) - mean*mean;
    float rstd = rsqrtf(var + 1e-5f);
    float ss = 0.f;
    #pragma unroll
    for (int i=0;i<6;i++) {
        int e = tid + i*256;
        float y = (vals[i]-mean)*rstd*w[e] + bb[e];
        out[(size_t)row*D_+e] = y;
        if (a2) {
            __nv_bfloat16 h,l; split_bf16(y,h,l);
            a2[(size_t)row*2*D_ + e]      = h;
            a2[(size_t)row*2*D_ + D_ + e] = l;
        }
        if (abh) {
            __half h,l; split_f16(y,h,l);
            abh[(size_t)row*2*D_ + e]      = h;
            abh[(size_t)row*2*D_ + D_ + e] = l;
        }
        ss += y*y;
    }
    if (norm_out) {
        for (int o=16;o;o>>=1) ss+=__shfl_xor_sync(~0u,ss,o);
        __syncthreads();
        if (lane==0) red[wid]=ss;
        __syncthreads();
        if (tid==0){ float t=0; for(int k=0;k<8;k++) t+=red[k]; norm_out[row]=sqrtf(t); }
    }
}

__global__ void __launch_bounds__(256) ca_scores_kernel(const float* __restrict__ mem)
{
    __shared__ float gs[NH_*D_];
    const int b = blockIdx.x, tid = threadIdx.x;
    const float4* gsrc = (const float4*)(g_g + (size_t)b*NH_*D_);
    for (int i=tid;i<NH_*D_/4;i+=256) ((float4*)gs)[i]=gsrc[i];
    __syncthreads();
    const int warp=tid>>5, lane=tid&31;
    const float* mb = mem + (size_t)b*S_*D_;
    const float scale = rsqrtf((float)DH_);
    const int sbase = blockIdx.y*128 + warp*16;
    for (int grp=0;grp<4;grp++) {
        int s0 = sbase + grp*4;
        float acc[NH_][4];
        #pragma unroll
        for (int h=0;h<NH_;h++)
            #pragma unroll
            for (int r2=0;r2<4;r2++) acc[h][r2]=0.f;
        #pragma unroll
        for (int i=0;i<12;i++) {
            int e = lane*4 + i*128;
            float4 m[4];
            #pragma unroll
            for (int r2=0;r2<4;r2++) m[r2]=*(const float4*)(mb+(size_t)(s0+r2)*D_+e);
            #pragma unroll
            for (int h=0;h<NH_;h++) {
                float4 gv=*(const float4*)(gs + h*D_ + e);
                #pragma unroll
                for (int r2=0;r2<4;r2++)
                    acc[h][r2] += gv.x*m[r2].x + gv.y*m[r2].y + gv.z*m[r2].z + gv.w*m[r2].w;
            }
        }
        #pragma unroll
        for (int h=0;h<NH_;h++)
            #pragma unroll
            for (int r2=0;r2<4;r2++) {
                float v=acc[h][r2];
                for (int o=16;o;o>>=1) v+=__shfl_xor_sync(~0u,v,o);
                if (lane==0) g_scores[((size_t)b*NH_+h)*S_ + s0+r2] = v*scale;
            }
    }
}

__global__ void __launch_bounds__(256) ca_softmax_kernel()
{
    const int row=blockIdx.x, tid=threadIdx.x;
    float* sp = g_scores + (size_t)row*S_;
    float v = sp[tid];
    __shared__ float red[16];
    int lane=tid&31, wid=tid>>5;
    float m=v;
    for (int o=16;o;o>>=1) m=fmaxf(m,__shfl_xor_sync(~0u,m,o));
    if (lane==0) red[wid]=m;
    __syncthreads();
    if (tid==0){ float mm=red[0]; for(int k=1;k<8;k++) mm=fmaxf(mm,red[k]); red[0]=mm; }
    __syncthreads();
    m=red[0];
    float e=__expf(v-m);
    float s=e;
    for (int o=16;o;o>>=1) s+=__shfl_xor_sync(~0u,s,o);
    __syncthreads();
    if (lane==0) red[8+wid]=s;
    __syncthreads();
    if (tid==0){ float t=0; for(int k=0;k<8;k++) t+=red[8+k]; red[8]=t; }
    __syncthreads();
    sp[tid]=e/red[8];
}

__global__ void __launch_bounds__(256) mtilde_kernel(const float* __restrict__ mem)
{
    __shared__ float at[NH_*S_];
    const int b=blockIdx.x, tid=threadIdx.x;
    for (int i=tid;i<NH_*S_;i+=256) at[i]=g_scores[(size_t)b*NH_*S_+i];
    __syncthreads();
    const int e = blockIdx.y*512 + tid*2;
    const float* mb = mem + (size_t)b*S_*D_;
    float2 acc[NH_];
    #pragma unroll
    for (int h=0;h<NH_;h++){ acc[h].x=0.f; acc[h].y=0.f; }
    for (int s=0;s<S_;s++) {
        float2 mv=*(const float2*)(mb+(size_t)s*D_+e);
        #pragma unroll
        for (int h=0;h<NH_;h++){
            float a=at[h*S_+s];
            acc[h].x=fmaf(a,mv.x,acc[h].x);
            acc[h].y=fmaf(a,mv.y,acc[h].y);
        }
    }
    #pragma unroll
    for (int h=0;h<NH_;h++) {
        *(float2*)(g_mt + (size_t)b*NH_*D_ + h*D_ + e) = acc[h];
        __nv_bfloat16 hx,lx,hy,ly;
        split_bf16(acc[h].x,hx,lx); split_bf16(acc[h].y,hy,ly);
        size_t base = (size_t)b*NH_*3072 + h*3072;
        g_mt2[base + e]   = hx; g_mt2[base + e+1]   = hy;
        g_mt2[base + D_ + e] = lx; g_mt2[base + D_ + e+1] = ly;
    }
}

__global__ void __launch_bounds__(256) pool_reduce_kernel(
    const float* __restrict__ ls, float* __restrict__ out)
{
    const int j=blockIdx.x, i=blockIdx.y, s=threadIdx.x;
    const float sc = rsqrtf((float)D_);
    float Sv = g_S[(size_t)i*BS_ + j*S_ + s] * sc;
    float Cv = g_S[(size_t)(B_+i)*BS_ + j*S_ + s];
    float nmv = g_nm[j*S_+s];
    __shared__ float red[16];
    int lane=s&31, wid=s>>5;
    float m=Sv;
    for (int o=16;o;o>>=1) m=fmaxf(m,__shfl_xor_sync(~0u,m,o));
    if (lane==0) red[wid]=m;
    __syncthreads();
    if (s==0){ float mm=red[0]; for(int k=1;k<8;k++) mm=fmaxf(mm,red[k]); red[0]=mm; }
    __syncthreads();
    m=red[0];
    float e = expf(Sv-m);
    float t1=e, t2=e*Cv/nmv;
    for (int o=16;o;o>>=1){ t1+=__shfl_xor_sync(~0u,t1,o); t2+=__shfl_xor_sync(~0u,t2,o); }
    __syncthreads();
    if (lane==0){ red[wid]=t1; red[8+wid]=t2; }
    __syncthreads();
    if (s==0) {
        float Z=0.f, Wv=0.f;
        for (int k=0;k<8;k++){ Z+=red[k]; Wv+=red[8+k]; }
        float val = expf(ls[0]) * Wv / (Z * g_nx[i]);
        out[(size_t)i*B_ + j] = val;
        out[(size_t)B_*B_ + (size_t)j*B_ + i] = val;
    }
}

__global__ void copy_xsq_kernel(float* __restrict__ out)
{
    int idx = blockIdx.x*256 + threadIdx.x;
    out[(size_t)2*B_*B_ + idx] = g_xsq[idx];
}

// =================== host =======================================================
template<typename T> static float* symf(T& s){ void* p=nullptr; cudaGetSymbolAddress(&p, s); return (float*)p; }
template<typename T> static __nv_bfloat16* symb(T& s){ void* p=nullptr; cudaGetSymbolAddress(&p, s); return (__nv_bfloat16*)p; }
template<typename T> static __half* symh(T& s){ void* p=nullptr; cudaGetSymbolAddress(&p, s); return (__half*)p; }

extern "C" void kernel_launch(void* const* d_in, const int* in_sizes, int n_in,
                              void* d_out, int out_size)
{
    const float* x        =(const float*)d_in[0];
    const float* mem      =(const float*)d_in[1];
    const float* emb_w    =(const float*)d_in[2];
    const float* emb_b    =(const float*)d_in[3];
    const float* sa_in_w  =(const float*)d_in[4];
    const float* sa_in_b  =(const float*)d_in[5];
    const float* sa_out_w =(const float*)d_in[6];
    const float* sa_out_b =(const float*)d_in[7];
    const float* ca_in_w  =(const float*)d_in[8];
    const float* ca_in_b  =(const float*)d_in[9];
    const float* ca_out_w =(const float*)d_in[10];
    const float* ca_out_b =(const float*)d_in[11];
    const float* lin1_w   =(const float*)d_in[12];
    const float* lin1_b   =(const float*)d_in[13];
    const float* lin2_w   =(const float*)d_in[14];
    const float* lin2_b   =(const float*)d_in[15];
    const float* ln1_w    =(const float*)d_in[16];
    const float* ln1_b    =(const float*)d_in[17];
    const float* ln2_w    =(const float*)d_in[18];
    const float* ln2_b    =(const float*)d_in[19];
    const float* ln3_w    =(const float*)d_in[20];
    const float* ln3_b    =(const float*)d_in[21];
    const float* fin_w    =(const float*)d_in[22];
    const float* fin_b    =(const float*)d_in[23];
    const float* attn_in_w=(const float*)d_in[24];
    const float* attn_in_b=(const float*)d_in[25];
    const float* logit_sc =(const float*)d_in[26];
    float* out = (float*)d_out;

    float* t0 = symf(g_t0);  float* v   = symf(g_v);
    float* t1 = symf(g_t1);  float* qp  = symf(g_qp);  float* gg  = symf(g_g);
    float* o   = symf(g_o);
    float* t2 = symf(g_t2);  float* h1  = symf(g_h1);
    float* t3 = symf(g_t3);  float* xsq = symf(g_xsq); float* qp2 = symf(g_qp2);
    float* qt = symf(g_qt);  float* nx  = symf(g_nx);  float* pt  = symf(g_part);
    __nv_bfloat16* a2   = symb(g_a2);
    __nv_bfloat16* mt2  = symb(g_mt2);
    __half*        abh  = symh(g_abh);
    __nv_bfloat16* wEmb = symb(g_w_emb);
    __nv_bfloat16* wSaV = symb(g_w_savv);
    __nv_bfloat16* wSaO = symb(g_w_saout);
    __nv_bfloat16* wCaQ = symb(g_w_cawq);
    __nv_bfloat16* wCaV = symb(g_w_cawv);
    __nv_bfloat16* wCaO = symb(g_w_caout);
    __nv_bfloat16* wL1  = symb(g_w_lin1);
    __nv_bfloat16* wL2  = symb(g_w_lin2);
    __nv_bfloat16* wAtQ = symb(g_w_attnq);

    const float* NOB = nullptr;
    __nv_bfloat16* NOA = nullptr;

    static cudaStream_t s2 = nullptr;
    static cudaEvent_t evFork = nullptr, evW = nullptr, evMem = nullptr;
    static cudaEvent_t evXsq = nullptr, evSide = nullptr;
    if (!s2) {
        cudaStreamCreateWithFlags(&s2, cudaStreamNonBlocking);
        cudaEventCreateWithFlags(&evFork, cudaEventDisableTiming);
        cudaEventCreateWithFlags(&evW,    cudaEventDisableTiming);
        cudaEventCreateWithFlags(&evMem,  cudaEventDisableTiming);
        cudaEventCreateWithFlags(&evXsq,  cudaEventDisableTiming);
        cudaEventCreateWithFlags(&evSide, cudaEventDisableTiming);
        cudaFuncSetAttribute(bigmm_half, cudaFuncAttributeMaxDynamicSharedMemorySize, SMEM_BH);
    }

    // ---- fork: side stream converts 9 weights then memory --------------------
    cudaEventRecord(evFork, 0);
    cudaStreamWaitEvent(s2, evFork, 0);
    {
        ConvJobs jobs;
        jobs.j[0] = { sa_in_w + (size_t)2*D_*D_, wSaV, D_, 1536 };
        jobs.j[1] = { sa_out_w,                  wSaO, D_, 1536 };
        jobs.j[2] = { ca_in_w,                   wCaQ, D_, 1536 };
        jobs.j[3] = { ca_in_w + (size_t)2*D_*D_, wCaV, D_, 1536 };
        jobs.j[4] = { ca_out_w,                  wCaO, D_, 1536 };
        jobs.j[5] = { lin1_w,                    wL1,  D_, 2048 };
        jobs.j[6] = { lin2_w,                    wL2,  FF_, 1536 };
        jobs.j[7] = { attn_in_w,                 wAtQ, D_, 1536 };
        jobs.j[8] = { emb_w,                     wEmb, DIN_, 1536 };
        conv_w_all<<<dim3(256, 9), 256, 0, s2>>>(jobs);
        cudaEventRecord(evW, s2);
        conv_mem_kernel<<<BS_/8, 256, 0, s2>>>(mem);
        cudaEventRecord(evMem, s2);
    }

    // ---- main stream: x conversion, wait weights ------------------------------
    conv_x_kernel<<<16, 256>>>(x);
    cudaStreamWaitEvent(0, evW, 0);

    // 1. t0 = x @ emb_w.T + emb_b
    gemm64_tc<<<dim3(24,6,1),256>>>(a2, 2*DIN_, 0, wEmb, 2*DIN_, 0, pt, DIN_);
    reduce_ks<<<dim3((B_*D_+255)/256,1),256>>>(pt, emb_b, 0, t0, D_, 0, 128, 1536, 6, 0,
                                               a2, 2*D_, D_, 0);
    // 2. SA (L=1)
    gemm64_tc<<<dim3(24,6,1),256>>>(a2, 2*D_, 0, wSaV, 2*D_, 0, pt, D_);
    reduce_ks<<<dim3((B_*D_+255)/256,1),256>>>(pt, sa_in_b+2*D_, 0, v, D_, 0, 128, 1536, 6, 0,
                                               a2, 2*D_, D_, 0);
    gemm64_tc<<<dim3(24,6,1),256>>>(a2, 2*D_, 0, wSaO, 2*D_, 0, pt, D_);
    // 3. t1 = LN(t0 + sa)
    reduce_ln<<<B_, 256>>>(pt, sa_out_b, t0, ln1_w, ln1_b, t1, a2, 6);
    // 4. CA q-proj + g
    gemm64_tc<<<dim3(24,6,1),256>>>(a2, 2*D_, 0, wCaQ, 2*D_, 0, pt, D_);
    reduce_ks<<<dim3((B_*D_+255)/256,1),256>>>(pt, ca_in_b, 0, qp, D_, 0, 128, 1536, 6, 0,
                                               NOA, 0, 0, 0);
    gemm_nn<64,64,16,4,4><<<dim3(D_/64, B_/64, NH_), 256>>>(
        qp, D_, DH_, ca_in_w + (size_t)D_*D_, D_, (long long)DH_*D_,
        NOB, 0, gg, NH_*D_, D_, DH_, 1, nullptr);
    // 5. CA scores / softmax / weighted memory
    ca_scores_kernel<<<dim3(B_,2), 256>>>(mem);
    ca_softmax_kernel<<<B_*NH_, 256>>>();
    mtilde_kernel<<<dim3(B_,3), 256>>>(mem);
    // 6. o_h ; ca -> fused LN2
    gemm64_tc<<<dim3(3,6,NH_),256>>>(mt2, NH_*3072, 3072, wCaV, 2*D_, (long long)DH_*2*D_, pt, D_);
    reduce_ks<<<dim3((128*DH_+255)/256,NH_),256>>>(pt, ca_in_b+2*D_, DH_, o, D_, DH_, 128, DH_, 6, 0,
                                                   a2, 2*D_, D_, DH_);
    gemm64_tc<<<dim3(24,6,1),256>>>(a2, 2*D_, 0, wCaO, 2*D_, 0, pt, D_);
    reduce_ln<<<B_, 256>>>(pt, ca_out_b, t1, ln2_w, ln2_b, t2, a2, 6);
    // 8. FF
    gemm64_tc<<<dim3(32,6,1),256>>>(a2, 2*D_, 0, wL1, 2*D_, 0, pt, D_);
    reduce_ks<<<dim3((B_*FF_+255)/256,1),256>>>(pt, lin1_b, 0, h1, FF_, 0, 128, 2048, 6, 1,
                                                a2, 2*FF_, FF_, 0);
    gemm64_tc<<<dim3(24,6,1),256>>>(a2, 2*FF_, 0, wL2, 2*FF_, 0, pt, FF_);
    // 9. t3 = LN(t2 + ff) ; x_sq = LN(t3) (+a2 bf16, +abh fp16 cosine half, +norm)
    reduce_ln<<<B_, 256>>>(pt, lin2_b, t2, ln3_w, ln3_b, t3, NOA, 6);
    ln_kernel<<<B_, 256>>>(t3, nullptr, fin_w, fin_b, xsq, nx, a2, abh + (size_t)128*2*D_);
    cudaEventRecord(evXsq, 0);

    // ---- side stream: qt projection branch (overlaps cosine bigmm) ------------
    cudaStreamWaitEvent(s2, evXsq, 0);
    gemm64_tc<<<dim3(24,6,1),256,0,s2>>>(a2, 2*D_, 0, wAtQ, 2*D_, 0, pt, D_);
    reduce_ks<<<dim3((B_*D_+255)/256,1),256,0,s2>>>(pt, attn_in_b, 0, qp2, D_, 0, 128, 1536, 6, 0,
                                                    NOA, 0, 0, 0);
    gemm_nn<64,64,16,4,4><<<dim3(D_/64, B_/64, 6), 256, 0, s2>>>(
        qp2, D_, 0, attn_in_w + (size_t)D_*D_, D_, 0,
        NOB, 0, nullptr, 0, 0, D_, 6, pt);
    reduce_ks<<<dim3((B_*D_+255)/256,1),256,0,s2>>>(pt, NOB, 0, qt, D_, 0, 128, 1536, 6, 0,
                                                    NOA, 0, 0, 0);
    conv_qt_kernel<<<16, 256, 0, s2>>>();
    copy_xsq_kernel<<<(B_*D_)/256, 256, 0, s2>>>(out);
    cudaEventRecord(evSide, s2);   // join point: ALL side-stream work ends here

    // ---- main stream: cosine bigmm (overlaps qt branch), then scores bigmm ----
    cudaStreamWaitEvent(0, evMem, 0);
    bigmm_half<<<BS_/128, 256, SMEM_BH>>>(128, 128);   // cosine: xsq rows
    cudaStreamWaitEvent(0, evSide, 0);                 // join side stream fully
    bigmm_half<<<BS_/128, 256, SMEM_BH>>>(0, 0);       // scores: qt rows

    // 12. final softmax-weighted cosine reduce
    pool_reduce_kernel<<<dim3(B_, B_), 256>>>(logit_sc, out);

    (void)in_sizes; (void)n_in; (void)out_size;
}

// round 12
// speedup vs baseline: 1.8150x; 1.1069x over previous
#include <cuda_runtime.h>
#include <cuda_bf16.h>
#include <cuda_fp16.h>
#include <math.h>
#include <stdint.h>

// Problem constants
#define B_    128
#define S_    256
#define D_    1536
#define DIN_  768
#define NH_   8
#define DH_   192
#define FF_   2048
#define BS_   (B_*S_)   // 32768

// ---------------- scratch (device globals; no cudaMalloc allowed) -------------
__device__ float g_t0 [B_*D_];
__device__ float g_v  [B_*D_];
__device__ float g_t1 [B_*D_];
__device__ float g_qp [B_*D_];
__device__ float g_g  [B_*NH_*D_];
__device__ float g_scores[B_*NH_*S_];
__device__ float g_mt [B_*NH_*D_];
__device__ float g_o  [B_*D_];
__device__ float g_t2 [B_*D_];
__device__ float g_h1 [B_*FF_];
__device__ float g_t3 [B_*D_];
__device__ float g_xsq[B_*D_];
__device__ float g_qp2[B_*D_];
__device__ float g_qt [B_*D_];
__device__ float g_S  [(size_t)2*B_*BS_];
__device__ float g_nm [B_*S_];
__device__ float g_nx [B_];
__device__ float g_part[1600*1024];                 // K-split partials
__device__ __half g_mb [(size_t)BS_*D_];            // memory fp16 (hi only)
__device__ __half g_abh[256*2*D_];                  // pooling A: [Ah|Al] per row
// activation + weight bf16 (hi||lo) buffers
__device__ __nv_bfloat16 g_a2 [128*4096];
__device__ __nv_bfloat16 g_mt2[128*NH_*3072];
__device__ __nv_bfloat16 g_w_emb  [1536*1536];
__device__ __nv_bfloat16 g_w_savv [1536*3072];
__device__ __nv_bfloat16 g_w_saout[1536*3072];
__device__ __nv_bfloat16 g_w_cawq [1536*3072];
__device__ __nv_bfloat16 g_w_cawv [1536*3072];
__device__ __nv_bfloat16 g_w_caout[1536*3072];
__device__ __nv_bfloat16 g_w_lin1 [2048*3072];
__device__ __nv_bfloat16 g_w_lin2 [1536*4096];
__device__ __nv_bfloat16 g_w_attnq[1536*3072];

// =================== common mma.sync macros =====================================
#define LDSM4(R0,R1,R2,R3,ADDR) \
    asm volatile("ldmatrix.sync.aligned.m8n8.x4.shared.b16 {%0,%1,%2,%3}, [%4];" \
        : "=r"(R0),"=r"(R1),"=r"(R2),"=r"(R3) : "r"(ADDR))
#define MMA16816(D,A,B0,B1) \
    asm volatile("mma.sync.aligned.m16n8k16.row.col.f32.bf16.bf16.f32 " \
        "{%0,%1,%2,%3}, {%4,%5,%6,%7}, {%8,%9}, {%0,%1,%2,%3};" \
        : "+f"((D)[0]),"+f"((D)[1]),"+f"((D)[2]),"+f"((D)[3]) \
        : "r"((A)[0]),"r"((A)[1]),"r"((A)[2]),"r"((A)[3]),"r"(B0),"r"(B1))
#define MMAF16(D,A,B0,B1) \
    asm volatile("mma.sync.aligned.m16n8k16.row.col.f32.f16.f16.f32 " \
        "{%0,%1,%2,%3}, {%4,%5,%6,%7}, {%8,%9}, {%0,%1,%2,%3};" \
        : "+f"((D)[0]),"+f"((D)[1]),"+f"((D)[2]),"+f"((D)[3]) \
        : "r"((A)[0]),"r"((A)[1]),"r"((A)[2]),"r"((A)[3]),"r"(B0),"r"(B1))
#define CPA16(DST,SRC) \
    asm volatile("cp.async.ca.shared.global [%0], [%1], 16;" \
        :: "r"((uint32_t)__cvta_generic_to_shared(DST)), "l"(SRC))

__device__ __forceinline__ void split_bf16(float f, __nv_bfloat16& h, __nv_bfloat16& l){
    h = __float2bfloat16(f);
    l = __float2bfloat16(f - __bfloat162float(h));
}
__device__ __forceinline__ void split_f16(float f, __half& h, __half& l){
    h = __float2half(f);
    l = __float2half(f - __half2float(h));
}

// =================== gemm64_tc2: window-fused 3-product bf16 GEMM ===============
#define G2SLD 40
#define SMEM_G2 ((2*128*G2SLD + 2*128*G2SLD + 2*64*G2SLD + 2*64*G2SLD)*2)  // 61440

__global__ void __launch_bounds__(256) gemm64_tc2(
    const __nv_bfloat16* __restrict__ A2, int lda2, long long strideA2,
    const __nv_bfloat16* __restrict__ W2, int ldw2, long long strideW2,
    float* __restrict__ partial, int K)
{
    extern __shared__ __nv_bfloat16 g2sm[];
    __nv_bfloat16* sAh = g2sm;                        // [2][128*G2SLD]
    __nv_bfloat16* sAl = sAh + 2*128*G2SLD;
    __nv_bfloat16* sWh = sAl + 2*128*G2SLD;           // [2][64*G2SLD]
    __nv_bfloat16* sWl = sWh + 2*64*G2SLD;

    const int tid = threadIdx.x;
    const int warp = tid>>5, lane = tid&31;
    const int wm = warp>>1, wn = warp&1;              // 4(m) x 2(n)
    const int bn = blockIdx.x*64;
    const int KS = gridDim.y;
    const int z  = blockIdx.z;
    const int Ntot = gridDim.x*64;
    A2 += (long long)z*strideA2;
    W2 += (long long)z*strideW2;
    const int nwin = (K/32)/KS;
    const int w0   = blockIdx.y*nwin;

    float acc[2][4][4];
    #pragma unroll
    for (int i=0;i<2;i++)
        #pragma unroll
        for (int j=0;j<4;j++)
            #pragma unroll
            for (int c=0;c<4;c++) acc[i][j][c]=0.f;

    #define G2_LOAD(BUF,W) do {                                                \
        int k0_ = (w0 + (W))*32;                                                \
        _Pragma("unroll")                                                       \
        for (int i=0;i<2;i++) {                                                 \
            int l = tid + i*256;                                                \
            int r = l>>2, sg = l&3;                                             \
            CPA16(&sAh[(BUF)*128*G2SLD + r*G2SLD + sg*8],                       \
                  A2 + (size_t)r*lda2 + k0_ + sg*8);                            \
            CPA16(&sAl[(BUF)*128*G2SLD + r*G2SLD + sg*8],                       \
                  A2 + (size_t)r*lda2 + K + k0_ + sg*8);                        \
        }                                                                       \
        { int r = tid>>2, sg = tid&3;                                           \
          CPA16(&sWh[(BUF)*64*G2SLD + r*G2SLD + sg*8],                          \
                W2 + (size_t)(bn+r)*ldw2 + k0_ + sg*8);                         \
          CPA16(&sWl[(BUF)*64*G2SLD + r*G2SLD + sg*8],                          \
                W2 + (size_t)(bn+r)*ldw2 + K + k0_ + sg*8); }                   \
        asm volatile("cp.async.commit_group;");                                 \
    } while(0)

    G2_LOAD(0, 0);
    for (int w=0; w<nwin; w++) {
        int buf = w & 1;
        asm volatile("cp.async.wait_group 0;");
        __syncthreads();
        if (w+1 < nwin) G2_LOAD(buf^1, w+1);
        __nv_bfloat16* ah = sAh + buf*128*G2SLD;
        __nv_bfloat16* al = sAl + buf*128*G2SLD;
        __nv_bfloat16* wh = sWh + buf*64*G2SLD;
        __nv_bfloat16* wl = sWl + buf*64*G2SLD;
        #pragma unroll
        for (int kk=0; kk<2; kk++) {
            const int kb = kk*16;
            uint32_t fah[2][4], fal[2][4], fbh[4][2], fbl[4][2];
            #pragma unroll
            for (int mf=0; mf<2; mf++) {
                int row = wm*32 + mf*16 + (lane&15);
                int ko  = kb + ((lane>>4)<<3);
                uint32_t adh = (uint32_t)__cvta_generic_to_shared(&ah[row*G2SLD + ko]);
                uint32_t adl = (uint32_t)__cvta_generic_to_shared(&al[row*G2SLD + ko]);
                LDSM4(fah[mf][0],fah[mf][1],fah[mf][2],fah[mf][3], adh);
                LDSM4(fal[mf][0],fal[mf][1],fal[mf][2],fal[mf][3], adl);
            }
            #pragma unroll
            for (int p=0; p<2; p++) {
                int nrow = wn*32 + p*16 + ((lane>>4)<<3) + (lane&7);
                int ko   = kb + (((lane>>3)&1)<<3);
                uint32_t adh = (uint32_t)__cvta_generic_to_shared(&wh[nrow*G2SLD + ko]);
                uint32_t adl = (uint32_t)__cvta_generic_to_shared(&wl[nrow*G2SLD + ko]);
                LDSM4(fbh[2*p][0],fbh[2*p][1],fbh[2*p+1][0],fbh[2*p+1][1], adh);
                LDSM4(fbl[2*p][0],fbl[2*p][1],fbl[2*p+1][0],fbl[2*p+1][1], adl);
            }
            #pragma unroll
            for (int mf=0; mf<2; mf++)
                #pragma unroll
                for (int nf=0; nf<4; nf++) {
                    MMA16816(acc[mf][nf], fah[mf], fbh[nf][0], fbh[nf][1]);
                    MMA16816(acc[mf][nf], fah[mf], fbl[nf][0], fbl[nf][1]);
                    MMA16816(acc[mf][nf], fal[mf], fbh[nf][0], fbh[nf][1]);
                }
        }
        __syncthreads();
    }
    const size_t pbase = (size_t)(z*KS + blockIdx.y)*128;
    #pragma unroll
    for (int mf=0; mf<2; mf++) {
        int m = wm*32 + mf*16 + (lane>>2);
        #pragma unroll
        for (int nf=0; nf<4; nf++) {
            int n = bn + wn*32 + nf*8 + ((lane&3)<<1);
            *(float2*)&partial[(pbase + m)*Ntot + n]     = make_float2(acc[mf][nf][0], acc[mf][nf][1]);
            *(float2*)&partial[(pbase + m+8)*Ntot + n]   = make_float2(acc[mf][nf][2], acc[mf][nf][3]);
        }
    }
}

// =================== reduce K-split partials (+bias/relu, + bf16 a2 out) ========
__global__ void __launch_bounds__(256) reduce_ks(
    const float* __restrict__ partial, const float* __restrict__ bias, int strideBias,
    float* __restrict__ C, int ldc, long long strideC,
    int Mtot, int Ntot, int KS, int relu,
    __nv_bfloat16* __restrict__ a2, int lda2, int loOff, int a2strideZ)
{
    const int zb = blockIdx.y;
    int idx = blockIdx.x*256 + threadIdx.x;
    if (idx >= Mtot*Ntot) return;
    int m = idx / Ntot, n = idx % Ntot;
    float s = 0.f;
    for (int c=0;c<KS;c++)
        s += partial[((size_t)(zb*KS+c)*Mtot + m)*Ntot + n];
    if (bias) s += bias[(size_t)zb*strideBias + n];
    if (relu) s = fmaxf(s, 0.f);
    C[(size_t)zb*strideC + (size_t)m*ldc + n] = s;
    if (a2) {
        __nv_bfloat16 h,l; split_bf16(s,h,l);
        size_t base = (size_t)zb*a2strideZ + (size_t)m*lda2 + n;
        a2[base] = h;
        a2[base + loOff] = l;
    }
}

// =================== fused reduce + residual + LayerNorm (+a2) ==================
__global__ void __launch_bounds__(256) reduce_ln(
    const float* __restrict__ partial, const float* __restrict__ bias,
    const float* __restrict__ resid,
    const float* __restrict__ w, const float* __restrict__ bb,
    float* __restrict__ out, __nv_bfloat16* __restrict__ a2, int KS)
{
    const int row = blockIdx.x, tid = threadIdx.x;
    float vals[6]; float s1=0.f, s2=0.f;
    #pragma unroll
    for (int i=0;i<6;i++) {
        int e = tid + i*256;
        float s = bias ? bias[e] : 0.f;
        for (int c=0;c<KS;c++)
            s += partial[((size_t)c*128 + row)*D_ + e];
        if (resid) s += resid[(size_t)row*D_ + e];
        vals[i]=s; s1+=s; s2+=s*s;
    }
    __shared__ float red[16];
    int lane=tid&31, wid=tid>>5;
    for (int o=16;o;o>>=1){ s1+=__shfl_xor_sync(~0u,s1,o); s2+=__shfl_xor_sync(~0u,s2,o); }
    if (lane==0){ red[wid]=s1; red[8+wid]=s2; }
    __syncthreads();
    if (tid==0){ float a1=0,a2s=0; for(int k=0;k<8;k++){a1+=red[k];a2s+=red[8+k];} red[0]=a1; red[8]=a2s; }
    __syncthreads();
    float mean = red[0]*(1.0f/D_);
    float var  = red[8]*(1.0f/D_) - mean*mean;
    float rstd = rsqrtf(var + 1e-5f);
    #pragma unroll
    for (int i=0;i<6;i++) {
        int e = tid + i*256;
        float y = (vals[i]-mean)*rstd*w[e] + bb[e];
        out[(size_t)row*D_+e] = y;
        if (a2) {
            __nv_bfloat16 h,l; split_bf16(y,h,l);
            a2[(size_t)row*2*D_ + e]      = h;
            a2[(size_t)row*2*D_ + D_ + e] = l;
        }
    }
}

// =================== fp32 gemm_nn (for gg / qt) ==================================
template<int BM,int BN,int BK,int TM,int TN>
__global__ void __launch_bounds__(256) gemm_nn(
    const float* __restrict__ A, int lda, long long strideA,
    const float* __restrict__ W, int ldw, long long strideW,
    const float* __restrict__ bias, int strideBias,
    float* __restrict__ C, int ldc, long long strideC,
    int K, int KS, float* __restrict__ partial)
{
    const int zb = blockIdx.z / KS, chunk = blockIdx.z % KS;
    const int Kc = K / KS;
    A += (long long)zb*strideA + chunk*Kc;
    W += (long long)zb*strideW + (size_t)chunk*Kc*ldw;
    C += (long long)zb*strideC;
    if (bias) bias += (long long)zb*strideBias;

    __shared__ float sA[BK][BM];
    __shared__ float sW[BK][BN];
    const int tid = threadIdx.x;
    const int bm = blockIdx.y*BM, bn = blockIdx.x*BN;
    const int tx = tid % (BN/TN), ty = tid / (BN/TN);
    float acc[TM][TN];
    #pragma unroll
    for (int i=0;i<TM;i++)
        #pragma unroll
        for (int j=0;j<TN;j++) acc[i][j]=0.f;

    for (int k0=0;k0<Kc;k0+=BK) {
        for (int i=tid;i<BM*(BK/4);i+=256) {
            int r=i/(BK/4), kv=i%(BK/4);
            float4 v=*(const float4*)(A+(size_t)(bm+r)*lda + k0 + kv*4);
            sA[kv*4+0][r]=v.x; sA[kv*4+1][r]=v.y; sA[kv*4+2][r]=v.z; sA[kv*4+3][r]=v.w;
        }
        for (int i=tid;i<BK*(BN/4);i+=256) {
            int kk=i/(BN/4), nv=i%(BN/4);
            *(float4*)&sW[kk][nv*4] = *(const float4*)(W+(size_t)(k0+kk)*ldw + bn + nv*4);
        }
        __syncthreads();
        #pragma unroll
        for (int kk=0;kk<BK;kk++) {
            float a[TM], w[TN];
            #pragma unroll
            for (int i=0;i<TM;i+=4) *(float4*)&a[i] = *(const float4*)&sA[kk][ty*TM+i];
            #pragma unroll
            for (int j=0;j<TN;j+=4) *(float4*)&w[j] = *(const float4*)&sW[kk][tx*TN+j];
            #pragma unroll
            for (int i=0;i<TM;i++)
                #pragma unroll
                for (int j=0;j<TN;j++) acc[i][j] = fmaf(a[i], w[j], acc[i][j]);
        }
        __syncthreads();
    }
    if (partial) {
        const int Mtot = gridDim.y*BM, Ntot = gridDim.x*BN;
        #pragma unroll
        for (int i=0;i<TM;i++) {
            int m = bm + ty*TM + i;
            #pragma unroll
            for (int j=0;j<TN;j+=4)
                *(float4*)&partial[((size_t)blockIdx.z*Mtot + m)*Ntot + bn + tx*TN + j]
                    = *(float4*)&acc[i][j];
        }
    } else {
        #pragma unroll
        for (int i=0;i<TM;i++) {
            int gm = bm + ty*TM + i;
            #pragma unroll
            for (int j=0;j<TN;j++) {
                int gn = bn + tx*TN + j;
                C[(size_t)gm*ldc + gn] = acc[i][j] + (bias ? bias[gn] : 0.f);
            }
        }
    }
}

// =================== conversions =================================================
__global__ void __launch_bounds__(256) conv_mem_kernel(const float* __restrict__ mem)
{
    const int row = blockIdx.x*8 + (threadIdx.x>>5);
    const int lane = threadIdx.x&31;
    const float* p = mem + (size_t)row*D_;
    __half* oh = g_mb + (size_t)row*D_;
    float ss = 0.f;
    #pragma unroll
    for (int i=0;i<12;i++) {
        int e = lane*4 + i*128;
        float4 v = *(const float4*)(p+e);
        ss += v.x*v.x + v.y*v.y + v.z*v.z + v.w*v.w;
        __align__(8) __half h[4];
        h[0]=__float2half(v.x); h[1]=__float2half(v.y);
        h[2]=__float2half(v.z); h[3]=__float2half(v.w);
        *(uint64_t*)(oh + e) = *(uint64_t*)h;
    }
    for (int o=16;o;o>>=1) ss += __shfl_xor_sync(~0u, ss, o);
    if (lane==0) g_nm[row] = sqrtf(ss);
}

struct ConvJob { const float* src; __nv_bfloat16* dst; int K; int rows; };
struct ConvJobs { ConvJob j[9]; };

__global__ void __launch_bounds__(256) conv_w_all(ConvJobs jobs)
{
    const ConvJob jb = jobs.j[blockIdx.y];
    const int row = blockIdx.x*8 + (threadIdx.x>>5);
    if (row >= jb.rows) return;
    const int lane = threadIdx.x&31;
    const int K = jb.K;
    const float* p = jb.src + (size_t)row*K;
    __nv_bfloat16* o = jb.dst + (size_t)row*2*K;
    for (int e=lane*4; e<K; e+=128) {
        float4 v = *(const float4*)(p+e);
        __align__(8) __nv_bfloat16 h[4], l[4];
        float f[4] = {v.x,v.y,v.z,v.w};
        #pragma unroll
        for (int c=0;c<4;c++) split_bf16(f[c], h[c], l[c]);
        *(uint64_t*)(o + e)     = *(uint64_t*)h;
        *(uint64_t*)(o + K + e) = *(uint64_t*)l;
    }
}

__global__ void __launch_bounds__(256) conv_qt_kernel()
{
    const int row = blockIdx.x*8 + (threadIdx.x>>5);
    const int lane = threadIdx.x&31;
    const float* p = g_qt + (size_t)row*D_;
    __half* o = g_abh + (size_t)row*2*D_;
    #pragma unroll
    for (int i=0;i<12;i++) {
        int e = lane*4 + i*128;
        float4 v = *(const float4*)(p+e);
        __align__(8) __half h[4], l[4];
        float f[4] = {v.x,v.y,v.z,v.w};
        #pragma unroll
        for (int c=0;c<4;c++) split_f16(f[c], h[c], l[c]);
        *(uint64_t*)(o + e)      = *(uint64_t*)h;
        *(uint64_t*)(o + D_ + e) = *(uint64_t*)l;
    }
}

__global__ void __launch_bounds__(256) conv_x_kernel(const float* __restrict__ x)
{
    const int row = blockIdx.x*8 + (threadIdx.x>>5);
    const int lane = threadIdx.x&31;
    const float* p = x + (size_t)row*DIN_;
    __nv_bfloat16* o = g_a2 + (size_t)row*2*DIN_;
    #pragma unroll
    for (int i=0;i<6;i++) {
        int e = lane*4 + i*128;
        float4 v = *(const float4*)(p+e);
        __align__(8) __nv_bfloat16 h[4], l[4];
        float f[4] = {v.x,v.y,v.z,v.w};
        #pragma unroll
        for (int c=0;c<4;c++) split_bf16(f[c], h[c], l[c]);
        *(uint64_t*)(o + e)        = *(uint64_t*)h;
        *(uint64_t*)(o + DIN_ + e) = *(uint64_t*)l;
    }
}

// =================== bigmm_half: fp16 2-product (proven R11) ====================
#define HSLD 40
#define HCHUNK 48          // 1536 / 32

__global__ void __launch_bounds__(256) bigmm_half(int aBase, int outBase)
{
    extern __shared__ __half hsm[];
    __half* sAh = hsm;                       // [2][128*HSLD]
    __half* sAl = sAh + 2*128*HSLD;
    __half* sB  = sAl + 2*128*HSLD;
    const int tid = threadIdx.x;
    const int warp = tid>>5, lane = tid&31;
    const int wm = warp>>2, wn = warp&3;
    const int nbase = blockIdx.x*128;

    float acc[4][4][4];
    #pragma unroll
    for (int i=0;i<4;i++)
        #pragma unroll
        for (int j=0;j<4;j++)
            #pragma unroll
            for (int c=0;c<4;c++) acc[i][j][c]=0.f;

    const int r0 = tid>>1;
    const int seg0 = (tid&1)*2;

    #define BH_LOAD(BUF,KC) do {                                               \
        int k0_ = (KC)*32;                                                      \
        _Pragma("unroll")                                                       \
        for (int i=0;i<2;i++) {                                                 \
            int seg = seg0 + i;                                                 \
            CPA16(&sAh[(BUF)*128*HSLD + r0*HSLD + seg*8],                       \
                  g_abh + (size_t)(aBase+r0)*2*D_ + k0_ + seg*8);               \
            CPA16(&sAl[(BUF)*128*HSLD + r0*HSLD + seg*8],                       \
                  g_abh + (size_t)(aBase+r0)*2*D_ + D_ + k0_ + seg*8);          \
            CPA16(&sB [(BUF)*128*HSLD + r0*HSLD + seg*8],                       \
                  g_mb + (size_t)(nbase+r0)*D_ + k0_ + seg*8);                  \
        }                                                                       \
        asm volatile("cp.async.commit_group;");                                 \
    } while(0)

    BH_LOAD(0, 0);
    for (int kc=0; kc<HCHUNK; kc++) {
        int buf = kc & 1;
        asm volatile("cp.async.wait_group 0;");
        __syncthreads();
        if (kc+1 < HCHUNK) BH_LOAD(buf^1, kc+1);
        __half* ah = sAh + buf*128*HSLD;
        __half* al = sAl + buf*128*HSLD;
        __half* bt = sB  + buf*128*HSLD;
        #pragma unroll
        for (int kk=0; kk<2; kk++) {
            const int kb = kk*16;
            uint32_t fah[4][4], fal[4][4], b[4][2];
            #pragma unroll
            for (int mf=0; mf<4; mf++) {
                int row = wm*64 + mf*16 + (lane&15);
                int ko  = kb + ((lane>>4)<<3);
                uint32_t adh = (uint32_t)__cvta_generic_to_shared(&ah[row*HSLD + ko]);
                uint32_t adl = (uint32_t)__cvta_generic_to_shared(&al[row*HSLD + ko]);
                LDSM4(fah[mf][0],fah[mf][1],fah[mf][2],fah[mf][3], adh);
                LDSM4(fal[mf][0],fal[mf][1],fal[mf][2],fal[mf][3], adl);
            }
            #pragma unroll
            for (int p=0; p<2; p++) {
                int nrow = wn*32 + p*16 + ((lane>>4)<<3) + (lane&7);
                int ko   = kb + (((lane>>3)&1)<<3);
                uint32_t ad = (uint32_t)__cvta_generic_to_shared(&bt[nrow*HSLD + ko]);
                LDSM4(b[2*p][0],b[2*p][1],b[2*p+1][0],b[2*p+1][1], ad);
            }
            #pragma unroll
            for (int mf=0; mf<4; mf++)
                #pragma unroll
                for (int nf=0; nf<4; nf++) {
                    MMAF16(acc[mf][nf], fah[mf], b[nf][0], b[nf][1]);
                    MMAF16(acc[mf][nf], fal[mf], b[nf][0], b[nf][1]);
                }
        }
        __syncthreads();
    }
    #pragma unroll
    for (int mf=0; mf<4; mf++) {
        int m = outBase + wm*64 + mf*16 + (lane>>2);
        #pragma unroll
        for (int nf=0; nf<4; nf++) {
            int n = nbase + wn*32 + nf*8 + ((lane&3)<<1);
            *(float2*)&g_S[(size_t)m*BS_ + n]     = make_float2(acc[mf][nf][0], acc[mf][nf][1]);
            *(float2*)&g_S[(size_t)(m+8)*BS_ + n] = make_float2(acc[mf][nf][2], acc[mf][nf][3]);
        }
    }
}
#define SMEM_BH (3*2*128*HSLD*2)   // 61440 bytes

// =================== LayerNorm (standalone, for fin; +fp16 abh out) =============
__global__ void __launch_bounds__(256) ln_kernel(
    const float* __restrict__ a, const float* __restrict__ r,
    const float* __restrict__ w, const float* __restrict__ bb,
    float* __restrict__ out, float* __restrict__ norm_out,
    __nv_bfloat16* __restrict__ a2, __half* __restrict__ abh)
{
    const int row = blockIdx.x, tid = threadIdx.x;
    const float* ap = a + (size_t)row*D_;
    const float* rp = r ? r + (size_t)row*D_ : nullptr;
    float vals[6]; float s1=0.f, s2=0.f;
    #pragma unroll
    for (int i=0;i<6;i++) {
        int e = tid + i*256;
        float v = ap[e] + (rp ? rp[e] : 0.f);
        vals[i]=v; s1+=v; s2+=v*v;
    }
    __shared__ float red[16];
    int lane=tid&31, wid=tid>>5;
    for (int o=16;o;o>>=1){ s1+=__shfl_xor_sync(~0u,s1,o); s2+=__shfl_xor_sync(~0u,s2,o); }
    if (lane==0){ red[wid]=s1; red[8+wid]=s2; }
    __syncthreads();
    if (tid==0){ float a1=0,a2s=0; for(int k=0;k<8;k++){a1+=red[k];a2s+=red[8+k];} red[0]=a1; red[8]=a2s; }
    __syncthreads();
    float mean = red[0]*(1.0f/D_);
    float var  = red[8]*(1.0f/D_) - mean*mean;
    float rstd = rsqrtf(var + 1e-5f);
    float ss = 0.f;
    #pragma unroll
    for (int i=0;i<6;i++) {
        int e = tid + i*256;
        float y = (vals[i]-mean)*rstd*w[e] + bb[e];
        out[(size_t)row*D_+e] = y;
        if (a2) {
            __nv_bfloat16 h,l; split_bf16(y,h,l);
            a2[(size_t)row*2*D_ + e]      = h;
            a2[(size_t)row*2*D_ + D_ + e] = l;
        }
        if (abh) {
            __half h,l; split_f16(y,h,l);
            abh[(size_t)row*2*D_ + e]      = h;
            abh[(size_t)row*2*D_ + D_ + e] = l;
        }
        ss += y*y;
    }
    if (norm_out) {
        for (int o=16;o;o>>=1) ss+=__shfl_xor_sync(~0u,ss,o);
        __syncthreads();
        if (lane==0) red[wid]=ss;
        __syncthreads();
        if (tid==0){ float t=0; for(int k=0;k<8;k++) t+=red[k]; norm_out[row]=sqrtf(t); }
    }
}

__global__ void __launch_bounds__(256) ca_scores_kernel(const float* __restrict__ mem)
{
    __shared__ float gs[NH_*D_];
    const int b = blockIdx.x, tid = threadIdx.x;
    const float4* gsrc = (const float4*)(g_g + (size_t)b*NH_*D_);
    for (int i=tid;i<NH_*D_/4;i+=256) ((float4*)gs)[i]=gsrc[i];
    __syncthreads();
    const int warp=tid>>5, lane=tid&31;
    const float* mb = mem + (size_t)b*S_*D_;
    const float scale = rsqrtf((float)DH_);
    const int sbase = blockIdx.y*128 + warp*16;
    for (int grp=0;grp<4;grp++) {
        int s0 = sbase + grp*4;
        float acc[NH_][4];
        #pragma unroll
        for (int h=0;h<NH_;h++)
            #pragma unroll
            for (int r2=0;r2<4;r2++) acc[h][r2]=0.f;
        #pragma unroll
        for (int i=0;i<12;i++) {
            int e = lane*4 + i*128;
            float4 m[4];
            #pragma unroll
            for (int r2=0;r2<4;r2++) m[r2]=*(const float4*)(mb+(size_t)(s0+r2)*D_+e);
            #pragma unroll
            for (int h=0;h<NH_;h++) {
                float4 gv=*(const float4*)(gs + h*D_ + e);
                #pragma unroll
                for (int r2=0;r2<4;r2++)
                    acc[h][r2] += gv.x*m[r2].x + gv.y*m[r2].y + gv.z*m[r2].z + gv.w*m[r2].w;
            }
        }
        #pragma unroll
        for (int h=0;h<NH_;h++)
            #pragma unroll
            for (int r2=0;r2<4;r2++) {
                float v=acc[h][r2];
                for (int o=16;o;o>>=1) v+=__shfl_xor_sync(~0u,v,o);
                if (lane==0) g_scores[((size_t)b*NH_+h)*S_ + s0+r2] = v*scale;
            }
    }
}

__global__ void __launch_bounds__(256) ca_softmax_kernel()
{
    const int row=blockIdx.x, tid=threadIdx.x;
    float* sp = g_scores + (size_t)row*S_;
    float v = sp[tid];
    __shared__ float red[16];
    int lane=tid&31, wid=tid>>5;
    float m=v;
    for (int o=16;o;o>>=1) m=fmaxf(m,__shfl_xor_sync(~0u,m,o));
    if (lane==0) red[wid]=m;
    __syncthreads();
    if (tid==0){ float mm=red[0]; for(int k=1;k<8;k++) mm=fmaxf(mm,red[k]); red[0]=mm; }
    __syncthreads();
    m=red[0];
    float e=__expf(v-m);
    float s=e;
    for (int o=16;o;o>>=1) s+=__shfl_xor_sync(~0u,s,o);
    __syncthreads();
    if (lane==0) red[8+wid]=s;
    __syncthreads();
    if (tid==0){ float t=0; for(int k=0;k<8;k++) t+=red[8+k]; red[8]=t; }
    __syncthreads();
    sp[tid]=e/red[8];
}

__global__ void __launch_bounds__(256) mtilde_kernel(const float* __restrict__ mem)
{
    __shared__ float at[NH_*S_];
    const int b=blockIdx.x, tid=threadIdx.x;
    for (int i=tid;i<NH_*S_;i+=256) at[i]=g_scores[(size_t)b*NH_*S_+i];
    __syncthreads();
    const int e = blockIdx.y*512 + tid*2;
    const float* mb = mem + (size_t)b*S_*D_;
    float2 acc[NH_];
    #pragma unroll
    for (int h=0;h<NH_;h++){ acc[h].x=0.f; acc[h].y=0.f; }
    for (int s=0;s<S_;s++) {
        float2 mv=*(const float2*)(mb+(size_t)s*D_+e);
        #pragma unroll
        for (int h=0;h<NH_;h++){
            float a=at[h*S_+s];
            acc[h].x=fmaf(a,mv.x,acc[h].x);
            acc[h].y=fmaf(a,mv.y,acc[h].y);
        }
    }
    #pragma unroll
    for (int h=0;h<NH_;h++) {
        *(float2*)(g_mt + (size_t)b*NH_*D_ + h*D_ + e) = acc[h];
        __nv_bfloat16 hx,lx,hy,ly;
        split_bf16(acc[h].x,hx,lx); split_bf16(acc[h].y,hy,ly);
        size_t base = (size_t)b*NH_*3072 + h*3072;
        g_mt2[base + e]   = hx; g_mt2[base + e+1]   = hy;
        g_mt2[base + D_ + e] = lx; g_mt2[base + D_ + e+1] = ly;
    }
}

__global__ void __launch_bounds__(256) pool_reduce_kernel(
    const float* __restrict__ ls, float* __restrict__ out)
{
    const int j=blockIdx.x, i=blockIdx.y, s=threadIdx.x;
    const float sc = rsqrtf((float)D_);
    float Sv = g_S[(size_t)i*BS_ + j*S_ + s] * sc;
    float Cv = g_S[(size_t)(B_+i)*BS_ + j*S_ + s];
    float nmv = g_nm[j*S_+s];
    __shared__ float red[16];
    int lane=s&31, wid=s>>5;
    float m=Sv;
    for (int o=16;o;o>>=1) m=fmaxf(m,__shfl_xor_sync(~0u,m,o));
    if (lane==0) red[wid]=m;
    __syncthreads();
    if (s==0){ float mm=red[0]; for(int k=1;k<8;k++) mm=fmaxf(mm,red[k]); red[0]=mm; }
    __syncthreads();
    m=red[0];
    float e = expf(Sv-m);
    float t1=e, t2=e*Cv/nmv;
    for (int o=16;o;o>>=1){ t1+=__shfl_xor_sync(~0u,t1,o); t2+=__shfl_xor_sync(~0u,t2,o); }
    __syncthreads();
    if (lane==0){ red[wid]=t1; red[8+wid]=t2; }
    __syncthreads();
    if (s==0) {
        float Z=0.f, Wv=0.f;
        for (int k=0;k<8;k++){ Z+=red[k]; Wv+=red[8+k]; }
        float val = expf(ls[0]) * Wv / (Z * g_nx[i]);
        out[(size_t)i*B_ + j] = val;
        out[(size_t)B_*B_ + (size_t)j*B_ + i] = val;
    }
}

__global__ void copy_xsq_kernel(float* __restrict__ out)
{
    int idx = blockIdx.x*256 + threadIdx.x;
    out[(size_t)2*B_*B_ + idx] = g_xsq[idx];
}

// =================== host =======================================================
template<typename T> static float* symf(T& s){ void* p=nullptr; cudaGetSymbolAddress(&p, s); return (float*)p; }
template<typename T> static __nv_bfloat16* symb(T& s){ void* p=nullptr; cudaGetSymbolAddress(&p, s); return (__nv_bfloat16*)p; }
template<typename T> static __half* symh(T& s){ void* p=nullptr; cudaGetSymbolAddress(&p, s); return (__half*)p; }

extern "C" void kernel_launch(void* const* d_in, const int* in_sizes, int n_in,
                              void* d_out, int out_size)
{
    const float* x        =(const float*)d_in[0];
    const float* mem      =(const float*)d_in[1];
    const float* emb_w    =(const float*)d_in[2];
    const float* emb_b    =(const float*)d_in[3];
    const float* sa_in_w  =(const float*)d_in[4];
    const float* sa_in_b  =(const float*)d_in[5];
    const float* sa_out_w =(const float*)d_in[6];
    const float* sa_out_b =(const float*)d_in[7];
    const float* ca_in_w  =(const float*)d_in[8];
    const float* ca_in_b  =(const float*)d_in[9];
    const float* ca_out_w =(const float*)d_in[10];
    const float* ca_out_b =(const float*)d_in[11];
    const float* lin1_w   =(const float*)d_in[12];
    const float* lin1_b   =(const float*)d_in[13];
    const float* lin2_w   =(const float*)d_in[14];
    const float* lin2_b   =(const float*)d_in[15];
    const float* ln1_w    =(const float*)d_in[16];
    const float* ln1_b    =(const float*)d_in[17];
    const float* ln2_w    =(const float*)d_in[18];
    const float* ln2_b    =(const float*)d_in[19];
    const float* ln3_w    =(const float*)d_in[20];
    const float* ln3_b    =(const float*)d_in[21];
    const float* fin_w    =(const float*)d_in[22];
    const float* fin_b    =(const float*)d_in[23];
    const float* attn_in_w=(const float*)d_in[24];
    const float* attn_in_b=(const float*)d_in[25];
    const float* logit_sc =(const float*)d_in[26];
    float* out = (float*)d_out;

    float* t0 = symf(g_t0);  float* v   = symf(g_v);
    float* t1 = symf(g_t1);  float* qp  = symf(g_qp);  float* gg  = symf(g_g);
    float* o   = symf(g_o);
    float* t2 = symf(g_t2);  float* h1  = symf(g_h1);
    float* t3 = symf(g_t3);  float* xsq = symf(g_xsq); float* qp2 = symf(g_qp2);
    float* qt = symf(g_qt);  float* nx  = symf(g_nx);  float* pt  = symf(g_part);
    __nv_bfloat16* a2   = symb(g_a2);
    __nv_bfloat16* mt2  = symb(g_mt2);
    __half*        abh  = symh(g_abh);
    __nv_bfloat16* wEmb = symb(g_w_emb);
    __nv_bfloat16* wSaV = symb(g_w_savv);
    __nv_bfloat16* wSaO = symb(g_w_saout);
    __nv_bfloat16* wCaQ = symb(g_w_cawq);
    __nv_bfloat16* wCaV = symb(g_w_cawv);
    __nv_bfloat16* wCaO = symb(g_w_caout);
    __nv_bfloat16* wL1  = symb(g_w_lin1);
    __nv_bfloat16* wL2  = symb(g_w_lin2);
    __nv_bfloat16* wAtQ = symb(g_w_attnq);

    const float* NOB = nullptr;
    __nv_bfloat16* NOA = nullptr;

    static cudaStream_t s2 = nullptr;
    static cudaEvent_t evFork = nullptr, evW = nullptr, evMem = nullptr;
    static cudaEvent_t evXsq = nullptr, evSide = nullptr;
    if (!s2) {
        cudaStreamCreateWithFlags(&s2, cudaStreamNonBlocking);
        cudaEventCreateWithFlags(&evFork, cudaEventDisableTiming);
        cudaEventCreateWithFlags(&evW,    cudaEventDisableTiming);
        cudaEventCreateWithFlags(&evMem,  cudaEventDisableTiming);
        cudaEventCreateWithFlags(&evXsq,  cudaEventDisableTiming);
        cudaEventCreateWithFlags(&evSide, cudaEventDisableTiming);
        cudaFuncSetAttribute(bigmm_half, cudaFuncAttributeMaxDynamicSharedMemorySize, SMEM_BH);
        cudaFuncSetAttribute(gemm64_tc2, cudaFuncAttributeMaxDynamicSharedMemorySize, SMEM_G2);
    }

    // ---- fork: side stream converts 9 weights then memory --------------------
    cudaEventRecord(evFork, 0);
    cudaStreamWaitEvent(s2, evFork, 0);
    {
        ConvJobs jobs;
        jobs.j[0] = { sa_in_w + (size_t)2*D_*D_, wSaV, D_, 1536 };
        jobs.j[1] = { sa_out_w,                  wSaO, D_, 1536 };
        jobs.j[2] = { ca_in_w,                   wCaQ, D_, 1536 };
        jobs.j[3] = { ca_in_w + (size_t)2*D_*D_, wCaV, D_, 1536 };
        jobs.j[4] = { ca_out_w,                  wCaO, D_, 1536 };
        jobs.j[5] = { lin1_w,                    wL1,  D_, 2048 };
        jobs.j[6] = { lin2_w,                    wL2,  FF_, 1536 };
        jobs.j[7] = { attn_in_w,                 wAtQ, D_, 1536 };
        jobs.j[8] = { emb_w,                     wEmb, DIN_, 1536 };
        conv_w_all<<<dim3(256, 9), 256, 0, s2>>>(jobs);
        cudaEventRecord(evW, s2);
        conv_mem_kernel<<<BS_/8, 256, 0, s2>>>(mem);
        cudaEventRecord(evMem, s2);
    }

    // ---- main stream: x conversion, wait weights ------------------------------
    conv_x_kernel<<<16, 256>>>(x);
    cudaStreamWaitEvent(0, evW, 0);

    // 1. t0 = x @ emb_w.T + emb_b  (K=768: 4 windows/block, KS=6)
    gemm64_tc2<<<dim3(24,6,1), 256, SMEM_G2>>>(a2, 2*DIN_, 0, wEmb, 2*DIN_, 0, pt, DIN_);
    reduce_ks<<<dim3((B_*D_+255)/256,1),256>>>(pt, emb_b, 0, t0, D_, 0, 128, 1536, 6, 0,
                                               a2, 2*D_, D_, 0);
    // 2. SA (L=1)
    gemm64_tc2<<<dim3(24,6,1), 256, SMEM_G2>>>(a2, 2*D_, 0, wSaV, 2*D_, 0, pt, D_);
    reduce_ks<<<dim3((B_*D_+255)/256,1),256>>>(pt, sa_in_b+2*D_, 0, v, D_, 0, 128, 1536, 6, 0,
                                               a2, 2*D_, D_, 0);
    gemm64_tc2<<<dim3(24,6,1), 256, SMEM_G2>>>(a2, 2*D_, 0, wSaO, 2*D_, 0, pt, D_);
    // 3. t1 = LN(t0 + sa)
    reduce_ln<<<B_, 256>>>(pt, sa_out_b, t0, ln1_w, ln1_b, t1, a2, 6);
    // 4. CA q-proj + g
    gemm64_tc2<<<dim3(24,6,1), 256, SMEM_G2>>>(a2, 2*D_, 0, wCaQ, 2*D_, 0, pt, D_);
    reduce_ks<<<dim3((B_*D_+255)/256,1),256>>>(pt, ca_in_b, 0, qp, D_, 0, 128, 1536, 6, 0,
                                               NOA, 0, 0, 0);
    gemm_nn<64,64,16,4,4><<<dim3(D_/64, B_/64, NH_), 256>>>(
        qp, D_, DH_, ca_in_w + (size_t)D_*D_, D_, (long long)DH_*D_,
        NOB, 0, gg, NH_*D_, D_, DH_, 1, nullptr);
    // 5. CA scores / softmax / weighted memory
    ca_scores_kernel<<<dim3(B_,2), 256>>>(mem);
    ca_softmax_kernel<<<B_*NH_, 256>>>();
    mtilde_kernel<<<dim3(B_,3), 256>>>(mem);
    // 6. o_h ; ca -> fused LN2
    gemm64_tc2<<<dim3(3,6,NH_), 256, SMEM_G2>>>(mt2, NH_*3072, 3072, wCaV, 2*D_, (long long)DH_*2*D_, pt, D_);
    reduce_ks<<<dim3((128*DH_+255)/256,NH_),256>>>(pt, ca_in_b+2*D_, DH_, o, D_, DH_, 128, DH_, 6, 0,
                                                   a2, 2*D_, D_, DH_);
    gemm64_tc2<<<dim3(24,6,1), 256, SMEM_G2>>>(a2, 2*D_, 0, wCaO, 2*D_, 0, pt, D_);
    reduce_ln<<<B_, 256>>>(pt, ca_out_b, t1, ln2_w, ln2_b, t2, a2, 6);
    // 8. FF: lin1 KS=6 ; lin2 K=2048 -> 64 windows, KS=8
    gemm64_tc2<<<dim3(32,6,1), 256, SMEM_G2>>>(a2, 2*D_, 0, wL1, 2*D_, 0, pt, D_);
    reduce_ks<<<dim3((B_*FF_+255)/256,1),256>>>(pt, lin1_b, 0, h1, FF_, 0, 128, 2048, 6, 1,
                                                a2, 2*FF_, FF_, 0);
    gemm64_tc2<<<dim3(24,8,1), 256, SMEM_G2>>>(a2, 2*FF_, 0, wL2, 2*FF_, 0, pt, FF_);
    // 9. t3 = LN(t2 + ff) [KS=8] ; x_sq = LN(t3) (+a2, +abh fp16, +norm)
    reduce_ln<<<B_, 256>>>(pt, lin2_b, t2, ln3_w, ln3_b, t3, NOA, 8);
    ln_kernel<<<B_, 256>>>(t3, nullptr, fin_w, fin_b, xsq, nx, a2, abh + (size_t)128*2*D_);
    cudaEventRecord(evXsq, 0);

    // ---- side stream: qt projection branch (overlaps cosine bigmm) ------------
    cudaStreamWaitEvent(s2, evXsq, 0);
    gemm64_tc2<<<dim3(24,6,1), 256, SMEM_G2, s2>>>(a2, 2*D_, 0, wAtQ, 2*D_, 0, pt, D_);
    reduce_ks<<<dim3((B_*D_+255)/256,1),256,0,s2>>>(pt, attn_in_b, 0, qp2, D_, 0, 128, 1536, 6, 0,
                                                    NOA, 0, 0, 0);
    gemm_nn<64,64,16,4,4><<<dim3(D_/64, B_/64, 6), 256, 0, s2>>>(
        qp2, D_, 0, attn_in_w + (size_t)D_*D_, D_, 0,
        NOB, 0, nullptr, 0, 0, D_, 6, pt);
    reduce_ks<<<dim3((B_*D_+255)/256,1),256,0,s2>>>(pt, NOB, 0, qt, D_, 0, 128, 1536, 6, 0,
                                                    NOA, 0, 0, 0);
    conv_qt_kernel<<<16, 256, 0, s2>>>();
    copy_xsq_kernel<<<(B_*D_)/256, 256, 0, s2>>>(out);
    cudaEventRecord(evSide, s2);

    // ---- main stream: cosine bigmm (overlaps qt branch), then scores bigmm ----
    cudaStreamWaitEvent(0, evMem, 0);
    bigmm_half<<<BS_/128, 256, SMEM_BH>>>(128, 128);   // cosine: xsq rows
    cudaStreamWaitEvent(0, evSide, 0);
    bigmm_half<<<BS_/128, 256, SMEM_BH>>>(0, 0);       // scores: qt rows

    // 12. final softmax-weighted cosine reduce
    pool_reduce_kernel<<<dim3(B_, B_), 256>>>(logit_sc, out);

    (void)in_sizes; (void)n_in; (void)out_size;
}

// round 13
// speedup vs baseline: 1.8773x; 1.0343x over previous
#include <cuda_runtime.h>
#include <cuda_bf16.h>
#include <cuda_fp16.h>
#include <math.h>
#include <stdint.h>

// Problem constants
#define B_    128
#define S_    256
#define D_    1536
#define DIN_  768
#define NH_   8
#define DH_   192
#define FF_   2048
#define BS_   (B_*S_)   // 32768

// ---------------- scratch (device globals; no cudaMalloc allowed) -------------
__device__ float g_t0 [B_*D_];
__device__ float g_v  [B_*D_];
__device__ float g_t1 [B_*D_];
__device__ float g_qp [B_*D_];
__device__ float g_g  [B_*NH_*D_];
__device__ float g_scores[B_*NH_*S_];
__device__ float g_o  [B_*D_];
__device__ float g_t2 [B_*D_];
__device__ float g_h1 [B_*FF_];
__device__ float g_t3 [B_*D_];
__device__ float g_xsq[B_*D_];
__device__ float g_qp2[B_*D_];
__device__ float g_qt [B_*D_];
__device__ float g_S  [(size_t)2*B_*BS_];
__device__ float g_nm [B_*S_];
__device__ float g_nx [B_];
__device__ float g_part[1600*1024];                 // K-split partials
__device__ __half g_mb [(size_t)BS_*D_];            // memory fp16 (hi only)
__device__ __half g_abh[256*2*D_];                  // pooling A: [Ah|Al] per row
// activation + weight bf16 (hi||lo) buffers
__device__ __nv_bfloat16 g_a2 [128*4096];
__device__ __nv_bfloat16 g_mt2[128*NH_*3072];
__device__ __nv_bfloat16 g_w_emb  [1536*1536];
__device__ __nv_bfloat16 g_w_savv [1536*3072];
__device__ __nv_bfloat16 g_w_saout[1536*3072];
__device__ __nv_bfloat16 g_w_cawq [1536*3072];
__device__ __nv_bfloat16 g_w_cawv [1536*3072];
__device__ __nv_bfloat16 g_w_caout[1536*3072];
__device__ __nv_bfloat16 g_w_lin1 [2048*3072];
__device__ __nv_bfloat16 g_w_lin2 [1536*4096];
__device__ __nv_bfloat16 g_w_attnq[1536*3072];

// =================== common mma.sync macros =====================================
#define LDSM4(R0,R1,R2,R3,ADDR) \
    asm volatile("ldmatrix.sync.aligned.m8n8.x4.shared.b16 {%0,%1,%2,%3}, [%4];" \
        : "=r"(R0),"=r"(R1),"=r"(R2),"=r"(R3) : "r"(ADDR))
#define MMA16816(D,A,B0,B1) \
    asm volatile("mma.sync.aligned.m16n8k16.row.col.f32.bf16.bf16.f32 " \
        "{%0,%1,%2,%3}, {%4,%5,%6,%7}, {%8,%9}, {%0,%1,%2,%3};" \
        : "+f"((D)[0]),"+f"((D)[1]),"+f"((D)[2]),"+f"((D)[3]) \
        : "r"((A)[0]),"r"((A)[1]),"r"((A)[2]),"r"((A)[3]),"r"(B0),"r"(B1))
#define MMAF16(D,A,B0,B1) \
    asm volatile("mma.sync.aligned.m16n8k16.row.col.f32.f16.f16.f32 " \
        "{%0,%1,%2,%3}, {%4,%5,%6,%7}, {%8,%9}, {%0,%1,%2,%3};" \
        : "+f"((D)[0]),"+f"((D)[1]),"+f"((D)[2]),"+f"((D)[3]) \
        : "r"((A)[0]),"r"((A)[1]),"r"((A)[2]),"r"((A)[3]),"r"(B0),"r"(B1))
#define CPA16(DST,SRC) \
    asm volatile("cp.async.ca.shared.global [%0], [%1], 16;" \
        :: "r"((uint32_t)__cvta_generic_to_shared(DST)), "l"(SRC))

__device__ __forceinline__ void split_bf16(float f, __nv_bfloat16& h, __nv_bfloat16& l){
    h = __float2bfloat16(f);
    l = __float2bfloat16(f - __bfloat162float(h));
}
__device__ __forceinline__ void split_f16(float f, __half& h, __half& l){
    h = __float2half(f);
    l = __float2half(f - __half2float(h));
}

// =================== gemm64_tc2: window-fused 3-product bf16 GEMM (proven) ======
#define G2SLD 40
#define SMEM_G2 ((2*128*G2SLD + 2*128*G2SLD + 2*64*G2SLD + 2*64*G2SLD)*2)  // 61440

__global__ void __launch_bounds__(256) gemm64_tc2(
    const __nv_bfloat16* __restrict__ A2, int lda2, long long strideA2,
    const __nv_bfloat16* __restrict__ W2, int ldw2, long long strideW2,
    float* __restrict__ partial, int K)
{
    extern __shared__ __nv_bfloat16 g2sm[];
    __nv_bfloat16* sAh = g2sm;                        // [2][128*G2SLD]
    __nv_bfloat16* sAl = sAh + 2*128*G2SLD;
    __nv_bfloat16* sWh = sAl + 2*128*G2SLD;           // [2][64*G2SLD]
    __nv_bfloat16* sWl = sWh + 2*64*G2SLD;

    const int tid = threadIdx.x;
    const int warp = tid>>5, lane = tid&31;
    const int wm = warp>>1, wn = warp&1;              // 4(m) x 2(n)
    const int bn = blockIdx.x*64;
    const int KS = gridDim.y;
    const int z  = blockIdx.z;
    const int Ntot = gridDim.x*64;
    A2 += (long long)z*strideA2;
    W2 += (long long)z*strideW2;
    const int nwin = (K/32)/KS;
    const int w0   = blockIdx.y*nwin;

    float acc[2][4][4];
    #pragma unroll
    for (int i=0;i<2;i++)
        #pragma unroll
        for (int j=0;j<4;j++)
            #pragma unroll
            for (int c=0;c<4;c++) acc[i][j][c]=0.f;

    #define G2_LOAD(BUF,W) do {                                                \
        int k0_ = (w0 + (W))*32;                                                \
        _Pragma("unroll")                                                       \
        for (int i=0;i<2;i++) {                                                 \
            int l = tid + i*256;                                                \
            int r = l>>2, sg = l&3;                                             \
            CPA16(&sAh[(BUF)*128*G2SLD + r*G2SLD + sg*8],                       \
                  A2 + (size_t)r*lda2 + k0_ + sg*8);                            \
            CPA16(&sAl[(BUF)*128*G2SLD + r*G2SLD + sg*8],                       \
                  A2 + (size_t)r*lda2 + K + k0_ + sg*8);                        \
        }                                                                       \
        { int r = tid>>2, sg = tid&3;                                           \
          CPA16(&sWh[(BUF)*64*G2SLD + r*G2SLD + sg*8],                          \
                W2 + (size_t)(bn+r)*ldw2 + k0_ + sg*8);                         \
          CPA16(&sWl[(BUF)*64*G2SLD + r*G2SLD + sg*8],                          \
                W2 + (size_t)(bn+r)*ldw2 + K + k0_ + sg*8); }                   \
        asm volatile("cp.async.commit_group;");                                 \
    } while(0)

    G2_LOAD(0, 0);
    for (int w=0; w<nwin; w++) {
        int buf = w & 1;
        asm volatile("cp.async.wait_group 0;");
        __syncthreads();
        if (w+1 < nwin) G2_LOAD(buf^1, w+1);
        __nv_bfloat16* ah = sAh + buf*128*G2SLD;
        __nv_bfloat16* al = sAl + buf*128*G2SLD;
        __nv_bfloat16* wh = sWh + buf*64*G2SLD;
        __nv_bfloat16* wl = sWl + buf*64*G2SLD;
        #pragma unroll
        for (int kk=0; kk<2; kk++) {
            const int kb = kk*16;
            uint32_t fah[2][4], fal[2][4], fbh[4][2], fbl[4][2];
            #pragma unroll
            for (int mf=0; mf<2; mf++) {
                int row = wm*32 + mf*16 + (lane&15);
                int ko  = kb + ((lane>>4)<<3);
                uint32_t adh = (uint32_t)__cvta_generic_to_shared(&ah[row*G2SLD + ko]);
                uint32_t adl = (uint32_t)__cvta_generic_to_shared(&al[row*G2SLD + ko]);
                LDSM4(fah[mf][0],fah[mf][1],fah[mf][2],fah[mf][3], adh);
                LDSM4(fal[mf][0],fal[mf][1],fal[mf][2],fal[mf][3], adl);
            }
            #pragma unroll
            for (int p=0; p<2; p++) {
                int nrow = wn*32 + p*16 + ((lane>>4)<<3) + (lane&7);
                int ko   = kb + (((lane>>3)&1)<<3);
                uint32_t adh = (uint32_t)__cvta_generic_to_shared(&wh[nrow*G2SLD + ko]);
                uint32_t adl = (uint32_t)__cvta_generic_to_shared(&wl[nrow*G2SLD + ko]);
                LDSM4(fbh[2*p][0],fbh[2*p][1],fbh[2*p+1][0],fbh[2*p+1][1], adh);
                LDSM4(fbl[2*p][0],fbl[2*p][1],fbl[2*p+1][0],fbl[2*p+1][1], adl);
            }
            #pragma unroll
            for (int mf=0; mf<2; mf++)
                #pragma unroll
                for (int nf=0; nf<4; nf++) {
                    MMA16816(acc[mf][nf], fah[mf], fbh[nf][0], fbh[nf][1]);
                    MMA16816(acc[mf][nf], fah[mf], fbl[nf][0], fbl[nf][1]);
                    MMA16816(acc[mf][nf], fal[mf], fbh[nf][0], fbh[nf][1]);
                }
        }
        __syncthreads();
    }
    const size_t pbase = (size_t)(z*KS + blockIdx.y)*128;
    #pragma unroll
    for (int mf=0; mf<2; mf++) {
        int m = wm*32 + mf*16 + (lane>>2);
        #pragma unroll
        for (int nf=0; nf<4; nf++) {
            int n = bn + wn*32 + nf*8 + ((lane&3)<<1);
            *(float2*)&partial[(pbase + m)*Ntot + n]     = make_float2(acc[mf][nf][0], acc[mf][nf][1]);
            *(float2*)&partial[(pbase + m+8)*Ntot + n]   = make_float2(acc[mf][nf][2], acc[mf][nf][3]);
        }
    }
}

// =================== reduce K-split partials (+bias/relu, + bf16 a2 out) ========
__global__ void __launch_bounds__(256) reduce_ks(
    const float* __restrict__ partial, const float* __restrict__ bias, int strideBias,
    float* __restrict__ C, int ldc, long long strideC,
    int Mtot, int Ntot, int KS, int relu,
    __nv_bfloat16* __restrict__ a2, int lda2, int loOff, int a2strideZ)
{
    const int zb = blockIdx.y;
    int idx = blockIdx.x*256 + threadIdx.x;
    if (idx >= Mtot*Ntot) return;
    int m = idx / Ntot, n = idx % Ntot;
    float s = 0.f;
    for (int c=0;c<KS;c++)
        s += partial[((size_t)(zb*KS+c)*Mtot + m)*Ntot + n];
    if (bias) s += bias[(size_t)zb*strideBias + n];
    if (relu) s = fmaxf(s, 0.f);
    C[(size_t)zb*strideC + (size_t)m*ldc + n] = s;
    if (a2) {
        __nv_bfloat16 h,l; split_bf16(s,h,l);
        size_t base = (size_t)zb*a2strideZ + (size_t)m*lda2 + n;
        a2[base] = h;
        a2[base + loOff] = l;
    }
}

// =================== fused reduce + residual + LayerNorm (+a2) ==================
__global__ void __launch_bounds__(256) reduce_ln(
    const float* __restrict__ partial, const float* __restrict__ bias,
    const float* __restrict__ resid,
    const float* __restrict__ w, const float* __restrict__ bb,
    float* __restrict__ out, __nv_bfloat16* __restrict__ a2, int KS)
{
    const int row = blockIdx.x, tid = threadIdx.x;
    float vals[6]; float s1=0.f, s2=0.f;
    #pragma unroll
    for (int i=0;i<6;i++) {
        int e = tid + i*256;
        float s = bias ? bias[e] : 0.f;
        for (int c=0;c<KS;c++)
            s += partial[((size_t)c*128 + row)*D_ + e];
        if (resid) s += resid[(size_t)row*D_ + e];
        vals[i]=s; s1+=s; s2+=s*s;
    }
    __shared__ float red[16];
    int lane=tid&31, wid=tid>>5;
    for (int o=16;o;o>>=1){ s1+=__shfl_xor_sync(~0u,s1,o); s2+=__shfl_xor_sync(~0u,s2,o); }
    if (lane==0){ red[wid]=s1; red[8+wid]=s2; }
    __syncthreads();
    if (tid==0){ float a1=0,a2s=0; for(int k=0;k<8;k++){a1+=red[k];a2s+=red[8+k];} red[0]=a1; red[8]=a2s; }
    __syncthreads();
    float mean = red[0]*(1.0f/D_);
    float var  = red[8]*(1.0f/D_) - mean*mean;
    float rstd = rsqrtf(var + 1e-5f);
    #pragma unroll
    for (int i=0;i<6;i++) {
        int e = tid + i*256;
        float y = (vals[i]-mean)*rstd*w[e] + bb[e];
        out[(size_t)row*D_+e] = y;
        if (a2) {
            __nv_bfloat16 h,l; split_bf16(y,h,l);
            a2[(size_t)row*2*D_ + e]      = h;
            a2[(size_t)row*2*D_ + D_ + e] = l;
        }
    }
}

// =================== fp32 gemm_nn (for gg / qt) ==================================
template<int BM,int BN,int BK,int TM,int TN>
__global__ void __launch_bounds__(256) gemm_nn(
    const float* __restrict__ A, int lda, long long strideA,
    const float* __restrict__ W, int ldw, long long strideW,
    const float* __restrict__ bias, int strideBias,
    float* __restrict__ C, int ldc, long long strideC,
    int K, int KS, float* __restrict__ partial)
{
    const int zb = blockIdx.z / KS, chunk = blockIdx.z % KS;
    const int Kc = K / KS;
    A += (long long)zb*strideA + chunk*Kc;
    W += (long long)zb*strideW + (size_t)chunk*Kc*ldw;
    C += (long long)zb*strideC;
    if (bias) bias += (long long)zb*strideBias;

    __shared__ float sA[BK][BM];
    __shared__ float sW[BK][BN];
    const int tid = threadIdx.x;
    const int bm = blockIdx.y*BM, bn = blockIdx.x*BN;
    const int tx = tid % (BN/TN), ty = tid / (BN/TN);
    float acc[TM][TN];
    #pragma unroll
    for (int i=0;i<TM;i++)
        #pragma unroll
        for (int j=0;j<TN;j++) acc[i][j]=0.f;

    for (int k0=0;k0<Kc;k0+=BK) {
        for (int i=tid;i<BM*(BK/4);i+=256) {
            int r=i/(BK/4), kv=i%(BK/4);
            float4 v=*(const float4*)(A+(size_t)(bm+r)*lda + k0 + kv*4);
            sA[kv*4+0][r]=v.x; sA[kv*4+1][r]=v.y; sA[kv*4+2][r]=v.z; sA[kv*4+3][r]=v.w;
        }
        for (int i=tid;i<BK*(BN/4);i+=256) {
            int kk=i/(BN/4), nv=i%(BN/4);
            *(float4*)&sW[kk][nv*4] = *(const float4*)(W+(size_t)(k0+kk)*ldw + bn + nv*4);
        }
        __syncthreads();
        #pragma unroll
        for (int kk=0;kk<BK;kk++) {
            float a[TM], w[TN];
            #pragma unroll
            for (int i=0;i<TM;i+=4) *(float4*)&a[i] = *(const float4*)&sA[kk][ty*TM+i];
            #pragma unroll
            for (int j=0;j<TN;j+=4) *(float4*)&w[j] = *(const float4*)&sW[kk][tx*TN+j];
            #pragma unroll
            for (int i=0;i<TM;i++)
                #pragma unroll
                for (int j=0;j<TN;j++) acc[i][j] = fmaf(a[i], w[j], acc[i][j]);
        }
        __syncthreads();
    }
    if (partial) {
        const int Mtot = gridDim.y*BM, Ntot = gridDim.x*BN;
        #pragma unroll
        for (int i=0;i<TM;i++) {
            int m = bm + ty*TM + i;
            #pragma unroll
            for (int j=0;j<TN;j+=4)
                *(float4*)&partial[((size_t)blockIdx.z*Mtot + m)*Ntot + bn + tx*TN + j]
                    = *(float4*)&acc[i][j];
        }
    } else {
        #pragma unroll
        for (int i=0;i<TM;i++) {
            int gm = bm + ty*TM + i;
            #pragma unroll
            for (int j=0;j<TN;j++) {
                int gn = bn + tx*TN + j;
                C[(size_t)gm*ldc + gn] = acc[i][j] + (bias ? bias[gn] : 0.f);
            }
        }
    }
}

// =================== conversions =================================================
__global__ void __launch_bounds__(256) conv_mem_kernel(const float* __restrict__ mem)
{
    const int row = blockIdx.x*8 + (threadIdx.x>>5);
    const int lane = threadIdx.x&31;
    const float* p = mem + (size_t)row*D_;
    __half* oh = g_mb + (size_t)row*D_;
    float ss = 0.f;
    #pragma unroll
    for (int i=0;i<12;i++) {
        int e = lane*4 + i*128;
        float4 v = *(const float4*)(p+e);
        ss += v.x*v.x + v.y*v.y + v.z*v.z + v.w*v.w;
        __align__(8) __half h[4];
        h[0]=__float2half(v.x); h[1]=__float2half(v.y);
        h[2]=__float2half(v.z); h[3]=__float2half(v.w);
        *(uint64_t*)(oh + e) = *(uint64_t*)h;
    }
    for (int o=16;o;o>>=1) ss += __shfl_xor_sync(~0u, ss, o);
    if (lane==0) g_nm[row] = sqrtf(ss);
}

struct ConvJob { const float* src; __nv_bfloat16* dst; int K; int rows; };
struct ConvJobs { ConvJob j[9]; };

__global__ void __launch_bounds__(256) conv_w_all(ConvJobs jobs)
{
    const ConvJob jb = jobs.j[blockIdx.y];
    const int row = blockIdx.x*8 + (threadIdx.x>>5);
    if (row >= jb.rows) return;
    const int lane = threadIdx.x&31;
    const int K = jb.K;
    const float* p = jb.src + (size_t)row*K;
    __nv_bfloat16* o = jb.dst + (size_t)row*2*K;
    for (int e=lane*4; e<K; e+=128) {
        float4 v = *(const float4*)(p+e);
        __align__(8) __nv_bfloat16 h[4], l[4];
        float f[4] = {v.x,v.y,v.z,v.w};
        #pragma unroll
        for (int c=0;c<4;c++) split_bf16(f[c], h[c], l[c]);
        *(uint64_t*)(o + e)     = *(uint64_t*)h;
        *(uint64_t*)(o + K + e) = *(uint64_t*)l;
    }
}

__global__ void __launch_bounds__(256) conv_qt_kernel()
{
    const int row = blockIdx.x*8 + (threadIdx.x>>5);
    const int lane = threadIdx.x&31;
    const float* p = g_qt + (size_t)row*D_;
    __half* o = g_abh + (size_t)row*2*D_;
    #pragma unroll
    for (int i=0;i<12;i++) {
        int e = lane*4 + i*128;
        float4 v = *(const float4*)(p+e);
        __align__(8) __half h[4], l[4];
        float f[4] = {v.x,v.y,v.z,v.w};
        #pragma unroll
        for (int c=0;c<4;c++) split_f16(f[c], h[c], l[c]);
        *(uint64_t*)(o + e)      = *(uint64_t*)h;
        *(uint64_t*)(o + D_ + e) = *(uint64_t*)l;
    }
}

__global__ void __launch_bounds__(256) conv_x_kernel(const float* __restrict__ x)
{
    const int row = blockIdx.x*8 + (threadIdx.x>>5);
    const int lane = threadIdx.x&31;
    const float* p = x + (size_t)row*DIN_;
    __nv_bfloat16* o = g_a2 + (size_t)row*2*DIN_;
    #pragma unroll
    for (int i=0;i<6;i++) {
        int e = lane*4 + i*128;
        float4 v = *(const float4*)(p+e);
        __align__(8) __nv_bfloat16 h[4], l[4];
        float f[4] = {v.x,v.y,v.z,v.w};
        #pragma unroll
        for (int c=0;c<4;c++) split_bf16(f[c], h[c], l[c]);
        *(uint64_t*)(o + e)        = *(uint64_t*)h;
        *(uint64_t*)(o + DIN_ + e) = *(uint64_t*)l;
    }
}

// =================== bigmm_half: fp16 2-product (proven R11/12) =================
#define HSLD 40
#define HCHUNK 48          // 1536 / 32

__global__ void __launch_bounds__(256) bigmm_half(int aBase, int outBase)
{
    extern __shared__ __half hsm[];
    __half* sAh = hsm;                       // [2][128*HSLD]
    __half* sAl = sAh + 2*128*HSLD;
    __half* sB  = sAl + 2*128*HSLD;
    const int tid = threadIdx.x;
    const int warp = tid>>5, lane = tid&31;
    const int wm = warp>>2, wn = warp&3;
    const int nbase = blockIdx.x*128;

    float acc[4][4][4];
    #pragma unroll
    for (int i=0;i<4;i++)
        #pragma unroll
        for (int j=0;j<4;j++)
            #pragma unroll
            for (int c=0;c<4;c++) acc[i][j][c]=0.f;

    const int r0 = tid>>1;
    const int seg0 = (tid&1)*2;

    #define BH_LOAD(BUF,KC) do {                                               \
        int k0_ = (KC)*32;                                                      \
        _Pragma("unroll")                                                       \
        for (int i=0;i<2;i++) {                                                 \
            int seg = seg0 + i;                                                 \
            CPA16(&sAh[(BUF)*128*HSLD + r0*HSLD + seg*8],                       \
                  g_abh + (size_t)(aBase+r0)*2*D_ + k0_ + seg*8);               \
            CPA16(&sAl[(BUF)*128*HSLD + r0*HSLD + seg*8],                       \
                  g_abh + (size_t)(aBase+r0)*2*D_ + D_ + k0_ + seg*8);          \
            CPA16(&sB [(BUF)*128*HSLD + r0*HSLD + seg*8],                       \
                  g_mb + (size_t)(nbase+r0)*D_ + k0_ + seg*8);                  \
        }                                                                       \
        asm volatile("cp.async.commit_group;");                                 \
    } while(0)

    BH_LOAD(0, 0);
    for (int kc=0; kc<HCHUNK; kc++) {
        int buf = kc & 1;
        asm volatile("cp.async.wait_group 0;");
        __syncthreads();
        if (kc+1 < HCHUNK) BH_LOAD(buf^1, kc+1);
        __half* ah = sAh + buf*128*HSLD;
        __half* al = sAl + buf*128*HSLD;
        __half* bt = sB  + buf*128*HSLD;
        #pragma unroll
        for (int kk=0; kk<2; kk++) {
            const int kb = kk*16;
            uint32_t fah[4][4], fal[4][4], b[4][2];
            #pragma unroll
            for (int mf=0; mf<4; mf++) {
                int row = wm*64 + mf*16 + (lane&15);
                int ko  = kb + ((lane>>4)<<3);
                uint32_t adh = (uint32_t)__cvta_generic_to_shared(&ah[row*HSLD + ko]);
                uint32_t adl = (uint32_t)__cvta_generic_to_shared(&al[row*HSLD + ko]);
                LDSM4(fah[mf][0],fah[mf][1],fah[mf][2],fah[mf][3], adh);
                LDSM4(fal[mf][0],fal[mf][1],fal[mf][2],fal[mf][3], adl);
            }
            #pragma unroll
            for (int p=0; p<2; p++) {
                int nrow = wn*32 + p*16 + ((lane>>4)<<3) + (lane&7);
                int ko   = kb + (((lane>>3)&1)<<3);
                uint32_t ad = (uint32_t)__cvta_generic_to_shared(&bt[nrow*HSLD + ko]);
                LDSM4(b[2*p][0],b[2*p][1],b[2*p+1][0],b[2*p+1][1], ad);
            }
            #pragma unroll
            for (int mf=0; mf<4; mf++)
                #pragma unroll
                for (int nf=0; nf<4; nf++) {
                    MMAF16(acc[mf][nf], fah[mf], b[nf][0], b[nf][1]);
                    MMAF16(acc[mf][nf], fal[mf], b[nf][0], b[nf][1]);
                }
        }
        __syncthreads();
    }
    #pragma unroll
    for (int mf=0; mf<4; mf++) {
        int m = outBase + wm*64 + mf*16 + (lane>>2);
        #pragma unroll
        for (int nf=0; nf<4; nf++) {
            int n = nbase + wn*32 + nf*8 + ((lane&3)<<1);
            *(float2*)&g_S[(size_t)m*BS_ + n]     = make_float2(acc[mf][nf][0], acc[mf][nf][1]);
            *(float2*)&g_S[(size_t)(m+8)*BS_ + n] = make_float2(acc[mf][nf][2], acc[mf][nf][3]);
        }
    }
}
#define SMEM_BH (3*2*128*HSLD*2)   // 61440 bytes

// =================== LayerNorm (standalone, for fin; +fp16 abh out) =============
__global__ void __launch_bounds__(256) ln_kernel(
    const float* __restrict__ a, const float* __restrict__ r,
    const float* __restrict__ w, const float* __restrict__ bb,
    float* __restrict__ out, float* __restrict__ norm_out,
    __nv_bfloat16* __restrict__ a2, __half* __restrict__ abh)
{
    const int row = blockIdx.x, tid = threadIdx.x;
    const float* ap = a + (size_t)row*D_;
    const float* rp = r ? r + (size_t)row*D_ : nullptr;
    float vals[6]; float s1=0.f, s2=0.f;
    #pragma unroll
    for (int i=0;i<6;i++) {
        int e = tid + i*256;
        float v = ap[e] + (rp ? rp[e] : 0.f);
        vals[i]=v; s1+=v; s2+=v*v;
    }
    __shared__ float red[16];
    int lane=tid&31, wid=tid>>5;
    for (int o=16;o;o>>=1){ s1+=__shfl_xor_sync(~0u,s1,o); s2+=__shfl_xor_sync(~0u,s2,o); }
    if (lane==0){ red[wid]=s1; red[8+wid]=s2; }
    __syncthreads();
    if (tid==0){ float a1=0,a2s=0; for(int k=0;k<8;k++){a1+=red[k];a2s+=red[8+k];} red[0]=a1; red[8]=a2s; }
    __syncthreads();
    float mean = red[0]*(1.0f/D_);
    float var  = red[8]*(1.0f/D_) - mean*mean;
    float rstd = rsqrtf(var + 1e-5f);
    float ss = 0.f;
    #pragma unroll
    for (int i=0;i<6;i++) {
        int e = tid + i*256;
        float y = (vals[i]-mean)*rstd*w[e] + bb[e];
        out[(size_t)row*D_+e] = y;
        if (a2) {
            __nv_bfloat16 h,l; split_bf16(y,h,l);
            a2[(size_t)row*2*D_ + e]      = h;
            a2[(size_t)row*2*D_ + D_ + e] = l;
        }
        if (abh) {
            __half h,l; split_f16(y,h,l);
            abh[(size_t)row*2*D_ + e]      = h;
            abh[(size_t)row*2*D_ + D_ + e] = l;
        }
        ss += y*y;
    }
    if (norm_out) {
        for (int o=16;o;o>>=1) ss+=__shfl_xor_sync(~0u,ss,o);
        __syncthreads();
        if (lane==0) red[wid]=ss;
        __syncthreads();
        if (tid==0){ float t=0; for(int k=0;k<8;k++) t+=red[k]; norm_out[row]=sqrtf(t); }
    }
}

// ========= CA scores from fp16 memory copy: scores[b,h,s] = g_mb[b,s]·g[b,h]/√DH =
__global__ void __launch_bounds__(256) ca_scores_kernel()
{
    __shared__ float gs[NH_*D_];
    const int b = blockIdx.x, tid = threadIdx.x;
    const float4* gsrc = (const float4*)(g_g + (size_t)b*NH_*D_);
    for (int i=tid;i<NH_*D_/4;i+=256) ((float4*)gs)[i]=gsrc[i];
    __syncthreads();
    const int warp=tid>>5, lane=tid&31;
    const __half* mb = g_mb + (size_t)b*S_*D_;
    const float scale = rsqrtf((float)DH_);
    const int sbase = blockIdx.y*128 + warp*16;
    for (int grp=0;grp<4;grp++) {
        int s0 = sbase + grp*4;
        float acc[NH_][4];
        #pragma unroll
        for (int h=0;h<NH_;h++)
            #pragma unroll
            for (int r2=0;r2<4;r2++) acc[h][r2]=0.f;
        #pragma unroll
        for (int i=0;i<12;i++) {
            int e = lane*4 + i*128;
            float4 m[4];
            #pragma unroll
            for (int r2=0;r2<4;r2++) {
                uint2 raw = *(const uint2*)(mb+(size_t)(s0+r2)*D_+e);
                __half2 p0 = *(__half2*)&raw.x;
                __half2 p1 = *(__half2*)&raw.y;
                float2 f0 = __half22float2(p0);
                float2 f1 = __half22float2(p1);
                m[r2] = make_float4(f0.x, f0.y, f1.x, f1.y);
            }
            #pragma unroll
            for (int h=0;h<NH_;h++) {
                float4 gv=*(const float4*)(gs + h*D_ + e);
                #pragma unroll
                for (int r2=0;r2<4;r2++)
                    acc[h][r2] += gv.x*m[r2].x + gv.y*m[r2].y + gv.z*m[r2].z + gv.w*m[r2].w;
            }
        }
        #pragma unroll
        for (int h=0;h<NH_;h++)
            #pragma unroll
            for (int r2=0;r2<4;r2++) {
                float v=acc[h][r2];
                for (int o=16;o;o>>=1) v+=__shfl_xor_sync(~0u,v,o);
                if (lane==0) g_scores[((size_t)b*NH_+h)*S_ + s0+r2] = v*scale;
            }
    }
}

__global__ void __launch_bounds__(256) ca_softmax_kernel()
{
    const int row=blockIdx.x, tid=threadIdx.x;
    float* sp = g_scores + (size_t)row*S_;
    float v = sp[tid];
    __shared__ float red[16];
    int lane=tid&31, wid=tid>>5;
    float m=v;
    for (int o=16;o;o>>=1) m=fmaxf(m,__shfl_xor_sync(~0u,m,o));
    if (lane==0) red[wid]=m;
    __syncthreads();
    if (tid==0){ float mm=red[0]; for(int k=1;k<8;k++) mm=fmaxf(mm,red[k]); red[0]=mm; }
    __syncthreads();
    m=red[0];
    float e=__expf(v-m);
    float s=e;
    for (int o=16;o;o>>=1) s+=__shfl_xor_sync(~0u,s,o);
    __syncthreads();
    if (lane==0) red[8+wid]=s;
    __syncthreads();
    if (tid==0){ float t=0; for(int k=0;k<8;k++) t+=red[8+k]; red[8]=t; }
    __syncthreads();
    sp[tid]=e/red[8];
}

// ========= m~[b,h] = sum_s attn[b,h,s] * g_mb[b,s,:] (fp16 memory) -> bf16 splits =
__global__ void __launch_bounds__(256) mtilde_kernel()
{
    __shared__ float at[NH_*S_];
    const int b=blockIdx.x, tid=threadIdx.x;
    for (int i=tid;i<NH_*S_;i+=256) at[i]=g_scores[(size_t)b*NH_*S_+i];
    __syncthreads();
    const int e = blockIdx.y*512 + tid*2;
    const __half* mb = g_mb + (size_t)b*S_*D_;
    float2 acc[NH_];
    #pragma unroll
    for (int h=0;h<NH_;h++){ acc[h].x=0.f; acc[h].y=0.f; }
    for (int s=0;s<S_;s++) {
        __half2 raw = *(const __half2*)(mb+(size_t)s*D_+e);
        float2 mv = __half22float2(raw);
        #pragma unroll
        for (int h=0;h<NH_;h++){
            float a=at[h*S_+s];
            acc[h].x=fmaf(a,mv.x,acc[h].x);
            acc[h].y=fmaf(a,mv.y,acc[h].y);
        }
    }
    #pragma unroll
    for (int h=0;h<NH_;h++) {
        __nv_bfloat16 hx,lx,hy,ly;
        split_bf16(acc[h].x,hx,lx); split_bf16(acc[h].y,hy,ly);
        size_t base = (size_t)b*NH_*3072 + h*3072;
        g_mt2[base + e]   = hx; g_mt2[base + e+1]   = hy;
        g_mt2[base + D_ + e] = lx; g_mt2[base + D_ + e+1] = ly;
    }
}

__global__ void __launch_bounds__(256) pool_reduce_kernel(
    const float* __restrict__ ls, float* __restrict__ out)
{
    const int j=blockIdx.x, i=blockIdx.y, s=threadIdx.x;
    const float sc = rsqrtf((float)D_);
    float Sv = g_S[(size_t)i*BS_ + j*S_ + s] * sc;
    float Cv = g_S[(size_t)(B_+i)*BS_ + j*S_ + s];
    float nmv = g_nm[j*S_+s];
    __shared__ float red[16];
    int lane=s&31, wid=s>>5;
    float m=Sv;
    for (int o=16;o;o>>=1) m=fmaxf(m,__shfl_xor_sync(~0u,m,o));
    if (lane==0) red[wid]=m;
    __syncthreads();
    if (s==0){ float mm=red[0]; for(int k=1;k<8;k++) mm=fmaxf(mm,red[k]); red[0]=mm; }
    __syncthreads();
    m=red[0];
    float e = expf(Sv-m);
    float t1=e, t2=e*Cv/nmv;
    for (int o=16;o;o>>=1){ t1+=__shfl_xor_sync(~0u,t1,o); t2+=__shfl_xor_sync(~0u,t2,o); }
    __syncthreads();
    if (lane==0){ red[wid]=t1; red[8+wid]=t2; }
    __syncthreads();
    if (s==0) {
        float Z=0.f, Wv=0.f;
        for (int k=0;k<8;k++){ Z+=red[k]; Wv+=red[8+k]; }
        float val = expf(ls[0]) * Wv / (Z * g_nx[i]);
        out[(size_t)i*B_ + j] = val;
        out[(size_t)B_*B_ + (size_t)j*B_ + i] = val;
    }
}

__global__ void copy_xsq_kernel(float* __restrict__ out)
{
    int idx = blockIdx.x*256 + threadIdx.x;
    out[(size_t)2*B_*B_ + idx] = g_xsq[idx];
}

// =================== host =======================================================
template<typename T> static float* symf(T& s){ void* p=nullptr; cudaGetSymbolAddress(&p, s); return (float*)p; }
template<typename T> static __nv_bfloat16* symb(T& s){ void* p=nullptr; cudaGetSymbolAddress(&p, s); return (__nv_bfloat16*)p; }
template<typename T> static __half* symh(T& s){ void* p=nullptr; cudaGetSymbolAddress(&p, s); return (__half*)p; }

extern "C" void kernel_launch(void* const* d_in, const int* in_sizes, int n_in,
                              void* d_out, int out_size)
{
    const float* x        =(const float*)d_in[0];
    const float* mem      =(const float*)d_in[1];
    const float* emb_w    =(const float*)d_in[2];
    const float* emb_b    =(const float*)d_in[3];
    const float* sa_in_w  =(const float*)d_in[4];
    const float* sa_in_b  =(const float*)d_in[5];
    const float* sa_out_w =(const float*)d_in[6];
    const float* sa_out_b =(const float*)d_in[7];
    const float* ca_in_w  =(const float*)d_in[8];
    const float* ca_in_b  =(const float*)d_in[9];
    const float* ca_out_w =(const float*)d_in[10];
    const float* ca_out_b =(const float*)d_in[11];
    const float* lin1_w   =(const float*)d_in[12];
    const float* lin1_b   =(const float*)d_in[13];
    const float* lin2_w   =(const float*)d_in[14];
    const float* lin2_b   =(const float*)d_in[15];
    const float* ln1_w    =(const float*)d_in[16];
    const float* ln1_b    =(const float*)d_in[17];
    const float* ln2_w    =(const float*)d_in[18];
    const float* ln2_b    =(const float*)d_in[19];
    const float* ln3_w    =(const float*)d_in[20];
    const float* ln3_b    =(const float*)d_in[21];
    const float* fin_w    =(const float*)d_in[22];
    const float* fin_b    =(const float*)d_in[23];
    const float* attn_in_w=(const float*)d_in[24];
    const float* attn_in_b=(const float*)d_in[25];
    const float* logit_sc =(const float*)d_in[26];
    float* out = (float*)d_out;

    float* t0 = symf(g_t0);  float* v   = symf(g_v);
    float* t1 = symf(g_t1);  float* qp  = symf(g_qp);  float* gg  = symf(g_g);
    float* o   = symf(g_o);
    float* t2 = symf(g_t2);  float* h1  = symf(g_h1);
    float* t3 = symf(g_t3);  float* xsq = symf(g_xsq); float* qp2 = symf(g_qp2);
    float* qt = symf(g_qt);  float* nx  = symf(g_nx);  float* pt  = symf(g_part);
    __nv_bfloat16* a2   = symb(g_a2);
    __nv_bfloat16* mt2  = symb(g_mt2);
    __half*        abh  = symh(g_abh);
    __nv_bfloat16* wEmb = symb(g_w_emb);
    __nv_bfloat16* wSaV = symb(g_w_savv);
    __nv_bfloat16* wSaO = symb(g_w_saout);
    __nv_bfloat16* wCaQ = symb(g_w_cawq);
    __nv_bfloat16* wCaV = symb(g_w_cawv);
    __nv_bfloat16* wCaO = symb(g_w_caout);
    __nv_bfloat16* wL1  = symb(g_w_lin1);
    __nv_bfloat16* wL2  = symb(g_w_lin2);
    __nv_bfloat16* wAtQ = symb(g_w_attnq);

    const float* NOB = nullptr;
    __nv_bfloat16* NOA = nullptr;

    static cudaStream_t s2 = nullptr;
    static cudaEvent_t evFork = nullptr, evW = nullptr, evMem = nullptr;
    static cudaEvent_t evXsq = nullptr, evSide = nullptr;
    if (!s2) {
        cudaStreamCreateWithFlags(&s2, cudaStreamNonBlocking);
        cudaEventCreateWithFlags(&evFork, cudaEventDisableTiming);
        cudaEventCreateWithFlags(&evW,    cudaEventDisableTiming);
        cudaEventCreateWithFlags(&evMem,  cudaEventDisableTiming);
        cudaEventCreateWithFlags(&evXsq,  cudaEventDisableTiming);
        cudaEventCreateWithFlags(&evSide, cudaEventDisableTiming);
        cudaFuncSetAttribute(bigmm_half, cudaFuncAttributeMaxDynamicSharedMemorySize, SMEM_BH);
        cudaFuncSetAttribute(gemm64_tc2, cudaFuncAttributeMaxDynamicSharedMemorySize, SMEM_G2);
    }

    // ---- fork: side stream converts 9 weights then memory --------------------
    cudaEventRecord(evFork, 0);
    cudaStreamWaitEvent(s2, evFork, 0);
    {
        ConvJobs jobs;
        jobs.j[0] = { sa_in_w + (size_t)2*D_*D_, wSaV, D_, 1536 };
        jobs.j[1] = { sa_out_w,                  wSaO, D_, 1536 };
        jobs.j[2] = { ca_in_w,                   wCaQ, D_, 1536 };
        jobs.j[3] = { ca_in_w + (size_t)2*D_*D_, wCaV, D_, 1536 };
        jobs.j[4] = { ca_out_w,                  wCaO, D_, 1536 };
        jobs.j[5] = { lin1_w,                    wL1,  D_, 2048 };
        jobs.j[6] = { lin2_w,                    wL2,  FF_, 1536 };
        jobs.j[7] = { attn_in_w,                 wAtQ, D_, 1536 };
        jobs.j[8] = { emb_w,                     wEmb, DIN_, 1536 };
        conv_w_all<<<dim3(256, 9), 256, 0, s2>>>(jobs);
        cudaEventRecord(evW, s2);
        conv_mem_kernel<<<BS_/8, 256, 0, s2>>>(mem);
        cudaEventRecord(evMem, s2);
    }

    // ---- main stream: x conversion, wait weights ------------------------------
    conv_x_kernel<<<16, 256>>>(x);
    cudaStreamWaitEvent(0, evW, 0);

    // 1. t0 = x @ emb_w.T + emb_b
    gemm64_tc2<<<dim3(24,6,1), 256, SMEM_G2>>>(a2, 2*DIN_, 0, wEmb, 2*DIN_, 0, pt, DIN_);
    reduce_ks<<<dim3((B_*D_+255)/256,1),256>>>(pt, emb_b, 0, t0, D_, 0, 128, 1536, 6, 0,
                                               a2, 2*D_, D_, 0);
    // 2. SA (L=1)
    gemm64_tc2<<<dim3(24,6,1), 256, SMEM_G2>>>(a2, 2*D_, 0, wSaV, 2*D_, 0, pt, D_);
    reduce_ks<<<dim3((B_*D_+255)/256,1),256>>>(pt, sa_in_b+2*D_, 0, v, D_, 0, 128, 1536, 6, 0,
                                               a2, 2*D_, D_, 0);
    gemm64_tc2<<<dim3(24,6,1), 256, SMEM_G2>>>(a2, 2*D_, 0, wSaO, 2*D_, 0, pt, D_);
    // 3. t1 = LN(t0 + sa)
    reduce_ln<<<B_, 256>>>(pt, sa_out_b, t0, ln1_w, ln1_b, t1, a2, 6);
    // 4. CA q-proj + g
    gemm64_tc2<<<dim3(24,6,1), 256, SMEM_G2>>>(a2, 2*D_, 0, wCaQ, 2*D_, 0, pt, D_);
    reduce_ks<<<dim3((B_*D_+255)/256,1),256>>>(pt, ca_in_b, 0, qp, D_, 0, 128, 1536, 6, 0,
                                               NOA, 0, 0, 0);
    gemm_nn<64,64,16,4,4><<<dim3(D_/64, B_/64, NH_), 256>>>(
        qp, D_, DH_, ca_in_w + (size_t)D_*D_, D_, (long long)DH_*D_,
        NOB, 0, gg, NH_*D_, D_, DH_, 1, nullptr);
    // 5. CA scores / softmax / weighted memory — now streaming fp16 g_mb
    cudaStreamWaitEvent(0, evMem, 0);
    ca_scores_kernel<<<dim3(B_,2), 256>>>();
    ca_softmax_kernel<<<B_*NH_, 256>>>();
    mtilde_kernel<<<dim3(B_,3), 256>>>();
    // 6. o_h ; ca -> fused LN2
    gemm64_tc2<<<dim3(3,6,NH_), 256, SMEM_G2>>>(mt2, NH_*3072, 3072, wCaV, 2*D_, (long long)DH_*2*D_, pt, D_);
    reduce_ks<<<dim3((128*DH_+255)/256,NH_),256>>>(pt, ca_in_b+2*D_, DH_, o, D_, DH_, 128, DH_, 6, 0,
                                                   a2, 2*D_, D_, DH_);
    gemm64_tc2<<<dim3(24,6,1), 256, SMEM_G2>>>(a2, 2*D_, 0, wCaO, 2*D_, 0, pt, D_);
    reduce_ln<<<B_, 256>>>(pt, ca_out_b, t1, ln2_w, ln2_b, t2, a2, 6);
    // 8. FF: lin1 KS=6 ; lin2 K=2048 -> KS=8
    gemm64_tc2<<<dim3(32,6,1), 256, SMEM_G2>>>(a2, 2*D_, 0, wL1, 2*D_, 0, pt, D_);
    reduce_ks<<<dim3((B_*FF_+255)/256,1),256>>>(pt, lin1_b, 0, h1, FF_, 0, 128, 2048, 6, 1,
                                                a2, 2*FF_, FF_, 0);
    gemm64_tc2<<<dim3(24,8,1), 256, SMEM_G2>>>(a2, 2*FF_, 0, wL2, 2*FF_, 0, pt, FF_);
    // 9. t3 = LN(t2 + ff) [KS=8] ; x_sq = LN(t3) (+a2, +abh fp16, +norm)
    reduce_ln<<<B_, 256>>>(pt, lin2_b, t2, ln3_w, ln3_b, t3, NOA, 8);
    ln_kernel<<<B_, 256>>>(t3, nullptr, fin_w, fin_b, xsq, nx, a2, abh + (size_t)128*2*D_);
    cudaEventRecord(evXsq, 0);

    // ---- side stream: qt projection branch (overlaps cosine bigmm) ------------
    cudaStreamWaitEvent(s2, evXsq, 0);
    gemm64_tc2<<<dim3(24,6,1), 256, SMEM_G2, s2>>>(a2, 2*D_, 0, wAtQ, 2*D_, 0, pt, D_);
    reduce_ks<<<dim3((B_*D_+255)/256,1),256,0,s2>>>(pt, attn_in_b, 0, qp2, D_, 0, 128, 1536, 6, 0,
                                                    NOA, 0, 0, 0);
    gemm_nn<64,64,16,4,4><<<dim3(D_/64, B_/64, 6), 256, 0, s2>>>(
        qp2, D_, 0, attn_in_w + (size_t)D_*D_, D_, 0,
        NOB, 0, nullptr, 0, 0, D_, 6, pt);
    reduce_ks<<<dim3((B_*D_+255)/256,1),256,0,s2>>>(pt, NOB, 0, qt, D_, 0, 128, 1536, 6, 0,
                                                    NOA, 0, 0, 0);
    conv_qt_kernel<<<16, 256, 0, s2>>>();
    copy_xsq_kernel<<<(B_*D_)/256, 256, 0, s2>>>(out);
    cudaEventRecord(evSide, s2);

    // ---- main stream: cosine bigmm (overlaps qt branch), then scores bigmm ----
    bigmm_half<<<BS_/128, 256, SMEM_BH>>>(128, 128);   // cosine: xsq rows
    cudaStreamWaitEvent(0, evSide, 0);
    bigmm_half<<<BS_/128, 256, SMEM_BH>>>(0, 0);       // scores: qt rows

    // 12. final softmax-weighted cosine reduce
    pool_reduce_kernel<<<dim3(B_, B_), 256>>>(logit_sc, out);

    (void)in_sizes; (void)n_in; (void)out_size;
}

// round 14
// speedup vs baseline: 2.0228x; 1.0775x over previous
#include <cuda_runtime.h>
#include <cuda_bf16.h>
#include <cuda_fp16.h>
#include <math.h>
#include <stdint.h>

// Problem constants
#define B_    128
#define S_    256
#define D_    1536
#define DIN_  768
#define NH_   8
#define DH_   192
#define FF_   2048
#define BS_   (B_*S_)   // 32768

// ---------------- scratch (device globals; no cudaMalloc allowed) -------------
__device__ float g_t0 [B_*D_];
__device__ float g_v  [B_*D_];
__device__ float g_t1 [B_*D_];
__device__ float g_qp [B_*D_];
__device__ float g_g  [B_*NH_*D_];
__device__ float g_scores[B_*NH_*S_];
__device__ float g_o  [B_*D_];
__device__ float g_t2 [B_*D_];
__device__ float g_h1 [B_*FF_];
__device__ float g_t3 [B_*D_];
__device__ float g_xsq[B_*D_];
__device__ float g_qp2[B_*D_];
__device__ float g_qt [B_*D_];
__device__ float g_S  [(size_t)2*B_*BS_];
__device__ float g_nm [B_*S_];
__device__ float g_nx [B_];
__device__ float g_part[1600*1024];                 // K-split partials
__device__ __half g_mb [(size_t)BS_*D_];            // memory fp16 (hi only)
__device__ __half g_abh[256*2*D_];                  // pooling A: [Ah|Al] per row
// activation + weight bf16 (hi||lo) buffers
__device__ __nv_bfloat16 g_a2 [128*4096];
__device__ __nv_bfloat16 g_mt2[128*NH_*3072];
__device__ __nv_bfloat16 g_w_emb  [1536*1536];
__device__ __nv_bfloat16 g_w_savv [1536*3072];
__device__ __nv_bfloat16 g_w_saout[1536*3072];
__device__ __nv_bfloat16 g_w_cawq [1536*3072];
__device__ __nv_bfloat16 g_w_cawv [1536*3072];
__device__ __nv_bfloat16 g_w_caout[1536*3072];
__device__ __nv_bfloat16 g_w_lin1 [2048*3072];
__device__ __nv_bfloat16 g_w_lin2 [1536*4096];
__device__ __nv_bfloat16 g_w_attnq[1536*3072];

// =================== common mma.sync macros =====================================
#define LDSM4(R0,R1,R2,R3,ADDR) \
    asm volatile("ldmatrix.sync.aligned.m8n8.x4.shared.b16 {%0,%1,%2,%3}, [%4];" \
        : "=r"(R0),"=r"(R1),"=r"(R2),"=r"(R3) : "r"(ADDR))
#define MMA16816(D,A,B0,B1) \
    asm volatile("mma.sync.aligned.m16n8k16.row.col.f32.bf16.bf16.f32 " \
        "{%0,%1,%2,%3}, {%4,%5,%6,%7}, {%8,%9}, {%0,%1,%2,%3};" \
        : "+f"((D)[0]),"+f"((D)[1]),"+f"((D)[2]),"+f"((D)[3]) \
        : "r"((A)[0]),"r"((A)[1]),"r"((A)[2]),"r"((A)[3]),"r"(B0),"r"(B1))
#define MMAF16(D,A,B0,B1) \
    asm volatile("mma.sync.aligned.m16n8k16.row.col.f32.f16.f16.f32 " \
        "{%0,%1,%2,%3}, {%4,%5,%6,%7}, {%8,%9}, {%0,%1,%2,%3};" \
        : "+f"((D)[0]),"+f"((D)[1]),"+f"((D)[2]),"+f"((D)[3]) \
        : "r"((A)[0]),"r"((A)[1]),"r"((A)[2]),"r"((A)[3]),"r"(B0),"r"(B1))
#define CPA16(DST,SRC) \
    asm volatile("cp.async.ca.shared.global [%0], [%1], 16;" \
        :: "r"((uint32_t)__cvta_generic_to_shared(DST)), "l"(SRC))

__device__ __forceinline__ void split_bf16(float f, __nv_bfloat16& h, __nv_bfloat16& l){
    h = __float2bfloat16(f);
    l = __float2bfloat16(f - __bfloat162float(h));
}
__device__ __forceinline__ void split_f16(float f, __half& h, __half& l){
    h = __float2half(f);
    l = __float2half(f - __half2float(h));
}

// =================== gemm64_tc2: window-fused 3-product bf16 GEMM (proven) ======
#define G2SLD 40
#define SMEM_G2 ((2*128*G2SLD + 2*128*G2SLD + 2*64*G2SLD + 2*64*G2SLD)*2)  // 61440

__global__ void __launch_bounds__(256) gemm64_tc2(
    const __nv_bfloat16* __restrict__ A2, int lda2, long long strideA2,
    const __nv_bfloat16* __restrict__ W2, int ldw2, long long strideW2,
    float* __restrict__ partial, int K)
{
    extern __shared__ __nv_bfloat16 g2sm[];
    __nv_bfloat16* sAh = g2sm;                        // [2][128*G2SLD]
    __nv_bfloat16* sAl = sAh + 2*128*G2SLD;
    __nv_bfloat16* sWh = sAl + 2*128*G2SLD;           // [2][64*G2SLD]
    __nv_bfloat16* sWl = sWh + 2*64*G2SLD;

    const int tid = threadIdx.x;
    const int warp = tid>>5, lane = tid&31;
    const int wm = warp>>1, wn = warp&1;              // 4(m) x 2(n)
    const int bn = blockIdx.x*64;
    const int KS = gridDim.y;
    const int z  = blockIdx.z;
    const int Ntot = gridDim.x*64;
    A2 += (long long)z*strideA2;
    W2 += (long long)z*strideW2;
    const int nwin = (K/32)/KS;
    const int w0   = blockIdx.y*nwin;

    float acc[2][4][4];
    #pragma unroll
    for (int i=0;i<2;i++)
        #pragma unroll
        for (int j=0;j<4;j++)
            #pragma unroll
            for (int c=0;c<4;c++) acc[i][j][c]=0.f;

    #define G2_LOAD(BUF,W) do {                                                \
        int k0_ = (w0 + (W))*32;                                                \
        _Pragma("unroll")                                                       \
        for (int i=0;i<2;i++) {                                                 \
            int l = tid + i*256;                                                \
            int r = l>>2, sg = l&3;                                             \
            CPA16(&sAh[(BUF)*128*G2SLD + r*G2SLD + sg*8],                       \
                  A2 + (size_t)r*lda2 + k0_ + sg*8);                            \
            CPA16(&sAl[(BUF)*128*G2SLD + r*G2SLD + sg*8],                       \
                  A2 + (size_t)r*lda2 + K + k0_ + sg*8);                        \
        }                                                                       \
        { int r = tid>>2, sg = tid&3;                                           \
          CPA16(&sWh[(BUF)*64*G2SLD + r*G2SLD + sg*8],                          \
                W2 + (size_t)(bn+r)*ldw2 + k0_ + sg*8);                         \
          CPA16(&sWl[(BUF)*64*G2SLD + r*G2SLD + sg*8],                          \
                W2 + (size_t)(bn+r)*ldw2 + K + k0_ + sg*8); }                   \
        asm volatile("cp.async.commit_group;");                                 \
    } while(0)

    G2_LOAD(0, 0);
    for (int w=0; w<nwin; w++) {
        int buf = w & 1;
        asm volatile("cp.async.wait_group 0;");
        __syncthreads();
        if (w+1 < nwin) G2_LOAD(buf^1, w+1);
        __nv_bfloat16* ah = sAh + buf*128*G2SLD;
        __nv_bfloat16* al = sAl + buf*128*G2SLD;
        __nv_bfloat16* wh = sWh + buf*64*G2SLD;
        __nv_bfloat16* wl = sWl + buf*64*G2SLD;
        #pragma unroll
        for (int kk=0; kk<2; kk++) {
            const int kb = kk*16;
            uint32_t fah[2][4], fal[2][4], fbh[4][2], fbl[4][2];
            #pragma unroll
            for (int mf=0; mf<2; mf++) {
                int row = wm*32 + mf*16 + (lane&15);
                int ko  = kb + ((lane>>4)<<3);
                uint32_t adh = (uint32_t)__cvta_generic_to_shared(&ah[row*G2SLD + ko]);
                uint32_t adl = (uint32_t)__cvta_generic_to_shared(&al[row*G2SLD + ko]);
                LDSM4(fah[mf][0],fah[mf][1],fah[mf][2],fah[mf][3], adh);
                LDSM4(fal[mf][0],fal[mf][1],fal[mf][2],fal[mf][3], adl);
            }
            #pragma unroll
            for (int p=0; p<2; p++) {
                int nrow = wn*32 + p*16 + ((lane>>4)<<3) + (lane&7);
                int ko   = kb + (((lane>>3)&1)<<3);
                uint32_t adh = (uint32_t)__cvta_generic_to_shared(&wh[nrow*G2SLD + ko]);
                uint32_t adl = (uint32_t)__cvta_generic_to_shared(&wl[nrow*G2SLD + ko]);
                LDSM4(fbh[2*p][0],fbh[2*p][1],fbh[2*p+1][0],fbh[2*p+1][1], adh);
                LDSM4(fbl[2*p][0],fbl[2*p][1],fbl[2*p+1][0],fbl[2*p+1][1], adl);
            }
            #pragma unroll
            for (int mf=0; mf<2; mf++)
                #pragma unroll
                for (int nf=0; nf<4; nf++) {
                    MMA16816(acc[mf][nf], fah[mf], fbh[nf][0], fbh[nf][1]);
                    MMA16816(acc[mf][nf], fah[mf], fbl[nf][0], fbl[nf][1]);
                    MMA16816(acc[mf][nf], fal[mf], fbh[nf][0], fbh[nf][1]);
                }
        }
        __syncthreads();
    }
    const size_t pbase = (size_t)(z*KS + blockIdx.y)*128;
    #pragma unroll
    for (int mf=0; mf<2; mf++) {
        int m = wm*32 + mf*16 + (lane>>2);
        #pragma unroll
        for (int nf=0; nf<4; nf++) {
            int n = bn + wn*32 + nf*8 + ((lane&3)<<1);
            *(float2*)&partial[(pbase + m)*Ntot + n]     = make_float2(acc[mf][nf][0], acc[mf][nf][1]);
            *(float2*)&partial[(pbase + m+8)*Ntot + n]   = make_float2(acc[mf][nf][2], acc[mf][nf][3]);
        }
    }
}

// =================== reduce K-split partials (+bias/relu, +bf16 a2, +fp16 ah) ===
__global__ void __launch_bounds__(256) reduce_ks(
    const float* __restrict__ partial, const float* __restrict__ bias, int strideBias,
    float* __restrict__ C, int ldc, long long strideC,
    int Mtot, int Ntot, int KS, int relu,
    __nv_bfloat16* __restrict__ a2, int lda2, int loOff, int a2strideZ,
    __half* __restrict__ ah, int ldah, int loOffH)
{
    const int zb = blockIdx.y;
    int idx = blockIdx.x*256 + threadIdx.x;
    if (idx >= Mtot*Ntot) return;
    int m = idx / Ntot, n = idx % Ntot;
    float s = 0.f;
    for (int c=0;c<KS;c++)
        s += partial[((size_t)(zb*KS+c)*Mtot + m)*Ntot + n];
    if (bias) s += bias[(size_t)zb*strideBias + n];
    if (relu) s = fmaxf(s, 0.f);
    C[(size_t)zb*strideC + (size_t)m*ldc + n] = s;
    if (a2) {
        __nv_bfloat16 h,l; split_bf16(s,h,l);
        size_t base = (size_t)zb*a2strideZ + (size_t)m*lda2 + n;
        a2[base] = h;
        a2[base + loOff] = l;
    }
    if (ah) {
        __half h,l; split_f16(s,h,l);
        size_t base = (size_t)m*ldah + n;
        ah[base] = h;
        ah[base + loOffH] = l;
    }
}

// =================== fused reduce + residual + LayerNorm (+a2) ==================
__global__ void __launch_bounds__(256) reduce_ln(
    const float* __restrict__ partial, const float* __restrict__ bias,
    const float* __restrict__ resid,
    const float* __restrict__ w, const float* __restrict__ bb,
    float* __restrict__ out, __nv_bfloat16* __restrict__ a2, int KS)
{
    const int row = blockIdx.x, tid = threadIdx.x;
    float vals[6]; float s1=0.f, s2=0.f;
    #pragma unroll
    for (int i=0;i<6;i++) {
        int e = tid + i*256;
        float s = bias ? bias[e] : 0.f;
        for (int c=0;c<KS;c++)
            s += partial[((size_t)c*128 + row)*D_ + e];
        if (resid) s += resid[(size_t)row*D_ + e];
        vals[i]=s; s1+=s; s2+=s*s;
    }
    __shared__ float red[16];
    int lane=tid&31, wid=tid>>5;
    for (int o=16;o;o>>=1){ s1+=__shfl_xor_sync(~0u,s1,o); s2+=__shfl_xor_sync(~0u,s2,o); }
    if (lane==0){ red[wid]=s1; red[8+wid]=s2; }
    __syncthreads();
    if (tid==0){ float a1=0,a2s=0; for(int k=0;k<8;k++){a1+=red[k];a2s+=red[8+k];} red[0]=a1; red[8]=a2s; }
    __syncthreads();
    float mean = red[0]*(1.0f/D_);
    float var  = red[8]*(1.0f/D_) - mean*mean;
    float rstd = rsqrtf(var + 1e-5f);
    #pragma unroll
    for (int i=0;i<6;i++) {
        int e = tid + i*256;
        float y = (vals[i]-mean)*rstd*w[e] + bb[e];
        out[(size_t)row*D_+e] = y;
        if (a2) {
            __nv_bfloat16 h,l; split_bf16(y,h,l);
            a2[(size_t)row*2*D_ + e]      = h;
            a2[(size_t)row*2*D_ + D_ + e] = l;
        }
    }
}

// =================== fp32 gemm_nn (for gg / qt) ==================================
template<int BM,int BN,int BK,int TM,int TN>
__global__ void __launch_bounds__(256) gemm_nn(
    const float* __restrict__ A, int lda, long long strideA,
    const float* __restrict__ W, int ldw, long long strideW,
    const float* __restrict__ bias, int strideBias,
    float* __restrict__ C, int ldc, long long strideC,
    int K, int KS, float* __restrict__ partial)
{
    const int zb = blockIdx.z / KS, chunk = blockIdx.z % KS;
    const int Kc = K / KS;
    A += (long long)zb*strideA + chunk*Kc;
    W += (long long)zb*strideW + (size_t)chunk*Kc*ldw;
    C += (long long)zb*strideC;
    if (bias) bias += (long long)zb*strideBias;

    __shared__ float sA[BK][BM];
    __shared__ float sW[BK][BN];
    const int tid = threadIdx.x;
    const int bm = blockIdx.y*BM, bn = blockIdx.x*BN;
    const int tx = tid % (BN/TN), ty = tid / (BN/TN);
    float acc[TM][TN];
    #pragma unroll
    for (int i=0;i<TM;i++)
        #pragma unroll
        for (int j=0;j<TN;j++) acc[i][j]=0.f;

    for (int k0=0;k0<Kc;k0+=BK) {
        for (int i=tid;i<BM*(BK/4);i+=256) {
            int r=i/(BK/4), kv=i%(BK/4);
            float4 v=*(const float4*)(A+(size_t)(bm+r)*lda + k0 + kv*4);
            sA[kv*4+0][r]=v.x; sA[kv*4+1][r]=v.y; sA[kv*4+2][r]=v.z; sA[kv*4+3][r]=v.w;
        }
        for (int i=tid;i<BK*(BN/4);i+=256) {
            int kk=i/(BN/4), nv=i%(BN/4);
            *(float4*)&sW[kk][nv*4] = *(const float4*)(W+(size_t)(k0+kk)*ldw + bn + nv*4);
        }
        __syncthreads();
        #pragma unroll
        for (int kk=0;kk<BK;kk++) {
            float a[TM], w[TN];
            #pragma unroll
            for (int i=0;i<TM;i+=4) *(float4*)&a[i] = *(const float4*)&sA[kk][ty*TM+i];
            #pragma unroll
            for (int j=0;j<TN;j+=4) *(float4*)&w[j] = *(const float4*)&sW[kk][tx*TN+j];
            #pragma unroll
            for (int i=0;i<TM;i++)
                #pragma unroll
                for (int j=0;j<TN;j++) acc[i][j] = fmaf(a[i], w[j], acc[i][j]);
        }
        __syncthreads();
    }
    if (partial) {
        const int Mtot = gridDim.y*BM, Ntot = gridDim.x*BN;
        #pragma unroll
        for (int i=0;i<TM;i++) {
            int m = bm + ty*TM + i;
            #pragma unroll
            for (int j=0;j<TN;j+=4)
                *(float4*)&partial[((size_t)blockIdx.z*Mtot + m)*Ntot + bn + tx*TN + j]
                    = *(float4*)&acc[i][j];
        }
    } else {
        #pragma unroll
        for (int i=0;i<TM;i++) {
            int gm = bm + ty*TM + i;
            #pragma unroll
            for (int j=0;j<TN;j++) {
                int gn = bn + tx*TN + j;
                C[(size_t)gm*ldc + gn] = acc[i][j] + (bias ? bias[gn] : 0.f);
            }
        }
    }
}

// =================== conversions =================================================
__global__ void __launch_bounds__(256) conv_mem_kernel(const float* __restrict__ mem)
{
    const int row = blockIdx.x*8 + (threadIdx.x>>5);
    const int lane = threadIdx.x&31;
    const float* p = mem + (size_t)row*D_;
    __half* oh = g_mb + (size_t)row*D_;
    float ss = 0.f;
    #pragma unroll
    for (int i=0;i<12;i++) {
        int e = lane*4 + i*128;
        float4 v = *(const float4*)(p+e);
        ss += v.x*v.x + v.y*v.y + v.z*v.z + v.w*v.w;
        __align__(8) __half h[4];
        h[0]=__float2half(v.x); h[1]=__float2half(v.y);
        h[2]=__float2half(v.z); h[3]=__float2half(v.w);
        *(uint64_t*)(oh + e) = *(uint64_t*)h;
    }
    for (int o=16;o;o>>=1) ss += __shfl_xor_sync(~0u, ss, o);
    if (lane==0) g_nm[row] = sqrtf(ss);
}

struct ConvJob { const float* src; __nv_bfloat16* dst; int K; int rows; };
struct ConvJobs { ConvJob j[9]; };

__global__ void __launch_bounds__(256) conv_w_all(ConvJobs jobs)
{
    const ConvJob jb = jobs.j[blockIdx.y];
    const int row = blockIdx.x*8 + (threadIdx.x>>5);
    if (row >= jb.rows) return;
    const int lane = threadIdx.x&31;
    const int K = jb.K;
    const float* p = jb.src + (size_t)row*K;
    __nv_bfloat16* o = jb.dst + (size_t)row*2*K;
    for (int e=lane*4; e<K; e+=128) {
        float4 v = *(const float4*)(p+e);
        __align__(8) __nv_bfloat16 h[4], l[4];
        float f[4] = {v.x,v.y,v.z,v.w};
        #pragma unroll
        for (int c=0;c<4;c++) split_bf16(f[c], h[c], l[c]);
        *(uint64_t*)(o + e)     = *(uint64_t*)h;
        *(uint64_t*)(o + K + e) = *(uint64_t*)l;
    }
}

__global__ void __launch_bounds__(256) conv_x_kernel(const float* __restrict__ x)
{
    const int row = blockIdx.x*8 + (threadIdx.x>>5);
    const int lane = threadIdx.x&31;
    const float* p = x + (size_t)row*DIN_;
    __nv_bfloat16* o = g_a2 + (size_t)row*2*DIN_;
    #pragma unroll
    for (int i=0;i<6;i++) {
        int e = lane*4 + i*128;
        float4 v = *(const float4*)(p+e);
        __align__(8) __nv_bfloat16 h[4], l[4];
        float f[4] = {v.x,v.y,v.z,v.w};
        #pragma unroll
        for (int c=0;c<4;c++) split_bf16(f[c], h[c], l[c]);
        *(uint64_t*)(o + e)        = *(uint64_t*)h;
        *(uint64_t*)(o + DIN_ + e) = *(uint64_t*)l;
    }
}

// =================== bigmm_half: fp16 2-product (proven; cosine half) ===========
#define HSLD 40
#define HCHUNK 48          // 1536 / 32

__global__ void __launch_bounds__(256) bigmm_half(int aBase, int outBase)
{
    extern __shared__ __half hsm[];
    __half* sAh = hsm;                       // [2][128*HSLD]
    __half* sAl = sAh + 2*128*HSLD;
    __half* sB  = sAl + 2*128*HSLD;
    const int tid = threadIdx.x;
    const int warp = tid>>5, lane = tid&31;
    const int wm = warp>>2, wn = warp&3;
    const int nbase = blockIdx.x*128;

    float acc[4][4][4];
    #pragma unroll
    for (int i=0;i<4;i++)
        #pragma unroll
        for (int j=0;j<4;j++)
            #pragma unroll
            for (int c=0;c<4;c++) acc[i][j][c]=0.f;

    const int r0 = tid>>1;
    const int seg0 = (tid&1)*2;

    #define BH_LOAD(BUF,KC) do {                                               \
        int k0_ = (KC)*32;                                                      \
        _Pragma("unroll")                                                       \
        for (int i=0;i<2;i++) {                                                 \
            int seg = seg0 + i;                                                 \
            CPA16(&sAh[(BUF)*128*HSLD + r0*HSLD + seg*8],                       \
                  g_abh + (size_t)(aBase+r0)*2*D_ + k0_ + seg*8);               \
            CPA16(&sAl[(BUF)*128*HSLD + r0*HSLD + seg*8],                       \
                  g_abh + (size_t)(aBase+r0)*2*D_ + D_ + k0_ + seg*8);          \
            CPA16(&sB [(BUF)*128*HSLD + r0*HSLD + seg*8],                       \
                  g_mb + (size_t)(nbase+r0)*D_ + k0_ + seg*8);                  \
        }                                                                       \
        asm volatile("cp.async.commit_group;");                                 \
    } while(0)

    BH_LOAD(0, 0);
    for (int kc=0; kc<HCHUNK; kc++) {
        int buf = kc & 1;
        asm volatile("cp.async.wait_group 0;");
        __syncthreads();
        if (kc+1 < HCHUNK) BH_LOAD(buf^1, kc+1);
        __half* ah = sAh + buf*128*HSLD;
        __half* al = sAl + buf*128*HSLD;
        __half* bt = sB  + buf*128*HSLD;
        #pragma unroll
        for (int kk=0; kk<2; kk++) {
            const int kb = kk*16;
            uint32_t fah[4][4], fal[4][4], b[4][2];
            #pragma unroll
            for (int mf=0; mf<4; mf++) {
                int row = wm*64 + mf*16 + (lane&15);
                int ko  = kb + ((lane>>4)<<3);
                uint32_t adh = (uint32_t)__cvta_generic_to_shared(&ah[row*HSLD + ko]);
                uint32_t adl = (uint32_t)__cvta_generic_to_shared(&al[row*HSLD + ko]);
                LDSM4(fah[mf][0],fah[mf][1],fah[mf][2],fah[mf][3], adh);
                LDSM4(fal[mf][0],fal[mf][1],fal[mf][2],fal[mf][3], adl);
            }
            #pragma unroll
            for (int p=0; p<2; p++) {
                int nrow = wn*32 + p*16 + ((lane>>4)<<3) + (lane&7);
                int ko   = kb + (((lane>>3)&1)<<3);
                uint32_t ad = (uint32_t)__cvta_generic_to_shared(&bt[nrow*HSLD + ko]);
                LDSM4(b[2*p][0],b[2*p][1],b[2*p+1][0],b[2*p+1][1], ad);
            }
            #pragma unroll
            for (int mf=0; mf<4; mf++)
                #pragma unroll
                for (int nf=0; nf<4; nf++) {
                    MMAF16(acc[mf][nf], fah[mf], b[nf][0], b[nf][1]);
                    MMAF16(acc[mf][nf], fal[mf], b[nf][0], b[nf][1]);
                }
        }
        __syncthreads();
    }
    #pragma unroll
    for (int mf=0; mf<4; mf++) {
        int m = outBase + wm*64 + mf*16 + (lane>>2);
        #pragma unroll
        for (int nf=0; nf<4; nf++) {
            int n = nbase + wn*32 + nf*8 + ((lane&3)<<1);
            *(float2*)&g_S[(size_t)m*BS_ + n]     = make_float2(acc[mf][nf][0], acc[mf][nf][1]);
            *(float2*)&g_S[(size_t)(m+8)*BS_ + n] = make_float2(acc[mf][nf][2], acc[mf][nf][3]);
        }
    }
}
#define SMEM_BH (3*2*128*HSLD*2)   // 61440 bytes

// ===== bigmm_half1: fp16 SINGLE-product (scores half; softmax damps A rounding) ==
__global__ void __launch_bounds__(256) bigmm_half1()
{
    extern __shared__ __half hsm1[];
    __half* sAh = hsm1;                      // [2][128*HSLD]
    __half* sB  = sAh + 2*128*HSLD;
    const int tid = threadIdx.x;
    const int warp = tid>>5, lane = tid&31;
    const int wm = warp>>2, wn = warp&3;
    const int nbase = blockIdx.x*128;

    float acc[4][4][4];
    #pragma unroll
    for (int i=0;i<4;i++)
        #pragma unroll
        for (int j=0;j<4;j++)
            #pragma unroll
            for (int c=0;c<4;c++) acc[i][j][c]=0.f;

    const int r0 = tid>>1;
    const int seg0 = (tid&1)*2;

    #define BH1_LOAD(BUF,KC) do {                                              \
        int k0_ = (KC)*32;                                                      \
        _Pragma("unroll")                                                       \
        for (int i=0;i<2;i++) {                                                 \
            int seg = seg0 + i;                                                 \
            CPA16(&sAh[(BUF)*128*HSLD + r0*HSLD + seg*8],                       \
                  g_abh + (size_t)r0*2*D_ + k0_ + seg*8);                       \
            CPA16(&sB [(BUF)*128*HSLD + r0*HSLD + seg*8],                       \
                  g_mb + (size_t)(nbase+r0)*D_ + k0_ + seg*8);                  \
        }                                                                       \
        asm volatile("cp.async.commit_group;");                                 \
    } while(0)

    BH1_LOAD(0, 0);
    for (int kc=0; kc<HCHUNK; kc++) {
        int buf = kc & 1;
        asm volatile("cp.async.wait_group 0;");
        __syncthreads();
        if (kc+1 < HCHUNK) BH1_LOAD(buf^1, kc+1);
        __half* ah = sAh + buf*128*HSLD;
        __half* bt = sB  + buf*128*HSLD;
        #pragma unroll
        for (int kk=0; kk<2; kk++) {
            const int kb = kk*16;
            uint32_t fah[4][4], b[4][2];
            #pragma unroll
            for (int mf=0; mf<4; mf++) {
                int row = wm*64 + mf*16 + (lane&15);
                int ko  = kb + ((lane>>4)<<3);
                uint32_t adh = (uint32_t)__cvta_generic_to_shared(&ah[row*HSLD + ko]);
                LDSM4(fah[mf][0],fah[mf][1],fah[mf][2],fah[mf][3], adh);
            }
            #pragma unroll
            for (int p=0; p<2; p++) {
                int nrow = wn*32 + p*16 + ((lane>>4)<<3) + (lane&7);
                int ko   = kb + (((lane>>3)&1)<<3);
                uint32_t ad = (uint32_t)__cvta_generic_to_shared(&bt[nrow*HSLD + ko]);
                LDSM4(b[2*p][0],b[2*p][1],b[2*p+1][0],b[2*p+1][1], ad);
            }
            #pragma unroll
            for (int mf=0; mf<4; mf++)
                #pragma unroll
                for (int nf=0; nf<4; nf++)
                    MMAF16(acc[mf][nf], fah[mf], b[nf][0], b[nf][1]);
        }
        __syncthreads();
    }
    #pragma unroll
    for (int mf=0; mf<4; mf++) {
        int m = wm*64 + mf*16 + (lane>>2);
        #pragma unroll
        for (int nf=0; nf<4; nf++) {
            int n = nbase + wn*32 + nf*8 + ((lane&3)<<1);
            *(float2*)&g_S[(size_t)m*BS_ + n]     = make_float2(acc[mf][nf][0], acc[mf][nf][1]);
            *(float2*)&g_S[(size_t)(m+8)*BS_ + n] = make_float2(acc[mf][nf][2], acc[mf][nf][3]);
        }
    }
}
#define SMEM_BH1 (2*2*128*HSLD*2)   // 40960 bytes

// =================== LayerNorm (fin; +fp16 abh out, +copy out) ==================
__global__ void __launch_bounds__(256) ln_kernel(
    const float* __restrict__ a, const float* __restrict__ r,
    const float* __restrict__ w, const float* __restrict__ bb,
    float* __restrict__ out, float* __restrict__ norm_out,
    __nv_bfloat16* __restrict__ a2, __half* __restrict__ abh,
    float* __restrict__ copyOut)
{
    const int row = blockIdx.x, tid = threadIdx.x;
    const float* ap = a + (size_t)row*D_;
    const float* rp = r ? r + (size_t)row*D_ : nullptr;
    float vals[6]; float s1=0.f, s2=0.f;
    #pragma unroll
    for (int i=0;i<6;i++) {
        int e = tid + i*256;
        float v = ap[e] + (rp ? rp[e] : 0.f);
        vals[i]=v; s1+=v; s2+=v*v;
    }
    __shared__ float red[16];
    int lane=tid&31, wid=tid>>5;
    for (int o=16;o;o>>=1){ s1+=__shfl_xor_sync(~0u,s1,o); s2+=__shfl_xor_sync(~0u,s2,o); }
    if (lane==0){ red[wid]=s1; red[8+wid]=s2; }
    __syncthreads();
    if (tid==0){ float a1=0,a2s=0; for(int k=0;k<8;k++){a1+=red[k];a2s+=red[8+k];} red[0]=a1; red[8]=a2s; }
    __syncthreads();
    float mean = red[0]*(1.0f/D_);
    float var  = red[8]*(1.0f/D_) - mean*mean;
    float rstd = rsqrtf(var + 1e-5f);
    float ss = 0.f;
    #pragma unroll
    for (int i=0;i<6;i++) {
        int e = tid + i*256;
        float y = (vals[i]-mean)*rstd*w[e] + bb[e];
        out[(size_t)row*D_+e] = y;
        if (copyOut) copyOut[(size_t)row*D_+e] = y;
        if (a2) {
            __nv_bfloat16 h,l; split_bf16(y,h,l);
            a2[(size_t)row*2*D_ + e]      = h;
            a2[(size_t)row*2*D_ + D_ + e] = l;
        }
        if (abh) {
            __half h,l; split_f16(y,h,l);
            abh[(size_t)row*2*D_ + e]      = h;
            abh[(size_t)row*2*D_ + D_ + e] = l;
        }
        ss += y*y;
    }
    if (norm_out) {
        for (int o=16;o;o>>=1) ss+=__shfl_xor_sync(~0u,ss,o);
        __syncthreads();
        if (lane==0) red[wid]=ss;
        __syncthreads();
        if (tid==0){ float t=0; for(int k=0;k<8;k++) t+=red[k]; norm_out[row]=sqrtf(t); }
    }
}

// ========= CA scores from fp16 memory copy =======================================
__global__ void __launch_bounds__(256) ca_scores_kernel()
{
    __shared__ float gs[NH_*D_];
    const int b = blockIdx.x, tid = threadIdx.x;
    const float4* gsrc = (const float4*)(g_g + (size_t)b*NH_*D_);
    for (int i=tid;i<NH_*D_/4;i+=256) ((float4*)gs)[i]=gsrc[i];
    __syncthreads();
    const int warp=tid>>5, lane=tid&31;
    const __half* mb = g_mb + (size_t)b*S_*D_;
    const float scale = rsqrtf((float)DH_);
    const int sbase = blockIdx.y*128 + warp*16;
    for (int grp=0;grp<4;grp++) {
        int s0 = sbase + grp*4;
        float acc[NH_][4];
        #pragma unroll
        for (int h=0;h<NH_;h++)
            #pragma unroll
            for (int r2=0;r2<4;r2++) acc[h][r2]=0.f;
        #pragma unroll
        for (int i=0;i<12;i++) {
            int e = lane*4 + i*128;
            float4 m[4];
            #pragma unroll
            for (int r2=0;r2<4;r2++) {
                uint2 raw = *(const uint2*)(mb+(size_t)(s0+r2)*D_+e);
                __half2 p0 = *(__half2*)&raw.x;
                __half2 p1 = *(__half2*)&raw.y;
                float2 f0 = __half22float2(p0);
                float2 f1 = __half22float2(p1);
                m[r2] = make_float4(f0.x, f0.y, f1.x, f1.y);
            }
            #pragma unroll
            for (int h=0;h<NH_;h++) {
                float4 gv=*(const float4*)(gs + h*D_ + e);
                #pragma unroll
                for (int r2=0;r2<4;r2++)
                    acc[h][r2] += gv.x*m[r2].x + gv.y*m[r2].y + gv.z*m[r2].z + gv.w*m[r2].w;
            }
        }
        #pragma unroll
        for (int h=0;h<NH_;h++)
            #pragma unroll
            for (int r2=0;r2<4;r2++) {
                float v=acc[h][r2];
                for (int o=16;o;o>>=1) v+=__shfl_xor_sync(~0u,v,o);
                if (lane==0) g_scores[((size_t)b*NH_+h)*S_ + s0+r2] = v*scale;
            }
    }
}

__global__ void __launch_bounds__(256) ca_softmax_kernel()
{
    const int row=blockIdx.x, tid=threadIdx.x;
    float* sp = g_scores + (size_t)row*S_;
    float v = sp[tid];
    __shared__ float red[16];
    int lane=tid&31, wid=tid>>5;
    float m=v;
    for (int o=16;o;o>>=1) m=fmaxf(m,__shfl_xor_sync(~0u,m,o));
    if (lane==0) red[wid]=m;
    __syncthreads();
    if (tid==0){ float mm=red[0]; for(int k=1;k<8;k++) mm=fmaxf(mm,red[k]); red[0]=mm; }
    __syncthreads();
    m=red[0];
    float e=__expf(v-m);
    float s=e;
    for (int o=16;o;o>>=1) s+=__shfl_xor_sync(~0u,s,o);
    __syncthreads();
    if (lane==0) red[8+wid]=s;
    __syncthreads();
    if (tid==0){ float t=0; for(int k=0;k<8;k++) t+=red[8+k]; red[8]=t; }
    __syncthreads();
    sp[tid]=e/red[8];
}

__global__ void __launch_bounds__(256) mtilde_kernel()
{
    __shared__ float at[NH_*S_];
    const int b=blockIdx.x, tid=threadIdx.x;
    for (int i=tid;i<NH_*S_;i+=256) at[i]=g_scores[(size_t)b*NH_*S_+i];
    __syncthreads();
    const int e = blockIdx.y*512 + tid*2;
    const __half* mb = g_mb + (size_t)b*S_*D_;
    float2 acc[NH_];
    #pragma unroll
    for (int h=0;h<NH_;h++){ acc[h].x=0.f; acc[h].y=0.f; }
    for (int s=0;s<S_;s++) {
        __half2 raw = *(const __half2*)(mb+(size_t)s*D_+e);
        float2 mv = __half22float2(raw);
        #pragma unroll
        for (int h=0;h<NH_;h++){
            float a=at[h*S_+s];
            acc[h].x=fmaf(a,mv.x,acc[h].x);
            acc[h].y=fmaf(a,mv.y,acc[h].y);
        }
    }
    #pragma unroll
    for (int h=0;h<NH_;h++) {
        __nv_bfloat16 hx,lx,hy,ly;
        split_bf16(acc[h].x,hx,lx); split_bf16(acc[h].y,hy,ly);
        size_t base = (size_t)b*NH_*3072 + h*3072;
        g_mt2[base + e]   = hx; g_mt2[base + e+1]   = hy;
        g_mt2[base + D_ + e] = lx; g_mt2[base + D_ + e+1] = ly;
    }
}

__global__ void __launch_bounds__(256) pool_reduce_kernel(
    const float* __restrict__ ls, float* __restrict__ out)
{
    const int j=blockIdx.x, i=blockIdx.y, s=threadIdx.x;
    const float sc = rsqrtf((float)D_);
    float Sv = g_S[(size_t)i*BS_ + j*S_ + s] * sc;
    float Cv = g_S[(size_t)(B_+i)*BS_ + j*S_ + s];
    float nmv = g_nm[j*S_+s];
    __shared__ float red[16];
    int lane=s&31, wid=s>>5;
    float m=Sv;
    for (int o=16;o;o>>=1) m=fmaxf(m,__shfl_xor_sync(~0u,m,o));
    if (lane==0) red[wid]=m;
    __syncthreads();
    if (s==0){ float mm=red[0]; for(int k=1;k<8;k++) mm=fmaxf(mm,red[k]); red[0]=mm; }
    __syncthreads();
    m=red[0];
    float e = expf(Sv-m);
    float t1=e, t2=e*Cv/nmv;
    for (int o=16;o;o>>=1){ t1+=__shfl_xor_sync(~0u,t1,o); t2+=__shfl_xor_sync(~0u,t2,o); }
    __syncthreads();
    if (lane==0){ red[wid]=t1; red[8+wid]=t2; }
    __syncthreads();
    if (s==0) {
        float Z=0.f, Wv=0.f;
        for (int k=0;k<8;k++){ Z+=red[k]; Wv+=red[8+k]; }
        float val = expf(ls[0]) * Wv / (Z * g_nx[i]);
        out[(size_t)i*B_ + j] = val;
        out[(size_t)B_*B_ + (size_t)j*B_ + i] = val;
    }
}

// =================== host =======================================================
template<typename T> static float* symf(T& s){ void* p=nullptr; cudaGetSymbolAddress(&p, s); return (float*)p; }
template<typename T> static __nv_bfloat16* symb(T& s){ void* p=nullptr; cudaGetSymbolAddress(&p, s); return (__nv_bfloat16*)p; }
template<typename T> static __half* symh(T& s){ void* p=nullptr; cudaGetSymbolAddress(&p, s); return (__half*)p; }

extern "C" void kernel_launch(void* const* d_in, const int* in_sizes, int n_in,
                              void* d_out, int out_size)
{
    const float* x        =(const float*)d_in[0];
    const float* mem      =(const float*)d_in[1];
    const float* emb_w    =(const float*)d_in[2];
    const float* emb_b    =(const float*)d_in[3];
    const float* sa_in_w  =(const float*)d_in[4];
    const float* sa_in_b  =(const float*)d_in[5];
    const float* sa_out_w =(const float*)d_in[6];
    const float* sa_out_b =(const float*)d_in[7];
    const float* ca_in_w  =(const float*)d_in[8];
    const float* ca_in_b  =(const float*)d_in[9];
    const float* ca_out_w =(const float*)d_in[10];
    const float* ca_out_b =(const float*)d_in[11];
    const float* lin1_w   =(const float*)d_in[12];
    const float* lin1_b   =(const float*)d_in[13];
    const float* lin2_w   =(const float*)d_in[14];
    const float* lin2_b   =(const float*)d_in[15];
    const float* ln1_w    =(const float*)d_in[16];
    const float* ln1_b    =(const float*)d_in[17];
    const float* ln2_w    =(const float*)d_in[18];
    const float* ln2_b    =(const float*)d_in[19];
    const float* ln3_w    =(const float*)d_in[20];
    const float* ln3_b    =(const float*)d_in[21];
    const float* fin_w    =(const float*)d_in[22];
    const float* fin_b    =(const float*)d_in[23];
    const float* attn_in_w=(const float*)d_in[24];
    const float* attn_in_b=(const float*)d_in[25];
    const float* logit_sc =(const float*)d_in[26];
    float* out = (float*)d_out;

    float* t0 = symf(g_t0);  float* v   = symf(g_v);
    float* t1 = symf(g_t1);  float* qp  = symf(g_qp);  float* gg  = symf(g_g);
    float* o   = symf(g_o);
    float* t2 = symf(g_t2);  float* h1  = symf(g_h1);
    float* t3 = symf(g_t3);  float* xsq = symf(g_xsq); float* qp2 = symf(g_qp2);
    float* qt = symf(g_qt);  float* nx  = symf(g_nx);  float* pt  = symf(g_part);
    __nv_bfloat16* a2   = symb(g_a2);
    __nv_bfloat16* mt2  = symb(g_mt2);
    __half*        abh  = symh(g_abh);
    __nv_bfloat16* wEmb = symb(g_w_emb);
    __nv_bfloat16* wSaV = symb(g_w_savv);
    __nv_bfloat16* wSaO = symb(g_w_saout);
    __nv_bfloat16* wCaQ = symb(g_w_cawq);
    __nv_bfloat16* wCaV = symb(g_w_cawv);
    __nv_bfloat16* wCaO = symb(g_w_caout);
    __nv_bfloat16* wL1  = symb(g_w_lin1);
    __nv_bfloat16* wL2  = symb(g_w_lin2);
    __nv_bfloat16* wAtQ = symb(g_w_attnq);

    const float* NOB = nullptr;
    __nv_bfloat16* NOA = nullptr;
    __half* NOH = nullptr;
    float* NOF = nullptr;

    static cudaStream_t s2 = nullptr;
    static cudaEvent_t evFork = nullptr, evW = nullptr, evMem = nullptr;
    static cudaEvent_t evXsq = nullptr, evSide = nullptr;
    if (!s2) {
        cudaStreamCreateWithFlags(&s2, cudaStreamNonBlocking);
        cudaEventCreateWithFlags(&evFork, cudaEventDisableTiming);
        cudaEventCreateWithFlags(&evW,    cudaEventDisableTiming);
        cudaEventCreateWithFlags(&evMem,  cudaEventDisableTiming);
        cudaEventCreateWithFlags(&evXsq,  cudaEventDisableTiming);
        cudaEventCreateWithFlags(&evSide, cudaEventDisableTiming);
        cudaFuncSetAttribute(bigmm_half,  cudaFuncAttributeMaxDynamicSharedMemorySize, SMEM_BH);
        cudaFuncSetAttribute(bigmm_half1, cudaFuncAttributeMaxDynamicSharedMemorySize, SMEM_BH1);
        cudaFuncSetAttribute(gemm64_tc2,  cudaFuncAttributeMaxDynamicSharedMemorySize, SMEM_G2);
    }

    // ---- fork: side stream converts 9 weights then memory --------------------
    cudaEventRecord(evFork, 0);
    cudaStreamWaitEvent(s2, evFork, 0);
    {
        ConvJobs jobs;
        jobs.j[0] = { sa_in_w + (size_t)2*D_*D_, wSaV, D_, 1536 };
        jobs.j[1] = { sa_out_w,                  wSaO, D_, 1536 };
        jobs.j[2] = { ca_in_w,                   wCaQ, D_, 1536 };
        jobs.j[3] = { ca_in_w + (size_t)2*D_*D_, wCaV, D_, 1536 };
        jobs.j[4] = { ca_out_w,                  wCaO, D_, 1536 };
        jobs.j[5] = { lin1_w,                    wL1,  D_, 2048 };
        jobs.j[6] = { lin2_w,                    wL2,  FF_, 1536 };
        jobs.j[7] = { attn_in_w,                 wAtQ, D_, 1536 };
        jobs.j[8] = { emb_w,                     wEmb, DIN_, 1536 };
        conv_w_all<<<dim3(256, 9), 256, 0, s2>>>(jobs);
        cudaEventRecord(evW, s2);
        conv_mem_kernel<<<BS_/8, 256, 0, s2>>>(mem);
        cudaEventRecord(evMem, s2);
    }

    // ---- main stream: x conversion, wait weights ------------------------------
    conv_x_kernel<<<16, 256>>>(x);
    cudaStreamWaitEvent(0, evW, 0);

    // 1. t0 = x @ emb_w.T + emb_b
    gemm64_tc2<<<dim3(24,6,1), 256, SMEM_G2>>>(a2, 2*DIN_, 0, wEmb, 2*DIN_, 0, pt, DIN_);
    reduce_ks<<<dim3((B_*D_+255)/256,1),256>>>(pt, emb_b, 0, t0, D_, 0, 128, 1536, 6, 0,
                                               a2, 2*D_, D_, 0, NOH, 0, 0);
    // 2. SA (L=1)
    gemm64_tc2<<<dim3(24,6,1), 256, SMEM_G2>>>(a2, 2*D_, 0, wSaV, 2*D_, 0, pt, D_);
    reduce_ks<<<dim3((B_*D_+255)/256,1),256>>>(pt, sa_in_b+2*D_, 0, v, D_, 0, 128, 1536, 6, 0,
                                               a2, 2*D_, D_, 0, NOH, 0, 0);
    gemm64_tc2<<<dim3(24,6,1), 256, SMEM_G2>>>(a2, 2*D_, 0, wSaO, 2*D_, 0, pt, D_);
    // 3. t1 = LN(t0 + sa)
    reduce_ln<<<B_, 256>>>(pt, sa_out_b, t0, ln1_w, ln1_b, t1, a2, 6);
    // 4. CA q-proj + g
    gemm64_tc2<<<dim3(24,6,1), 256, SMEM_G2>>>(a2, 2*D_, 0, wCaQ, 2*D_, 0, pt, D_);
    reduce_ks<<<dim3((B_*D_+255)/256,1),256>>>(pt, ca_in_b, 0, qp, D_, 0, 128, 1536, 6, 0,
                                               NOA, 0, 0, 0, NOH, 0, 0);
    gemm_nn<64,64,16,4,4><<<dim3(D_/64, B_/64, NH_), 256>>>(
        qp, D_, DH_, ca_in_w + (size_t)D_*D_, D_, (long long)DH_*D_,
        NOB, 0, gg, NH_*D_, D_, DH_, 1, nullptr);
    // 5. CA scores / softmax / weighted memory (fp16 g_mb)
    cudaStreamWaitEvent(0, evMem, 0);
    ca_scores_kernel<<<dim3(B_,2), 256>>>();
    ca_softmax_kernel<<<B_*NH_, 256>>>();
    mtilde_kernel<<<dim3(B_,3), 256>>>();
    // 6. o_h ; ca -> fused LN2
    gemm64_tc2<<<dim3(3,6,NH_), 256, SMEM_G2>>>(mt2, NH_*3072, 3072, wCaV, 2*D_, (long long)DH_*2*D_, pt, D_);
    reduce_ks<<<dim3((128*DH_+255)/256,NH_),256>>>(pt, ca_in_b+2*D_, DH_, o, D_, DH_, 128, DH_, 6, 0,
                                                   a2, 2*D_, D_, DH_, NOH, 0, 0);
    gemm64_tc2<<<dim3(24,6,1), 256, SMEM_G2>>>(a2, 2*D_, 0, wCaO, 2*D_, 0, pt, D_);
    reduce_ln<<<B_, 256>>>(pt, ca_out_b, t1, ln2_w, ln2_b, t2, a2, 6);
    // 8. FF
    gemm64_tc2<<<dim3(32,6,1), 256, SMEM_G2>>>(a2, 2*D_, 0, wL1, 2*D_, 0, pt, D_);
    reduce_ks<<<dim3((B_*FF_+255)/256,1),256>>>(pt, lin1_b, 0, h1, FF_, 0, 128, 2048, 6, 1,
                                                a2, 2*FF_, FF_, 0, NOH, 0, 0);
    gemm64_tc2<<<dim3(24,8,1), 256, SMEM_G2>>>(a2, 2*FF_, 0, wL2, 2*FF_, 0, pt, FF_);
    // 9. t3 = LN(t2 + ff) [KS=8] ; x_sq = LN(t3) (+a2, +abh rows 128.., +copy out2)
    reduce_ln<<<B_, 256>>>(pt, lin2_b, t2, ln3_w, ln3_b, t3, NOA, 8);
    ln_kernel<<<B_, 256>>>(t3, nullptr, fin_w, fin_b, xsq, nx, a2,
                           abh + (size_t)128*2*D_, out + (size_t)2*B_*B_);
    cudaEventRecord(evXsq, 0);

    // ---- side stream: qt projection branch (overlaps cosine bigmm) ------------
    cudaStreamWaitEvent(s2, evXsq, 0);
    gemm64_tc2<<<dim3(24,6,1), 256, SMEM_G2, s2>>>(a2, 2*D_, 0, wAtQ, 2*D_, 0, pt, D_);
    reduce_ks<<<dim3((B_*D_+255)/256,1),256,0,s2>>>(pt, attn_in_b, 0, qp2, D_, 0, 128, 1536, 6, 0,
                                                    NOA, 0, 0, 0, NOH, 0, 0);
    gemm_nn<64,64,16,4,4><<<dim3(D_/64, B_/64, 6), 256, 0, s2>>>(
        qp2, D_, 0, attn_in_w + (size_t)D_*D_, D_, 0,
        NOB, 0, nullptr, 0, 0, D_, 6, pt);
    reduce_ks<<<dim3((B_*D_+255)/256,1),256,0,s2>>>(pt, NOB, 0, qt, D_, 0, 128, 1536, 6, 0,
                                                    NOA, 0, 0, 0, abh, 2*D_, D_);  // qt -> g_abh rows 0-127
    cudaEventRecord(evSide, s2);

    // ---- main stream: cosine bigmm (2-product), then scores bigmm (1-product) --
    bigmm_half<<<BS_/128, 256, SMEM_BH>>>(128, 128);   // cosine: xsq rows
    cudaStreamWaitEvent(0, evSide, 0);
    bigmm_half1<<<BS_/128, 256, SMEM_BH1>>>();         // scores: qt rows, Ah only

    // 12. final softmax-weighted cosine reduce
    pool_reduce_kernel<<<dim3(B_, B_), 256>>>(logit_sc, out);

    (void)in_sizes; (void)n_in; (void)out_size;
}

// round 15
// speedup vs baseline: 2.0529x; 1.0149x over previous
#include <cuda_runtime.h>
#include <cuda_bf16.h>
#include <cuda_fp16.h>
#include <math.h>
#include <stdint.h>

// Problem constants
#define B_    128
#define S_    256
#define D_    1536
#define DIN_  768
#define NH_   8
#define DH_   192
#define FF_   2048
#define BS_   (B_*S_)   // 32768

// ---------------- scratch (device globals; no cudaMalloc allowed) -------------
__device__ float g_t0 [B_*D_];
__device__ float g_v  [B_*D_];
__device__ float g_t1 [B_*D_];
__device__ float g_qp [B_*D_];
__device__ float g_g  [B_*NH_*D_];
__device__ float g_scores[B_*NH_*S_];
__device__ float g_o  [B_*D_];
__device__ float g_t2 [B_*D_];
__device__ float g_h1 [B_*FF_];
__device__ float g_t3 [B_*D_];
__device__ float g_xsq[B_*D_];
__device__ float g_qp2[B_*D_];
__device__ float g_qt [B_*D_];
__device__ float g_S  [(size_t)2*B_*BS_];
__device__ float g_nm [B_*S_];
__device__ float g_nx [B_];
__device__ float g_part[3400*1024];                 // K-split partials (13.9 MB)
__device__ __half g_mb [(size_t)BS_*D_];            // memory fp16 (hi only)
__device__ __half g_abh[256*2*D_];                  // pooling A: [Ah|Al] per row
// activation + weight bf16 (hi||lo) buffers
__device__ __nv_bfloat16 g_a2 [128*4096];
__device__ __nv_bfloat16 g_mt2[128*NH_*3072];
__device__ __nv_bfloat16 g_qph[128*NH_*2*DH_];      // qp per-head [hi192|lo192]
__device__ __nv_bfloat16 g_wkt[(size_t)NH_*D_*2*DH_]; // Wk^T per head: [e][hi192|lo192]
__device__ __nv_bfloat16 g_w_emb  [1536*1536];
__device__ __nv_bfloat16 g_w_savv [1536*3072];
__device__ __nv_bfloat16 g_w_saout[1536*3072];
__device__ __nv_bfloat16 g_w_cawq [1536*3072];
__device__ __nv_bfloat16 g_w_cawv [1536*3072];
__device__ __nv_bfloat16 g_w_caout[1536*3072];
__device__ __nv_bfloat16 g_w_lin1 [2048*3072];
__device__ __nv_bfloat16 g_w_lin2 [1536*4096];
__device__ __nv_bfloat16 g_w_attnq[1536*3072];

// =================== common mma.sync macros =====================================
#define LDSM4(R0,R1,R2,R3,ADDR) \
    asm volatile("ldmatrix.sync.aligned.m8n8.x4.shared.b16 {%0,%1,%2,%3}, [%4];" \
        : "=r"(R0),"=r"(R1),"=r"(R2),"=r"(R3) : "r"(ADDR))
#define MMA16816(D,A,B0,B1) \
    asm volatile("mma.sync.aligned.m16n8k16.row.col.f32.bf16.bf16.f32 " \
        "{%0,%1,%2,%3}, {%4,%5,%6,%7}, {%8,%9}, {%0,%1,%2,%3};" \
        : "+f"((D)[0]),"+f"((D)[1]),"+f"((D)[2]),"+f"((D)[3]) \
        : "r"((A)[0]),"r"((A)[1]),"r"((A)[2]),"r"((A)[3]),"r"(B0),"r"(B1))
#define MMAF16(D,A,B0,B1) \
    asm volatile("mma.sync.aligned.m16n8k16.row.col.f32.f16.f16.f32 " \
        "{%0,%1,%2,%3}, {%4,%5,%6,%7}, {%8,%9}, {%0,%1,%2,%3};" \
        : "+f"((D)[0]),"+f"((D)[1]),"+f"((D)[2]),"+f"((D)[3]) \
        : "r"((A)[0]),"r"((A)[1]),"r"((A)[2]),"r"((A)[3]),"r"(B0),"r"(B1))
#define CPA16(DST,SRC) \
    asm volatile("cp.async.ca.shared.global [%0], [%1], 16;" \
        :: "r"((uint32_t)__cvta_generic_to_shared(DST)), "l"(SRC))

__device__ __forceinline__ void split_bf16(float f, __nv_bfloat16& h, __nv_bfloat16& l){
    h = __float2bfloat16(f);
    l = __float2bfloat16(f - __bfloat162float(h));
}
__device__ __forceinline__ void split_f16(float f, __half& h, __half& l){
    h = __float2half(f);
    l = __float2half(f - __half2float(h));
}

// =================== gemm64_tc2: window-fused 3-product bf16 GEMM (proven) ======
#define G2SLD 40
#define SMEM_G2 ((2*128*G2SLD + 2*128*G2SLD + 2*64*G2SLD + 2*64*G2SLD)*2)  // 61440

__global__ void __launch_bounds__(256) gemm64_tc2(
    const __nv_bfloat16* __restrict__ A2, int lda2, long long strideA2,
    const __nv_bfloat16* __restrict__ W2, int ldw2, long long strideW2,
    float* __restrict__ partial, int K)
{
    extern __shared__ __nv_bfloat16 g2sm[];
    __nv_bfloat16* sAh = g2sm;                        // [2][128*G2SLD]
    __nv_bfloat16* sAl = sAh + 2*128*G2SLD;
    __nv_bfloat16* sWh = sAl + 2*128*G2SLD;           // [2][64*G2SLD]
    __nv_bfloat16* sWl = sWh + 2*64*G2SLD;

    const int tid = threadIdx.x;
    const int warp = tid>>5, lane = tid&31;
    const int wm = warp>>1, wn = warp&1;              // 4(m) x 2(n)
    const int bn = blockIdx.x*64;
    const int KS = gridDim.y;
    const int z  = blockIdx.z;
    const int Ntot = gridDim.x*64;
    A2 += (long long)z*strideA2;
    W2 += (long long)z*strideW2;
    const int nwin = (K/32)/KS;
    const int w0   = blockIdx.y*nwin;

    float acc[2][4][4];
    #pragma unroll
    for (int i=0;i<2;i++)
        #pragma unroll
        for (int j=0;j<4;j++)
            #pragma unroll
            for (int c=0;c<4;c++) acc[i][j][c]=0.f;

    #define G2_LOAD(BUF,W) do {                                                \
        int k0_ = (w0 + (W))*32;                                                \
        _Pragma("unroll")                                                       \
        for (int i=0;i<2;i++) {                                                 \
            int l = tid + i*256;                                                \
            int r = l>>2, sg = l&3;                                             \
            CPA16(&sAh[(BUF)*128*G2SLD + r*G2SLD + sg*8],                       \
                  A2 + (size_t)r*lda2 + k0_ + sg*8);                            \
            CPA16(&sAl[(BUF)*128*G2SLD + r*G2SLD + sg*8],                       \
                  A2 + (size_t)r*lda2 + K + k0_ + sg*8);                        \
        }                                                                       \
        { int r = tid>>2, sg = tid&3;                                           \
          CPA16(&sWh[(BUF)*64*G2SLD + r*G2SLD + sg*8],                          \
                W2 + (size_t)(bn+r)*ldw2 + k0_ + sg*8);                         \
          CPA16(&sWl[(BUF)*64*G2SLD + r*G2SLD + sg*8],                          \
                W2 + (size_t)(bn+r)*ldw2 + K + k0_ + sg*8); }                   \
        asm volatile("cp.async.commit_group;");                                 \
    } while(0)

    G2_LOAD(0, 0);
    for (int w=0; w<nwin; w++) {
        int buf = w & 1;
        asm volatile("cp.async.wait_group 0;");
        __syncthreads();
        if (w+1 < nwin) G2_LOAD(buf^1, w+1);
        __nv_bfloat16* ah = sAh + buf*128*G2SLD;
        __nv_bfloat16* al = sAl + buf*128*G2SLD;
        __nv_bfloat16* wh = sWh + buf*64*G2SLD;
        __nv_bfloat16* wl = sWl + buf*64*G2SLD;
        #pragma unroll
        for (int kk=0; kk<2; kk++) {
            const int kb = kk*16;
            uint32_t fah[2][4], fal[2][4], fbh[4][2], fbl[4][2];
            #pragma unroll
            for (int mf=0; mf<2; mf++) {
                int row = wm*32 + mf*16 + (lane&15);
                int ko  = kb + ((lane>>4)<<3);
                uint32_t adh = (uint32_t)__cvta_generic_to_shared(&ah[row*G2SLD + ko]);
                uint32_t adl = (uint32_t)__cvta_generic_to_shared(&al[row*G2SLD + ko]);
                LDSM4(fah[mf][0],fah[mf][1],fah[mf][2],fah[mf][3], adh);
                LDSM4(fal[mf][0],fal[mf][1],fal[mf][2],fal[mf][3], adl);
            }
            #pragma unroll
            for (int p=0; p<2; p++) {
                int nrow = wn*32 + p*16 + ((lane>>4)<<3) + (lane&7);
                int ko   = kb + (((lane>>3)&1)<<3);
                uint32_t adh = (uint32_t)__cvta_generic_to_shared(&wh[nrow*G2SLD + ko]);
                uint32_t adl = (uint32_t)__cvta_generic_to_shared(&wl[nrow*G2SLD + ko]);
                LDSM4(fbh[2*p][0],fbh[2*p][1],fbh[2*p+1][0],fbh[2*p+1][1], adh);
                LDSM4(fbl[2*p][0],fbl[2*p][1],fbl[2*p+1][0],fbl[2*p+1][1], adl);
            }
            #pragma unroll
            for (int mf=0; mf<2; mf++)
                #pragma unroll
                for (int nf=0; nf<4; nf++) {
                    MMA16816(acc[mf][nf], fah[mf], fbh[nf][0], fbh[nf][1]);
                    MMA16816(acc[mf][nf], fah[mf], fbl[nf][0], fbl[nf][1]);
                    MMA16816(acc[mf][nf], fal[mf], fbh[nf][0], fbh[nf][1]);
                }
        }
        __syncthreads();
    }
    const size_t pbase = (size_t)(z*KS + blockIdx.y)*128;
    #pragma unroll
    for (int mf=0; mf<2; mf++) {
        int m = wm*32 + mf*16 + (lane>>2);
        #pragma unroll
        for (int nf=0; nf<4; nf++) {
            int n = bn + wn*32 + nf*8 + ((lane&3)<<1);
            *(float2*)&partial[(pbase + m)*Ntot + n]     = make_float2(acc[mf][nf][0], acc[mf][nf][1]);
            *(float2*)&partial[(pbase + m+8)*Ntot + n]   = make_float2(acc[mf][nf][2], acc[mf][nf][3]);
        }
    }
}

// ========== reduce K-split partials (+bias/relu, +bf16 a2, +fp16 ah, +head split)
__global__ void __launch_bounds__(256) reduce_ks(
    const float* __restrict__ partial, const float* __restrict__ bias, int strideBias,
    float* __restrict__ C, int ldc, long long strideC,
    int Mtot, int Ntot, int KS, int relu,
    __nv_bfloat16* __restrict__ a2, int lda2, int loOff, int a2strideZ,
    __half* __restrict__ ah, int ldah, int loOffH,
    __nv_bfloat16* __restrict__ hd, int headK)
{
    const int zb = blockIdx.y;
    int idx = blockIdx.x*256 + threadIdx.x;
    if (idx >= Mtot*Ntot) return;
    int m = idx / Ntot, n = idx % Ntot;
    float s = 0.f;
    for (int c=0;c<KS;c++)
        s += partial[((size_t)(zb*KS+c)*Mtot + m)*Ntot + n];
    if (bias) s += bias[(size_t)zb*strideBias + n];
    if (relu) s = fmaxf(s, 0.f);
    C[(size_t)zb*strideC + (size_t)m*ldc + n] = s;
    if (a2) {
        __nv_bfloat16 h,l; split_bf16(s,h,l);
        size_t base = (size_t)zb*a2strideZ + (size_t)m*lda2 + n;
        a2[base] = h;
        a2[base + loOff] = l;
    }
    if (ah) {
        __half h,l; split_f16(s,h,l);
        size_t base = (size_t)m*ldah + n;
        ah[base] = h;
        ah[base + loOffH] = l;
    }
    if (hd) {
        __nv_bfloat16 h,l; split_bf16(s,h,l);
        int head = n / headK, id2 = n - head*headK;
        size_t base = (size_t)m*(NH_*2*headK) + (size_t)head*(2*headK) + id2;
        hd[base] = h;
        hd[base + headK] = l;
    }
}

// =================== fused reduce + residual + LayerNorm (+a2) ==================
__global__ void __launch_bounds__(256) reduce_ln(
    const float* __restrict__ partial, const float* __restrict__ bias,
    const float* __restrict__ resid,
    const float* __restrict__ w, const float* __restrict__ bb,
    float* __restrict__ out, __nv_bfloat16* __restrict__ a2, int KS)
{
    const int row = blockIdx.x, tid = threadIdx.x;
    float vals[6]; float s1=0.f, s2=0.f;
    #pragma unroll
    for (int i=0;i<6;i++) {
        int e = tid + i*256;
        float s = bias ? bias[e] : 0.f;
        for (int c=0;c<KS;c++)
            s += partial[((size_t)c*128 + row)*D_ + e];
        if (resid) s += resid[(size_t)row*D_ + e];
        vals[i]=s; s1+=s; s2+=s*s;
    }
    __shared__ float red[16];
    int lane=tid&31, wid=tid>>5;
    for (int o=16;o;o>>=1){ s1+=__shfl_xor_sync(~0u,s1,o); s2+=__shfl_xor_sync(~0u,s2,o); }
    if (lane==0){ red[wid]=s1; red[8+wid]=s2; }
    __syncthreads();
    if (tid==0){ float a1=0,a2s=0; for(int k=0;k<8;k++){a1+=red[k];a2s+=red[8+k];} red[0]=a1; red[8]=a2s; }
    __syncthreads();
    float mean = red[0]*(1.0f/D_);
    float var  = red[8]*(1.0f/D_) - mean*mean;
    float rstd = rsqrtf(var + 1e-5f);
    #pragma unroll
    for (int i=0;i<6;i++) {
        int e = tid + i*256;
        float y = (vals[i]-mean)*rstd*w[e] + bb[e];
        out[(size_t)row*D_+e] = y;
        if (a2) {
            __nv_bfloat16 h,l; split_bf16(y,h,l);
            a2[(size_t)row*2*D_ + e]      = h;
            a2[(size_t)row*2*D_ + D_ + e] = l;
        }
    }
}

// =================== fp32 gemm_nn (for qt branch) ================================
template<int BM,int BN,int BK,int TM,int TN>
__global__ void __launch_bounds__(256) gemm_nn(
    const float* __restrict__ A, int lda, long long strideA,
    const float* __restrict__ W, int ldw, long long strideW,
    const float* __restrict__ bias, int strideBias,
    float* __restrict__ C, int ldc, long long strideC,
    int K, int KS, float* __restrict__ partial)
{
    const int zb = blockIdx.z / KS, chunk = blockIdx.z % KS;
    const int Kc = K / KS;
    A += (long long)zb*strideA + chunk*Kc;
    W += (long long)zb*strideW + (size_t)chunk*Kc*ldw;
    C += (long long)zb*strideC;
    if (bias) bias += (long long)zb*strideBias;

    __shared__ float sA[BK][BM];
    __shared__ float sW[BK][BN];
    const int tid = threadIdx.x;
    const int bm = blockIdx.y*BM, bn = blockIdx.x*BN;
    const int tx = tid % (BN/TN), ty = tid / (BN/TN);
    float acc[TM][TN];
    #pragma unroll
    for (int i=0;i<TM;i++)
        #pragma unroll
        for (int j=0;j<TN;j++) acc[i][j]=0.f;

    for (int k0=0;k0<Kc;k0+=BK) {
        for (int i=tid;i<BM*(BK/4);i+=256) {
            int r=i/(BK/4), kv=i%(BK/4);
            float4 v=*(const float4*)(A+(size_t)(bm+r)*lda + k0 + kv*4);
            sA[kv*4+0][r]=v.x; sA[kv*4+1][r]=v.y; sA[kv*4+2][r]=v.z; sA[kv*4+3][r]=v.w;
        }
        for (int i=tid;i<BK*(BN/4);i+=256) {
            int kk=i/(BN/4), nv=i%(BN/4);
            *(float4*)&sW[kk][nv*4] = *(const float4*)(W+(size_t)(k0+kk)*ldw + bn + nv*4);
        }
        __syncthreads();
        #pragma unroll
        for (int kk=0;kk<BK;kk++) {
            float a[TM], w[TN];
            #pragma unroll
            for (int i=0;i<TM;i+=4) *(float4*)&a[i] = *(const float4*)&sA[kk][ty*TM+i];
            #pragma unroll
            for (int j=0;j<TN;j+=4) *(float4*)&w[j] = *(const float4*)&sW[kk][tx*TN+j];
            #pragma unroll
            for (int i=0;i<TM;i++)
                #pragma unroll
                for (int j=0;j<TN;j++) acc[i][j] = fmaf(a[i], w[j], acc[i][j]);
        }
        __syncthreads();
    }
    if (partial) {
        const int Mtot = gridDim.y*BM, Ntot = gridDim.x*BN;
        #pragma unroll
        for (int i=0;i<TM;i++) {
            int m = bm + ty*TM + i;
            #pragma unroll
            for (int j=0;j<TN;j+=4)
                *(float4*)&partial[((size_t)blockIdx.z*Mtot + m)*Ntot + bn + tx*TN + j]
                    = *(float4*)&acc[i][j];
        }
    } else {
        #pragma unroll
        for (int i=0;i<TM;i++) {
            int gm = bm + ty*TM + i;
            #pragma unroll
            for (int j=0;j<TN;j++) {
                int gn = bn + tx*TN + j;
                C[(size_t)gm*ldc + gn] = acc[i][j] + (bias ? bias[gn] : 0.f);
            }
        }
    }
}

// =================== conversions =================================================
__global__ void __launch_bounds__(256) conv_mem_kernel(const float* __restrict__ mem)
{
    const int row = blockIdx.x*8 + (threadIdx.x>>5);
    const int lane = threadIdx.x&31;
    const float* p = mem + (size_t)row*D_;
    __half* oh = g_mb + (size_t)row*D_;
    float ss = 0.f;
    #pragma unroll
    for (int i=0;i<12;i++) {
        int e = lane*4 + i*128;
        float4 v = *(const float4*)(p+e);
        ss += v.x*v.x + v.y*v.y + v.z*v.z + v.w*v.w;
        __align__(8) __half h[4];
        h[0]=__float2half(v.x); h[1]=__float2half(v.y);
        h[2]=__float2half(v.z); h[3]=__float2half(v.w);
        *(uint64_t*)(oh + e) = *(uint64_t*)h;
    }
    for (int o=16;o;o>>=1) ss += __shfl_xor_sync(~0u, ss, o);
    if (lane==0) g_nm[row] = sqrtf(ss);
}

struct ConvJob { const float* src; __nv_bfloat16* dst; int K; int rows; };
struct ConvJobs { ConvJob j[9]; };

__global__ void __launch_bounds__(256) conv_w_all(ConvJobs jobs)
{
    const ConvJob jb = jobs.j[blockIdx.y];
    const int row = blockIdx.x*8 + (threadIdx.x>>5);
    if (row >= jb.rows) return;
    const int lane = threadIdx.x&31;
    const int K = jb.K;
    const float* p = jb.src + (size_t)row*K;
    __nv_bfloat16* o = jb.dst + (size_t)row*2*K;
    for (int e=lane*4; e<K; e+=128) {
        float4 v = *(const float4*)(p+e);
        __align__(8) __nv_bfloat16 h[4], l[4];
        float f[4] = {v.x,v.y,v.z,v.w};
        #pragma unroll
        for (int c=0;c<4;c++) split_bf16(f[c], h[c], l[c]);
        *(uint64_t*)(o + e)     = *(uint64_t*)h;
        *(uint64_t*)(o + K + e) = *(uint64_t*)l;
    }
}

// Wk (rows r = h*192+., cols e) -> g_wkt[h][e][hi192|lo192] via smem transpose.
__global__ void __launch_bounds__(256) conv_wkt(const float* __restrict__ wk)
{
    __shared__ float tile[32][33];
    const int h = blockIdx.z;
    const int e0 = blockIdx.x*32, r0 = blockIdx.y*32;
    const int tx = threadIdx.x & 31, ty = threadIdx.x >> 5;  // 32 x 8
    #pragma unroll
    for (int i=0;i<4;i++) {
        int r = r0 + ty + 8*i;
        tile[ty+8*i][tx] = wk[(size_t)(h*DH_ + r)*D_ + e0 + tx];
    }
    __syncthreads();
    __nv_bfloat16* dst = g_wkt + (size_t)h*D_*2*DH_;
    #pragma unroll
    for (int i=0;i<4;i++) {
        int e = e0 + ty + 8*i;
        float v = tile[tx][ty+8*i];
        __nv_bfloat16 hh,ll; split_bf16(v,hh,ll);
        dst[(size_t)e*2*DH_ + r0 + tx]        = hh;
        dst[(size_t)e*2*DH_ + DH_ + r0 + tx]  = ll;
    }
}

__global__ void __launch_bounds__(256) conv_x_kernel(const float* __restrict__ x)
{
    const int row = blockIdx.x*8 + (threadIdx.x>>5);
    const int lane = threadIdx.x&31;
    const float* p = x + (size_t)row*DIN_;
    __nv_bfloat16* o = g_a2 + (size_t)row*2*DIN_;
    #pragma unroll
    for (int i=0;i<6;i++) {
        int e = lane*4 + i*128;
        float4 v = *(const float4*)(p+e);
        __align__(8) __nv_bfloat16 h[4], l[4];
        float f[4] = {v.x,v.y,v.z,v.w};
        #pragma unroll
        for (int c=0;c<4;c++) split_bf16(f[c], h[c], l[c]);
        *(uint64_t*)(o + e)        = *(uint64_t*)h;
        *(uint64_t*)(o + DIN_ + e) = *(uint64_t*)l;
    }
}

// =================== bigmm_half: fp16 2-product (proven; cosine half) ===========
#define HSLD 40
#define HCHUNK 48          // 1536 / 32

__global__ void __launch_bounds__(256) bigmm_half(int aBase, int outBase)
{
    extern __shared__ __half hsm[];
    __half* sAh = hsm;                       // [2][128*HSLD]
    __half* sAl = sAh + 2*128*HSLD;
    __half* sB  = sAl + 2*128*HSLD;
    const int tid = threadIdx.x;
    const int warp = tid>>5, lane = tid&31;
    const int wm = warp>>2, wn = warp&3;
    const int nbase = blockIdx.x*128;

    float acc[4][4][4];
    #pragma unroll
    for (int i=0;i<4;i++)
        #pragma unroll
        for (int j=0;j<4;j++)
            #pragma unroll
            for (int c=0;c<4;c++) acc[i][j][c]=0.f;

    const int r0 = tid>>1;
    const int seg0 = (tid&1)*2;

    #define BH_LOAD(BUF,KC) do {                                               \
        int k0_ = (KC)*32;                                                      \
        _Pragma("unroll")                                                       \
        for (int i=0;i<2;i++) {                                                 \
            int seg = seg0 + i;                                                 \
            CPA16(&sAh[(BUF)*128*HSLD + r0*HSLD + seg*8],                       \
                  g_abh + (size_t)(aBase+r0)*2*D_ + k0_ + seg*8);               \
            CPA16(&sAl[(BUF)*128*HSLD + r0*HSLD + seg*8],                       \
                  g_abh + (size_t)(aBase+r0)*2*D_ + D_ + k0_ + seg*8);          \
            CPA16(&sB [(BUF)*128*HSLD + r0*HSLD + seg*8],                       \
                  g_mb + (size_t)(nbase+r0)*D_ + k0_ + seg*8);                  \
        }                                                                       \
        asm volatile("cp.async.commit_group;");                                 \
    } while(0)

    BH_LOAD(0, 0);
    for (int kc=0; kc<HCHUNK; kc++) {
        int buf = kc & 1;
        asm volatile("cp.async.wait_group 0;");
        __syncthreads();
        if (kc+1 < HCHUNK) BH_LOAD(buf^1, kc+1);
        __half* ah = sAh + buf*128*HSLD;
        __half* al = sAl + buf*128*HSLD;
        __half* bt = sB  + buf*128*HSLD;
        #pragma unroll
        for (int kk=0; kk<2; kk++) {
            const int kb = kk*16;
            uint32_t fah[4][4], fal[4][4], b[4][2];
            #pragma unroll
            for (int mf=0; mf<4; mf++) {
                int row = wm*64 + mf*16 + (lane&15);
                int ko  = kb + ((lane>>4)<<3);
                uint32_t adh = (uint32_t)__cvta_generic_to_shared(&ah[row*HSLD + ko]);
                uint32_t adl = (uint32_t)__cvta_generic_to_shared(&al[row*HSLD + ko]);
                LDSM4(fah[mf][0],fah[mf][1],fah[mf][2],fah[mf][3], adh);
                LDSM4(fal[mf][0],fal[mf][1],fal[mf][2],fal[mf][3], adl);
            }
            #pragma unroll
            for (int p=0; p<2; p++) {
                int nrow = wn*32 + p*16 + ((lane>>4)<<3) + (lane&7);
                int ko   = kb + (((lane>>3)&1)<<3);
                uint32_t ad = (uint32_t)__cvta_generic_to_shared(&bt[nrow*HSLD + ko]);
                LDSM4(b[2*p][0],b[2*p][1],b[2*p+1][0],b[2*p+1][1], ad);
            }
            #pragma unroll
            for (int mf=0; mf<4; mf++)
                #pragma unroll
                for (int nf=0; nf<4; nf++) {
                    MMAF16(acc[mf][nf], fah[mf], b[nf][0], b[nf][1]);
                    MMAF16(acc[mf][nf], fal[mf], b[nf][0], b[nf][1]);
                }
        }
        __syncthreads();
    }
    #pragma unroll
    for (int mf=0; mf<4; mf++) {
        int m = outBase + wm*64 + mf*16 + (lane>>2);
        #pragma unroll
        for (int nf=0; nf<4; nf++) {
            int n = nbase + wn*32 + nf*8 + ((lane&3)<<1);
            *(float2*)&g_S[(size_t)m*BS_ + n]     = make_float2(acc[mf][nf][0], acc[mf][nf][1]);
            *(float2*)&g_S[(size_t)(m+8)*BS_ + n] = make_float2(acc[mf][nf][2], acc[mf][nf][3]);
        }
    }
}
#define SMEM_BH (3*2*128*HSLD*2)   // 61440 bytes

// ===== bigmm_half1: fp16 SINGLE-product (scores half) ============================
__global__ void __launch_bounds__(256) bigmm_half1()
{
    extern __shared__ __half hsm1[];
    __half* sAh = hsm1;                      // [2][128*HSLD]
    __half* sB  = sAh + 2*128*HSLD;
    const int tid = threadIdx.x;
    const int warp = tid>>5, lane = tid&31;
    const int wm = warp>>2, wn = warp&3;
    const int nbase = blockIdx.x*128;

    float acc[4][4][4];
    #pragma unroll
    for (int i=0;i<4;i++)
        #pragma unroll
        for (int j=0;j<4;j++)
            #pragma unroll
            for (int c=0;c<4;c++) acc[i][j][c]=0.f;

    const int r0 = tid>>1;
    const int seg0 = (tid&1)*2;

    #define BH1_LOAD(BUF,KC) do {                                              \
        int k0_ = (KC)*32;                                                      \
        _Pragma("unroll")                                                       \
        for (int i=0;i<2;i++) {                                                 \
            int seg = seg0 + i;                                                 \
            CPA16(&sAh[(BUF)*128*HSLD + r0*HSLD + seg*8],                       \
                  g_abh + (size_t)r0*2*D_ + k0_ + seg*8);                       \
            CPA16(&sB [(BUF)*128*HSLD + r0*HSLD + seg*8],                       \
                  g_mb + (size_t)(nbase+r0)*D_ + k0_ + seg*8);                  \
        }                                                                       \
        asm volatile("cp.async.commit_group;");                                 \
    } while(0)

    BH1_LOAD(0, 0);
    for (int kc=0; kc<HCHUNK; kc++) {
        int buf = kc & 1;
        asm volatile("cp.async.wait_group 0;");
        __syncthreads();
        if (kc+1 < HCHUNK) BH1_LOAD(buf^1, kc+1);
        __half* ah = sAh + buf*128*HSLD;
        __half* bt = sB  + buf*128*HSLD;
        #pragma unroll
        for (int kk=0; kk<2; kk++) {
            const int kb = kk*16;
            uint32_t fah[4][4], b[4][2];
            #pragma unroll
            for (int mf=0; mf<4; mf++) {
                int row = wm*64 + mf*16 + (lane&15);
                int ko  = kb + ((lane>>4)<<3);
                uint32_t adh = (uint32_t)__cvta_generic_to_shared(&ah[row*HSLD + ko]);
                LDSM4(fah[mf][0],fah[mf][1],fah[mf][2],fah[mf][3], adh);
            }
            #pragma unroll
            for (int p=0; p<2; p++) {
                int nrow = wn*32 + p*16 + ((lane>>4)<<3) + (lane&7);
                int ko   = kb + (((lane>>3)&1)<<3);
                uint32_t ad = (uint32_t)__cvta_generic_to_shared(&bt[nrow*HSLD + ko]);
                LDSM4(b[2*p][0],b[2*p][1],b[2*p+1][0],b[2*p+1][1], ad);
            }
            #pragma unroll
            for (int mf=0; mf<4; mf++)
                #pragma unroll
                for (int nf=0; nf<4; nf++)
                    MMAF16(acc[mf][nf], fah[mf], b[nf][0], b[nf][1]);
        }
        __syncthreads();
    }
    #pragma unroll
    for (int mf=0; mf<4; mf++) {
        int m = wm*64 + mf*16 + (lane>>2);
        #pragma unroll
        for (int nf=0; nf<4; nf++) {
            int n = nbase + wn*32 + nf*8 + ((lane&3)<<1);
            *(float2*)&g_S[(size_t)m*BS_ + n]     = make_float2(acc[mf][nf][0], acc[mf][nf][1]);
            *(float2*)&g_S[(size_t)(m+8)*BS_ + n] = make_float2(acc[mf][nf][2], acc[mf][nf][3]);
        }
    }
}
#define SMEM_BH1 (2*2*128*HSLD*2)   // 40960 bytes

// =================== LayerNorm (fin; +fp16 abh out, +copy out) ==================
__global__ void __launch_bounds__(256) ln_kernel(
    const float* __restrict__ a, const float* __restrict__ r,
    const float* __restrict__ w, const float* __restrict__ bb,
    float* __restrict__ out, float* __restrict__ norm_out,
    __nv_bfloat16* __restrict__ a2, __half* __restrict__ abh,
    float* __restrict__ copyOut)
{
    const int row = blockIdx.x, tid = threadIdx.x;
    const float* ap = a + (size_t)row*D_;
    const float* rp = r ? r + (size_t)row*D_ : nullptr;
    float vals[6]; float s1=0.f, s2=0.f;
    #pragma unroll
    for (int i=0;i<6;i++) {
        int e = tid + i*256;
        float v = ap[e] + (rp ? rp[e] : 0.f);
        vals[i]=v; s1+=v; s2+=v*v;
    }
    __shared__ float red[16];
    int lane=tid&31, wid=tid>>5;
    for (int o=16;o;o>>=1){ s1+=__shfl_xor_sync(~0u,s1,o); s2+=__shfl_xor_sync(~0u,s2,o); }
    if (lane==0){ red[wid]=s1; red[8+wid]=s2; }
    __syncthreads();
    if (tid==0){ float a1=0,a2s=0; for(int k=0;k<8;k++){a1+=red[k];a2s+=red[8+k];} red[0]=a1; red[8]=a2s; }
    __syncthreads();
    float mean = red[0]*(1.0f/D_);
    float var  = red[8]*(1.0f/D_) - mean*mean;
    float rstd = rsqrtf(var + 1e-5f);
    float ss = 0.f;
    #pragma unroll
    for (int i=0;i<6;i++) {
        int e = tid + i*256;
        float y = (vals[i]-mean)*rstd*w[e] + bb[e];
        out[(size_t)row*D_+e] = y;
        if (copyOut) copyOut[(size_t)row*D_+e] = y;
        if (a2) {
            __nv_bfloat16 h,l; split_bf16(y,h,l);
            a2[(size_t)row*2*D_ + e]      = h;
            a2[(size_t)row*2*D_ + D_ + e] = l;
        }
        if (abh) {
            __half h,l; split_f16(y,h,l);
            abh[(size_t)row*2*D_ + e]      = h;
            abh[(size_t)row*2*D_ + D_ + e] = l;
        }
        ss += y*y;
    }
    if (norm_out) {
        for (int o=16;o;o>>=1) ss+=__shfl_xor_sync(~0u,ss,o);
        __syncthreads();
        if (lane==0) red[wid]=ss;
        __syncthreads();
        if (tid==0){ float t=0; for(int k=0;k<8;k++) t+=red[k]; norm_out[row]=sqrtf(t); }
    }
}

// ========= CA scores from fp16 memory copy =======================================
__global__ void __launch_bounds__(256) ca_scores_kernel()
{
    __shared__ float gs[NH_*D_];
    const int b = blockIdx.x, tid = threadIdx.x;
    const float4* gsrc = (const float4*)(g_g + (size_t)b*NH_*D_);
    for (int i=tid;i<NH_*D_/4;i+=256) ((float4*)gs)[i]=gsrc[i];
    __syncthreads();
    const int warp=tid>>5, lane=tid&31;
    const __half* mb = g_mb + (size_t)b*S_*D_;
    const float scale = rsqrtf((float)DH_);
    const int sbase = blockIdx.y*128 + warp*16;
    for (int grp=0;grp<4;grp++) {
        int s0 = sbase + grp*4;
        float acc[NH_][4];
        #pragma unroll
        for (int h=0;h<NH_;h++)
            #pragma unroll
            for (int r2=0;r2<4;r2++) acc[h][r2]=0.f;
        #pragma unroll
        for (int i=0;i<12;i++) {
            int e = lane*4 + i*128;
            float4 m[4];
            #pragma unroll
            for (int r2=0;r2<4;r2++) {
                uint2 raw = *(const uint2*)(mb+(size_t)(s0+r2)*D_+e);
                __half2 p0 = *(__half2*)&raw.x;
                __half2 p1 = *(__half2*)&raw.y;
                float2 f0 = __half22float2(p0);
                float2 f1 = __half22float2(p1);
                m[r2] = make_float4(f0.x, f0.y, f1.x, f1.y);
            }
            #pragma unroll
            for (int h=0;h<NH_;h++) {
                float4 gv=*(const float4*)(gs + h*D_ + e);
                #pragma unroll
                for (int r2=0;r2<4;r2++)
                    acc[h][r2] += gv.x*m[r2].x + gv.y*m[r2].y + gv.z*m[r2].z + gv.w*m[r2].w;
            }
        }
        #pragma unroll
        for (int h=0;h<NH_;h++)
            #pragma unroll
            for (int r2=0;r2<4;r2++) {
                float v=acc[h][r2];
                for (int o=16;o;o>>=1) v+=__shfl_xor_sync(~0u,v,o);
                if (lane==0) g_scores[((size_t)b*NH_+h)*S_ + s0+r2] = v*scale;
            }
    }
}

__global__ void __launch_bounds__(256) ca_softmax_kernel()
{
    const int row=blockIdx.x, tid=threadIdx.x;
    float* sp = g_scores + (size_t)row*S_;
    float v = sp[tid];
    __shared__ float red[16];
    int lane=tid&31, wid=tid>>5;
    float m=v;
    for (int o=16;o;o>>=1) m=fmaxf(m,__shfl_xor_sync(~0u,m,o));
    if (lane==0) red[wid]=m;
    __syncthreads();
    if (tid==0){ float mm=red[0]; for(int k=1;k<8;k++) mm=fmaxf(mm,red[k]); red[0]=mm; }
    __syncthreads();
    m=red[0];
    float e=__expf(v-m);
    float s=e;
    for (int o=16;o;o>>=1) s+=__shfl_xor_sync(~0u,s,o);
    __syncthreads();
    if (lane==0) red[8+wid]=s;
    __syncthreads();
    if (tid==0){ float t=0; for(int k=0;k<8;k++) t+=red[8+k]; red[8]=t; }
    __syncthreads();
    sp[tid]=e/red[8];
}

__global__ void __launch_bounds__(256) mtilde_kernel()
{
    __shared__ float at[NH_*S_];
    const int b=blockIdx.x, tid=threadIdx.x;
    for (int i=tid;i<NH_*S_;i+=256) at[i]=g_scores[(size_t)b*NH_*S_+i];
    __syncthreads();
    const int e = blockIdx.y*512 + tid*2;
    const __half* mb = g_mb + (size_t)b*S_*D_;
    float2 acc[NH_];
    #pragma unroll
    for (int h=0;h<NH_;h++){ acc[h].x=0.f; acc[h].y=0.f; }
    for (int s=0;s<S_;s++) {
        __half2 raw = *(const __half2*)(mb+(size_t)s*D_+e);
        float2 mv = __half22float2(raw);
        #pragma unroll
        for (int h=0;h<NH_;h++){
            float a=at[h*S_+s];
            acc[h].x=fmaf(a,mv.x,acc[h].x);
            acc[h].y=fmaf(a,mv.y,acc[h].y);
        }
    }
    #pragma unroll
    for (int h=0;h<NH_;h++) {
        __nv_bfloat16 hx,lx,hy,ly;
        split_bf16(acc[h].x,hx,lx); split_bf16(acc[h].y,hy,ly);
        size_t base = (size_t)b*NH_*3072 + h*3072;
        g_mt2[base + e]   = hx; g_mt2[base + e+1]   = hy;
        g_mt2[base + D_ + e] = lx; g_mt2[base + D_ + e+1] = ly;
    }
}

__global__ void __launch_bounds__(256) pool_reduce_kernel(
    const float* __restrict__ ls, float* __restrict__ out)
{
    const int j=blockIdx.x, i=blockIdx.y, s=threadIdx.x;
    const float sc = rsqrtf((float)D_);
    float Sv = g_S[(size_t)i*BS_ + j*S_ + s] * sc;
    float Cv = g_S[(size_t)(B_+i)*BS_ + j*S_ + s];
    float nmv = g_nm[j*S_+s];
    __shared__ float red[16];
    int lane=s&31, wid=s>>5;
    float m=Sv;
    for (int o=16;o;o>>=1) m=fmaxf(m,__shfl_xor_sync(~0u,m,o));
    if (lane==0) red[wid]=m;
    __syncthreads();
    if (s==0){ float mm=red[0]; for(int k=1;k<8;k++) mm=fmaxf(mm,red[k]); red[0]=mm; }
    __syncthreads();
    m=red[0];
    float e = expf(Sv-m);
    float t1=e, t2=e*Cv/nmv;
    for (int o=16;o;o>>=1){ t1+=__shfl_xor_sync(~0u,t1,o); t2+=__shfl_xor_sync(~0u,t2,o); }
    __syncthreads();
    if (lane==0){ red[wid]=t1; red[8+wid]=t2; }
    __syncthreads();
    if (s==0) {
        float Z=0.f, Wv=0.f;
        for (int k=0;k<8;k++){ Z+=red[k]; Wv+=red[8+k]; }
        float val = expf(ls[0]) * Wv / (Z * g_nx[i]);
        out[(size_t)i*B_ + j] = val;
        out[(size_t)B_*B_ + (size_t)j*B_ + i] = val;
    }
}

// =================== host =======================================================
template<typename T> static float* symf(T& s){ void* p=nullptr; cudaGetSymbolAddress(&p, s); return (float*)p; }
template<typename T> static __nv_bfloat16* symb(T& s){ void* p=nullptr; cudaGetSymbolAddress(&p, s); return (__nv_bfloat16*)p; }
template<typename T> static __half* symh(T& s){ void* p=nullptr; cudaGetSymbolAddress(&p, s); return (__half*)p; }

extern "C" void kernel_launch(void* const* d_in, const int* in_sizes, int n_in,
                              void* d_out, int out_size)
{
    const float* x        =(const float*)d_in[0];
    const float* mem      =(const float*)d_in[1];
    const float* emb_w    =(const float*)d_in[2];
    const float* emb_b    =(const float*)d_in[3];
    const float* sa_in_w  =(const float*)d_in[4];
    const float* sa_in_b  =(const float*)d_in[5];
    const float* sa_out_w =(const float*)d_in[6];
    const float* sa_out_b =(const float*)d_in[7];
    const float* ca_in_w  =(const float*)d_in[8];
    const float* ca_in_b  =(const float*)d_in[9];
    const float* ca_out_w =(const float*)d_in[10];
    const float* ca_out_b =(const float*)d_in[11];
    const float* lin1_w   =(const float*)d_in[12];
    const float* lin1_b   =(const float*)d_in[13];
    const float* lin2_w   =(const float*)d_in[14];
    const float* lin2_b   =(const float*)d_in[15];
    const float* ln1_w    =(const float*)d_in[16];
    const float* ln1_b    =(const float*)d_in[17];
    const float* ln2_w    =(const float*)d_in[18];
    const float* ln2_b    =(const float*)d_in[19];
    const float* ln3_w    =(const float*)d_in[20];
    const float* ln3_b    =(const float*)d_in[21];
    const float* fin_w    =(const float*)d_in[22];
    const float* fin_b    =(const float*)d_in[23];
    const float* attn_in_w=(const float*)d_in[24];
    const float* attn_in_b=(const float*)d_in[25];
    const float* logit_sc =(const float*)d_in[26];
    float* out = (float*)d_out;

    float* t0 = symf(g_t0);  float* v   = symf(g_v);
    float* t1 = symf(g_t1);  float* qp  = symf(g_qp);  float* gg  = symf(g_g);
    float* o   = symf(g_o);
    float* t2 = symf(g_t2);  float* h1  = symf(g_h1);
    float* t3 = symf(g_t3);  float* xsq = symf(g_xsq); float* qp2 = symf(g_qp2);
    float* qt = symf(g_qt);  float* nx  = symf(g_nx);  float* pt  = symf(g_part);
    __nv_bfloat16* a2   = symb(g_a2);
    __nv_bfloat16* mt2  = symb(g_mt2);
    __nv_bfloat16* qph  = symb(g_qph);
    __nv_bfloat16* wkt  = symb(g_wkt);
    __half*        abh  = symh(g_abh);
    __nv_bfloat16* wEmb = symb(g_w_emb);
    __nv_bfloat16* wSaV = symb(g_w_savv);
    __nv_bfloat16* wSaO = symb(g_w_saout);
    __nv_bfloat16* wCaQ = symb(g_w_cawq);
    __nv_bfloat16* wCaV = symb(g_w_cawv);
    __nv_bfloat16* wCaO = symb(g_w_caout);
    __nv_bfloat16* wL1  = symb(g_w_lin1);
    __nv_bfloat16* wL2  = symb(g_w_lin2);
    __nv_bfloat16* wAtQ = symb(g_w_attnq);

    const float* NOB = nullptr;
    __nv_bfloat16* NOA = nullptr;
    __half* NOH = nullptr;

    static cudaStream_t s2 = nullptr;
    static cudaEvent_t evFork = nullptr, evW = nullptr, evWk = nullptr, evMem = nullptr;
    static cudaEvent_t evXsq = nullptr, evSide = nullptr;
    if (!s2) {
        cudaStreamCreateWithFlags(&s2, cudaStreamNonBlocking);
        cudaEventCreateWithFlags(&evFork, cudaEventDisableTiming);
        cudaEventCreateWithFlags(&evW,    cudaEventDisableTiming);
        cudaEventCreateWithFlags(&evWk,   cudaEventDisableTiming);
        cudaEventCreateWithFlags(&evMem,  cudaEventDisableTiming);
        cudaEventCreateWithFlags(&evXsq,  cudaEventDisableTiming);
        cudaEventCreateWithFlags(&evSide, cudaEventDisableTiming);
        cudaFuncSetAttribute(bigmm_half,  cudaFuncAttributeMaxDynamicSharedMemorySize, SMEM_BH);
        cudaFuncSetAttribute(bigmm_half1, cudaFuncAttributeMaxDynamicSharedMemorySize, SMEM_BH1);
        cudaFuncSetAttribute(gemm64_tc2,  cudaFuncAttributeMaxDynamicSharedMemorySize, SMEM_G2);
    }

    // ---- fork: side stream converts 9 weights, Wk^T, then memory --------------
    cudaEventRecord(evFork, 0);
    cudaStreamWaitEvent(s2, evFork, 0);
    {
        ConvJobs jobs;
        jobs.j[0] = { sa_in_w + (size_t)2*D_*D_, wSaV, D_, 1536 };
        jobs.j[1] = { sa_out_w,                  wSaO, D_, 1536 };
        jobs.j[2] = { ca_in_w,                   wCaQ, D_, 1536 };
        jobs.j[3] = { ca_in_w + (size_t)2*D_*D_, wCaV, D_, 1536 };
        jobs.j[4] = { ca_out_w,                  wCaO, D_, 1536 };
        jobs.j[5] = { lin1_w,                    wL1,  D_, 2048 };
        jobs.j[6] = { lin2_w,                    wL2,  FF_, 1536 };
        jobs.j[7] = { attn_in_w,                 wAtQ, D_, 1536 };
        jobs.j[8] = { emb_w,                     wEmb, DIN_, 1536 };
        conv_w_all<<<dim3(256, 9), 256, 0, s2>>>(jobs);
        cudaEventRecord(evW, s2);
        conv_wkt<<<dim3(D_/32, DH_/32, NH_), 256, 0, s2>>>(ca_in_w + (size_t)D_*D_);
        cudaEventRecord(evWk, s2);
        conv_mem_kernel<<<BS_/8, 256, 0, s2>>>(mem);
        cudaEventRecord(evMem, s2);
    }

    // ---- main stream: x conversion, wait weights ------------------------------
    conv_x_kernel<<<16, 256>>>(x);
    cudaStreamWaitEvent(0, evW, 0);

    // 1. t0 = x @ emb_w.T + emb_b  (K=768: 24 windows, KS=12)
    gemm64_tc2<<<dim3(24,12,1), 256, SMEM_G2>>>(a2, 2*DIN_, 0, wEmb, 2*DIN_, 0, pt, DIN_);
    reduce_ks<<<dim3((B_*D_+255)/256,1),256>>>(pt, emb_b, 0, t0, D_, 0, 128, 1536, 12, 0,
                                               a2, 2*D_, D_, 0, NOH, 0, 0, NOA, 0);
    // 2. SA (L=1)
    gemm64_tc2<<<dim3(24,12,1), 256, SMEM_G2>>>(a2, 2*D_, 0, wSaV, 2*D_, 0, pt, D_);
    reduce_ks<<<dim3((B_*D_+255)/256,1),256>>>(pt, sa_in_b+2*D_, 0, v, D_, 0, 128, 1536, 12, 0,
                                               a2, 2*D_, D_, 0, NOH, 0, 0, NOA, 0);
    gemm64_tc2<<<dim3(24,12,1), 256, SMEM_G2>>>(a2, 2*D_, 0, wSaO, 2*D_, 0, pt, D_);
    // 3. t1 = LN(t0 + sa)
    reduce_ln<<<B_, 256>>>(pt, sa_out_b, t0, ln1_w, ln1_b, t1, a2, 12);
    // 4. CA q-proj (emit per-head split qph), then gg = batched tensor GEMM
    gemm64_tc2<<<dim3(24,12,1), 256, SMEM_G2>>>(a2, 2*D_, 0, wCaQ, 2*D_, 0, pt, D_);
    reduce_ks<<<dim3((B_*D_+255)/256,1),256>>>(pt, ca_in_b, 0, qp, D_, 0, 128, 1536, 12, 0,
                                               NOA, 0, 0, 0, NOH, 0, 0, qph, DH_);
    cudaStreamWaitEvent(0, evWk, 0);
    gemm64_tc2<<<dim3(24,2,NH_), 256, SMEM_G2>>>(qph, NH_*2*DH_, 2*DH_,
                                                 wkt, 2*DH_, (long long)D_*2*DH_, pt, DH_);
    reduce_ks<<<dim3((B_*D_+255)/256,NH_),256>>>(pt, NOB, 0, gg, NH_*D_, D_, 128, 1536, 2, 0,
                                                 NOA, 0, 0, 0, NOH, 0, 0, NOA, 0);
    // 5. CA scores / softmax / weighted memory (fp16 g_mb)
    cudaStreamWaitEvent(0, evMem, 0);
    ca_scores_kernel<<<dim3(B_,2), 256>>>();
    ca_softmax_kernel<<<B_*NH_, 256>>>();
    mtilde_kernel<<<dim3(B_,3), 256>>>();
    // 6. o_h ; ca -> fused LN2
    gemm64_tc2<<<dim3(3,12,NH_), 256, SMEM_G2>>>(mt2, NH_*3072, 3072, wCaV, 2*D_, (long long)DH_*2*D_, pt, D_);
    reduce_ks<<<dim3((128*DH_+255)/256,NH_),256>>>(pt, ca_in_b+2*D_, DH_, o, D_, DH_, 128, DH_, 12, 0,
                                                   a2, 2*D_, D_, DH_, NOH, 0, 0, NOA, 0);
    gemm64_tc2<<<dim3(24,12,1), 256, SMEM_G2>>>(a2, 2*D_, 0, wCaO, 2*D_, 0, pt, D_);
    reduce_ln<<<B_, 256>>>(pt, ca_out_b, t1, ln2_w, ln2_b, t2, a2, 12);
    // 8. FF: lin1 KS=12 ; lin2 K=2048 -> KS=16
    gemm64_tc2<<<dim3(32,12,1), 256, SMEM_G2>>>(a2, 2*D_, 0, wL1, 2*D_, 0, pt, D_);
    reduce_ks<<<dim3((B_*FF_+255)/256,1),256>>>(pt, lin1_b, 0, h1, FF_, 0, 128, 2048, 12, 1,
                                                a2, 2*FF_, FF_, 0, NOH, 0, 0, NOA, 0);
    gemm64_tc2<<<dim3(24,16,1), 256, SMEM_G2>>>(a2, 2*FF_, 0, wL2, 2*FF_, 0, pt, FF_);
    // 9. t3 = LN(t2 + ff) [KS=16] ; x_sq = LN(t3) (+a2, +abh rows 128.., +copy out2)
    reduce_ln<<<B_, 256>>>(pt, lin2_b, t2, ln3_w, ln3_b, t3, NOA, 16);
    ln_kernel<<<B_, 256>>>(t3, nullptr, fin_w, fin_b, xsq, nx, a2,
                           abh + (size_t)128*2*D_, out + (size_t)2*B_*B_);
    cudaEventRecord(evXsq, 0);

    // ---- side stream: qt projection branch (overlaps cosine bigmm) ------------
    cudaStreamWaitEvent(s2, evXsq, 0);
    gemm64_tc2<<<dim3(24,12,1), 256, SMEM_G2, s2>>>(a2, 2*D_, 0, wAtQ, 2*D_, 0, pt, D_);
    reduce_ks<<<dim3((B_*D_+255)/256,1),256,0,s2>>>(pt, attn_in_b, 0, qp2, D_, 0, 128, 1536, 12, 0,
                                                    NOA, 0, 0, 0, NOH, 0, 0, NOA, 0);
    gemm_nn<64,64,16,4,4><<<dim3(D_/64, B_/64, 6), 256, 0, s2>>>(
        qp2, D_, 0, attn_in_w + (size_t)D_*D_, D_, 0,
        NOB, 0, nullptr, 0, 0, D_, 6, pt);
    reduce_ks<<<dim3((B_*D_+255)/256,1),256,0,s2>>>(pt, NOB, 0, qt, D_, 0, 128, 1536, 6, 0,
                                                    NOA, 0, 0, 0, abh, 2*D_, D_, NOA, 0);
    cudaEventRecord(evSide, s2);

    // ---- main stream: cosine bigmm (2-product), then scores bigmm (1-product) --
    bigmm_half<<<BS_/128, 256, SMEM_BH>>>(128, 128);   // cosine: xsq rows
    cudaStreamWaitEvent(0, evSide, 0);
    bigmm_half1<<<BS_/128, 256, SMEM_BH1>>>();         // scores: qt rows, Ah only

    // 12. final softmax-weighted cosine reduce
    pool_reduce_kernel<<<dim3(B_, B_), 256>>>(logit_sc, out);

    (void)in_sizes; (void)n_in; (void)out_size;
}

// round 16
// speedup vs baseline: 2.1984x; 1.0709x over previous
#include <cuda_runtime.h>
#include <cuda_bf16.h>
#include <cuda_fp16.h>
#include <math.h>
#include <stdint.h>

// Problem constants
#define B_    128
#define S_    256
#define D_    1536
#define DIN_  768
#define NH_   8
#define DH_   192
#define FF_   2048
#define BS_   (B_*S_)   // 32768

// ---------------- scratch (device globals; no cudaMalloc allowed) -------------
__device__ float g_t0 [B_*D_];
__device__ float g_v  [B_*D_];
__device__ float g_t1 [B_*D_];
__device__ float g_qp [B_*D_];
__device__ float g_g  [B_*NH_*D_];
__device__ float g_scores[B_*NH_*S_];
__device__ float g_o  [B_*D_];
__device__ float g_t2 [B_*D_];
__device__ float g_h1 [B_*FF_];
__device__ float g_t3 [B_*D_];
__device__ float g_xsq[B_*D_];
__device__ float g_qp2[B_*D_];
__device__ float g_qt [B_*D_];
__device__ float g_S  [(size_t)2*B_*BS_];
__device__ float g_nm [B_*S_];
__device__ float g_nx [B_];
__device__ float g_part[3400*1024];                 // K-split partials (13.9 MB)
__device__ __half g_mb [(size_t)BS_*D_];            // memory fp16 (hi only)
__device__ __half g_abh[256*2*D_];                  // pooling A: [Ah|Al] per row
// activation + weight bf16 (hi||lo) buffers
__device__ __nv_bfloat16 g_a2 [128*4096];
__device__ __nv_bfloat16 g_mt2[128*NH_*3072];
__device__ __nv_bfloat16 g_qph[128*NH_*2*DH_];      // qp per-head splits / qp2 splits
__device__ __nv_bfloat16 g_wkt[(size_t)NH_*D_*2*DH_]; // Wk^T per head: [e][hi192|lo192]
__device__ __nv_bfloat16 g_wk2t[(size_t)D_*2*D_];     // Wk2^T: [n][hi1536|lo1536]
__device__ __nv_bfloat16 g_w_emb  [1536*1536];
__device__ __nv_bfloat16 g_w_savv [1536*3072];
__device__ __nv_bfloat16 g_w_saout[1536*3072];
__device__ __nv_bfloat16 g_w_cawq [1536*3072];
__device__ __nv_bfloat16 g_w_cawv [1536*3072];
__device__ __nv_bfloat16 g_w_caout[1536*3072];
__device__ __nv_bfloat16 g_w_lin1 [2048*3072];
__device__ __nv_bfloat16 g_w_lin2 [1536*4096];
__device__ __nv_bfloat16 g_w_attnq[1536*3072];

// =================== common mma.sync macros =====================================
#define LDSM4(R0,R1,R2,R3,ADDR) \
    asm volatile("ldmatrix.sync.aligned.m8n8.x4.shared.b16 {%0,%1,%2,%3}, [%4];" \
        : "=r"(R0),"=r"(R1),"=r"(R2),"=r"(R3) : "r"(ADDR))
#define MMA16816(D,A,B0,B1) \
    asm volatile("mma.sync.aligned.m16n8k16.row.col.f32.bf16.bf16.f32 " \
        "{%0,%1,%2,%3}, {%4,%5,%6,%7}, {%8,%9}, {%0,%1,%2,%3};" \
        : "+f"((D)[0]),"+f"((D)[1]),"+f"((D)[2]),"+f"((D)[3]) \
        : "r"((A)[0]),"r"((A)[1]),"r"((A)[2]),"r"((A)[3]),"r"(B0),"r"(B1))
#define MMAF16(D,A,B0,B1) \
    asm volatile("mma.sync.aligned.m16n8k16.row.col.f32.f16.f16.f32 " \
        "{%0,%1,%2,%3}, {%4,%5,%6,%7}, {%8,%9}, {%0,%1,%2,%3};" \
        : "+f"((D)[0]),"+f"((D)[1]),"+f"((D)[2]),"+f"((D)[3]) \
        : "r"((A)[0]),"r"((A)[1]),"r"((A)[2]),"r"((A)[3]),"r"(B0),"r"(B1))
#define CPA16(DST,SRC) \
    asm volatile("cp.async.ca.shared.global [%0], [%1], 16;" \
        :: "r"((uint32_t)__cvta_generic_to_shared(DST)), "l"(SRC))

__device__ __forceinline__ void split_bf16(float f, __nv_bfloat16& h, __nv_bfloat16& l){
    h = __float2bfloat16(f);
    l = __float2bfloat16(f - __bfloat162float(h));
}
__device__ __forceinline__ void split_f16(float f, __half& h, __half& l){
    h = __float2half(f);
    l = __float2half(f - __half2float(h));
}

// =================== gemm64_tc2: window-fused 3-product bf16 GEMM (proven) ======
#define G2SLD 40
#define SMEM_G2 ((2*128*G2SLD + 2*128*G2SLD + 2*64*G2SLD + 2*64*G2SLD)*2)  // 61440

__global__ void __launch_bounds__(256) gemm64_tc2(
    const __nv_bfloat16* __restrict__ A2, int lda2, long long strideA2,
    const __nv_bfloat16* __restrict__ W2, int ldw2, long long strideW2,
    float* __restrict__ partial, int K)
{
    extern __shared__ __nv_bfloat16 g2sm[];
    __nv_bfloat16* sAh = g2sm;                        // [2][128*G2SLD]
    __nv_bfloat16* sAl = sAh + 2*128*G2SLD;
    __nv_bfloat16* sWh = sAl + 2*128*G2SLD;           // [2][64*G2SLD]
    __nv_bfloat16* sWl = sWh + 2*64*G2SLD;

    const int tid = threadIdx.x;
    const int warp = tid>>5, lane = tid&31;
    const int wm = warp>>1, wn = warp&1;              // 4(m) x 2(n)
    const int bn = blockIdx.x*64;
    const int KS = gridDim.y;
    const int z  = blockIdx.z;
    const int Ntot = gridDim.x*64;
    A2 += (long long)z*strideA2;
    W2 += (long long)z*strideW2;
    const int nwin = (K/32)/KS;
    const int w0   = blockIdx.y*nwin;

    float acc[2][4][4];
    #pragma unroll
    for (int i=0;i<2;i++)
        #pragma unroll
        for (int j=0;j<4;j++)
            #pragma unroll
            for (int c=0;c<4;c++) acc[i][j][c]=0.f;

    #define G2_LOAD(BUF,W) do {                                                \
        int k0_ = (w0 + (W))*32;                                                \
        _Pragma("unroll")                                                       \
        for (int i=0;i<2;i++) {                                                 \
            int l = tid + i*256;                                                \
            int r = l>>2, sg = l&3;                                             \
            CPA16(&sAh[(BUF)*128*G2SLD + r*G2SLD + sg*8],                       \
                  A2 + (size_t)r*lda2 + k0_ + sg*8);                            \
            CPA16(&sAl[(BUF)*128*G2SLD + r*G2SLD + sg*8],                       \
                  A2 + (size_t)r*lda2 + K + k0_ + sg*8);                        \
        }                                                                       \
        { int r = tid>>2, sg = tid&3;                                           \
          CPA16(&sWh[(BUF)*64*G2SLD + r*G2SLD + sg*8],                          \
                W2 + (size_t)(bn+r)*ldw2 + k0_ + sg*8);                         \
          CPA16(&sWl[(BUF)*64*G2SLD + r*G2SLD + sg*8],                          \
                W2 + (size_t)(bn+r)*ldw2 + K + k0_ + sg*8); }                   \
        asm volatile("cp.async.commit_group;");                                 \
    } while(0)

    G2_LOAD(0, 0);
    for (int w=0; w<nwin; w++) {
        int buf = w & 1;
        asm volatile("cp.async.wait_group 0;");
        __syncthreads();
        if (w+1 < nwin) G2_LOAD(buf^1, w+1);
        __nv_bfloat16* ah = sAh + buf*128*G2SLD;
        __nv_bfloat16* al = sAl + buf*128*G2SLD;
        __nv_bfloat16* wh = sWh + buf*64*G2SLD;
        __nv_bfloat16* wl = sWl + buf*64*G2SLD;
        #pragma unroll
        for (int kk=0; kk<2; kk++) {
            const int kb = kk*16;
            uint32_t fah[2][4], fal[2][4], fbh[4][2], fbl[4][2];
            #pragma unroll
            for (int mf=0; mf<2; mf++) {
                int row = wm*32 + mf*16 + (lane&15);
                int ko  = kb + ((lane>>4)<<3);
                uint32_t adh = (uint32_t)__cvta_generic_to_shared(&ah[row*G2SLD + ko]);
                uint32_t adl = (uint32_t)__cvta_generic_to_shared(&al[row*G2SLD + ko]);
                LDSM4(fah[mf][0],fah[mf][1],fah[mf][2],fah[mf][3], adh);
                LDSM4(fal[mf][0],fal[mf][1],fal[mf][2],fal[mf][3], adl);
            }
            #pragma unroll
            for (int p=0; p<2; p++) {
                int nrow = wn*32 + p*16 + ((lane>>4)<<3) + (lane&7);
                int ko   = kb + (((lane>>3)&1)<<3);
                uint32_t adh = (uint32_t)__cvta_generic_to_shared(&wh[nrow*G2SLD + ko]);
                uint32_t adl = (uint32_t)__cvta_generic_to_shared(&wl[nrow*G2SLD + ko]);
                LDSM4(fbh[2*p][0],fbh[2*p][1],fbh[2*p+1][0],fbh[2*p+1][1], adh);
                LDSM4(fbl[2*p][0],fbl[2*p][1],fbl[2*p+1][0],fbl[2*p+1][1], adl);
            }
            #pragma unroll
            for (int mf=0; mf<2; mf++)
                #pragma unroll
                for (int nf=0; nf<4; nf++) {
                    MMA16816(acc[mf][nf], fah[mf], fbh[nf][0], fbh[nf][1]);
                    MMA16816(acc[mf][nf], fah[mf], fbl[nf][0], fbl[nf][1]);
                    MMA16816(acc[mf][nf], fal[mf], fbh[nf][0], fbh[nf][1]);
                }
        }
        __syncthreads();
    }
    const size_t pbase = (size_t)(z*KS + blockIdx.y)*128;
    #pragma unroll
    for (int mf=0; mf<2; mf++) {
        int m = wm*32 + mf*16 + (lane>>2);
        #pragma unroll
        for (int nf=0; nf<4; nf++) {
            int n = bn + wn*32 + nf*8 + ((lane&3)<<1);
            *(float2*)&partial[(pbase + m)*Ntot + n]     = make_float2(acc[mf][nf][0], acc[mf][nf][1]);
            *(float2*)&partial[(pbase + m+8)*Ntot + n]   = make_float2(acc[mf][nf][2], acc[mf][nf][3]);
        }
    }
}

// ========== reduce K-split partials (+bias/relu, +bf16 a2, +fp16 ah, +head split)
__global__ void __launch_bounds__(256) reduce_ks(
    const float* __restrict__ partial, const float* __restrict__ bias, int strideBias,
    float* __restrict__ C, int ldc, long long strideC,
    int Mtot, int Ntot, int KS, int relu,
    __nv_bfloat16* __restrict__ a2, int lda2, int loOff, int a2strideZ,
    __half* __restrict__ ah, int ldah, int loOffH,
    __nv_bfloat16* __restrict__ hd, int headK)
{
    const int zb = blockIdx.y;
    int idx = blockIdx.x*256 + threadIdx.x;
    if (idx >= Mtot*Ntot) return;
    int m = idx / Ntot, n = idx % Ntot;
    float s = 0.f;
    for (int c=0;c<KS;c++)
        s += partial[((size_t)(zb*KS+c)*Mtot + m)*Ntot + n];
    if (bias) s += bias[(size_t)zb*strideBias + n];
    if (relu) s = fmaxf(s, 0.f);
    C[(size_t)zb*strideC + (size_t)m*ldc + n] = s;
    if (a2) {
        __nv_bfloat16 h,l; split_bf16(s,h,l);
        size_t base = (size_t)zb*a2strideZ + (size_t)m*lda2 + n;
        a2[base] = h;
        a2[base + loOff] = l;
    }
    if (ah) {
        __half h,l; split_f16(s,h,l);
        size_t base = (size_t)m*ldah + n;
        ah[base] = h;
        ah[base + loOffH] = l;
    }
    if (hd) {
        __nv_bfloat16 h,l; split_bf16(s,h,l);
        int head = n / headK, id2 = n - head*headK;
        size_t base = (size_t)m*(NH_*2*headK) + (size_t)head*(2*headK) + id2;
        hd[base] = h;
        hd[base + headK] = l;
    }
}

// =================== fused reduce + residual + LayerNorm (+a2) ==================
__global__ void __launch_bounds__(256) reduce_ln(
    const float* __restrict__ partial, const float* __restrict__ bias,
    const float* __restrict__ resid,
    const float* __restrict__ w, const float* __restrict__ bb,
    float* __restrict__ out, __nv_bfloat16* __restrict__ a2, int KS)
{
    const int row = blockIdx.x, tid = threadIdx.x;
    float vals[6]; float s1=0.f, s2=0.f;
    #pragma unroll
    for (int i=0;i<6;i++) {
        int e = tid + i*256;
        float s = bias ? bias[e] : 0.f;
        for (int c=0;c<KS;c++)
            s += partial[((size_t)c*128 + row)*D_ + e];
        if (resid) s += resid[(size_t)row*D_ + e];
        vals[i]=s; s1+=s; s2+=s*s;
    }
    __shared__ float red[16];
    int lane=tid&31, wid=tid>>5;
    for (int o=16;o;o>>=1){ s1+=__shfl_xor_sync(~0u,s1,o); s2+=__shfl_xor_sync(~0u,s2,o); }
    if (lane==0){ red[wid]=s1; red[8+wid]=s2; }
    __syncthreads();
    if (tid==0){ float a1=0,a2s=0; for(int k=0;k<8;k++){a1+=red[k];a2s+=red[8+k];} red[0]=a1; red[8]=a2s; }
    __syncthreads();
    float mean = red[0]*(1.0f/D_);
    float var  = red[8]*(1.0f/D_) - mean*mean;
    float rstd = rsqrtf(var + 1e-5f);
    #pragma unroll
    for (int i=0;i<6;i++) {
        int e = tid + i*256;
        float y = (vals[i]-mean)*rstd*w[e] + bb[e];
        out[(size_t)row*D_+e] = y;
        if (a2) {
            __nv_bfloat16 h,l; split_bf16(y,h,l);
            a2[(size_t)row*2*D_ + e]      = h;
            a2[(size_t)row*2*D_ + D_ + e] = l;
        }
    }
}

// =================== conversions =================================================
__global__ void __launch_bounds__(256) conv_mem_kernel(const float* __restrict__ mem)
{
    const int row = blockIdx.x*8 + (threadIdx.x>>5);
    const int lane = threadIdx.x&31;
    const float* p = mem + (size_t)row*D_;
    __half* oh = g_mb + (size_t)row*D_;
    float ss = 0.f;
    #pragma unroll
    for (int i=0;i<12;i++) {
        int e = lane*4 + i*128;
        float4 v = *(const float4*)(p+e);
        ss += v.x*v.x + v.y*v.y + v.z*v.z + v.w*v.w;
        __align__(8) __half h[4];
        h[0]=__float2half(v.x); h[1]=__float2half(v.y);
        h[2]=__float2half(v.z); h[3]=__float2half(v.w);
        *(uint64_t*)(oh + e) = *(uint64_t*)h;
    }
    for (int o=16;o;o>>=1) ss += __shfl_xor_sync(~0u, ss, o);
    if (lane==0) g_nm[row] = sqrtf(ss);
}

struct ConvJob { const float* src; __nv_bfloat16* dst; int K; int rows; };
struct ConvJobs { ConvJob j[9]; };

__global__ void __launch_bounds__(256) conv_w_all(ConvJobs jobs)
{
    const ConvJob jb = jobs.j[blockIdx.y];
    const int row = blockIdx.x*8 + (threadIdx.x>>5);
    if (row >= jb.rows) return;
    const int lane = threadIdx.x&31;
    const int K = jb.K;
    const float* p = jb.src + (size_t)row*K;
    __nv_bfloat16* o = jb.dst + (size_t)row*2*K;
    for (int e=lane*4; e<K; e+=128) {
        float4 v = *(const float4*)(p+e);
        __align__(8) __nv_bfloat16 h[4], l[4];
        float f[4] = {v.x,v.y,v.z,v.w};
        #pragma unroll
        for (int c=0;c<4;c++) split_bf16(f[c], h[c], l[c]);
        *(uint64_t*)(o + e)     = *(uint64_t*)h;
        *(uint64_t*)(o + K + e) = *(uint64_t*)l;
    }
}

// Wk (rows r = h*192+., cols e) -> g_wkt[h][e][hi192|lo192] via smem transpose.
__global__ void __launch_bounds__(256) conv_wkt(const float* __restrict__ wk)
{
    __shared__ float tile[32][33];
    const int h = blockIdx.z;
    const int e0 = blockIdx.x*32, r0 = blockIdx.y*32;
    const int tx = threadIdx.x & 31, ty = threadIdx.x >> 5;  // 32 x 8
    #pragma unroll
    for (int i=0;i<4;i++) {
        int r = r0 + ty + 8*i;
        tile[ty+8*i][tx] = wk[(size_t)(h*DH_ + r)*D_ + e0 + tx];
    }
    __syncthreads();
    __nv_bfloat16* dst = g_wkt + (size_t)h*D_*2*DH_;
    #pragma unroll
    for (int i=0;i<4;i++) {
        int e = e0 + ty + 8*i;
        float v = tile[tx][ty+8*i];
        __nv_bfloat16 hh,ll; split_bf16(v,hh,ll);
        dst[(size_t)e*2*DH_ + r0 + tx]        = hh;
        dst[(size_t)e*2*DH_ + DH_ + r0 + tx]  = ll;
    }
}

// Wk2 (rows q, cols n; 1536x1536) -> g_wk2t[n][hi1536(q)|lo1536(q)]
__global__ void __launch_bounds__(256) conv_wt2(const float* __restrict__ w)
{
    __shared__ float tile[32][33];
    const int n0 = blockIdx.x*32, q0 = blockIdx.y*32;
    const int tx = threadIdx.x & 31, ty = threadIdx.x >> 5;  // 32 x 8
    #pragma unroll
    for (int i=0;i<4;i++) {
        int q = q0 + ty + 8*i;
        tile[ty+8*i][tx] = w[(size_t)q*D_ + n0 + tx];
    }
    __syncthreads();
    #pragma unroll
    for (int i=0;i<4;i++) {
        int n = n0 + ty + 8*i;
        int q = q0 + tx;
        float v = tile[tx][ty+8*i];
        __nv_bfloat16 hh,ll; split_bf16(v,hh,ll);
        g_wk2t[(size_t)n*2*D_ + q]       = hh;
        g_wk2t[(size_t)n*2*D_ + D_ + q]  = ll;
    }
}

__global__ void __launch_bounds__(256) conv_x_kernel(const float* __restrict__ x)
{
    const int row = blockIdx.x*8 + (threadIdx.x>>5);
    const int lane = threadIdx.x&31;
    const float* p = x + (size_t)row*DIN_;
    __nv_bfloat16* o = g_a2 + (size_t)row*2*DIN_;
    #pragma unroll
    for (int i=0;i<6;i++) {
        int e = lane*4 + i*128;
        float4 v = *(const float4*)(p+e);
        __align__(8) __nv_bfloat16 h[4], l[4];
        float f[4] = {v.x,v.y,v.z,v.w};
        #pragma unroll
        for (int c=0;c<4;c++) split_bf16(f[c], h[c], l[c]);
        *(uint64_t*)(o + e)        = *(uint64_t*)h;
        *(uint64_t*)(o + DIN_ + e) = *(uint64_t*)l;
    }
}

// ===== bigmm_half1: fp16 SINGLE-product pooling GEMM (both halves) ===============
#define HSLD 40
#define HCHUNK 48          // 1536 / 32

__global__ void __launch_bounds__(256) bigmm_half1(int aBase, int outBase)
{
    extern __shared__ __half hsm1[];
    __half* sAh = hsm1;                      // [2][128*HSLD]
    __half* sB  = sAh + 2*128*HSLD;
    const int tid = threadIdx.x;
    const int warp = tid>>5, lane = tid&31;
    const int wm = warp>>2, wn = warp&3;
    const int nbase = blockIdx.x*128;

    float acc[4][4][4];
    #pragma unroll
    for (int i=0;i<4;i++)
        #pragma unroll
        for (int j=0;j<4;j++)
            #pragma unroll
            for (int c=0;c<4;c++) acc[i][j][c]=0.f;

    const int r0 = tid>>1;
    const int seg0 = (tid&1)*2;

    #define BH1_LOAD(BUF,KC) do {                                              \
        int k0_ = (KC)*32;                                                      \
        _Pragma("unroll")                                                       \
        for (int i=0;i<2;i++) {                                                 \
            int seg = seg0 + i;                                                 \
            CPA16(&sAh[(BUF)*128*HSLD + r0*HSLD + seg*8],                       \
                  g_abh + (size_t)(aBase+r0)*2*D_ + k0_ + seg*8);               \
            CPA16(&sB [(BUF)*128*HSLD + r0*HSLD + seg*8],                       \
                  g_mb + (size_t)(nbase+r0)*D_ + k0_ + seg*8);                  \
        }                                                                       \
        asm volatile("cp.async.commit_group;");                                 \
    } while(0)

    BH1_LOAD(0, 0);
    for (int kc=0; kc<HCHUNK; kc++) {
        int buf = kc & 1;
        asm volatile("cp.async.wait_group 0;");
        __syncthreads();
        if (kc+1 < HCHUNK) BH1_LOAD(buf^1, kc+1);
        __half* ah = sAh + buf*128*HSLD;
        __half* bt = sB  + buf*128*HSLD;
        #pragma unroll
        for (int kk=0; kk<2; kk++) {
            const int kb = kk*16;
            uint32_t fah[4][4], b[4][2];
            #pragma unroll
            for (int mf=0; mf<4; mf++) {
                int row = wm*64 + mf*16 + (lane&15);
                int ko  = kb + ((lane>>4)<<3);
                uint32_t adh = (uint32_t)__cvta_generic_to_shared(&ah[row*HSLD + ko]);
                LDSM4(fah[mf][0],fah[mf][1],fah[mf][2],fah[mf][3], adh);
            }
            #pragma unroll
            for (int p=0; p<2; p++) {
                int nrow = wn*32 + p*16 + ((lane>>4)<<3) + (lane&7);
                int ko   = kb + (((lane>>3)&1)<<3);
                uint32_t ad = (uint32_t)__cvta_generic_to_shared(&bt[nrow*HSLD + ko]);
                LDSM4(b[2*p][0],b[2*p][1],b[2*p+1][0],b[2*p+1][1], ad);
            }
            #pragma unroll
            for (int mf=0; mf<4; mf++)
                #pragma unroll
                for (int nf=0; nf<4; nf++)
                    MMAF16(acc[mf][nf], fah[mf], b[nf][0], b[nf][1]);
        }
        __syncthreads();
    }
    #pragma unroll
    for (int mf=0; mf<4; mf++) {
        int m = outBase + wm*64 + mf*16 + (lane>>2);
        #pragma unroll
        for (int nf=0; nf<4; nf++) {
            int n = nbase + wn*32 + nf*8 + ((lane&3)<<1);
            *(float2*)&g_S[(size_t)m*BS_ + n]     = make_float2(acc[mf][nf][0], acc[mf][nf][1]);
            *(float2*)&g_S[(size_t)(m+8)*BS_ + n] = make_float2(acc[mf][nf][2], acc[mf][nf][3]);
        }
    }
}
#define SMEM_BH1 (2*2*128*HSLD*2)   // 40960 bytes

// =================== LayerNorm (fin; +fp16 abh out, +copy out) ==================
__global__ void __launch_bounds__(256) ln_kernel(
    const float* __restrict__ a, const float* __restrict__ r,
    const float* __restrict__ w, const float* __restrict__ bb,
    float* __restrict__ out, float* __restrict__ norm_out,
    __nv_bfloat16* __restrict__ a2, __half* __restrict__ abh,
    float* __restrict__ copyOut)
{
    const int row = blockIdx.x, tid = threadIdx.x;
    const float* ap = a + (size_t)row*D_;
    const float* rp = r ? r + (size_t)row*D_ : nullptr;
    float vals[6]; float s1=0.f, s2=0.f;
    #pragma unroll
    for (int i=0;i<6;i++) {
        int e = tid + i*256;
        float v = ap[e] + (rp ? rp[e] : 0.f);
        vals[i]=v; s1+=v; s2+=v*v;
    }
    __shared__ float red[16];
    int lane=tid&31, wid=tid>>5;
    for (int o=16;o;o>>=1){ s1+=__shfl_xor_sync(~0u,s1,o); s2+=__shfl_xor_sync(~0u,s2,o); }
    if (lane==0){ red[wid]=s1; red[8+wid]=s2; }
    __syncthreads();
    if (tid==0){ float a1=0,a2s=0; for(int k=0;k<8;k++){a1+=red[k];a2s+=red[8+k];} red[0]=a1; red[8]=a2s; }
    __syncthreads();
    float mean = red[0]*(1.0f/D_);
    float var  = red[8]*(1.0f/D_) - mean*mean;
    float rstd = rsqrtf(var + 1e-5f);
    float ss = 0.f;
    #pragma unroll
    for (int i=0;i<6;i++) {
        int e = tid + i*256;
        float y = (vals[i]-mean)*rstd*w[e] + bb[e];
        out[(size_t)row*D_+e] = y;
        if (copyOut) copyOut[(size_t)row*D_+e] = y;
        if (a2) {
            __nv_bfloat16 h,l; split_bf16(y,h,l);
            a2[(size_t)row*2*D_ + e]      = h;
            a2[(size_t)row*2*D_ + D_ + e] = l;
        }
        if (abh) {
            __half h,l; split_f16(y,h,l);
            abh[(size_t)row*2*D_ + e]      = h;
            abh[(size_t)row*2*D_ + D_ + e] = l;
        }
        ss += y*y;
    }
    if (norm_out) {
        for (int o=16;o;o>>=1) ss+=__shfl_xor_sync(~0u,ss,o);
        __syncthreads();
        if (lane==0) red[wid]=ss;
        __syncthreads();
        if (tid==0){ float t=0; for(int k=0;k<8;k++) t+=red[k]; norm_out[row]=sqrtf(t); }
    }
}

// ========= CA scores from fp16 memory copy =======================================
__global__ void __launch_bounds__(256) ca_scores_kernel()
{
    __shared__ float gs[NH_*D_];
    const int b = blockIdx.x, tid = threadIdx.x;
    const float4* gsrc = (const float4*)(g_g + (size_t)b*NH_*D_);
    for (int i=tid;i<NH_*D_/4;i+=256) ((float4*)gs)[i]=gsrc[i];
    __syncthreads();
    const int warp=tid>>5, lane=tid&31;
    const __half* mb = g_mb + (size_t)b*S_*D_;
    const float scale = rsqrtf((float)DH_);
    const int sbase = blockIdx.y*128 + warp*16;
    for (int grp=0;grp<4;grp++) {
        int s0 = sbase + grp*4;
        float acc[NH_][4];
        #pragma unroll
        for (int h=0;h<NH_;h++)
            #pragma unroll
            for (int r2=0;r2<4;r2++) acc[h][r2]=0.f;
        #pragma unroll
        for (int i=0;i<12;i++) {
            int e = lane*4 + i*128;
            float4 m[4];
            #pragma unroll
            for (int r2=0;r2<4;r2++) {
                uint2 raw = *(const uint2*)(mb+(size_t)(s0+r2)*D_+e);
                __half2 p0 = *(__half2*)&raw.x;
                __half2 p1 = *(__half2*)&raw.y;
                float2 f0 = __half22float2(p0);
                float2 f1 = __half22float2(p1);
                m[r2] = make_float4(f0.x, f0.y, f1.x, f1.y);
            }
            #pragma unroll
            for (int h=0;h<NH_;h++) {
                float4 gv=*(const float4*)(gs + h*D_ + e);
                #pragma unroll
                for (int r2=0;r2<4;r2++)
                    acc[h][r2] += gv.x*m[r2].x + gv.y*m[r2].y + gv.z*m[r2].z + gv.w*m[r2].w;
            }
        }
        #pragma unroll
        for (int h=0;h<NH_;h++)
            #pragma unroll
            for (int r2=0;r2<4;r2++) {
                float v=acc[h][r2];
                for (int o=16;o;o>>=1) v+=__shfl_xor_sync(~0u,v,o);
                if (lane==0) g_scores[((size_t)b*NH_+h)*S_ + s0+r2] = v*scale;
            }
    }
}

__global__ void __launch_bounds__(256) ca_softmax_kernel()
{
    const int row=blockIdx.x, tid=threadIdx.x;
    float* sp = g_scores + (size_t)row*S_;
    float v = sp[tid];
    __shared__ float red[16];
    int lane=tid&31, wid=tid>>5;
    float m=v;
    for (int o=16;o;o>>=1) m=fmaxf(m,__shfl_xor_sync(~0u,m,o));
    if (lane==0) red[wid]=m;
    __syncthreads();
    if (tid==0){ float mm=red[0]; for(int k=1;k<8;k++) mm=fmaxf(mm,red[k]); red[0]=mm; }
    __syncthreads();
    m=red[0];
    float e=__expf(v-m);
    float s=e;
    for (int o=16;o;o>>=1) s+=__shfl_xor_sync(~0u,s,o);
    __syncthreads();
    if (lane==0) red[8+wid]=s;
    __syncthreads();
    if (tid==0){ float t=0; for(int k=0;k<8;k++) t+=red[8+k]; red[8]=t; }
    __syncthreads();
    sp[tid]=e/red[8];
}

__global__ void __launch_bounds__(256) mtilde_kernel()
{
    __shared__ float at[NH_*S_];
    const int b=blockIdx.x, tid=threadIdx.x;
    for (int i=tid;i<NH_*S_;i+=256) at[i]=g_scores[(size_t)b*NH_*S_+i];
    __syncthreads();
    const int e = blockIdx.y*512 + tid*2;
    const __half* mb = g_mb + (size_t)b*S_*D_;
    float2 acc[NH_];
    #pragma unroll
    for (int h=0;h<NH_;h++){ acc[h].x=0.f; acc[h].y=0.f; }
    for (int s=0;s<S_;s++) {
        __half2 raw = *(const __half2*)(mb+(size_t)s*D_+e);
        float2 mv = __half22float2(raw);
        #pragma unroll
        for (int h=0;h<NH_;h++){
            float a=at[h*S_+s];
            acc[h].x=fmaf(a,mv.x,acc[h].x);
            acc[h].y=fmaf(a,mv.y,acc[h].y);
        }
    }
    #pragma unroll
    for (int h=0;h<NH_;h++) {
        __nv_bfloat16 hx,lx,hy,ly;
        split_bf16(acc[h].x,hx,lx); split_bf16(acc[h].y,hy,ly);
        size_t base = (size_t)b*NH_*3072 + h*3072;
        g_mt2[base + e]   = hx; g_mt2[base + e+1]   = hy;
        g_mt2[base + D_ + e] = lx; g_mt2[base + D_ + e+1] = ly;
    }
}

__global__ void __launch_bounds__(256) pool_reduce_kernel(
    const float* __restrict__ ls, float* __restrict__ out)
{
    const int j=blockIdx.x, i=blockIdx.y, s=threadIdx.x;
    const float sc = rsqrtf((float)D_);
    float Sv = g_S[(size_t)i*BS_ + j*S_ + s] * sc;
    float Cv = g_S[(size_t)(B_+i)*BS_ + j*S_ + s];
    float nmv = g_nm[j*S_+s];
    __shared__ float red[16];
    int lane=s&31, wid=s>>5;
    float m=Sv;
    for (int o=16;o;o>>=1) m=fmaxf(m,__shfl_xor_sync(~0u,m,o));
    if (lane==0) red[wid]=m;
    __syncthreads();
    if (s==0){ float mm=red[0]; for(int k=1;k<8;k++) mm=fmaxf(mm,red[k]); red[0]=mm; }
    __syncthreads();
    m=red[0];
    float e = expf(Sv-m);
    float t1=e, t2=e*Cv/nmv;
    for (int o=16;o;o>>=1){ t1+=__shfl_xor_sync(~0u,t1,o); t2+=__shfl_xor_sync(~0u,t2,o); }
    __syncthreads();
    if (lane==0){ red[wid]=t1; red[8+wid]=t2; }
    __syncthreads();
    if (s==0) {
        float Z=0.f, Wv=0.f;
        for (int k=0;k<8;k++){ Z+=red[k]; Wv+=red[8+k]; }
        float val = expf(ls[0]) * Wv / (Z * g_nx[i]);
        out[(size_t)i*B_ + j] = val;
        out[(size_t)B_*B_ + (size_t)j*B_ + i] = val;
    }
}

// =================== host =======================================================
template<typename T> static float* symf(T& s){ void* p=nullptr; cudaGetSymbolAddress(&p, s); return (float*)p; }
template<typename T> static __nv_bfloat16* symb(T& s){ void* p=nullptr; cudaGetSymbolAddress(&p, s); return (__nv_bfloat16*)p; }
template<typename T> static __half* symh(T& s){ void* p=nullptr; cudaGetSymbolAddress(&p, s); return (__half*)p; }

extern "C" void kernel_launch(void* const* d_in, const int* in_sizes, int n_in,
                              void* d_out, int out_size)
{
    const float* x        =(const float*)d_in[0];
    const float* mem      =(const float*)d_in[1];
    const float* emb_w    =(const float*)d_in[2];
    const float* emb_b    =(const float*)d_in[3];
    const float* sa_in_w  =(const float*)d_in[4];
    const float* sa_in_b  =(const float*)d_in[5];
    const float* sa_out_w =(const float*)d_in[6];
    const float* sa_out_b =(const float*)d_in[7];
    const float* ca_in_w  =(const float*)d_in[8];
    const float* ca_in_b  =(const float*)d_in[9];
    const float* ca_out_w =(const float*)d_in[10];
    const float* ca_out_b =(const float*)d_in[11];
    const float* lin1_w   =(const float*)d_in[12];
    const float* lin1_b   =(const float*)d_in[13];
    const float* lin2_w   =(const float*)d_in[14];
    const float* lin2_b   =(const float*)d_in[15];
    const float* ln1_w    =(const float*)d_in[16];
    const float* ln1_b    =(const float*)d_in[17];
    const float* ln2_w    =(const float*)d_in[18];
    const float* ln2_b    =(const float*)d_in[19];
    const float* ln3_w    =(const float*)d_in[20];
    const float* ln3_b    =(const float*)d_in[21];
    const float* fin_w    =(const float*)d_in[22];
    const float* fin_b    =(const float*)d_in[23];
    const float* attn_in_w=(const float*)d_in[24];
    const float* attn_in_b=(const float*)d_in[25];
    const float* logit_sc =(const float*)d_in[26];
    float* out = (float*)d_out;

    float* t0 = symf(g_t0);  float* v   = symf(g_v);
    float* t1 = symf(g_t1);  float* qp  = symf(g_qp);  float* gg  = symf(g_g);
    float* o   = symf(g_o);
    float* t2 = symf(g_t2);  float* h1  = symf(g_h1);
    float* t3 = symf(g_t3);  float* xsq = symf(g_xsq); float* qp2 = symf(g_qp2);
    float* qt = symf(g_qt);  float* nx  = symf(g_nx);  float* pt  = symf(g_part);
    __nv_bfloat16* a2   = symb(g_a2);
    __nv_bfloat16* mt2  = symb(g_mt2);
    __nv_bfloat16* qph  = symb(g_qph);
    __nv_bfloat16* wkt  = symb(g_wkt);
    __nv_bfloat16* wk2t = symb(g_wk2t);
    __half*        abh  = symh(g_abh);
    __nv_bfloat16* wEmb = symb(g_w_emb);
    __nv_bfloat16* wSaV = symb(g_w_savv);
    __nv_bfloat16* wSaO = symb(g_w_saout);
    __nv_bfloat16* wCaQ = symb(g_w_cawq);
    __nv_bfloat16* wCaV = symb(g_w_cawv);
    __nv_bfloat16* wCaO = symb(g_w_caout);
    __nv_bfloat16* wL1  = symb(g_w_lin1);
    __nv_bfloat16* wL2  = symb(g_w_lin2);
    __nv_bfloat16* wAtQ = symb(g_w_attnq);

    const float* NOB = nullptr;
    __nv_bfloat16* NOA = nullptr;
    __half* NOH = nullptr;

    static cudaStream_t s2 = nullptr;
    static cudaEvent_t evFork = nullptr, evW = nullptr, evWk = nullptr, evMem = nullptr;
    static cudaEvent_t evXsq = nullptr, evSide = nullptr;
    if (!s2) {
        cudaStreamCreateWithFlags(&s2, cudaStreamNonBlocking);
        cudaEventCreateWithFlags(&evFork, cudaEventDisableTiming);
        cudaEventCreateWithFlags(&evW,    cudaEventDisableTiming);
        cudaEventCreateWithFlags(&evWk,   cudaEventDisableTiming);
        cudaEventCreateWithFlags(&evMem,  cudaEventDisableTiming);
        cudaEventCreateWithFlags(&evXsq,  cudaEventDisableTiming);
        cudaEventCreateWithFlags(&evSide, cudaEventDisableTiming);
        cudaFuncSetAttribute(bigmm_half1, cudaFuncAttributeMaxDynamicSharedMemorySize, SMEM_BH1);
        cudaFuncSetAttribute(gemm64_tc2,  cudaFuncAttributeMaxDynamicSharedMemorySize, SMEM_G2);
    }

    // ---- fork: side stream converts weights, Wk^T, Wk2^T, then memory ---------
    cudaEventRecord(evFork, 0);
    cudaStreamWaitEvent(s2, evFork, 0);
    {
        ConvJobs jobs;
        jobs.j[0] = { sa_in_w + (size_t)2*D_*D_, wSaV, D_, 1536 };
        jobs.j[1] = { sa_out_w,                  wSaO, D_, 1536 };
        jobs.j[2] = { ca_in_w,                   wCaQ, D_, 1536 };
        jobs.j[3] = { ca_in_w + (size_t)2*D_*D_, wCaV, D_, 1536 };
        jobs.j[4] = { ca_out_w,                  wCaO, D_, 1536 };
        jobs.j[5] = { lin1_w,                    wL1,  D_, 2048 };
        jobs.j[6] = { lin2_w,                    wL2,  FF_, 1536 };
        jobs.j[7] = { attn_in_w,                 wAtQ, D_, 1536 };
        jobs.j[8] = { emb_w,                     wEmb, DIN_, 1536 };
        conv_w_all<<<dim3(256, 9), 256, 0, s2>>>(jobs);
        cudaEventRecord(evW, s2);
        conv_wkt<<<dim3(D_/32, DH_/32, NH_), 256, 0, s2>>>(ca_in_w + (size_t)D_*D_);
        cudaEventRecord(evWk, s2);
        conv_wt2<<<dim3(D_/32, D_/32), 256, 0, s2>>>(attn_in_w + (size_t)D_*D_);
        conv_mem_kernel<<<BS_/8, 256, 0, s2>>>(mem);
        cudaEventRecord(evMem, s2);
    }

    // ---- main stream: x conversion, wait weights ------------------------------
    conv_x_kernel<<<16, 256>>>(x);
    cudaStreamWaitEvent(0, evW, 0);

    // 1. t0 = x @ emb_w.T + emb_b
    gemm64_tc2<<<dim3(24,12,1), 256, SMEM_G2>>>(a2, 2*DIN_, 0, wEmb, 2*DIN_, 0, pt, DIN_);
    reduce_ks<<<dim3((B_*D_+255)/256,1),256>>>(pt, emb_b, 0, t0, D_, 0, 128, 1536, 12, 0,
                                               a2, 2*D_, D_, 0, NOH, 0, 0, NOA, 0);
    // 2. SA (L=1)
    gemm64_tc2<<<dim3(24,12,1), 256, SMEM_G2>>>(a2, 2*D_, 0, wSaV, 2*D_, 0, pt, D_);
    reduce_ks<<<dim3((B_*D_+255)/256,1),256>>>(pt, sa_in_b+2*D_, 0, v, D_, 0, 128, 1536, 12, 0,
                                               a2, 2*D_, D_, 0, NOH, 0, 0, NOA, 0);
    gemm64_tc2<<<dim3(24,12,1), 256, SMEM_G2>>>(a2, 2*D_, 0, wSaO, 2*D_, 0, pt, D_);
    // 3. t1 = LN(t0 + sa)
    reduce_ln<<<B_, 256>>>(pt, sa_out_b, t0, ln1_w, ln1_b, t1, a2, 12);
    // 4. CA q-proj (emit per-head split qph), then gg = batched tensor GEMM
    gemm64_tc2<<<dim3(24,12,1), 256, SMEM_G2>>>(a2, 2*D_, 0, wCaQ, 2*D_, 0, pt, D_);
    reduce_ks<<<dim3((B_*D_+255)/256,1),256>>>(pt, ca_in_b, 0, qp, D_, 0, 128, 1536, 12, 0,
                                               NOA, 0, 0, 0, NOH, 0, 0, qph, DH_);
    cudaStreamWaitEvent(0, evWk, 0);
    gemm64_tc2<<<dim3(24,2,NH_), 256, SMEM_G2>>>(qph, NH_*2*DH_, 2*DH_,
                                                 wkt, 2*DH_, (long long)D_*2*DH_, pt, DH_);
    reduce_ks<<<dim3((B_*D_+255)/256,NH_),256>>>(pt, NOB, 0, gg, NH_*D_, D_, 128, 1536, 2, 0,
                                                 NOA, 0, 0, 0, NOH, 0, 0, NOA, 0);
    // 5. CA scores / softmax / weighted memory (fp16 g_mb)
    cudaStreamWaitEvent(0, evMem, 0);
    ca_scores_kernel<<<dim3(B_,2), 256>>>();
    ca_softmax_kernel<<<B_*NH_, 256>>>();
    mtilde_kernel<<<dim3(B_,3), 256>>>();
    // 6. o_h ; ca -> fused LN2
    gemm64_tc2<<<dim3(3,12,NH_), 256, SMEM_G2>>>(mt2, NH_*3072, 3072, wCaV, 2*D_, (long long)DH_*2*D_, pt, D_);
    reduce_ks<<<dim3((128*DH_+255)/256,NH_),256>>>(pt, ca_in_b+2*D_, DH_, o, D_, DH_, 128, DH_, 12, 0,
                                                   a2, 2*D_, D_, DH_, NOH, 0, 0, NOA, 0);
    gemm64_tc2<<<dim3(24,12,1), 256, SMEM_G2>>>(a2, 2*D_, 0, wCaO, 2*D_, 0, pt, D_);
    reduce_ln<<<B_, 256>>>(pt, ca_out_b, t1, ln2_w, ln2_b, t2, a2, 12);
    // 8. FF: lin1 KS=12 ; lin2 K=2048 -> KS=16
    gemm64_tc2<<<dim3(32,12,1), 256, SMEM_G2>>>(a2, 2*D_, 0, wL1, 2*D_, 0, pt, D_);
    reduce_ks<<<dim3((B_*FF_+255)/256,1),256>>>(pt, lin1_b, 0, h1, FF_, 0, 128, 2048, 12, 1,
                                                a2, 2*FF_, FF_, 0, NOH, 0, 0, NOA, 0);
    gemm64_tc2<<<dim3(24,16,1), 256, SMEM_G2>>>(a2, 2*FF_, 0, wL2, 2*FF_, 0, pt, FF_);
    // 9. t3 = LN(t2 + ff) [KS=16] ; x_sq = LN(t3) (+a2, +abh rows 128.., +copy out2)
    reduce_ln<<<B_, 256>>>(pt, lin2_b, t2, ln3_w, ln3_b, t3, NOA, 16);
    ln_kernel<<<B_, 256>>>(t3, nullptr, fin_w, fin_b, xsq, nx, a2,
                           abh + (size_t)128*2*D_, out + (size_t)2*B_*B_);
    cudaEventRecord(evXsq, 0);

    // ---- side stream: qt projection branch (all tensor; overlaps cosine bigmm) -
    cudaStreamWaitEvent(s2, evXsq, 0);
    gemm64_tc2<<<dim3(24,12,1), 256, SMEM_G2, s2>>>(a2, 2*D_, 0, wAtQ, 2*D_, 0, pt, D_);
    reduce_ks<<<dim3((B_*D_+255)/256,1),256,0,s2>>>(pt, attn_in_b, 0, qp2, D_, 0, 128, 1536, 12, 0,
                                                    qph, 2*D_, D_, 0, NOH, 0, 0, NOA, 0);
    gemm64_tc2<<<dim3(24,12,1), 256, SMEM_G2, s2>>>(qph, 2*D_, 0, wk2t, 2*D_, 0, pt, D_);
    reduce_ks<<<dim3((B_*D_+255)/256,1),256,0,s2>>>(pt, NOB, 0, qt, D_, 0, 128, 1536, 12, 0,
                                                    NOA, 0, 0, 0, abh, 2*D_, D_, NOA, 0);
    cudaEventRecord(evSide, s2);

    // ---- main stream: cosine bigmm (1-product), then scores bigmm (1-product) --
    bigmm_half1<<<BS_/128, 256, SMEM_BH1>>>(128, 128);  // cosine: xsq rows
    cudaStreamWaitEvent(0, evSide, 0);
    bigmm_half1<<<BS_/128, 256, SMEM_BH1>>>(0, 0);      // scores: qt rows

    // 12. final softmax-weighted cosine reduce
    pool_reduce_kernel<<<dim3(B_, B_), 256>>>(logit_sc, out);

    (void)in_sizes; (void)n_in; (void)out_size;
}

// round 17
// speedup vs baseline: 2.2157x; 1.0079x over previous
#include <cuda_runtime.h>
#include <cuda_bf16.h>
#include <cuda_fp16.h>
#include <math.h>
#include <stdint.h>

// Problem constants
#define B_    128
#define S_    256
#define D_    1536
#define DIN_  768
#define NH_   8
#define DH_   192
#define FF_   2048
#define BS_   (B_*S_)   // 32768

// ---------------- scratch (device globals; no cudaMalloc allowed) -------------
__device__ float g_t0 [B_*D_];
__device__ float g_v  [B_*D_];
__device__ float g_t1 [B_*D_];
__device__ float g_qp [B_*D_];
__device__ float g_g  [B_*NH_*D_];
__device__ float g_scores[B_*NH_*S_];
__device__ float g_o  [B_*D_];
__device__ float g_t2 [B_*D_];
__device__ float g_h1 [B_*FF_];
__device__ float g_t3 [B_*D_];
__device__ float g_xsq[B_*D_];
__device__ float g_qp2[B_*D_];
__device__ float g_qt [B_*D_];
__device__ float g_S  [(size_t)2*B_*BS_];
__device__ float g_nm [B_*S_];
__device__ float g_nx [B_];
__device__ float g_part[3400*1024];                 // K-split partials (13.9 MB)
__device__ __half g_mb [(size_t)BS_*D_];            // memory fp16 (hi only)
__device__ __half g_abh[256*2*D_];                  // pooling A: [Ah|Al] per row
// activation + weight bf16 (hi||lo) buffers
__device__ __nv_bfloat16 g_a2 [128*4096];
__device__ __nv_bfloat16 g_mt2[128*NH_*3072];
__device__ __nv_bfloat16 g_qph[128*NH_*2*DH_];      // qp per-head splits / qp2 splits
__device__ __nv_bfloat16 g_wkt[(size_t)NH_*D_*2*DH_]; // Wk^T per head: [e][hi192|lo192]
__device__ __nv_bfloat16 g_wk2t[(size_t)D_*2*D_];     // Wk2^T: [n][hi1536|lo1536]
__device__ __nv_bfloat16 g_w_emb  [1536*1536];
__device__ __nv_bfloat16 g_w_savv [1536*3072];
__device__ __nv_bfloat16 g_w_saout[1536*3072];
__device__ __nv_bfloat16 g_w_cawq [1536*3072];
__device__ __nv_bfloat16 g_w_cawv [1536*3072];
__device__ __nv_bfloat16 g_w_caout[1536*3072];
__device__ __nv_bfloat16 g_w_lin1 [2048*3072];
__device__ __nv_bfloat16 g_w_lin2 [1536*4096];
__device__ __nv_bfloat16 g_w_attnq[1536*3072];

// =================== common mma.sync macros =====================================
#define LDSM4(R0,R1,R2,R3,ADDR) \
    asm volatile("ldmatrix.sync.aligned.m8n8.x4.shared.b16 {%0,%1,%2,%3}, [%4];" \
        : "=r"(R0),"=r"(R1),"=r"(R2),"=r"(R3) : "r"(ADDR))
#define MMA16816(D,A,B0,B1) \
    asm volatile("mma.sync.aligned.m16n8k16.row.col.f32.bf16.bf16.f32 " \
        "{%0,%1,%2,%3}, {%4,%5,%6,%7}, {%8,%9}, {%0,%1,%2,%3};" \
        : "+f"((D)[0]),"+f"((D)[1]),"+f"((D)[2]),"+f"((D)[3]) \
        : "r"((A)[0]),"r"((A)[1]),"r"((A)[2]),"r"((A)[3]),"r"(B0),"r"(B1))
#define MMAF16(D,A,B0,B1) \
    asm volatile("mma.sync.aligned.m16n8k16.row.col.f32.f16.f16.f32 " \
        "{%0,%1,%2,%3}, {%4,%5,%6,%7}, {%8,%9}, {%0,%1,%2,%3};" \
        : "+f"((D)[0]),"+f"((D)[1]),"+f"((D)[2]),"+f"((D)[3]) \
        : "r"((A)[0]),"r"((A)[1]),"r"((A)[2]),"r"((A)[3]),"r"(B0),"r"(B1))
#define CPA16(DST,SRC) \
    asm volatile("cp.async.ca.shared.global [%0], [%1], 16;" \
        :: "r"((uint32_t)__cvta_generic_to_shared(DST)), "l"(SRC))

__device__ __forceinline__ void split_bf16(float f, __nv_bfloat16& h, __nv_bfloat16& l){
    h = __float2bfloat16(f);
    l = __float2bfloat16(f - __bfloat162float(h));
}
__device__ __forceinline__ void split_f16(float f, __half& h, __half& l){
    h = __float2half(f);
    l = __float2half(f - __half2float(h));
}

// =================== gemm64_tc2: window-fused 3-product bf16 GEMM (proven) ======
#define G2SLD 40
#define SMEM_G2 ((2*128*G2SLD + 2*128*G2SLD + 2*64*G2SLD + 2*64*G2SLD)*2)  // 61440

__global__ void __launch_bounds__(256) gemm64_tc2(
    const __nv_bfloat16* __restrict__ A2, int lda2, long long strideA2,
    const __nv_bfloat16* __restrict__ W2, int ldw2, long long strideW2,
    float* __restrict__ partial, int K)
{
    extern __shared__ __nv_bfloat16 g2sm[];
    __nv_bfloat16* sAh = g2sm;                        // [2][128*G2SLD]
    __nv_bfloat16* sAl = sAh + 2*128*G2SLD;
    __nv_bfloat16* sWh = sAl + 2*128*G2SLD;           // [2][64*G2SLD]
    __nv_bfloat16* sWl = sWh + 2*64*G2SLD;

    const int tid = threadIdx.x;
    const int warp = tid>>5, lane = tid&31;
    const int wm = warp>>1, wn = warp&1;              // 4(m) x 2(n)
    const int bn = blockIdx.x*64;
    const int KS = gridDim.y;
    const int z  = blockIdx.z;
    const int Ntot = gridDim.x*64;
    A2 += (long long)z*strideA2;
    W2 += (long long)z*strideW2;
    const int nwin = (K/32)/KS;
    const int w0   = blockIdx.y*nwin;

    float acc[2][4][4];
    #pragma unroll
    for (int i=0;i<2;i++)
        #pragma unroll
        for (int j=0;j<4;j++)
            #pragma unroll
            for (int c=0;c<4;c++) acc[i][j][c]=0.f;

    #define G2_LOAD(BUF,W) do {                                                \
        int k0_ = (w0 + (W))*32;                                                \
        _Pragma("unroll")                                                       \
        for (int i=0;i<2;i++) {                                                 \
            int l = tid + i*256;                                                \
            int r = l>>2, sg = l&3;                                             \
            CPA16(&sAh[(BUF)*128*G2SLD + r*G2SLD + sg*8],                       \
                  A2 + (size_t)r*lda2 + k0_ + sg*8);                            \
            CPA16(&sAl[(BUF)*128*G2SLD + r*G2SLD + sg*8],                       \
                  A2 + (size_t)r*lda2 + K + k0_ + sg*8);                        \
        }                                                                       \
        { int r = tid>>2, sg = tid&3;                                           \
          CPA16(&sWh[(BUF)*64*G2SLD + r*G2SLD + sg*8],                          \
                W2 + (size_t)(bn+r)*ldw2 + k0_ + sg*8);                         \
          CPA16(&sWl[(BUF)*64*G2SLD + r*G2SLD + sg*8],                          \
                W2 + (size_t)(bn+r)*ldw2 + K + k0_ + sg*8); }                   \
        asm volatile("cp.async.commit_group;");                                 \
    } while(0)

    G2_LOAD(0, 0);
    for (int w=0; w<nwin; w++) {
        int buf = w & 1;
        asm volatile("cp.async.wait_group 0;");
        __syncthreads();
        if (w+1 < nwin) G2_LOAD(buf^1, w+1);
        __nv_bfloat16* ah = sAh + buf*128*G2SLD;
        __nv_bfloat16* al = sAl + buf*128*G2SLD;
        __nv_bfloat16* wh = sWh + buf*64*G2SLD;
        __nv_bfloat16* wl = sWl + buf*64*G2SLD;
        #pragma unroll
        for (int kk=0; kk<2; kk++) {
            const int kb = kk*16;
            uint32_t fah[2][4], fal[2][4], fbh[4][2], fbl[4][2];
            #pragma unroll
            for (int mf=0; mf<2; mf++) {
                int row = wm*32 + mf*16 + (lane&15);
                int ko  = kb + ((lane>>4)<<3);
                uint32_t adh = (uint32_t)__cvta_generic_to_shared(&ah[row*G2SLD + ko]);
                uint32_t adl = (uint32_t)__cvta_generic_to_shared(&al[row*G2SLD + ko]);
                LDSM4(fah[mf][0],fah[mf][1],fah[mf][2],fah[mf][3], adh);
                LDSM4(fal[mf][0],fal[mf][1],fal[mf][2],fal[mf][3], adl);
            }
            #pragma unroll
            for (int p=0; p<2; p++) {
                int nrow = wn*32 + p*16 + ((lane>>4)<<3) + (lane&7);
                int ko   = kb + (((lane>>3)&1)<<3);
                uint32_t adh = (uint32_t)__cvta_generic_to_shared(&wh[nrow*G2SLD + ko]);
                uint32_t adl = (uint32_t)__cvta_generic_to_shared(&wl[nrow*G2SLD + ko]);
                LDSM4(fbh[2*p][0],fbh[2*p][1],fbh[2*p+1][0],fbh[2*p+1][1], adh);
                LDSM4(fbl[2*p][0],fbl[2*p][1],fbl[2*p+1][0],fbl[2*p+1][1], adl);
            }
            #pragma unroll
            for (int mf=0; mf<2; mf++)
                #pragma unroll
                for (int nf=0; nf<4; nf++) {
                    MMA16816(acc[mf][nf], fah[mf], fbh[nf][0], fbh[nf][1]);
                    MMA16816(acc[mf][nf], fah[mf], fbl[nf][0], fbl[nf][1]);
                    MMA16816(acc[mf][nf], fal[mf], fbh[nf][0], fbh[nf][1]);
                }
        }
        __syncthreads();
    }
    const size_t pbase = (size_t)(z*KS + blockIdx.y)*128;
    #pragma unroll
    for (int mf=0; mf<2; mf++) {
        int m = wm*32 + mf*16 + (lane>>2);
        #pragma unroll
        for (int nf=0; nf<4; nf++) {
            int n = bn + wn*32 + nf*8 + ((lane&3)<<1);
            *(float2*)&partial[(pbase + m)*Ntot + n]     = make_float2(acc[mf][nf][0], acc[mf][nf][1]);
            *(float2*)&partial[(pbase + m+8)*Ntot + n]   = make_float2(acc[mf][nf][2], acc[mf][nf][3]);
        }
    }
}

// ========== reduce K-split partials (+bias/relu, +bf16 a2, +fp16 ah, +head split)
__global__ void __launch_bounds__(256) reduce_ks(
    const float* __restrict__ partial, const float* __restrict__ bias, int strideBias,
    float* __restrict__ C, int ldc, long long strideC,
    int Mtot, int Ntot, int KS, int relu,
    __nv_bfloat16* __restrict__ a2, int lda2, int loOff, int a2strideZ,
    __half* __restrict__ ah, int ldah, int loOffH,
    __nv_bfloat16* __restrict__ hd, int headK)
{
    const int zb = blockIdx.y;
    int idx = blockIdx.x*256 + threadIdx.x;
    if (idx >= Mtot*Ntot) return;
    int m = idx / Ntot, n = idx % Ntot;
    float s = 0.f;
    for (int c=0;c<KS;c++)
        s += partial[((size_t)(zb*KS+c)*Mtot + m)*Ntot + n];
    if (bias) s += bias[(size_t)zb*strideBias + n];
    if (relu) s = fmaxf(s, 0.f);
    C[(size_t)zb*strideC + (size_t)m*ldc + n] = s;
    if (a2) {
        __nv_bfloat16 h,l; split_bf16(s,h,l);
        size_t base = (size_t)zb*a2strideZ + (size_t)m*lda2 + n;
        a2[base] = h;
        a2[base + loOff] = l;
    }
    if (ah) {
        __half h,l; split_f16(s,h,l);
        size_t base = (size_t)m*ldah + n;
        ah[base] = h;
        ah[base + loOffH] = l;
    }
    if (hd) {
        __nv_bfloat16 h,l; split_bf16(s,h,l);
        int head = n / headK, id2 = n - head*headK;
        size_t base = (size_t)m*(NH_*2*headK) + (size_t)head*(2*headK) + id2;
        hd[base] = h;
        hd[base + headK] = l;
    }
}

// =================== fused reduce + residual + LayerNorm (+a2) ==================
__global__ void __launch_bounds__(256) reduce_ln(
    const float* __restrict__ partial, const float* __restrict__ bias,
    const float* __restrict__ resid,
    const float* __restrict__ w, const float* __restrict__ bb,
    float* __restrict__ out, __nv_bfloat16* __restrict__ a2, int KS)
{
    const int row = blockIdx.x, tid = threadIdx.x;
    float vals[6]; float s1=0.f, s2=0.f;
    #pragma unroll
    for (int i=0;i<6;i++) {
        int e = tid + i*256;
        float s = bias ? bias[e] : 0.f;
        for (int c=0;c<KS;c++)
            s += partial[((size_t)c*128 + row)*D_ + e];
        if (resid) s += resid[(size_t)row*D_ + e];
        vals[i]=s; s1+=s; s2+=s*s;
    }
    __shared__ float red[16];
    int lane=tid&31, wid=tid>>5;
    for (int o=16;o;o>>=1){ s1+=__shfl_xor_sync(~0u,s1,o); s2+=__shfl_xor_sync(~0u,s2,o); }
    if (lane==0){ red[wid]=s1; red[8+wid]=s2; }
    __syncthreads();
    if (tid==0){ float a1=0,a2s=0; for(int k=0;k<8;k++){a1+=red[k];a2s+=red[8+k];} red[0]=a1; red[8]=a2s; }
    __syncthreads();
    float mean = red[0]*(1.0f/D_);
    float var  = red[8]*(1.0f/D_) - mean*mean;
    float rstd = rsqrtf(var + 1e-5f);
    #pragma unroll
    for (int i=0;i<6;i++) {
        int e = tid + i*256;
        float y = (vals[i]-mean)*rstd*w[e] + bb[e];
        out[(size_t)row*D_+e] = y;
        if (a2) {
            __nv_bfloat16 h,l; split_bf16(y,h,l);
            a2[(size_t)row*2*D_ + e]      = h;
            a2[(size_t)row*2*D_ + D_ + e] = l;
        }
    }
}

// =================== conversions =================================================
__global__ void __launch_bounds__(256) conv_mem_kernel(const float* __restrict__ mem)
{
    const int row = blockIdx.x*8 + (threadIdx.x>>5);
    const int lane = threadIdx.x&31;
    const float* p = mem + (size_t)row*D_;
    __half* oh = g_mb + (size_t)row*D_;
    float ss = 0.f;
    #pragma unroll
    for (int i=0;i<12;i++) {
        int e = lane*4 + i*128;
        float4 v = *(const float4*)(p+e);
        ss += v.x*v.x + v.y*v.y + v.z*v.z + v.w*v.w;
        __align__(8) __half h[4];
        h[0]=__float2half(v.x); h[1]=__float2half(v.y);
        h[2]=__float2half(v.z); h[3]=__float2half(v.w);
        *(uint64_t*)(oh + e) = *(uint64_t*)h;
    }
    for (int o=16;o;o>>=1) ss += __shfl_xor_sync(~0u, ss, o);
    if (lane==0) g_nm[row] = sqrtf(ss);
}

struct ConvJob { const float* src; __nv_bfloat16* dst; int K; int rows; };
struct ConvJobs { ConvJob j[9]; };

__global__ void __launch_bounds__(256) conv_w_all(ConvJobs jobs)
{
    const ConvJob jb = jobs.j[blockIdx.y];
    const int row = blockIdx.x*8 + (threadIdx.x>>5);
    if (row >= jb.rows) return;
    const int lane = threadIdx.x&31;
    const int K = jb.K;
    const float* p = jb.src + (size_t)row*K;
    __nv_bfloat16* o = jb.dst + (size_t)row*2*K;
    for (int e=lane*4; e<K; e+=128) {
        float4 v = *(const float4*)(p+e);
        __align__(8) __nv_bfloat16 h[4], l[4];
        float f[4] = {v.x,v.y,v.z,v.w};
        #pragma unroll
        for (int c=0;c<4;c++) split_bf16(f[c], h[c], l[c]);
        *(uint64_t*)(o + e)     = *(uint64_t*)h;
        *(uint64_t*)(o + K + e) = *(uint64_t*)l;
    }
}

// Wk (rows r = h*192+., cols e) -> g_wkt[h][e][hi192|lo192] via smem transpose.
__global__ void __launch_bounds__(256) conv_wkt(const float* __restrict__ wk)
{
    __shared__ float tile[32][33];
    const int h = blockIdx.z;
    const int e0 = blockIdx.x*32, r0 = blockIdx.y*32;
    const int tx = threadIdx.x & 31, ty = threadIdx.x >> 5;  // 32 x 8
    #pragma unroll
    for (int i=0;i<4;i++) {
        int r = r0 + ty + 8*i;
        tile[ty+8*i][tx] = wk[(size_t)(h*DH_ + r)*D_ + e0 + tx];
    }
    __syncthreads();
    __nv_bfloat16* dst = g_wkt + (size_t)h*D_*2*DH_;
    #pragma unroll
    for (int i=0;i<4;i++) {
        int e = e0 + ty + 8*i;
        float v = tile[tx][ty+8*i];
        __nv_bfloat16 hh,ll; split_bf16(v,hh,ll);
        dst[(size_t)e*2*DH_ + r0 + tx]        = hh;
        dst[(size_t)e*2*DH_ + DH_ + r0 + tx]  = ll;
    }
}

// Wk2 (rows q, cols n; 1536x1536) -> g_wk2t[n][hi1536(q)|lo1536(q)]
__global__ void __launch_bounds__(256) conv_wt2(const float* __restrict__ w)
{
    __shared__ float tile[32][33];
    const int n0 = blockIdx.x*32, q0 = blockIdx.y*32;
    const int tx = threadIdx.x & 31, ty = threadIdx.x >> 5;  // 32 x 8
    #pragma unroll
    for (int i=0;i<4;i++) {
        int q = q0 + ty + 8*i;
        tile[ty+8*i][tx] = w[(size_t)q*D_ + n0 + tx];
    }
    __syncthreads();
    #pragma unroll
    for (int i=0;i<4;i++) {
        int n = n0 + ty + 8*i;
        int q = q0 + tx;
        float v = tile[tx][ty+8*i];
        __nv_bfloat16 hh,ll; split_bf16(v,hh,ll);
        g_wk2t[(size_t)n*2*D_ + q]       = hh;
        g_wk2t[(size_t)n*2*D_ + D_ + q]  = ll;
    }
}

__global__ void __launch_bounds__(256) conv_x_kernel(const float* __restrict__ x)
{
    const int row = blockIdx.x*8 + (threadIdx.x>>5);
    const int lane = threadIdx.x&31;
    const float* p = x + (size_t)row*DIN_;
    __nv_bfloat16* o = g_a2 + (size_t)row*2*DIN_;
    #pragma unroll
    for (int i=0;i<6;i++) {
        int e = lane*4 + i*128;
        float4 v = *(const float4*)(p+e);
        __align__(8) __nv_bfloat16 h[4], l[4];
        float f[4] = {v.x,v.y,v.z,v.w};
        #pragma unroll
        for (int c=0;c<4;c++) split_bf16(f[c], h[c], l[c]);
        *(uint64_t*)(o + e)        = *(uint64_t*)h;
        *(uint64_t*)(o + DIN_ + e) = *(uint64_t*)l;
    }
}

// ===== bigmm_half1: fp16 SINGLE-product pooling GEMM (both halves) ===============
#define HSLD 40
#define HCHUNK 48          // 1536 / 32

__global__ void __launch_bounds__(256) bigmm_half1(int aBase, int outBase)
{
    extern __shared__ __half hsm1[];
    __half* sAh = hsm1;                      // [2][128*HSLD]
    __half* sB  = sAh + 2*128*HSLD;
    const int tid = threadIdx.x;
    const int warp = tid>>5, lane = tid&31;
    const int wm = warp>>2, wn = warp&3;
    const int nbase = blockIdx.x*128;

    float acc[4][4][4];
    #pragma unroll
    for (int i=0;i<4;i++)
        #pragma unroll
        for (int j=0;j<4;j++)
            #pragma unroll
            for (int c=0;c<4;c++) acc[i][j][c]=0.f;

    const int r0 = tid>>1;
    const int seg0 = (tid&1)*2;

    #define BH1_LOAD(BUF,KC) do {                                              \
        int k0_ = (KC)*32;                                                      \
        _Pragma("unroll")                                                       \
        for (int i=0;i<2;i++) {                                                 \
            int seg = seg0 + i;                                                 \
            CPA16(&sAh[(BUF)*128*HSLD + r0*HSLD + seg*8],                       \
                  g_abh + (size_t)(aBase+r0)*2*D_ + k0_ + seg*8);               \
            CPA16(&sB [(BUF)*128*HSLD + r0*HSLD + seg*8],                       \
                  g_mb + (size_t)(nbase+r0)*D_ + k0_ + seg*8);                  \
        }                                                                       \
        asm volatile("cp.async.commit_group;");                                 \
    } while(0)

    BH1_LOAD(0, 0);
    for (int kc=0; kc<HCHUNK; kc++) {
        int buf = kc & 1;
        asm volatile("cp.async.wait_group 0;");
        __syncthreads();
        if (kc+1 < HCHUNK) BH1_LOAD(buf^1, kc+1);
        __half* ah = sAh + buf*128*HSLD;
        __half* bt = sB  + buf*128*HSLD;
        #pragma unroll
        for (int kk=0; kk<2; kk++) {
            const int kb = kk*16;
            uint32_t fah[4][4], b[4][2];
            #pragma unroll
            for (int mf=0; mf<4; mf++) {
                int row = wm*64 + mf*16 + (lane&15);
                int ko  = kb + ((lane>>4)<<3);
                uint32_t adh = (uint32_t)__cvta_generic_to_shared(&ah[row*HSLD + ko]);
                LDSM4(fah[mf][0],fah[mf][1],fah[mf][2],fah[mf][3], adh);
            }
            #pragma unroll
            for (int p=0; p<2; p++) {
                int nrow = wn*32 + p*16 + ((lane>>4)<<3) + (lane&7);
                int ko   = kb + (((lane>>3)&1)<<3);
                uint32_t ad = (uint32_t)__cvta_generic_to_shared(&bt[nrow*HSLD + ko]);
                LDSM4(b[2*p][0],b[2*p][1],b[2*p+1][0],b[2*p+1][1], ad);
            }
            #pragma unroll
            for (int mf=0; mf<4; mf++)
                #pragma unroll
                for (int nf=0; nf<4; nf++)
                    MMAF16(acc[mf][nf], fah[mf], b[nf][0], b[nf][1]);
        }
        __syncthreads();
    }
    #pragma unroll
    for (int mf=0; mf<4; mf++) {
        int m = outBase + wm*64 + mf*16 + (lane>>2);
        #pragma unroll
        for (int nf=0; nf<4; nf++) {
            int n = nbase + wn*32 + nf*8 + ((lane&3)<<1);
            *(float2*)&g_S[(size_t)m*BS_ + n]     = make_float2(acc[mf][nf][0], acc[mf][nf][1]);
            *(float2*)&g_S[(size_t)(m+8)*BS_ + n] = make_float2(acc[mf][nf][2], acc[mf][nf][3]);
        }
    }
}
#define SMEM_BH1 (2*2*128*HSLD*2)   // 40960 bytes

// =================== LayerNorm (fin; +fp16 abh out, +copy out) ==================
__global__ void __launch_bounds__(256) ln_kernel(
    const float* __restrict__ a, const float* __restrict__ r,
    const float* __restrict__ w, const float* __restrict__ bb,
    float* __restrict__ out, float* __restrict__ norm_out,
    __nv_bfloat16* __restrict__ a2, __half* __restrict__ abh,
    float* __restrict__ copyOut)
{
    const int row = blockIdx.x, tid = threadIdx.x;
    const float* ap = a + (size_t)row*D_;
    const float* rp = r ? r + (size_t)row*D_ : nullptr;
    float vals[6]; float s1=0.f, s2=0.f;
    #pragma unroll
    for (int i=0;i<6;i++) {
        int e = tid + i*256;
        float v = ap[e] + (rp ? rp[e] : 0.f);
        vals[i]=v; s1+=v; s2+=v*v;
    }
    __shared__ float red[16];
    int lane=tid&31, wid=tid>>5;
    for (int o=16;o;o>>=1){ s1+=__shfl_xor_sync(~0u,s1,o); s2+=__shfl_xor_sync(~0u,s2,o); }
    if (lane==0){ red[wid]=s1; red[8+wid]=s2; }
    __syncthreads();
    if (tid==0){ float a1=0,a2s=0; for(int k=0;k<8;k++){a1+=red[k];a2s+=red[8+k];} red[0]=a1; red[8]=a2s; }
    __syncthreads();
    float mean = red[0]*(1.0f/D_);
    float var  = red[8]*(1.0f/D_) - mean*mean;
    float rstd = rsqrtf(var + 1e-5f);
    float ss = 0.f;
    #pragma unroll
    for (int i=0;i<6;i++) {
        int e = tid + i*256;
        float y = (vals[i]-mean)*rstd*w[e] + bb[e];
        out[(size_t)row*D_+e] = y;
        if (copyOut) copyOut[(size_t)row*D_+e] = y;
        if (a2) {
            __nv_bfloat16 h,l; split_bf16(y,h,l);
            a2[(size_t)row*2*D_ + e]      = h;
            a2[(size_t)row*2*D_ + D_ + e] = l;
        }
        if (abh) {
            __half h,l; split_f16(y,h,l);
            abh[(size_t)row*2*D_ + e]      = h;
            abh[(size_t)row*2*D_ + D_ + e] = l;
        }
        ss += y*y;
    }
    if (norm_out) {
        for (int o=16;o;o>>=1) ss+=__shfl_xor_sync(~0u,ss,o);
        __syncthreads();
        if (lane==0) red[wid]=ss;
        __syncthreads();
        if (tid==0){ float t=0; for(int k=0;k<8;k++) t+=red[k]; norm_out[row]=sqrtf(t); }
    }
}

// ========= CA scores from fp16 memory copy =======================================
__global__ void __launch_bounds__(256) ca_scores_kernel()
{
    __shared__ float gs[NH_*D_];
    const int b = blockIdx.x, tid = threadIdx.x;
    const float4* gsrc = (const float4*)(g_g + (size_t)b*NH_*D_);
    for (int i=tid;i<NH_*D_/4;i+=256) ((float4*)gs)[i]=gsrc[i];
    __syncthreads();
    const int warp=tid>>5, lane=tid&31;
    const __half* mb = g_mb + (size_t)b*S_*D_;
    const float scale = rsqrtf((float)DH_);
    const int sbase = blockIdx.y*128 + warp*16;
    for (int grp=0;grp<4;grp++) {
        int s0 = sbase + grp*4;
        float acc[NH_][4];
        #pragma unroll
        for (int h=0;h<NH_;h++)
            #pragma unroll
            for (int r2=0;r2<4;r2++) acc[h][r2]=0.f;
        #pragma unroll
        for (int i=0;i<12;i++) {
            int e = lane*4 + i*128;
            float4 m[4];
            #pragma unroll
            for (int r2=0;r2<4;r2++) {
                uint2 raw = *(const uint2*)(mb+(size_t)(s0+r2)*D_+e);
                __half2 p0 = *(__half2*)&raw.x;
                __half2 p1 = *(__half2*)&raw.y;
                float2 f0 = __half22float2(p0);
                float2 f1 = __half22float2(p1);
                m[r2] = make_float4(f0.x, f0.y, f1.x, f1.y);
            }
            #pragma unroll
            for (int h=0;h<NH_;h++) {
                float4 gv=*(const float4*)(gs + h*D_ + e);
                #pragma unroll
                for (int r2=0;r2<4;r2++)
                    acc[h][r2] += gv.x*m[r2].x + gv.y*m[r2].y + gv.z*m[r2].z + gv.w*m[r2].w;
            }
        }
        #pragma unroll
        for (int h=0;h<NH_;h++)
            #pragma unroll
            for (int r2=0;r2<4;r2++) {
                float v=acc[h][r2];
                for (int o=16;o;o>>=1) v+=__shfl_xor_sync(~0u,v,o);
                if (lane==0) g_scores[((size_t)b*NH_+h)*S_ + s0+r2] = v*scale;
            }
    }
}

// ========= mtilde with FUSED softmax (scores raw-scaled in g_scores) =============
__global__ void __launch_bounds__(256) mtilde_kernel()
{
    __shared__ float at[NH_*S_];
    const int b=blockIdx.x, tid=threadIdx.x;
    for (int i=tid;i<NH_*S_;i+=256) at[i]=g_scores[(size_t)b*NH_*S_+i];
    __syncthreads();
    // softmax per head row: warp wz handles h = wz (8 warps, 8 heads)
    {
        const int wz = tid>>5, lane = tid&31;
        float v[8]; float m = -1e30f;
        #pragma unroll
        for (int c=0;c<8;c++){ v[c] = at[wz*S_ + lane + c*32]; m = fmaxf(m, v[c]); }
        for (int o=16;o;o>>=1) m = fmaxf(m, __shfl_xor_sync(~0u,m,o));
        float s = 0.f;
        #pragma unroll
        for (int c=0;c<8;c++){ v[c] = __expf(v[c]-m); s += v[c]; }
        for (int o=16;o;o>>=1) s += __shfl_xor_sync(~0u,s,o);
        float inv = 1.f/s;
        #pragma unroll
        for (int c=0;c<8;c++) at[wz*S_ + lane + c*32] = v[c]*inv;
    }
    __syncthreads();
    const int e = blockIdx.y*512 + tid*2;
    const __half* mb = g_mb + (size_t)b*S_*D_;
    float2 acc[NH_];
    #pragma unroll
    for (int h=0;h<NH_;h++){ acc[h].x=0.f; acc[h].y=0.f; }
    for (int s=0;s<S_;s++) {
        __half2 raw = *(const __half2*)(mb+(size_t)s*D_+e);
        float2 mv = __half22float2(raw);
        #pragma unroll
        for (int h=0;h<NH_;h++){
            float a=at[h*S_+s];
            acc[h].x=fmaf(a,mv.x,acc[h].x);
            acc[h].y=fmaf(a,mv.y,acc[h].y);
        }
    }
    #pragma unroll
    for (int h=0;h<NH_;h++) {
        __nv_bfloat16 hx,lx,hy,ly;
        split_bf16(acc[h].x,hx,lx); split_bf16(acc[h].y,hy,ly);
        size_t base = (size_t)b*NH_*3072 + h*3072;
        g_mt2[base + e]   = hx; g_mt2[base + e+1]   = hy;
        g_mt2[base + D_ + e] = lx; g_mt2[base + D_ + e+1] = ly;
    }
}

// ========= pool reduce: one WARP per (i,j) pair ==================================
__global__ void __launch_bounds__(256) pool_reduce_kernel(
    const float* __restrict__ ls, float* __restrict__ out)
{
    const int wz = threadIdx.x>>5, lane = threadIdx.x&31;
    const int pair = blockIdx.x*8 + wz;           // 0..16383
    const int i = pair >> 7, j = pair & 127;
    const float sc = rsqrtf((float)D_);
    float Sv[8], Wt[8];
    float m = -1e30f;
    #pragma unroll
    for (int c=0;c<8;c++) {
        int s = lane + c*32;
        Sv[c] = g_S[(size_t)i*BS_ + j*S_ + s] * sc;
        float Cv = g_S[(size_t)(B_+i)*BS_ + j*S_ + s];
        Wt[c] = Cv / g_nm[j*S_+s];
        m = fmaxf(m, Sv[c]);
    }
    for (int o=16;o;o>>=1) m = fmaxf(m, __shfl_xor_sync(~0u,m,o));
    float Z=0.f, Wv=0.f;
    #pragma unroll
    for (int c=0;c<8;c++) {
        float e = expf(Sv[c]-m);
        Z += e; Wv += e*Wt[c];
    }
    for (int o=16;o;o>>=1){ Z+=__shfl_xor_sync(~0u,Z,o); Wv+=__shfl_xor_sync(~0u,Wv,o); }
    if (lane==0) {
        float val = expf(ls[0]) * Wv / (Z * g_nx[i]);
        out[(size_t)i*B_ + j] = val;
        out[(size_t)B_*B_ + (size_t)j*B_ + i] = val;
    }
}

// =================== host =======================================================
template<typename T> static float* symf(T& s){ void* p=nullptr; cudaGetSymbolAddress(&p, s); return (float*)p; }
template<typename T> static __nv_bfloat16* symb(T& s){ void* p=nullptr; cudaGetSymbolAddress(&p, s); return (__nv_bfloat16*)p; }
template<typename T> static __half* symh(T& s){ void* p=nullptr; cudaGetSymbolAddress(&p, s); return (__half*)p; }

extern "C" void kernel_launch(void* const* d_in, const int* in_sizes, int n_in,
                              void* d_out, int out_size)
{
    const float* x        =(const float*)d_in[0];
    const float* mem      =(const float*)d_in[1];
    const float* emb_w    =(const float*)d_in[2];
    const float* emb_b    =(const float*)d_in[3];
    const float* sa_in_w  =(const float*)d_in[4];
    const float* sa_in_b  =(const float*)d_in[5];
    const float* sa_out_w =(const float*)d_in[6];
    const float* sa_out_b =(const float*)d_in[7];
    const float* ca_in_w  =(const float*)d_in[8];
    const float* ca_in_b  =(const float*)d_in[9];
    const float* ca_out_w =(const float*)d_in[10];
    const float* ca_out_b =(const float*)d_in[11];
    const float* lin1_w   =(const float*)d_in[12];
    const float* lin1_b   =(const float*)d_in[13];
    const float* lin2_w   =(const float*)d_in[14];
    const float* lin2_b   =(const float*)d_in[15];
    const float* ln1_w    =(const float*)d_in[16];
    const float* ln1_b    =(const float*)d_in[17];
    const float* ln2_w    =(const float*)d_in[18];
    const float* ln2_b    =(const float*)d_in[19];
    const float* ln3_w    =(const float*)d_in[20];
    const float* ln3_b    =(const float*)d_in[21];
    const float* fin_w    =(const float*)d_in[22];
    const float* fin_b    =(const float*)d_in[23];
    const float* attn_in_w=(const float*)d_in[24];
    const float* attn_in_b=(const float*)d_in[25];
    const float* logit_sc =(const float*)d_in[26];
    float* out = (float*)d_out;

    float* t0 = symf(g_t0);  float* v   = symf(g_v);
    float* t1 = symf(g_t1);  float* qp  = symf(g_qp);  float* gg  = symf(g_g);
    float* o   = symf(g_o);
    float* t2 = symf(g_t2);  float* h1  = symf(g_h1);
    float* t3 = symf(g_t3);  float* xsq = symf(g_xsq); float* qp2 = symf(g_qp2);
    float* qt = symf(g_qt);  float* nx  = symf(g_nx);  float* pt  = symf(g_part);
    __nv_bfloat16* a2   = symb(g_a2);
    __nv_bfloat16* mt2  = symb(g_mt2);
    __nv_bfloat16* qph  = symb(g_qph);
    __nv_bfloat16* wkt  = symb(g_wkt);
    __nv_bfloat16* wk2t = symb(g_wk2t);
    __half*        abh  = symh(g_abh);
    __nv_bfloat16* wEmb = symb(g_w_emb);
    __nv_bfloat16* wSaV = symb(g_w_savv);
    __nv_bfloat16* wSaO = symb(g_w_saout);
    __nv_bfloat16* wCaQ = symb(g_w_cawq);
    __nv_bfloat16* wCaV = symb(g_w_cawv);
    __nv_bfloat16* wCaO = symb(g_w_caout);
    __nv_bfloat16* wL1  = symb(g_w_lin1);
    __nv_bfloat16* wL2  = symb(g_w_lin2);
    __nv_bfloat16* wAtQ = symb(g_w_attnq);

    const float* NOB = nullptr;
    __nv_bfloat16* NOA = nullptr;
    __half* NOH = nullptr;

    static cudaStream_t s2 = nullptr;
    static cudaEvent_t evFork = nullptr, evW = nullptr, evWk = nullptr, evMem = nullptr;
    static cudaEvent_t evXsq = nullptr, evSide = nullptr;
    if (!s2) {
        cudaStreamCreateWithFlags(&s2, cudaStreamNonBlocking);
        cudaEventCreateWithFlags(&evFork, cudaEventDisableTiming);
        cudaEventCreateWithFlags(&evW,    cudaEventDisableTiming);
        cudaEventCreateWithFlags(&evWk,   cudaEventDisableTiming);
        cudaEventCreateWithFlags(&evMem,  cudaEventDisableTiming);
        cudaEventCreateWithFlags(&evXsq,  cudaEventDisableTiming);
        cudaEventCreateWithFlags(&evSide, cudaEventDisableTiming);
        cudaFuncSetAttribute(bigmm_half1, cudaFuncAttributeMaxDynamicSharedMemorySize, SMEM_BH1);
        cudaFuncSetAttribute(gemm64_tc2,  cudaFuncAttributeMaxDynamicSharedMemorySize, SMEM_G2);
    }

    // ---- fork: side stream converts weights, Wk^T, Wk2^T, then memory ---------
    cudaEventRecord(evFork, 0);
    cudaStreamWaitEvent(s2, evFork, 0);
    {
        ConvJobs jobs;
        jobs.j[0] = { sa_in_w + (size_t)2*D_*D_, wSaV, D_, 1536 };
        jobs.j[1] = { sa_out_w,                  wSaO, D_, 1536 };
        jobs.j[2] = { ca_in_w,                   wCaQ, D_, 1536 };
        jobs.j[3] = { ca_in_w + (size_t)2*D_*D_, wCaV, D_, 1536 };
        jobs.j[4] = { ca_out_w,                  wCaO, D_, 1536 };
        jobs.j[5] = { lin1_w,                    wL1,  D_, 2048 };
        jobs.j[6] = { lin2_w,                    wL2,  FF_, 1536 };
        jobs.j[7] = { attn_in_w,                 wAtQ, D_, 1536 };
        jobs.j[8] = { emb_w,                     wEmb, DIN_, 1536 };
        conv_w_all<<<dim3(256, 9), 256, 0, s2>>>(jobs);
        cudaEventRecord(evW, s2);
        conv_wkt<<<dim3(D_/32, DH_/32, NH_), 256, 0, s2>>>(ca_in_w + (size_t)D_*D_);
        cudaEventRecord(evWk, s2);
        conv_wt2<<<dim3(D_/32, D_/32), 256, 0, s2>>>(attn_in_w + (size_t)D_*D_);
        conv_mem_kernel<<<BS_/8, 256, 0, s2>>>(mem);
        cudaEventRecord(evMem, s2);
    }

    // ---- main stream: x conversion, wait weights ------------------------------
    conv_x_kernel<<<16, 256>>>(x);
    cudaStreamWaitEvent(0, evW, 0);

    // 1. t0 = x @ emb_w.T + emb_b
    gemm64_tc2<<<dim3(24,12,1), 256, SMEM_G2>>>(a2, 2*DIN_, 0, wEmb, 2*DIN_, 0, pt, DIN_);
    reduce_ks<<<dim3((B_*D_+255)/256,1),256>>>(pt, emb_b, 0, t0, D_, 0, 128, 1536, 12, 0,
                                               a2, 2*D_, D_, 0, NOH, 0, 0, NOA, 0);
    // 2. SA (L=1)
    gemm64_tc2<<<dim3(24,12,1), 256, SMEM_G2>>>(a2, 2*D_, 0, wSaV, 2*D_, 0, pt, D_);
    reduce_ks<<<dim3((B_*D_+255)/256,1),256>>>(pt, sa_in_b+2*D_, 0, v, D_, 0, 128, 1536, 12, 0,
                                               a2, 2*D_, D_, 0, NOH, 0, 0, NOA, 0);
    gemm64_tc2<<<dim3(24,12,1), 256, SMEM_G2>>>(a2, 2*D_, 0, wSaO, 2*D_, 0, pt, D_);
    // 3. t1 = LN(t0 + sa)
    reduce_ln<<<B_, 256>>>(pt, sa_out_b, t0, ln1_w, ln1_b, t1, a2, 12);
    // 4. CA q-proj (emit per-head split qph), then gg = batched tensor GEMM
    gemm64_tc2<<<dim3(24,12,1), 256, SMEM_G2>>>(a2, 2*D_, 0, wCaQ, 2*D_, 0, pt, D_);
    reduce_ks<<<dim3((B_*D_+255)/256,1),256>>>(pt, ca_in_b, 0, qp, D_, 0, 128, 1536, 12, 0,
                                               NOA, 0, 0, 0, NOH, 0, 0, qph, DH_);
    cudaStreamWaitEvent(0, evWk, 0);
    gemm64_tc2<<<dim3(24,2,NH_), 256, SMEM_G2>>>(qph, NH_*2*DH_, 2*DH_,
                                                 wkt, 2*DH_, (long long)D_*2*DH_, pt, DH_);
    reduce_ks<<<dim3((B_*D_+255)/256,NH_),256>>>(pt, NOB, 0, gg, NH_*D_, D_, 128, 1536, 2, 0,
                                                 NOA, 0, 0, 0, NOH, 0, 0, NOA, 0);
    // 5. CA scores (raw, scaled) / fused softmax+mtilde (fp16 g_mb)
    cudaStreamWaitEvent(0, evMem, 0);
    ca_scores_kernel<<<dim3(B_,2), 256>>>();
    mtilde_kernel<<<dim3(B_,3), 256>>>();
    // 6. o_h ; ca -> fused LN2
    gemm64_tc2<<<dim3(3,12,NH_), 256, SMEM_G2>>>(mt2, NH_*3072, 3072, wCaV, 2*D_, (long long)DH_*2*D_, pt, D_);
    reduce_ks<<<dim3((128*DH_+255)/256,NH_),256>>>(pt, ca_in_b+2*D_, DH_, o, D_, DH_, 128, DH_, 12, 0,
                                                   a2, 2*D_, D_, DH_, NOH, 0, 0, NOA, 0);
    gemm64_tc2<<<dim3(24,12,1), 256, SMEM_G2>>>(a2, 2*D_, 0, wCaO, 2*D_, 0, pt, D_);
    reduce_ln<<<B_, 256>>>(pt, ca_out_b, t1, ln2_w, ln2_b, t2, a2, 12);
    // 8. FF: lin1 KS=12 ; lin2 K=2048 -> KS=16
    gemm64_tc2<<<dim3(32,12,1), 256, SMEM_G2>>>(a2, 2*D_, 0, wL1, 2*D_, 0, pt, D_);
    reduce_ks<<<dim3((B_*FF_+255)/256,1),256>>>(pt, lin1_b, 0, h1, FF_, 0, 128, 2048, 12, 1,
                                                a2, 2*FF_, FF_, 0, NOH, 0, 0, NOA, 0);
    gemm64_tc2<<<dim3(24,16,1), 256, SMEM_G2>>>(a2, 2*FF_, 0, wL2, 2*FF_, 0, pt, FF_);
    // 9. t3 = LN(t2 + ff) [KS=16] ; x_sq = LN(t3) (+a2, +abh rows 128.., +copy out2)
    reduce_ln<<<B_, 256>>>(pt, lin2_b, t2, ln3_w, ln3_b, t3, NOA, 16);
    ln_kernel<<<B_, 256>>>(t3, nullptr, fin_w, fin_b, xsq, nx, a2,
                           abh + (size_t)128*2*D_, out + (size_t)2*B_*B_);
    cudaEventRecord(evXsq, 0);

    // ---- side stream: qt projection branch (all tensor; overlaps cosine bigmm) -
    cudaStreamWaitEvent(s2, evXsq, 0);
    gemm64_tc2<<<dim3(24,12,1), 256, SMEM_G2, s2>>>(a2, 2*D_, 0, wAtQ, 2*D_, 0, pt, D_);
    reduce_ks<<<dim3((B_*D_+255)/256,1),256,0,s2>>>(pt, attn_in_b, 0, qp2, D_, 0, 128, 1536, 12, 0,
                                                    qph, 2*D_, D_, 0, NOH, 0, 0, NOA, 0);
    gemm64_tc2<<<dim3(24,12,1), 256, SMEM_G2, s2>>>(qph, 2*D_, 0, wk2t, 2*D_, 0, pt, D_);
    reduce_ks<<<dim3((B_*D_+255)/256,1),256,0,s2>>>(pt, NOB, 0, qt, D_, 0, 128, 1536, 12, 0,
                                                    NOA, 0, 0, 0, abh, 2*D_, D_, NOA, 0);
    cudaEventRecord(evSide, s2);

    // ---- main stream: cosine bigmm (1-product), then scores bigmm (1-product) --
    bigmm_half1<<<BS_/128, 256, SMEM_BH1>>>(128, 128);  // cosine: xsq rows
    cudaStreamWaitEvent(0, evSide, 0);
    bigmm_half1<<<BS_/128, 256, SMEM_BH1>>>(0, 0);      // scores: qt rows

    // 12. final softmax-weighted cosine reduce (warp per pair)
    pool_reduce_kernel<<<2048, 256>>>(logit_sc, out);

    (void)in_sizes; (void)n_in; (void)out_size;
}